// round 4
// baseline (speedup 1.0000x reference)
#include <cuda_runtime.h>
#include <math.h>

// ---------------- problem constants ----------------
#define BQ    2
#define TT    8
#define CDIM  192
#define NSP   576          // H*W
#define TOK   9216         // B*T*N
#define DI    384          // d_inner
#define DS    16           // d_state
#define DTR   12
#define MLPH  768
#define XZW   1536         // merged in_proj width (s:768 | t:768)

// ---------------- scratch (device globals; allocation-free) ----------------
__device__ float g_xn[TOK*CDIM];          // layernormed x
__device__ float g_short[TOK*CDIM];       // shortcut (token order)
__device__ float g_xz[TOK*XZW];           // merged in_proj out, token order
__device__ float g_u[2][TOK*DI];          // conv+silu output (token order)
__device__ float g_delta[2][TOK*DI];
__device__ float g_dbc[2][TOK*64];        // x_proj output, padded to 64 (dt:0-11, B:12-27, C:28-43)
__device__ float g_y[TOK*2*DI];           // merged gated scan outputs (token order)
__device__ float g_x2[TOK*CDIM];          // after fusion residual
__device__ float g_h[TOK*CDIM];           // ln2 output
__device__ float g_hid[TOK*MLPH];         // mlp hidden
__device__ float g_Win[XZW*CDIM];         // concat [s_in_proj; t_in_proj]
__device__ float g_W12[CDIM*2*DI];        // folded fusion @ out_proj (concat)
__device__ float g_xpwP[2][64*DI];        // x_proj weights padded to 64 rows
__device__ float g_A[2][DI*DS];           // -exp(A_log)
__device__ float g_cwT[2][4*DI];          // conv weights transposed [k][d]
__device__ float g_dpwT[2][DTR*DI];       // dt_proj transposed [rr][d]

// ---------------- prep ----------------
__global__ void prep_kernel(const float* __restrict__ sAlog, const float* __restrict__ tAlog,
                            const float* __restrict__ fw,
                            const float* __restrict__ soutw, const float* __restrict__ toutw,
                            const float* __restrict__ scw, const float* __restrict__ tcw,
                            const float* __restrict__ sdpw, const float* __restrict__ tdpw,
                            const float* __restrict__ sinw, const float* __restrict__ tinw,
                            const float* __restrict__ sxpw, const float* __restrict__ txpw)
{
    int i = blockIdx.x * blockDim.x + threadIdx.x;
    if (i < 2*DI*DS) {
        int m = i / (DI*DS), j = i % (DI*DS);
        g_A[m][j] = -expf(m ? tAlog[j] : sAlog[j]);
    }
    if (i < 2*4*DI) {
        int m = i / (4*DI), rem = i % (4*DI);
        int k = rem / DI, d = rem % DI;
        g_cwT[m][k*DI + d] = (m ? tcw : scw)[d*4 + k];
    }
    if (i < 2*DTR*DI) {
        int m = i / (DTR*DI), rem = i % (DTR*DI);
        int rr = rem / DI, d = rem % DI;
        g_dpwT[m][rr*DI + d] = (m ? tdpw : sdpw)[d*DTR + rr];
    }
    if (i < 2*64*DI) {    // padded x_proj weights
        int m = i / (64*DI), rem = i % (64*DI);
        int row = rem / DI, col = rem % DI;
        g_xpwP[m][rem] = (row < DTR + 2*DS) ? (m ? txpw : sxpw)[row*DI + col] : 0.f;
    }
    if (i < XZW*CDIM) {   // concat in_proj weights
        int row = i / CDIM;
        g_Win[i] = (row < 768) ? sinw[i] : tinw[i - 768*CDIM];
    }
    if (i < CDIM*2*DI) {  // fold out_proj into fusion
        int c = i / (2*DI), q = i % (2*DI);
        int m = q / DI, j = q % DI;
        const float* ow = m ? toutw : soutw;
        const float* fr = fw + c*(2*CDIM) + m*CDIM;
        float acc = 0.f;
        #pragma unroll 4
        for (int cp = 0; cp < CDIM; cp++)
            acc = fmaf(fr[cp], ow[cp*DI + j], acc);
        g_W12[i] = acc;
    }
}

// ---------------- LN1 with tiled transpose (src is [BT, C, N]) ----------------
__global__ __launch_bounds__(256) void ln1_kernel(const float* __restrict__ src,
                                                  const float* __restrict__ w, const float* __restrict__ b)
{
    __shared__ float s[CDIM][33];
    int bt = blockIdx.x;
    int n0 = blockIdx.y * 32;
    int tid = threadIdx.x;
    #pragma unroll
    for (int i = 0; i < 24; i++) {
        int idx = tid + 256*i;
        int c = idx >> 5, nl = idx & 31;
        s[c][nl] = src[((size_t)bt*CDIM + c)*NSP + n0 + nl];
    }
    __syncthreads();
    int warp = tid >> 5, lane = tid & 31;
    for (int jj = 0; jj < 4; jj++) {
        int tt = warp + 8*jj;
        float v[6];
        #pragma unroll
        for (int j = 0; j < 6; j++) v[j] = s[lane + 32*j][tt];
        float sum = 0.f;
        #pragma unroll
        for (int j = 0; j < 6; j++) sum += v[j];
        #pragma unroll
        for (int o = 16; o > 0; o >>= 1) sum += __shfl_xor_sync(0xffffffffu, sum, o);
        float mean = sum * (1.f/CDIM);
        float q = 0.f;
        #pragma unroll
        for (int j = 0; j < 6; j++) { float d = v[j]-mean; q += d*d; }
        #pragma unroll
        for (int o = 16; o > 0; o >>= 1) q += __shfl_xor_sync(0xffffffffu, q, o);
        float rstd = rsqrtf(q * (1.f/CDIM) + 1e-5f);
        size_t tok = (size_t)bt*NSP + n0 + tt;
        #pragma unroll
        for (int j = 0; j < 6; j++) {
            int c = lane + 32*j;
            g_xn[tok*CDIM + c] = (v[j]-mean)*rstd*w[c] + b[c];
            g_short[tok*CDIM + c] = v[j];
        }
    }
}

// ---------------- LN2 (contiguous, warp per token) ----------------
__global__ void ln2_kernel(const float* __restrict__ src, float* __restrict__ dst,
                           const float* __restrict__ w, const float* __restrict__ b)
{
    int tok  = blockIdx.x * 4 + (threadIdx.x >> 5);
    int lane = threadIdx.x & 31;
    const float* base = src + (size_t)tok * CDIM;
    float v[6];
    #pragma unroll
    for (int j = 0; j < 6; j++) v[j] = base[lane + 32*j];
    float s = 0.f;
    #pragma unroll
    for (int j = 0; j < 6; j++) s += v[j];
    #pragma unroll
    for (int o = 16; o > 0; o >>= 1) s += __shfl_xor_sync(0xffffffffu, s, o);
    float mean = s * (1.f / CDIM);
    float q = 0.f;
    #pragma unroll
    for (int j = 0; j < 6; j++) { float d = v[j] - mean; q += d * d; }
    #pragma unroll
    for (int o = 16; o > 0; o >>= 1) q += __shfl_xor_sync(0xffffffffu, q, o);
    float rstd = rsqrtf(q * (1.f / CDIM) + 1e-5f);
    #pragma unroll
    for (int j = 0; j < 6; j++) {
        int c = lane + 32*j;
        dst[(size_t)tok * CDIM + c] = (v[j] - mean) * rstd * w[c] + b[c];
    }
}

// ---------------- gemm128: 128x128 tile, Ktile=32, 8x8 micro, double-buffered ----------
// C[M,N] = act(A @ B^T + bias); flags bit0: gelu
__global__ __launch_bounds__(256) void gemm128_kernel(
    const float* __restrict__ A, const float* __restrict__ B, float* __restrict__ C,
    const float* __restrict__ bias, int M, int N, int K, int flags)
{
    __shared__ float As[2][32][132];
    __shared__ float Bs[2][32][132];
    int tid = threadIdx.x;
    int m0 = blockIdx.y * 128, n0 = blockIdx.x * 128;

    int rowL = tid >> 2;               // 0..63 (loads rows rowL and rowL+64)
    int kL   = (tid & 3) * 8;          // 0,8,16,24
    const float* Arow0 = A + (size_t)(m0 + rowL)      * K + kL;
    const float* Arow1 = A + (size_t)(m0 + rowL + 64) * K + kL;
    const float* Brow0 = B + (size_t)(n0 + rowL)      * K + kL;
    const float* Brow1 = B + (size_t)(n0 + rowL + 64) * K + kL;

    int ty = tid >> 4, tx = tid & 15;
    float acc[8][8];
    #pragma unroll
    for (int i = 0; i < 8; i++)
        #pragma unroll
        for (int j = 0; j < 8; j++) acc[i][j] = 0.f;

    // preload tile 0
    {
        float4 a0 = *reinterpret_cast<const float4*>(Arow0);
        float4 a1 = *reinterpret_cast<const float4*>(Arow0 + 4);
        float4 a2 = *reinterpret_cast<const float4*>(Arow1);
        float4 a3 = *reinterpret_cast<const float4*>(Arow1 + 4);
        float4 b0 = *reinterpret_cast<const float4*>(Brow0);
        float4 b1 = *reinterpret_cast<const float4*>(Brow0 + 4);
        float4 b2 = *reinterpret_cast<const float4*>(Brow1);
        float4 b3 = *reinterpret_cast<const float4*>(Brow1 + 4);
        float av[8] = {a0.x,a0.y,a0.z,a0.w,a1.x,a1.y,a1.z,a1.w};
        float aw[8] = {a2.x,a2.y,a2.z,a2.w,a3.x,a3.y,a3.z,a3.w};
        float bv[8] = {b0.x,b0.y,b0.z,b0.w,b1.x,b1.y,b1.z,b1.w};
        float bw[8] = {b2.x,b2.y,b2.z,b2.w,b3.x,b3.y,b3.z,b3.w};
        #pragma unroll
        for (int j = 0; j < 8; j++) {
            As[0][kL+j][rowL]    = av[j];
            As[0][kL+j][rowL+64] = aw[j];
            Bs[0][kL+j][rowL]    = bv[j];
            Bs[0][kL+j][rowL+64] = bw[j];
        }
    }
    __syncthreads();

    int p = 0;
    for (int kt = 0; kt < K; kt += 32) {
        float av[8], aw[8], bv[8], bw[8];
        bool more = (kt + 32) < K;
        if (more) {
            float4 a0 = *reinterpret_cast<const float4*>(Arow0 + kt + 32);
            float4 a1 = *reinterpret_cast<const float4*>(Arow0 + kt + 36);
            float4 a2 = *reinterpret_cast<const float4*>(Arow1 + kt + 32);
            float4 a3 = *reinterpret_cast<const float4*>(Arow1 + kt + 36);
            float4 b0 = *reinterpret_cast<const float4*>(Brow0 + kt + 32);
            float4 b1 = *reinterpret_cast<const float4*>(Brow0 + kt + 36);
            float4 b2 = *reinterpret_cast<const float4*>(Brow1 + kt + 32);
            float4 b3 = *reinterpret_cast<const float4*>(Brow1 + kt + 36);
            av[0]=a0.x;av[1]=a0.y;av[2]=a0.z;av[3]=a0.w;av[4]=a1.x;av[5]=a1.y;av[6]=a1.z;av[7]=a1.w;
            aw[0]=a2.x;aw[1]=a2.y;aw[2]=a2.z;aw[3]=a2.w;aw[4]=a3.x;aw[5]=a3.y;aw[6]=a3.z;aw[7]=a3.w;
            bv[0]=b0.x;bv[1]=b0.y;bv[2]=b0.z;bv[3]=b0.w;bv[4]=b1.x;bv[5]=b1.y;bv[6]=b1.z;bv[7]=b1.w;
            bw[0]=b2.x;bw[1]=b2.y;bw[2]=b2.z;bw[3]=b2.w;bw[4]=b3.x;bw[5]=b3.y;bw[6]=b3.z;bw[7]=b3.w;
        }
        #pragma unroll
        for (int kk = 0; kk < 32; kk++) {
            float4 x0 = *reinterpret_cast<const float4*>(&As[p][kk][ty*8]);
            float4 x1 = *reinterpret_cast<const float4*>(&As[p][kk][ty*8+4]);
            float4 y0 = *reinterpret_cast<const float4*>(&Bs[p][kk][tx*8]);
            float4 y1 = *reinterpret_cast<const float4*>(&Bs[p][kk][tx*8+4]);
            float aa[8] = {x0.x,x0.y,x0.z,x0.w,x1.x,x1.y,x1.z,x1.w};
            float bb[8] = {y0.x,y0.y,y0.z,y0.w,y1.x,y1.y,y1.z,y1.w};
            #pragma unroll
            for (int i = 0; i < 8; i++)
                #pragma unroll
                for (int j = 0; j < 8; j++) acc[i][j] = fmaf(aa[i], bb[j], acc[i][j]);
        }
        if (more) {
            int q = p ^ 1;
            #pragma unroll
            for (int j = 0; j < 8; j++) {
                As[q][kL+j][rowL]    = av[j];
                As[q][kL+j][rowL+64] = aw[j];
                Bs[q][kL+j][rowL]    = bv[j];
                Bs[q][kL+j][rowL+64] = bw[j];
            }
        }
        __syncthreads();
        p ^= 1;
    }

    float bb8[8] = {0,0,0,0,0,0,0,0};
    if (bias) {
        float4 t0 = *reinterpret_cast<const float4*>(&bias[n0 + tx*8]);
        float4 t1 = *reinterpret_cast<const float4*>(&bias[n0 + tx*8 + 4]);
        bb8[0]=t0.x;bb8[1]=t0.y;bb8[2]=t0.z;bb8[3]=t0.w;bb8[4]=t1.x;bb8[5]=t1.y;bb8[6]=t1.z;bb8[7]=t1.w;
    }
    #pragma unroll
    for (int i = 0; i < 8; i++) {
        int mm = m0 + ty*8 + i;
        size_t off = (size_t)mm * N + n0 + tx*8;
        float v[8];
        #pragma unroll
        for (int j = 0; j < 8; j++) v[j] = acc[i][j] + bb8[j];
        if (flags & 1) {
            #pragma unroll
            for (int j = 0; j < 8; j++)
                v[j] = 0.5f * v[j] * (1.f + erff(v[j] * 0.70710678118654752f));
        }
        *reinterpret_cast<float4*>(&C[off])   = make_float4(v[0],v[1],v[2],v[3]);
        *reinterpret_cast<float4*>(&C[off+4]) = make_float4(v[4],v[5],v[6],v[7]);
    }
}

// ---------------- gemm64: 128x64 tile, Ktile=16, 8x4 micro, double-buffered -------------
// flags bit0: gelu; bit2: transposed store to [bt, c, n]
__global__ __launch_bounds__(256) void gemm64_kernel(
    const float* __restrict__ A, const float* __restrict__ B, float* __restrict__ C,
    const float* __restrict__ bias, const float* __restrict__ addend,
    int M, int N, int K, int flags)
{
    __shared__ float As[2][16][132];
    __shared__ float Bs[2][16][68];
    int tid = threadIdx.x;
    int m0 = blockIdx.y * 128, n0 = blockIdx.x * 64;

    int rowA = tid >> 2;
    int kA   = (tid & 3) * 4;
    const float* Arow0 = A + (size_t)(m0 + rowA)      * K + kA;
    const float* Arow1 = A + (size_t)(m0 + rowA + 64) * K + kA;
    const float* Brow  = B + (size_t)(n0 + rowA)      * K + kA;

    int ty = tid >> 4, tx = tid & 15;
    float acc[8][4];
    #pragma unroll
    for (int i = 0; i < 8; i++)
        #pragma unroll
        for (int j = 0; j < 4; j++) acc[i][j] = 0.f;

    {
        float4 a0 = *reinterpret_cast<const float4*>(Arow0);
        float4 a1 = *reinterpret_cast<const float4*>(Arow1);
        float4 b0 = *reinterpret_cast<const float4*>(Brow);
        As[0][kA+0][rowA] = a0.x; As[0][kA+1][rowA] = a0.y; As[0][kA+2][rowA] = a0.z; As[0][kA+3][rowA] = a0.w;
        As[0][kA+0][rowA+64] = a1.x; As[0][kA+1][rowA+64] = a1.y; As[0][kA+2][rowA+64] = a1.z; As[0][kA+3][rowA+64] = a1.w;
        Bs[0][kA+0][rowA] = b0.x; Bs[0][kA+1][rowA] = b0.y; Bs[0][kA+2][rowA] = b0.z; Bs[0][kA+3][rowA] = b0.w;
    }
    __syncthreads();

    int p = 0;
    for (int kt = 0; kt < K; kt += 16) {
        float4 na0, na1, nb0;
        bool more = (kt + 16) < K;
        if (more) {
            na0 = *reinterpret_cast<const float4*>(Arow0 + kt + 16);
            na1 = *reinterpret_cast<const float4*>(Arow1 + kt + 16);
            nb0 = *reinterpret_cast<const float4*>(Brow  + kt + 16);
        }
        #pragma unroll
        for (int kk = 0; kk < 16; kk++) {
            float4 av0 = *reinterpret_cast<const float4*>(&As[p][kk][ty*8]);
            float4 av1 = *reinterpret_cast<const float4*>(&As[p][kk][ty*8+4]);
            float4 bv  = *reinterpret_cast<const float4*>(&Bs[p][kk][tx*4]);
            float aa[8] = {av0.x,av0.y,av0.z,av0.w,av1.x,av1.y,av1.z,av1.w};
            float bb[4] = {bv.x,bv.y,bv.z,bv.w};
            #pragma unroll
            for (int i = 0; i < 8; i++)
                #pragma unroll
                for (int j = 0; j < 4; j++) acc[i][j] = fmaf(aa[i], bb[j], acc[i][j]);
        }
        if (more) {
            int q = p ^ 1;
            As[q][kA+0][rowA] = na0.x; As[q][kA+1][rowA] = na0.y; As[q][kA+2][rowA] = na0.z; As[q][kA+3][rowA] = na0.w;
            As[q][kA+0][rowA+64] = na1.x; As[q][kA+1][rowA+64] = na1.y; As[q][kA+2][rowA+64] = na1.z; As[q][kA+3][rowA+64] = na1.w;
            Bs[q][kA+0][rowA] = nb0.x; Bs[q][kA+1][rowA] = nb0.y; Bs[q][kA+2][rowA] = nb0.z; Bs[q][kA+3][rowA] = nb0.w;
        }
        __syncthreads();
        p ^= 1;
    }

    float4 bb4 = make_float4(0.f,0.f,0.f,0.f);
    if (bias) bb4 = *reinterpret_cast<const float4*>(&bias[n0 + tx*4]);
    #pragma unroll
    for (int i = 0; i < 8; i++) {
        int mm = m0 + ty*8 + i;
        size_t off = (size_t)mm * N + n0 + tx*4;
        float v[4] = {acc[i][0] + bb4.x, acc[i][1] + bb4.y, acc[i][2] + bb4.z, acc[i][3] + bb4.w};
        if (addend) {
            float4 ad = *reinterpret_cast<const float4*>(&addend[off]);
            v[0] += ad.x; v[1] += ad.y; v[2] += ad.z; v[3] += ad.w;
        }
        if (flags & 1) {
            #pragma unroll
            for (int j = 0; j < 4; j++)
                v[j] = 0.5f * v[j] * (1.f + erff(v[j] * 0.70710678118654752f));
        }
        if (flags & 4) {   // transposed store: token mm -> out[bt, c, n]
            int bt = mm / NSP, n = mm % NSP;
            #pragma unroll
            for (int j = 0; j < 4; j++)
                C[((size_t)bt*CDIM + n0 + tx*4 + j)*NSP + n] = v[j];
        } else {
            *reinterpret_cast<float4*>(&C[off]) = make_float4(v[0], v[1], v[2], v[3]);
        }
    }
}

// ---------------- conv4 depthwise + silu (coalesced) ----------------
__global__ __launch_bounds__(384) void conv_kernel(const float* __restrict__ scb,
                                                   const float* __restrict__ tcb)
{
    int m = blockIdx.y;
    int r = blockIdx.x;
    int d = threadIdx.x;
    int pos  = m ? ((r / NSP) & (TT-1)) : (r % NSP);
    int strd = m ? NSP : 1;
    const float* cb = m ? tcb : scb;
    float acc = cb[d];
    #pragma unroll
    for (int k = 0; k < 4; k++) {
        if (pos - 3 + k >= 0)
            acc = fmaf(g_cwT[m][k*DI + d], g_xz[(size_t)(r - (3-k)*strd) * XZW + m*768 + d], acc);
    }
    g_u[m][(size_t)r * DI + d] = acc / (1.f + __expf(-acc));
}

// ---------------- delta: softplus(dbc[:,:12] @ dpw^T + dpb), 16 tokens/block ------------
__global__ __launch_bounds__(384) void delta_kernel(const float* __restrict__ sdpb,
                                                    const float* __restrict__ tdpb)
{
    __shared__ float sw[DTR][DI];
    __shared__ float sdbc[16][DTR];
    int m = blockIdx.y;
    int r0 = blockIdx.x * 16;
    int d = threadIdx.x;
    const float* dpb = m ? tdpb : sdpb;
    #pragma unroll
    for (int rr = 0; rr < DTR; rr++)
        sw[rr][d] = g_dpwT[m][rr*DI + d];
    if (d < 16*DTR) {
        int t = d / DTR, c = d % DTR;
        sdbc[t][c] = g_dbc[m][(size_t)(r0 + t)*64 + c];
    }
    __syncthreads();
    float base = dpb[d];
    #pragma unroll 4
    for (int t = 0; t < 16; t++) {
        float acc = base;
        #pragma unroll
        for (int rr = 0; rr < DTR; rr++)
            acc = fmaf(sdbc[t][rr], sw[rr][d], acc);
        g_delta[m][(size_t)(r0 + t)*DI + d] = (acc > 15.f) ? acc : log1pf(__expf(acc));
    }
}

// ---------------- selective scan: warp = (seq, 2 d's); lane = (sub, state n) ------------
__global__ void scan_kernel(int m, int nseq, int L, int rstride, const float* __restrict__ Dp)
{
    int gw   = (blockIdx.x * blockDim.x + threadIdx.x) >> 5;
    int lane = threadIdx.x & 31;
    int seq  = gw / (DI/2);
    int dp   = gw % (DI/2);
    if (seq >= nseq) return;
    int sub = lane >> 4, n = lane & 15;
    int d = dp * 2 + sub;

    float a  = g_A[m][d*DS + n];
    float Dd = Dp[d];
    const float* delta = g_delta[m];
    const float* u     = g_u[m];
    const float* dbc   = g_dbc[m];
    int ycol = m * DI + d;
    int zcol = m * 768 + 384 + d;

    int base = (rstride == 1) ? seq * L
                              : (seq / NSP) * (TT * NSP) + (seq % NSP);

    float h = 0.f;
    for (int pos = 0; pos < L; pos += 4) {
        int r[4];
        float dl[4], uu[4], Bv[4], Cv[4];
        #pragma unroll
        for (int j = 0; j < 4; j++) {
            r[j] = base + (pos + j) * rstride;
            dl[j] = __ldg(&delta[(size_t)r[j]*DI + d]);
            uu[j] = __ldg(&u[(size_t)r[j]*DI + d]);
            Bv[j] = __ldg(&dbc[(size_t)r[j]*64 + DTR + n]);
            Cv[j] = __ldg(&dbc[(size_t)r[j]*64 + DTR + DS + n]);
        }
        float dA[4], dBu[4];
        #pragma unroll
        for (int j = 0; j < 4; j++) {
            dA[j]  = __expf(dl[j] * a);
            dBu[j] = dl[j] * uu[j] * Bv[j];
        }
        float part[4];
        #pragma unroll
        for (int j = 0; j < 4; j++) {
            h = fmaf(h, dA[j], dBu[j]);
            part[j] = h * Cv[j];
        }
        #pragma unroll
        for (int off = 1; off <= 8; off <<= 1)
            #pragma unroll
            for (int j = 0; j < 4; j++)
                part[j] += __shfl_xor_sync(0xffffffffu, part[j], off);
        if (n == 0) {
            #pragma unroll
            for (int j = 0; j < 4; j++) {
                float z  = g_xz[(size_t)r[j]*XZW + zcol];
                float g  = z / (1.f + __expf(-z));
                g_y[(size_t)r[j] * (2*DI) + ycol] = (part[j] + uu[j] * Dd) * g;
            }
        }
    }
}

// ---------------- host launcher ----------------
extern "C" void kernel_launch(void* const* d_in, const int* in_sizes, int n_in,
                              void* d_out, int out_size)
{
    const float* x_in   = (const float*)d_in[0];
    const float* n1w    = (const float*)d_in[1];
    const float* n1b    = (const float*)d_in[2];
    const float* s_inw  = (const float*)d_in[3];
    const float* s_cw   = (const float*)d_in[4];
    const float* s_cb   = (const float*)d_in[5];
    const float* s_xpw  = (const float*)d_in[6];
    const float* s_dpw  = (const float*)d_in[7];
    const float* s_dpb  = (const float*)d_in[8];
    const float* s_Alog = (const float*)d_in[9];
    const float* s_D    = (const float*)d_in[10];
    const float* s_outw = (const float*)d_in[11];
    const float* t_inw  = (const float*)d_in[12];
    const float* t_cw   = (const float*)d_in[13];
    const float* t_cb   = (const float*)d_in[14];
    const float* t_xpw  = (const float*)d_in[15];
    const float* t_dpw  = (const float*)d_in[16];
    const float* t_dpb  = (const float*)d_in[17];
    const float* t_Alog = (const float*)d_in[18];
    const float* t_D    = (const float*)d_in[19];
    const float* t_outw = (const float*)d_in[20];
    const float* fw     = (const float*)d_in[21];
    const float* fb     = (const float*)d_in[22];
    const float* n2w    = (const float*)d_in[23];
    const float* n2b    = (const float*)d_in[24];
    const float* w1     = (const float*)d_in[25];
    const float* b1     = (const float*)d_in[26];
    const float* w2     = (const float*)d_in[27];
    const float* b2     = (const float*)d_in[28];
    float* out = (float*)d_out;

    float *p_xn, *p_short, *p_xz, *p_y, *p_x2, *p_h, *p_hid, *p_W12, *p_Win, *p_u, *p_dbc, *p_xpwP;
    cudaGetSymbolAddress((void**)&p_xn,   g_xn);
    cudaGetSymbolAddress((void**)&p_short,g_short);
    cudaGetSymbolAddress((void**)&p_xz,   g_xz);
    cudaGetSymbolAddress((void**)&p_y,    g_y);
    cudaGetSymbolAddress((void**)&p_x2,   g_x2);
    cudaGetSymbolAddress((void**)&p_h,    g_h);
    cudaGetSymbolAddress((void**)&p_hid,  g_hid);
    cudaGetSymbolAddress((void**)&p_W12,  g_W12);
    cudaGetSymbolAddress((void**)&p_Win,  g_Win);
    cudaGetSymbolAddress((void**)&p_u,    g_u);
    cudaGetSymbolAddress((void**)&p_dbc,  g_dbc);
    cudaGetSymbolAddress((void**)&p_xpwP, g_xpwP);

    // 0. prep
    prep_kernel<<<1152, 256>>>(s_Alog, t_Alog, fw, s_outw, t_outw,
                               s_cw, t_cw, s_dpw, t_dpw, s_inw, t_inw, s_xpw, t_xpw);

    // 1. transpose + LN1 (keeps shortcut)
    ln1_kernel<<<dim3(16, 18), 256>>>(x_in, n1w, n1b);

    // 2. merged in_proj GEMM (N=1536)
    gemm128_kernel<<<dim3(XZW/128, TOK/128), 256>>>(p_xn, p_Win, p_xz, nullptr, TOK, XZW, CDIM, 0);

    // 3. conv+silu
    conv_kernel<<<dim3(TOK, 2), 384>>>(s_cb, t_cb);

    // 4. dbc = u @ xpwP^T (padded N=64) for both mambas
    gemm64_kernel<<<dim3(1, TOK/128), 256>>>(p_u,                     p_xpwP,          p_dbc,          nullptr, nullptr, TOK, 64, DI, 0);
    gemm64_kernel<<<dim3(1, TOK/128), 256>>>(p_u + (size_t)TOK*DI,    p_xpwP + 64*DI,  p_dbc + TOK*64, nullptr, nullptr, TOK, 64, DI, 0);

    // 5. delta = softplus(dt @ dpw^T + dpb)
    delta_kernel<<<dim3(TOK/16, 2), 384>>>(s_dpb, t_dpb);

    // 6. selective scans
    scan_kernel<<<(16   * (DI/2)) / 4, 128>>>(0, 16,      NSP, 1,   s_D);
    scan_kernel<<<(1152 * (DI/2)) / 4, 128>>>(1, BQ*NSP,  TT,  NSP, t_D);

    // 7. merged out_proj + fusion + residual: x2 = short + fb + y @ W12^T  (K=768)
    gemm64_kernel<<<dim3(CDIM/64, TOK/128), 256>>>(p_y, p_W12, p_x2, fb, p_short, TOK, CDIM, 2*DI, 0);

    // 8. LN2 + MLP (mlp2 stores directly transposed into d_out)
    ln2_kernel<<<TOK/4, 128>>>(p_x2, p_h, n2w, n2b);
    gemm128_kernel<<<dim3(MLPH/128, TOK/128), 256>>>(p_h, w1, p_hid, b1, TOK, MLPH, CDIM, 1);
    gemm64_kernel<<<dim3(CDIM/64, TOK/128), 256>>>(p_hid, w2, out, b2, p_x2, TOK, CDIM, MLPH, 4);
}

// round 5
// speedup vs baseline: 1.0743x; 1.0743x over previous
#include <cuda_runtime.h>
#include <math.h>

// ---------------- problem constants ----------------
#define BQ    2
#define TT    8
#define CDIM  192
#define NSP   576          // H*W
#define TOK   9216         // B*T*N
#define DI    384          // d_inner
#define DS    16           // d_state
#define DTR   12
#define MLPH  768
#define XZW   1536         // merged in_proj width (s:768 | t:768)

typedef unsigned long long u64;

__device__ __forceinline__ u64 packf2(float a) {
    u64 r;
    asm("mov.b64 %0, {%1, %1};" : "=l"(r) : "r"(__float_as_uint(a)));
    return r;
}
__device__ __forceinline__ void fma2(u64& acc, u64 a, u64 b) {
    asm("fma.rn.f32x2 %0, %1, %2, %0;" : "+l"(acc) : "l"(a), "l"(b));
}
__device__ __forceinline__ float2 unpackf2(u64 v) {
    unsigned lo, hi;
    asm("mov.b64 {%0, %1}, %2;" : "=r"(lo), "=r"(hi) : "l"(v));
    return make_float2(__uint_as_float(lo), __uint_as_float(hi));
}

// ---------------- scratch (device globals; allocation-free) ----------------
__device__ float g_xn[TOK*CDIM];
__device__ float g_short[TOK*CDIM];
__device__ float g_xz[TOK*XZW];
__device__ float g_u[2][TOK*DI];
__device__ float g_delta[2][TOK*DI];
__device__ float g_dbc[2][TOK*64];        // dt:0-11, B:12-27, C:28-43
__device__ float g_y[TOK*2*DI];
__device__ float g_x2[TOK*CDIM];
__device__ float g_h[TOK*CDIM];
__device__ float g_hid[TOK*MLPH];
__device__ float g_Win[XZW*CDIM];
__device__ float g_W12[CDIM*2*DI];
__device__ float g_xpwP[2][64*DI];
__device__ float g_A[2][DI*DS];
__device__ float g_cwT[2][4*DI];
__device__ float g_dpwT[2][DTR*DI];

// ---------------- prep ----------------
__global__ void prep_kernel(const float* __restrict__ sAlog, const float* __restrict__ tAlog,
                            const float* __restrict__ fw,
                            const float* __restrict__ soutw, const float* __restrict__ toutw,
                            const float* __restrict__ scw, const float* __restrict__ tcw,
                            const float* __restrict__ sdpw, const float* __restrict__ tdpw,
                            const float* __restrict__ sinw, const float* __restrict__ tinw,
                            const float* __restrict__ sxpw, const float* __restrict__ txpw)
{
    int i = blockIdx.x * blockDim.x + threadIdx.x;
    if (i < 2*DI*DS) {
        int m = i / (DI*DS), j = i % (DI*DS);
        g_A[m][j] = -expf(m ? tAlog[j] : sAlog[j]);
    }
    if (i < 2*4*DI) {
        int m = i / (4*DI), rem = i % (4*DI);
        int k = rem / DI, d = rem % DI;
        g_cwT[m][k*DI + d] = (m ? tcw : scw)[d*4 + k];
    }
    if (i < 2*DTR*DI) {
        int m = i / (DTR*DI), rem = i % (DTR*DI);
        int rr = rem / DI, d = rem % DI;
        g_dpwT[m][rr*DI + d] = (m ? tdpw : sdpw)[d*DTR + rr];
    }
    if (i < 2*64*DI) {
        int m = i / (64*DI), rem = i % (64*DI);
        int row = rem / DI, col = rem % DI;
        g_xpwP[m][rem] = (row < DTR + 2*DS) ? (m ? txpw : sxpw)[row*DI + col] : 0.f;
    }
    if (i < XZW*CDIM) {
        int row = i / CDIM;
        g_Win[i] = (row < 768) ? sinw[i] : tinw[i - 768*CDIM];
    }
    if (i < CDIM*2*DI) {
        int c = i / (2*DI), q = i % (2*DI);
        int m = q / DI, j = q % DI;
        const float* ow = m ? toutw : soutw;
        const float* fr = fw + c*(2*CDIM) + m*CDIM;
        float acc = 0.f;
        #pragma unroll 4
        for (int cp = 0; cp < CDIM; cp++)
            acc = fmaf(fr[cp], ow[cp*DI + j], acc);
        g_W12[i] = acc;
    }
}

// ---------------- LN1 with tiled transpose (src is [BT, C, N]) ----------------
__global__ __launch_bounds__(256) void ln1_kernel(const float* __restrict__ src,
                                                  const float* __restrict__ w, const float* __restrict__ b)
{
    __shared__ float s[CDIM][33];
    int bt = blockIdx.x;
    int n0 = blockIdx.y * 32;
    int tid = threadIdx.x;
    #pragma unroll
    for (int i = 0; i < 24; i++) {
        int idx = tid + 256*i;
        int c = idx >> 5, nl = idx & 31;
        s[c][nl] = src[((size_t)bt*CDIM + c)*NSP + n0 + nl];
    }
    __syncthreads();
    int warp = tid >> 5, lane = tid & 31;
    for (int jj = 0; jj < 4; jj++) {
        int tt = warp + 8*jj;
        float v[6];
        #pragma unroll
        for (int j = 0; j < 6; j++) v[j] = s[lane + 32*j][tt];
        float sum = 0.f;
        #pragma unroll
        for (int j = 0; j < 6; j++) sum += v[j];
        #pragma unroll
        for (int o = 16; o > 0; o >>= 1) sum += __shfl_xor_sync(0xffffffffu, sum, o);
        float mean = sum * (1.f/CDIM);
        float q = 0.f;
        #pragma unroll
        for (int j = 0; j < 6; j++) { float d = v[j]-mean; q += d*d; }
        #pragma unroll
        for (int o = 16; o > 0; o >>= 1) q += __shfl_xor_sync(0xffffffffu, q, o);
        float rstd = rsqrtf(q * (1.f/CDIM) + 1e-5f);
        size_t tok = (size_t)bt*NSP + n0 + tt;
        #pragma unroll
        for (int j = 0; j < 6; j++) {
            int c = lane + 32*j;
            g_xn[tok*CDIM + c] = (v[j]-mean)*rstd*w[c] + b[c];
            g_short[tok*CDIM + c] = v[j];
        }
    }
}

// ---------------- LN2 (contiguous, warp per token) ----------------
__global__ void ln2_kernel(const float* __restrict__ src, float* __restrict__ dst,
                           const float* __restrict__ w, const float* __restrict__ b)
{
    int tok  = blockIdx.x * 4 + (threadIdx.x >> 5);
    int lane = threadIdx.x & 31;
    const float* base = src + (size_t)tok * CDIM;
    float v[6];
    #pragma unroll
    for (int j = 0; j < 6; j++) v[j] = base[lane + 32*j];
    float s = 0.f;
    #pragma unroll
    for (int j = 0; j < 6; j++) s += v[j];
    #pragma unroll
    for (int o = 16; o > 0; o >>= 1) s += __shfl_xor_sync(0xffffffffu, s, o);
    float mean = s * (1.f / CDIM);
    float q = 0.f;
    #pragma unroll
    for (int j = 0; j < 6; j++) { float d = v[j] - mean; q += d * d; }
    #pragma unroll
    for (int o = 16; o > 0; o >>= 1) q += __shfl_xor_sync(0xffffffffu, q, o);
    float rstd = rsqrtf(q * (1.f / CDIM) + 1e-5f);
    #pragma unroll
    for (int j = 0; j < 6; j++) {
        int c = lane + 32*j;
        dst[(size_t)tok * CDIM + c] = (v[j] - mean) * rstd * w[c] + b[c];
    }
}

// ---------------- gemm128: 128x128 tile, Ktile=32, 8x8 micro, f32x2 FMA ----------------
__global__ __launch_bounds__(256) void gemm128_kernel(
    const float* __restrict__ A, const float* __restrict__ B, float* __restrict__ C,
    const float* __restrict__ bias, int M, int N, int K, int flags)
{
    __shared__ __align__(16) float As[2][32][132];
    __shared__ __align__(16) float Bs[2][32][132];
    int tid = threadIdx.x;
    int m0 = blockIdx.y * 128, n0 = blockIdx.x * 128;

    int rowL = tid >> 2;
    int kL   = (tid & 3) * 8;
    const float* Arow0 = A + (size_t)(m0 + rowL)      * K + kL;
    const float* Arow1 = A + (size_t)(m0 + rowL + 64) * K + kL;
    const float* Brow0 = B + (size_t)(n0 + rowL)      * K + kL;
    const float* Brow1 = B + (size_t)(n0 + rowL + 64) * K + kL;

    int ty = tid >> 4, tx = tid & 15;
    u64 acc[8][4];
    #pragma unroll
    for (int i = 0; i < 8; i++)
        #pragma unroll
        for (int j = 0; j < 4; j++) acc[i][j] = 0ull;

    {
        float4 a0 = *reinterpret_cast<const float4*>(Arow0);
        float4 a1 = *reinterpret_cast<const float4*>(Arow0 + 4);
        float4 a2 = *reinterpret_cast<const float4*>(Arow1);
        float4 a3 = *reinterpret_cast<const float4*>(Arow1 + 4);
        float4 b0 = *reinterpret_cast<const float4*>(Brow0);
        float4 b1 = *reinterpret_cast<const float4*>(Brow0 + 4);
        float4 b2 = *reinterpret_cast<const float4*>(Brow1);
        float4 b3 = *reinterpret_cast<const float4*>(Brow1 + 4);
        float av[8] = {a0.x,a0.y,a0.z,a0.w,a1.x,a1.y,a1.z,a1.w};
        float aw[8] = {a2.x,a2.y,a2.z,a2.w,a3.x,a3.y,a3.z,a3.w};
        float bv[8] = {b0.x,b0.y,b0.z,b0.w,b1.x,b1.y,b1.z,b1.w};
        float bw[8] = {b2.x,b2.y,b2.z,b2.w,b3.x,b3.y,b3.z,b3.w};
        #pragma unroll
        for (int j = 0; j < 8; j++) {
            As[0][kL+j][rowL]    = av[j];
            As[0][kL+j][rowL+64] = aw[j];
            Bs[0][kL+j][rowL]    = bv[j];
            Bs[0][kL+j][rowL+64] = bw[j];
        }
    }
    __syncthreads();

    int p = 0;
    for (int kt = 0; kt < K; kt += 32) {
        float av[8], aw[8], bv[8], bw[8];
        bool more = (kt + 32) < K;
        if (more) {
            float4 a0 = *reinterpret_cast<const float4*>(Arow0 + kt + 32);
            float4 a1 = *reinterpret_cast<const float4*>(Arow0 + kt + 36);
            float4 a2 = *reinterpret_cast<const float4*>(Arow1 + kt + 32);
            float4 a3 = *reinterpret_cast<const float4*>(Arow1 + kt + 36);
            float4 b0 = *reinterpret_cast<const float4*>(Brow0 + kt + 32);
            float4 b1 = *reinterpret_cast<const float4*>(Brow0 + kt + 36);
            float4 b2 = *reinterpret_cast<const float4*>(Brow1 + kt + 32);
            float4 b3 = *reinterpret_cast<const float4*>(Brow1 + kt + 36);
            av[0]=a0.x;av[1]=a0.y;av[2]=a0.z;av[3]=a0.w;av[4]=a1.x;av[5]=a1.y;av[6]=a1.z;av[7]=a1.w;
            aw[0]=a2.x;aw[1]=a2.y;aw[2]=a2.z;aw[3]=a2.w;aw[4]=a3.x;aw[5]=a3.y;aw[6]=a3.z;aw[7]=a3.w;
            bv[0]=b0.x;bv[1]=b0.y;bv[2]=b0.z;bv[3]=b0.w;bv[4]=b1.x;bv[5]=b1.y;bv[6]=b1.z;bv[7]=b1.w;
            bw[0]=b2.x;bw[1]=b2.y;bw[2]=b2.z;bw[3]=b2.w;bw[4]=b3.x;bw[5]=b3.y;bw[6]=b3.z;bw[7]=b3.w;
        }
        #pragma unroll
        for (int kk = 0; kk < 32; kk++) {
            float4 x0 = *reinterpret_cast<const float4*>(&As[p][kk][ty*8]);
            float4 x1 = *reinterpret_cast<const float4*>(&As[p][kk][ty*8+4]);
            ulonglong2 y0 = *reinterpret_cast<const ulonglong2*>(&Bs[p][kk][tx*8]);
            ulonglong2 y1 = *reinterpret_cast<const ulonglong2*>(&Bs[p][kk][tx*8+4]);
            u64 bb[4] = {y0.x, y0.y, y1.x, y1.y};
            float aa[8] = {x0.x,x0.y,x0.z,x0.w,x1.x,x1.y,x1.z,x1.w};
            #pragma unroll
            for (int i = 0; i < 8; i++) {
                u64 ap = packf2(aa[i]);
                #pragma unroll
                for (int j = 0; j < 4; j++) fma2(acc[i][j], ap, bb[j]);
            }
        }
        if (more) {
            int q = p ^ 1;
            #pragma unroll
            for (int j = 0; j < 8; j++) {
                As[q][kL+j][rowL]    = av[j];
                As[q][kL+j][rowL+64] = aw[j];
                Bs[q][kL+j][rowL]    = bv[j];
                Bs[q][kL+j][rowL+64] = bw[j];
            }
        }
        __syncthreads();
        p ^= 1;
    }

    float bb8[8] = {0,0,0,0,0,0,0,0};
    if (bias) {
        float4 t0 = *reinterpret_cast<const float4*>(&bias[n0 + tx*8]);
        float4 t1 = *reinterpret_cast<const float4*>(&bias[n0 + tx*8 + 4]);
        bb8[0]=t0.x;bb8[1]=t0.y;bb8[2]=t0.z;bb8[3]=t0.w;bb8[4]=t1.x;bb8[5]=t1.y;bb8[6]=t1.z;bb8[7]=t1.w;
    }
    #pragma unroll
    for (int i = 0; i < 8; i++) {
        int mm = m0 + ty*8 + i;
        size_t off = (size_t)mm * N + n0 + tx*8;
        float v[8];
        #pragma unroll
        for (int j = 0; j < 4; j++) {
            float2 t = unpackf2(acc[i][j]);
            v[2*j]   = t.x + bb8[2*j];
            v[2*j+1] = t.y + bb8[2*j+1];
        }
        if (flags & 1) {
            #pragma unroll
            for (int j = 0; j < 8; j++)
                v[j] = 0.5f * v[j] * (1.f + erff(v[j] * 0.70710678118654752f));
        }
        *reinterpret_cast<float4*>(&C[off])   = make_float4(v[0],v[1],v[2],v[3]);
        *reinterpret_cast<float4*>(&C[off+4]) = make_float4(v[4],v[5],v[6],v[7]);
    }
}

// ---------------- gemm64: 128x64 tile, Ktile=16, 8x4 micro, f32x2 FMA -------------------
// flags bit0: gelu; bit2: transposed store; bit3: use blockIdx.z to split [A|B|C] halves
__global__ __launch_bounds__(256) void gemm64_kernel(
    const float* __restrict__ A, const float* __restrict__ B, float* __restrict__ C,
    const float* __restrict__ bias, const float* __restrict__ addend,
    int M, int N, int K, int flags)
{
    __shared__ __align__(16) float As[2][16][132];
    __shared__ __align__(16) float Bs[2][16][68];
    int tid = threadIdx.x;
    int m0 = blockIdx.y * 128, n0 = blockIdx.x * 64;
    if (flags & 8) {
        int z = blockIdx.z;
        A += (size_t)z * M * K;
        B += (size_t)z * N * K;
        C += (size_t)z * M * N;
    }

    int rowA = tid >> 2;
    int kA   = (tid & 3) * 4;
    const float* Arow0 = A + (size_t)(m0 + rowA)      * K + kA;
    const float* Arow1 = A + (size_t)(m0 + rowA + 64) * K + kA;
    const float* Brow  = B + (size_t)(n0 + rowA)      * K + kA;

    int ty = tid >> 4, tx = tid & 15;
    u64 acc[8][2];
    #pragma unroll
    for (int i = 0; i < 8; i++) { acc[i][0] = 0ull; acc[i][1] = 0ull; }

    {
        float4 a0 = *reinterpret_cast<const float4*>(Arow0);
        float4 a1 = *reinterpret_cast<const float4*>(Arow1);
        float4 b0 = *reinterpret_cast<const float4*>(Brow);
        As[0][kA+0][rowA] = a0.x; As[0][kA+1][rowA] = a0.y; As[0][kA+2][rowA] = a0.z; As[0][kA+3][rowA] = a0.w;
        As[0][kA+0][rowA+64] = a1.x; As[0][kA+1][rowA+64] = a1.y; As[0][kA+2][rowA+64] = a1.z; As[0][kA+3][rowA+64] = a1.w;
        Bs[0][kA+0][rowA] = b0.x; Bs[0][kA+1][rowA] = b0.y; Bs[0][kA+2][rowA] = b0.z; Bs[0][kA+3][rowA] = b0.w;
    }
    __syncthreads();

    int p = 0;
    for (int kt = 0; kt < K; kt += 16) {
        float4 na0, na1, nb0;
        bool more = (kt + 16) < K;
        if (more) {
            na0 = *reinterpret_cast<const float4*>(Arow0 + kt + 16);
            na1 = *reinterpret_cast<const float4*>(Arow1 + kt + 16);
            nb0 = *reinterpret_cast<const float4*>(Brow  + kt + 16);
        }
        #pragma unroll
        for (int kk = 0; kk < 16; kk++) {
            float4 av0 = *reinterpret_cast<const float4*>(&As[p][kk][ty*8]);
            float4 av1 = *reinterpret_cast<const float4*>(&As[p][kk][ty*8+4]);
            ulonglong2 y0 = *reinterpret_cast<const ulonglong2*>(&Bs[p][kk][tx*4]);
            u64 bb[2] = {y0.x, y0.y};
            float aa[8] = {av0.x,av0.y,av0.z,av0.w,av1.x,av1.y,av1.z,av1.w};
            #pragma unroll
            for (int i = 0; i < 8; i++) {
                u64 ap = packf2(aa[i]);
                fma2(acc[i][0], ap, bb[0]);
                fma2(acc[i][1], ap, bb[1]);
            }
        }
        if (more) {
            int q = p ^ 1;
            As[q][kA+0][rowA] = na0.x; As[q][kA+1][rowA] = na0.y; As[q][kA+2][rowA] = na0.z; As[q][kA+3][rowA] = na0.w;
            As[q][kA+0][rowA+64] = na1.x; As[q][kA+1][rowA+64] = na1.y; As[q][kA+2][rowA+64] = na1.z; As[q][kA+3][rowA+64] = na1.w;
            Bs[q][kA+0][rowA] = nb0.x; Bs[q][kA+1][rowA] = nb0.y; Bs[q][kA+2][rowA] = nb0.z; Bs[q][kA+3][rowA] = nb0.w;
        }
        __syncthreads();
        p ^= 1;
    }

    float4 bb4 = make_float4(0.f,0.f,0.f,0.f);
    if (bias) bb4 = *reinterpret_cast<const float4*>(&bias[n0 + tx*4]);
    #pragma unroll
    for (int i = 0; i < 8; i++) {
        int mm = m0 + ty*8 + i;
        size_t off = (size_t)mm * N + n0 + tx*4;
        float2 t0 = unpackf2(acc[i][0]);
        float2 t1 = unpackf2(acc[i][1]);
        float v[4] = {t0.x + bb4.x, t0.y + bb4.y, t1.x + bb4.z, t1.y + bb4.w};
        if (addend) {
            float4 ad = *reinterpret_cast<const float4*>(&addend[off]);
            v[0] += ad.x; v[1] += ad.y; v[2] += ad.z; v[3] += ad.w;
        }
        if (flags & 1) {
            #pragma unroll
            for (int j = 0; j < 4; j++)
                v[j] = 0.5f * v[j] * (1.f + erff(v[j] * 0.70710678118654752f));
        }
        if (flags & 4) {
            int bt = mm / NSP, n = mm % NSP;
            #pragma unroll
            for (int j = 0; j < 4; j++)
                C[((size_t)bt*CDIM + n0 + tx*4 + j)*NSP + n] = v[j];
        } else {
            *reinterpret_cast<float4*>(&C[off]) = make_float4(v[0], v[1], v[2], v[3]);
        }
    }
}

// ---------------- conv4 depthwise + silu ----------------
__global__ __launch_bounds__(384) void conv_kernel(const float* __restrict__ scb,
                                                   const float* __restrict__ tcb)
{
    int m = blockIdx.y;
    int r = blockIdx.x;
    int d = threadIdx.x;
    int pos  = m ? ((r / NSP) & (TT-1)) : (r % NSP);
    int strd = m ? NSP : 1;
    const float* cb = m ? tcb : scb;
    float acc = cb[d];
    #pragma unroll
    for (int k = 0; k < 4; k++) {
        if (pos - 3 + k >= 0)
            acc = fmaf(g_cwT[m][k*DI + d], g_xz[(size_t)(r - (3-k)*strd) * XZW + m*768 + d], acc);
    }
    g_u[m][(size_t)r * DI + d] = acc / (1.f + __expf(-acc));
}

// ---------------- delta: softplus(dbc[:,:12] @ dpw^T + dpb), 16 tokens/block ------------
__global__ __launch_bounds__(384) void delta_kernel(const float* __restrict__ sdpb,
                                                    const float* __restrict__ tdpb)
{
    __shared__ float sw[DTR][DI];
    __shared__ float sdbc[16][DTR];
    int m = blockIdx.y;
    int r0 = blockIdx.x * 16;
    int d = threadIdx.x;
    const float* dpb = m ? tdpb : sdpb;
    #pragma unroll
    for (int rr = 0; rr < DTR; rr++)
        sw[rr][d] = g_dpwT[m][rr*DI + d];
    if (d < 16*DTR) {
        int t = d / DTR, c = d % DTR;
        sdbc[t][c] = g_dbc[m][(size_t)(r0 + t)*64 + c];
    }
    __syncthreads();
    float base = dpb[d];
    #pragma unroll 4
    for (int t = 0; t < 16; t++) {
        float acc = base;
        #pragma unroll
        for (int rr = 0; rr < DTR; rr++)
            acc = fmaf(sdbc[t][rr], sw[rr][d], acc);
        g_delta[m][(size_t)(r0 + t)*DI + d] = (acc > 15.f) ? acc : log1pf(__expf(acc));
    }
}

// ---------------- selective scan ----------------
__global__ void scan_kernel(int m, int nseq, int L, int rstride, const float* __restrict__ Dp)
{
    int gw   = (blockIdx.x * blockDim.x + threadIdx.x) >> 5;
    int lane = threadIdx.x & 31;
    int seq  = gw / (DI/2);
    int dp   = gw % (DI/2);
    if (seq >= nseq) return;
    int sub = lane >> 4, n = lane & 15;
    int d = dp * 2 + sub;

    float a  = g_A[m][d*DS + n];
    float Dd = Dp[d];
    const float* delta = g_delta[m];
    const float* u     = g_u[m];
    const float* dbc   = g_dbc[m];
    int ycol = m * DI + d;
    int zcol = m * 768 + 384 + d;

    int base = (rstride == 1) ? seq * L
                              : (seq / NSP) * (TT * NSP) + (seq % NSP);

    float h = 0.f;
    for (int pos = 0; pos < L; pos += 4) {
        int r[4];
        float dl[4], uu[4], Bv[4], Cv[4];
        #pragma unroll
        for (int j = 0; j < 4; j++) {
            r[j] = base + (pos + j) * rstride;
            dl[j] = __ldg(&delta[(size_t)r[j]*DI + d]);
            uu[j] = __ldg(&u[(size_t)r[j]*DI + d]);
            Bv[j] = __ldg(&dbc[(size_t)r[j]*64 + DTR + n]);
            Cv[j] = __ldg(&dbc[(size_t)r[j]*64 + DTR + DS + n]);
        }
        float dA[4], dBu[4];
        #pragma unroll
        for (int j = 0; j < 4; j++) {
            dA[j]  = __expf(dl[j] * a);
            dBu[j] = dl[j] * uu[j] * Bv[j];
        }
        float part[4];
        #pragma unroll
        for (int j = 0; j < 4; j++) {
            h = fmaf(h, dA[j], dBu[j]);
            part[j] = h * Cv[j];
        }
        #pragma unroll
        for (int off = 1; off <= 8; off <<= 1)
            #pragma unroll
            for (int j = 0; j < 4; j++)
                part[j] += __shfl_xor_sync(0xffffffffu, part[j], off);
        if (n == 0) {
            #pragma unroll
            for (int j = 0; j < 4; j++) {
                float z  = g_xz[(size_t)r[j]*XZW + zcol];
                float g  = z / (1.f + __expf(-z));
                g_y[(size_t)r[j] * (2*DI) + ycol] = (part[j] + uu[j] * Dd) * g;
            }
        }
    }
}

// ---------------- host launcher ----------------
extern "C" void kernel_launch(void* const* d_in, const int* in_sizes, int n_in,
                              void* d_out, int out_size)
{
    const float* x_in   = (const float*)d_in[0];
    const float* n1w    = (const float*)d_in[1];
    const float* n1b    = (const float*)d_in[2];
    const float* s_inw  = (const float*)d_in[3];
    const float* s_cw   = (const float*)d_in[4];
    const float* s_cb   = (const float*)d_in[5];
    const float* s_xpw  = (const float*)d_in[6];
    const float* s_dpw  = (const float*)d_in[7];
    const float* s_dpb  = (const float*)d_in[8];
    const float* s_Alog = (const float*)d_in[9];
    const float* s_D    = (const float*)d_in[10];
    const float* s_outw = (const float*)d_in[11];
    const float* t_inw  = (const float*)d_in[12];
    const float* t_cw   = (const float*)d_in[13];
    const float* t_cb   = (const float*)d_in[14];
    const float* t_xpw  = (const float*)d_in[15];
    const float* t_dpw  = (const float*)d_in[16];
    const float* t_dpb  = (const float*)d_in[17];
    const float* t_Alog = (const float*)d_in[18];
    const float* t_D    = (const float*)d_in[19];
    const float* t_outw = (const float*)d_in[20];
    const float* fw     = (const float*)d_in[21];
    const float* fb     = (const float*)d_in[22];
    const float* n2w    = (const float*)d_in[23];
    const float* n2b    = (const float*)d_in[24];
    const float* w1     = (const float*)d_in[25];
    const float* b1     = (const float*)d_in[26];
    const float* w2     = (const float*)d_in[27];
    const float* b2     = (const float*)d_in[28];
    float* out = (float*)d_out;

    float *p_xn, *p_short, *p_xz, *p_y, *p_x2, *p_h, *p_hid, *p_W12, *p_Win, *p_u, *p_dbc, *p_xpwP;
    cudaGetSymbolAddress((void**)&p_xn,   g_xn);
    cudaGetSymbolAddress((void**)&p_short,g_short);
    cudaGetSymbolAddress((void**)&p_xz,   g_xz);
    cudaGetSymbolAddress((void**)&p_y,    g_y);
    cudaGetSymbolAddress((void**)&p_x2,   g_x2);
    cudaGetSymbolAddress((void**)&p_h,    g_h);
    cudaGetSymbolAddress((void**)&p_hid,  g_hid);
    cudaGetSymbolAddress((void**)&p_W12,  g_W12);
    cudaGetSymbolAddress((void**)&p_Win,  g_Win);
    cudaGetSymbolAddress((void**)&p_u,    g_u);
    cudaGetSymbolAddress((void**)&p_dbc,  g_dbc);
    cudaGetSymbolAddress((void**)&p_xpwP, g_xpwP);

    // 0. prep
    prep_kernel<<<1152, 256>>>(s_Alog, t_Alog, fw, s_outw, t_outw,
                               s_cw, t_cw, s_dpw, t_dpw, s_inw, t_inw, s_xpw, t_xpw);

    // 1. transpose + LN1
    ln1_kernel<<<dim3(16, 18), 256>>>(x_in, n1w, n1b);

    // 2. merged in_proj GEMM (N=1536)
    gemm128_kernel<<<dim3(XZW/128, TOK/128), 256>>>(p_xn, p_Win, p_xz, nullptr, TOK, XZW, CDIM, 0);

    // 3. conv+silu
    conv_kernel<<<dim3(TOK, 2), 384>>>(s_cb, t_cb);

    // 4. dbc = u @ xpwP^T, both mambas in one launch (z splits)
    gemm64_kernel<<<dim3(1, TOK/128, 2), 256>>>(p_u, p_xpwP, p_dbc, nullptr, nullptr, TOK, 64, DI, 8);

    // 5. delta = softplus(dt @ dpw^T + dpb)
    delta_kernel<<<dim3(TOK/16, 2), 384>>>(s_dpb, t_dpb);

    // 6. selective scans
    scan_kernel<<<(16   * (DI/2)) / 4, 128>>>(0, 16,      NSP, 1,   s_D);
    scan_kernel<<<(1152 * (DI/2)) / 4, 128>>>(1, BQ*NSP,  TT,  NSP, t_D);

    // 7. merged out_proj + fusion + residual (K=768)
    gemm64_kernel<<<dim3(CDIM/64, TOK/128), 256>>>(p_y, p_W12, p_x2, fb, p_short, TOK, CDIM, 2*DI, 0);

    // 8. LN2 + MLP (mlp2 stores directly transposed into d_out)
    ln2_kernel<<<TOK/4, 128>>>(p_x2, p_h, n2w, n2b);
    gemm128_kernel<<<dim3(MLPH/128, TOK/128), 256>>>(p_h, w1, p_hid, b1, TOK, MLPH, CDIM, 1);
    gemm64_kernel<<<dim3(CDIM/64, TOK/128), 256>>>(p_hid, w2, out, b2, p_x2, TOK, CDIM, MLPH, 4);
}

// round 6
// speedup vs baseline: 1.2626x; 1.1753x over previous
#include <cuda_runtime.h>
#include <math.h>
#include <stdint.h>

// ---------------- problem constants ----------------
#define BQ    2
#define TT    8
#define CDIM  192
#define NSP   576          // H*W
#define TOK   9216         // B*T*N
#define DI    384          // d_inner
#define DS    16           // d_state
#define DTR   12
#define MLPH  768
#define XZW   1536         // merged in_proj width (s:768 | t:768)

// ---------------- scratch (device globals; allocation-free) ----------------
__device__ float g_xn[TOK*CDIM];
__device__ float g_short[TOK*CDIM];
__device__ float g_xz[TOK*XZW];
__device__ float g_u[2][TOK*DI];
__device__ float g_delta[2][TOK*DI];
__device__ float g_dbc[2][TOK*64];        // dt:0-11, B:12-27, C:28-43
__device__ float g_y[TOK*2*DI];
__device__ float g_x2[TOK*CDIM];
__device__ float g_h[TOK*CDIM];
__device__ float g_hid[TOK*MLPH];
__device__ float g_Win[XZW*CDIM];
__device__ float g_W12[CDIM*2*DI];
__device__ float g_xpwP[2][64*DI];
__device__ float g_A[2][DI*DS];
__device__ float g_cwT[2][4*DI];
__device__ float g_dpwT[2][DTR*DI];

// ---------------- tf32 helpers ----------------
__device__ __forceinline__ uint32_t f2tf(float f) {
    uint32_t r;
    asm("cvt.rna.tf32.f32 %0, %1;" : "=r"(r) : "f"(f));
    return r;
}
__device__ __forceinline__ void mma_tf32(float c[4], const uint32_t a[4], const uint32_t b[2]) {
    asm("mma.sync.aligned.m16n8k8.row.col.f32.tf32.tf32.f32 "
        "{%0,%1,%2,%3}, {%4,%5,%6,%7}, {%8,%9}, {%0,%1,%2,%3};"
        : "+f"(c[0]), "+f"(c[1]), "+f"(c[2]), "+f"(c[3])
        : "r"(a[0]), "r"(a[1]), "r"(a[2]), "r"(a[3]), "r"(b[0]), "r"(b[1]));
}

// ---------------- prep ----------------
__global__ void prep_kernel(const float* __restrict__ sAlog, const float* __restrict__ tAlog,
                            const float* __restrict__ fw,
                            const float* __restrict__ soutw, const float* __restrict__ toutw,
                            const float* __restrict__ scw, const float* __restrict__ tcw,
                            const float* __restrict__ sdpw, const float* __restrict__ tdpw,
                            const float* __restrict__ sinw, const float* __restrict__ tinw,
                            const float* __restrict__ sxpw, const float* __restrict__ txpw)
{
    int i = blockIdx.x * blockDim.x + threadIdx.x;
    if (i < 2*DI*DS) {
        int m = i / (DI*DS), j = i % (DI*DS);
        g_A[m][j] = -expf(m ? tAlog[j] : sAlog[j]);
    }
    if (i < 2*4*DI) {
        int m = i / (4*DI), rem = i % (4*DI);
        int k = rem / DI, d = rem % DI;
        g_cwT[m][k*DI + d] = (m ? tcw : scw)[d*4 + k];
    }
    if (i < 2*DTR*DI) {
        int m = i / (DTR*DI), rem = i % (DTR*DI);
        int rr = rem / DI, d = rem % DI;
        g_dpwT[m][rr*DI + d] = (m ? tdpw : sdpw)[d*DTR + rr];
    }
    if (i < 2*64*DI) {
        int m = i / (64*DI), rem = i % (64*DI);
        int row = rem / DI, col = rem % DI;
        g_xpwP[m][rem] = (row < DTR + 2*DS) ? (m ? txpw : sxpw)[row*DI + col] : 0.f;
    }
    if (i < XZW*CDIM) {
        int row = i / CDIM;
        g_Win[i] = (row < 768) ? sinw[i] : tinw[i - 768*CDIM];
    }
    if (i < CDIM*2*DI) {
        int c = i / (2*DI), q = i % (2*DI);
        int m = q / DI, j = q % DI;
        const float* ow = m ? toutw : soutw;
        const float* fr = fw + c*(2*CDIM) + m*CDIM;
        float acc = 0.f;
        #pragma unroll 4
        for (int cp = 0; cp < CDIM; cp++)
            acc = fmaf(fr[cp], ow[cp*DI + j], acc);
        g_W12[i] = acc;
    }
}

// ---------------- LN1 with tiled transpose (src is [BT, C, N]) ----------------
__global__ __launch_bounds__(256) void ln1_kernel(const float* __restrict__ src,
                                                  const float* __restrict__ w, const float* __restrict__ b)
{
    __shared__ float s[CDIM][33];
    int bt = blockIdx.x;
    int n0 = blockIdx.y * 32;
    int tid = threadIdx.x;
    #pragma unroll
    for (int i = 0; i < 24; i++) {
        int idx = tid + 256*i;
        int c = idx >> 5, nl = idx & 31;
        s[c][nl] = src[((size_t)bt*CDIM + c)*NSP + n0 + nl];
    }
    __syncthreads();
    int warp = tid >> 5, lane = tid & 31;
    for (int jj = 0; jj < 4; jj++) {
        int tt = warp + 8*jj;
        float v[6];
        #pragma unroll
        for (int j = 0; j < 6; j++) v[j] = s[lane + 32*j][tt];
        float sum = 0.f;
        #pragma unroll
        for (int j = 0; j < 6; j++) sum += v[j];
        #pragma unroll
        for (int o = 16; o > 0; o >>= 1) sum += __shfl_xor_sync(0xffffffffu, sum, o);
        float mean = sum * (1.f/CDIM);
        float q = 0.f;
        #pragma unroll
        for (int j = 0; j < 6; j++) { float d = v[j]-mean; q += d*d; }
        #pragma unroll
        for (int o = 16; o > 0; o >>= 1) q += __shfl_xor_sync(0xffffffffu, q, o);
        float rstd = rsqrtf(q * (1.f/CDIM) + 1e-5f);
        size_t tok = (size_t)bt*NSP + n0 + tt;
        #pragma unroll
        for (int j = 0; j < 6; j++) {
            int c = lane + 32*j;
            g_xn[tok*CDIM + c] = (v[j]-mean)*rstd*w[c] + b[c];
            g_short[tok*CDIM + c] = v[j];
        }
    }
}

// ---------------- LN2 (contiguous, warp per token) ----------------
__global__ void ln2_kernel(const float* __restrict__ src, float* __restrict__ dst,
                           const float* __restrict__ w, const float* __restrict__ b)
{
    int tok  = blockIdx.x * 4 + (threadIdx.x >> 5);
    int lane = threadIdx.x & 31;
    const float* base = src + (size_t)tok * CDIM;
    float v[6];
    #pragma unroll
    for (int j = 0; j < 6; j++) v[j] = base[lane + 32*j];
    float s = 0.f;
    #pragma unroll
    for (int j = 0; j < 6; j++) s += v[j];
    #pragma unroll
    for (int o = 16; o > 0; o >>= 1) s += __shfl_xor_sync(0xffffffffu, s, o);
    float mean = s * (1.f / CDIM);
    float q = 0.f;
    #pragma unroll
    for (int j = 0; j < 6; j++) { float d = v[j] - mean; q += d * d; }
    #pragma unroll
    for (int o = 16; o > 0; o >>= 1) q += __shfl_xor_sync(0xffffffffu, q, o);
    float rstd = rsqrtf(q * (1.f / CDIM) + 1e-5f);
    #pragma unroll
    for (int j = 0; j < 6; j++) {
        int c = lane + 32*j;
        dst[(size_t)tok * CDIM + c] = (v[j] - mean) * rstd * w[c] + b[c];
    }
}

// ---------------- tgemm: tf32 tensor-core GEMM -------------------------------------------
// C[M,N] = act(A[M,K] @ B[N,K]^T + bias + addend)
// Block: 128x128, 256 threads (8 warps at 32x64 each). Ktile=16, double-buffered.
// smem row padded to 20 floats -> bank = (20*m + k) & 31 conflict-free for the frag pattern.
// flags: bit0 gelu | bit2 transposed store [bt,c,n] | bit3 z-split A/B/C halves
// Requirements: M % 128 == 0, K % 16 == 0. N arbitrary (guards).
__global__ __launch_bounds__(256) void tgemm_kernel(
    const float* __restrict__ A, const float* __restrict__ B, float* __restrict__ C,
    const float* __restrict__ bias, const float* __restrict__ addend,
    int M, int N, int K, int flags)
{
    __shared__ uint32_t As[2][128][20];
    __shared__ uint32_t Bs[2][128][20];
    int tid = threadIdx.x;
    int m0 = blockIdx.y * 128, n0 = blockIdx.x * 128;
    if (flags & 8) {
        int z = blockIdx.z;
        A += (size_t)z * M * K;
        B += (size_t)z * N * K;
        C += (size_t)z * M * N;
    }

    // global->smem mapping: 256 threads, each loads 8 floats of one row (2x float4)
    int lrow = tid >> 1;               // 0..127
    int lk   = (tid & 1) * 8;          // 0 or 8
    const float* Ap = A + (size_t)(m0 + lrow) * K + lk;
    bool bval = (n0 + lrow) < N;
    const float* Bp = B + (size_t)(n0 + lrow) * K + lk;

    // preload ktile 0
    {
        float4 a0 = *reinterpret_cast<const float4*>(Ap);
        float4 a1 = *reinterpret_cast<const float4*>(Ap + 4);
        float4 b0 = make_float4(0.f,0.f,0.f,0.f), b1 = b0;
        if (bval) {
            b0 = *reinterpret_cast<const float4*>(Bp);
            b1 = *reinterpret_cast<const float4*>(Bp + 4);
        }
        float av[8] = {a0.x,a0.y,a0.z,a0.w,a1.x,a1.y,a1.z,a1.w};
        float bv[8] = {b0.x,b0.y,b0.z,b0.w,b1.x,b1.y,b1.z,b1.w};
        #pragma unroll
        for (int j = 0; j < 8; j++) {
            As[0][lrow][lk+j] = f2tf(av[j]);
            Bs[0][lrow][lk+j] = f2tf(bv[j]);
        }
    }
    __syncthreads();

    int wid = tid >> 5, lane = tid & 31;
    int wm = wid >> 1;        // 0..3 -> m offset wm*32
    int wn = wid & 1;         // 0..1 -> n offset wn*64
    int lr = lane >> 2, lc = lane & 3;

    float acc[2][8][4];
    #pragma unroll
    for (int mt = 0; mt < 2; mt++)
        #pragma unroll
        for (int nt = 0; nt < 8; nt++)
            #pragma unroll
            for (int j = 0; j < 4; j++) acc[mt][nt][j] = 0.f;

    int p = 0;
    for (int kt = 0; kt < K; kt += 16) {
        float av[8], bv[8];
        bool more = (kt + 16) < K;
        if (more) {
            float4 a0 = *reinterpret_cast<const float4*>(Ap + kt + 16);
            float4 a1 = *reinterpret_cast<const float4*>(Ap + kt + 20);
            float4 b0 = make_float4(0.f,0.f,0.f,0.f), b1 = b0;
            if (bval) {
                b0 = *reinterpret_cast<const float4*>(Bp + kt + 16);
                b1 = *reinterpret_cast<const float4*>(Bp + kt + 20);
            }
            av[0]=a0.x;av[1]=a0.y;av[2]=a0.z;av[3]=a0.w;av[4]=a1.x;av[5]=a1.y;av[6]=a1.z;av[7]=a1.w;
            bv[0]=b0.x;bv[1]=b0.y;bv[2]=b0.z;bv[3]=b0.w;bv[4]=b1.x;bv[5]=b1.y;bv[6]=b1.z;bv[7]=b1.w;
        }
        #pragma unroll
        for (int ks = 0; ks < 16; ks += 8) {
            uint32_t afr[2][4];
            #pragma unroll
            for (int mt = 0; mt < 2; mt++) {
                int row = wm*32 + mt*16 + lr;
                afr[mt][0] = As[p][row    ][ks + lc];
                afr[mt][1] = As[p][row + 8][ks + lc];
                afr[mt][2] = As[p][row    ][ks + lc + 4];
                afr[mt][3] = As[p][row + 8][ks + lc + 4];
            }
            uint32_t bfr[8][2];
            #pragma unroll
            for (int nt = 0; nt < 8; nt++) {
                int row = wn*64 + nt*8 + lr;
                bfr[nt][0] = Bs[p][row][ks + lc];
                bfr[nt][1] = Bs[p][row][ks + lc + 4];
            }
            #pragma unroll
            for (int mt = 0; mt < 2; mt++)
                #pragma unroll
                for (int nt = 0; nt < 8; nt++)
                    mma_tf32(acc[mt][nt], afr[mt], bfr[nt]);
        }
        if (more) {
            int q = p ^ 1;
            #pragma unroll
            for (int j = 0; j < 8; j++) {
                As[q][lrow][lk+j] = f2tf(av[j]);
                Bs[q][lrow][lk+j] = f2tf(bv[j]);
            }
        }
        __syncthreads();
        p ^= 1;
    }

    // epilogue
    #pragma unroll
    for (int nt = 0; nt < 8; nt++) {
        int col = n0 + wn*64 + nt*8 + lc*2;
        if (col >= N) continue;
        float b0 = 0.f, b1 = 0.f;
        if (bias) { b0 = bias[col]; b1 = bias[col+1]; }
        #pragma unroll
        for (int mt = 0; mt < 2; mt++) {
            int r0 = m0 + wm*32 + mt*16 + lr;
            int r1 = r0 + 8;
            float v00 = acc[mt][nt][0] + b0;
            float v01 = acc[mt][nt][1] + b1;
            float v10 = acc[mt][nt][2] + b0;
            float v11 = acc[mt][nt][3] + b1;
            if (addend) {
                const float* ad0 = addend + (size_t)r0*N + col;
                const float* ad1 = addend + (size_t)r1*N + col;
                v00 += ad0[0]; v01 += ad0[1];
                v10 += ad1[0]; v11 += ad1[1];
            }
            if (flags & 1) {
                v00 = 0.5f*v00*(1.f + erff(v00*0.70710678118654752f));
                v01 = 0.5f*v01*(1.f + erff(v01*0.70710678118654752f));
                v10 = 0.5f*v10*(1.f + erff(v10*0.70710678118654752f));
                v11 = 0.5f*v11*(1.f + erff(v11*0.70710678118654752f));
            }
            if (flags & 4) {   // transposed store: token r -> out[bt, c, n]
                int bt0 = r0 / NSP, nn0 = r0 % NSP;
                int bt1 = r1 / NSP, nn1 = r1 % NSP;
                C[((size_t)bt0*CDIM + col  )*NSP + nn0] = v00;
                C[((size_t)bt0*CDIM + col+1)*NSP + nn0] = v01;
                C[((size_t)bt1*CDIM + col  )*NSP + nn1] = v10;
                C[((size_t)bt1*CDIM + col+1)*NSP + nn1] = v11;
            } else {
                *reinterpret_cast<float2*>(&C[(size_t)r0*N + col]) = make_float2(v00, v01);
                *reinterpret_cast<float2*>(&C[(size_t)r1*N + col]) = make_float2(v10, v11);
            }
        }
    }
}

// ---------------- conv4 depthwise + silu ----------------
__global__ __launch_bounds__(384) void conv_kernel(const float* __restrict__ scb,
                                                   const float* __restrict__ tcb)
{
    int m = blockIdx.y;
    int r = blockIdx.x;
    int d = threadIdx.x;
    int pos  = m ? ((r / NSP) & (TT-1)) : (r % NSP);
    int strd = m ? NSP : 1;
    const float* cb = m ? tcb : scb;
    float acc = cb[d];
    #pragma unroll
    for (int k = 0; k < 4; k++) {
        if (pos - 3 + k >= 0)
            acc = fmaf(g_cwT[m][k*DI + d], g_xz[(size_t)(r - (3-k)*strd) * XZW + m*768 + d], acc);
    }
    g_u[m][(size_t)r * DI + d] = acc / (1.f + __expf(-acc));
}

// ---------------- delta: softplus(dbc[:,:12] @ dpw^T + dpb), 16 tokens/block ------------
__global__ __launch_bounds__(384) void delta_kernel(const float* __restrict__ sdpb,
                                                    const float* __restrict__ tdpb)
{
    __shared__ float sw[DTR][DI];
    __shared__ float sdbc[16][DTR];
    int m = blockIdx.y;
    int r0 = blockIdx.x * 16;
    int d = threadIdx.x;
    const float* dpb = m ? tdpb : sdpb;
    #pragma unroll
    for (int rr = 0; rr < DTR; rr++)
        sw[rr][d] = g_dpwT[m][rr*DI + d];
    if (d < 16*DTR) {
        int t = d / DTR, c = d % DTR;
        sdbc[t][c] = g_dbc[m][(size_t)(r0 + t)*64 + c];
    }
    __syncthreads();
    float base = dpb[d];
    #pragma unroll 4
    for (int t = 0; t < 16; t++) {
        float acc = base;
        #pragma unroll
        for (int rr = 0; rr < DTR; rr++)
            acc = fmaf(sdbc[t][rr], sw[rr][d], acc);
        g_delta[m][(size_t)(r0 + t)*DI + d] = (acc > 15.f) ? acc : log1pf(__expf(acc));
    }
}

// ---------------- selective scan ----------------
__global__ void scan_kernel(int m, int nseq, int L, int rstride, const float* __restrict__ Dp)
{
    int gw   = (blockIdx.x * blockDim.x + threadIdx.x) >> 5;
    int lane = threadIdx.x & 31;
    int seq  = gw / (DI/2);
    int dp   = gw % (DI/2);
    if (seq >= nseq) return;
    int sub = lane >> 4, n = lane & 15;
    int d = dp * 2 + sub;

    float a  = g_A[m][d*DS + n];
    float Dd = Dp[d];
    const float* delta = g_delta[m];
    const float* u     = g_u[m];
    const float* dbc   = g_dbc[m];
    int ycol = m * DI + d;
    int zcol = m * 768 + 384 + d;

    int base = (rstride == 1) ? seq * L
                              : (seq / NSP) * (TT * NSP) + (seq % NSP);

    float h = 0.f;
    for (int pos = 0; pos < L; pos += 4) {
        int r[4];
        float dl[4], uu[4], Bv[4], Cv[4];
        #pragma unroll
        for (int j = 0; j < 4; j++) {
            r[j] = base + (pos + j) * rstride;
            dl[j] = __ldg(&delta[(size_t)r[j]*DI + d]);
            uu[j] = __ldg(&u[(size_t)r[j]*DI + d]);
            Bv[j] = __ldg(&dbc[(size_t)r[j]*64 + DTR + n]);
            Cv[j] = __ldg(&dbc[(size_t)r[j]*64 + DTR + DS + n]);
        }
        float dA[4], dBu[4];
        #pragma unroll
        for (int j = 0; j < 4; j++) {
            dA[j]  = __expf(dl[j] * a);
            dBu[j] = dl[j] * uu[j] * Bv[j];
        }
        float part[4];
        #pragma unroll
        for (int j = 0; j < 4; j++) {
            h = fmaf(h, dA[j], dBu[j]);
            part[j] = h * Cv[j];
        }
        #pragma unroll
        for (int off = 1; off <= 8; off <<= 1)
            #pragma unroll
            for (int j = 0; j < 4; j++)
                part[j] += __shfl_xor_sync(0xffffffffu, part[j], off);
        if (n == 0) {
            #pragma unroll
            for (int j = 0; j < 4; j++) {
                float z  = g_xz[(size_t)r[j]*XZW + zcol];
                float g  = z / (1.f + __expf(-z));
                g_y[(size_t)r[j] * (2*DI) + ycol] = (part[j] + uu[j] * Dd) * g;
            }
        }
    }
}

// ---------------- host launcher ----------------
extern "C" void kernel_launch(void* const* d_in, const int* in_sizes, int n_in,
                              void* d_out, int out_size)
{
    const float* x_in   = (const float*)d_in[0];
    const float* n1w    = (const float*)d_in[1];
    const float* n1b    = (const float*)d_in[2];
    const float* s_inw  = (const float*)d_in[3];
    const float* s_cw   = (const float*)d_in[4];
    const float* s_cb   = (const float*)d_in[5];
    const float* s_xpw  = (const float*)d_in[6];
    const float* s_dpw  = (const float*)d_in[7];
    const float* s_dpb  = (const float*)d_in[8];
    const float* s_Alog = (const float*)d_in[9];
    const float* s_D    = (const float*)d_in[10];
    const float* s_outw = (const float*)d_in[11];
    const float* t_inw  = (const float*)d_in[12];
    const float* t_cw   = (const float*)d_in[13];
    const float* t_cb   = (const float*)d_in[14];
    const float* t_xpw  = (const float*)d_in[15];
    const float* t_dpw  = (const float*)d_in[16];
    const float* t_dpb  = (const float*)d_in[17];
    const float* t_Alog = (const float*)d_in[18];
    const float* t_D    = (const float*)d_in[19];
    const float* t_outw = (const float*)d_in[20];
    const float* fw     = (const float*)d_in[21];
    const float* fb     = (const float*)d_in[22];
    const float* n2w    = (const float*)d_in[23];
    const float* n2b    = (const float*)d_in[24];
    const float* w1     = (const float*)d_in[25];
    const float* b1     = (const float*)d_in[26];
    const float* w2     = (const float*)d_in[27];
    const float* b2     = (const float*)d_in[28];
    float* out = (float*)d_out;

    float *p_xn, *p_short, *p_xz, *p_y, *p_x2, *p_h, *p_hid, *p_W12, *p_Win, *p_u, *p_dbc, *p_xpwP;
    cudaGetSymbolAddress((void**)&p_xn,   g_xn);
    cudaGetSymbolAddress((void**)&p_short,g_short);
    cudaGetSymbolAddress((void**)&p_xz,   g_xz);
    cudaGetSymbolAddress((void**)&p_y,    g_y);
    cudaGetSymbolAddress((void**)&p_x2,   g_x2);
    cudaGetSymbolAddress((void**)&p_h,    g_h);
    cudaGetSymbolAddress((void**)&p_hid,  g_hid);
    cudaGetSymbolAddress((void**)&p_W12,  g_W12);
    cudaGetSymbolAddress((void**)&p_Win,  g_Win);
    cudaGetSymbolAddress((void**)&p_u,    g_u);
    cudaGetSymbolAddress((void**)&p_dbc,  g_dbc);
    cudaGetSymbolAddress((void**)&p_xpwP, g_xpwP);

    // 0. prep
    prep_kernel<<<1152, 256>>>(s_Alog, t_Alog, fw, s_outw, t_outw,
                               s_cw, t_cw, s_dpw, t_dpw, s_inw, t_inw, s_xpw, t_xpw);

    // 1. transpose + LN1
    ln1_kernel<<<dim3(16, 18), 256>>>(x_in, n1w, n1b);

    // 2. merged in_proj GEMM (N=1536, K=192) — tf32 tensor cores
    tgemm_kernel<<<dim3(XZW/128, TOK/128), 256>>>(p_xn, p_Win, p_xz, nullptr, nullptr, TOK, XZW, CDIM, 0);

    // 3. conv+silu
    conv_kernel<<<dim3(TOK, 2), 384>>>(s_cb, t_cb);

    // 4. dbc = u @ xpwP^T  (N=64 padded, K=384), both mambas via z
    tgemm_kernel<<<dim3(1, TOK/128, 2), 256>>>(p_u, p_xpwP, p_dbc, nullptr, nullptr, TOK, 64, DI, 8);

    // 5. delta = softplus(dt @ dpw^T + dpb)
    delta_kernel<<<dim3(TOK/16, 2), 384>>>(s_dpb, t_dpb);

    // 6. selective scans
    scan_kernel<<<(16   * (DI/2)) / 4, 128>>>(0, 16,      NSP, 1,   s_D);
    scan_kernel<<<(1152 * (DI/2)) / 4, 128>>>(1, BQ*NSP,  TT,  NSP, t_D);

    // 7. merged out_proj + fusion + residual (N=192, K=768)
    tgemm_kernel<<<dim3(2, TOK/128), 256>>>(p_y, p_W12, p_x2, fb, p_short, TOK, CDIM, 2*DI, 0);

    // 8. LN2 + MLP (mlp2 stores directly transposed into d_out)
    ln2_kernel<<<TOK/4, 128>>>(p_x2, p_h, n2w, n2b);
    tgemm_kernel<<<dim3(MLPH/128, TOK/128), 256>>>(p_h, w1, p_hid, b1, nullptr, TOK, MLPH, CDIM, 1);
    tgemm_kernel<<<dim3(2, TOK/128), 256>>>(p_hid, w2, out, b2, p_x2, TOK, CDIM, MLPH, 4);
}

// round 7
// speedup vs baseline: 2.5488x; 2.0187x over previous
#include <cuda_runtime.h>
#include <math.h>
#include <stdint.h>

// ---------------- problem constants ----------------
#define BQ    2
#define TT    8
#define CDIM  192
#define NSP   576          // H*W
#define TOK   9216         // B*T*N
#define DI    384          // d_inner
#define DS    16           // d_state
#define DTR   12
#define MLPH  768
#define XZW   1536         // merged in_proj width (s:768 | t:768)

// ---------------- scratch (device globals; allocation-free) ----------------
__device__ float g_xn[TOK*CDIM];
__device__ float g_short[TOK*CDIM];
__device__ float g_xz[TOK*XZW];
__device__ float g_u[2][TOK*DI];
__device__ float g_delta[2][TOK*DI];
__device__ float g_dbc[2][TOK*64];        // dt:0-11, B:12-27, C:28-43
__device__ float g_y[TOK*2*DI];
__device__ float g_x2[TOK*CDIM];
__device__ float g_h[TOK*CDIM];
__device__ float g_hid[TOK*MLPH];
__device__ float g_Win[XZW*CDIM];
__device__ float g_W12[CDIM*2*DI];
__device__ float g_xpwP[2][64*DI];
__device__ float g_A[2][DI*DS];
__device__ float g_cwT[2][4*DI];
__device__ float g_dpwT[2][DTR*DI];

// ---------------- tf32 helpers ----------------
__device__ __forceinline__ uint32_t f2tf(float f) {
    uint32_t r;
    asm("cvt.rna.tf32.f32 %0, %1;" : "=r"(r) : "f"(f));
    return r;
}
__device__ __forceinline__ void mma_tf32(float c[4], const uint32_t a[4], const uint32_t b[2]) {
    asm("mma.sync.aligned.m16n8k8.row.col.f32.tf32.tf32.f32 "
        "{%0,%1,%2,%3}, {%4,%5,%6,%7}, {%8,%9}, {%0,%1,%2,%3};"
        : "+f"(c[0]), "+f"(c[1]), "+f"(c[2]), "+f"(c[3])
        : "r"(a[0]), "r"(a[1]), "r"(a[2]), "r"(a[3]), "r"(b[0]), "r"(b[1]));
}

// ---------------- prep ----------------
__global__ void prep_kernel(const float* __restrict__ sAlog, const float* __restrict__ tAlog,
                            const float* __restrict__ fw,
                            const float* __restrict__ soutw, const float* __restrict__ toutw,
                            const float* __restrict__ scw, const float* __restrict__ tcw,
                            const float* __restrict__ sdpw, const float* __restrict__ tdpw,
                            const float* __restrict__ sinw, const float* __restrict__ tinw,
                            const float* __restrict__ sxpw, const float* __restrict__ txpw)
{
    int i = blockIdx.x * blockDim.x + threadIdx.x;
    if (i < 2*DI*DS) {
        int m = i / (DI*DS), j = i % (DI*DS);
        g_A[m][j] = -expf(m ? tAlog[j] : sAlog[j]);
    }
    if (i < 2*4*DI) {
        int m = i / (4*DI), rem = i % (4*DI);
        int k = rem / DI, d = rem % DI;
        g_cwT[m][k*DI + d] = (m ? tcw : scw)[d*4 + k];
    }
    if (i < 2*DTR*DI) {
        int m = i / (DTR*DI), rem = i % (DTR*DI);
        int rr = rem / DI, d = rem % DI;
        g_dpwT[m][rr*DI + d] = (m ? tdpw : sdpw)[d*DTR + rr];
    }
    if (i < 2*64*DI) {
        int m = i / (64*DI), rem = i % (64*DI);
        int row = rem / DI, col = rem % DI;
        g_xpwP[m][rem] = (row < DTR + 2*DS) ? (m ? txpw : sxpw)[row*DI + col] : 0.f;
    }
    if (i < XZW*CDIM) {
        int row = i / CDIM;
        g_Win[i] = (row < 768) ? sinw[i] : tinw[i - 768*CDIM];
    }
    if (i < CDIM*2*DI) {
        int c = i / (2*DI), q = i % (2*DI);
        int m = q / DI, j = q % DI;
        const float* ow = m ? toutw : soutw;
        const float* fr = fw + c*(2*CDIM) + m*CDIM;
        float acc = 0.f;
        #pragma unroll 4
        for (int cp = 0; cp < CDIM; cp++)
            acc = fmaf(fr[cp], ow[cp*DI + j], acc);
        g_W12[i] = acc;
    }
}

// ---------------- LN1 with tiled transpose (src is [BT, C, N]) ----------------
__global__ __launch_bounds__(256) void ln1_kernel(const float* __restrict__ src,
                                                  const float* __restrict__ w, const float* __restrict__ b)
{
    __shared__ float s[CDIM][33];
    int bt = blockIdx.x;
    int n0 = blockIdx.y * 32;
    int tid = threadIdx.x;
    #pragma unroll
    for (int i = 0; i < 24; i++) {
        int idx = tid + 256*i;
        int c = idx >> 5, nl = idx & 31;
        s[c][nl] = src[((size_t)bt*CDIM + c)*NSP + n0 + nl];
    }
    __syncthreads();
    int warp = tid >> 5, lane = tid & 31;
    for (int jj = 0; jj < 4; jj++) {
        int tt = warp + 8*jj;
        float v[6];
        #pragma unroll
        for (int j = 0; j < 6; j++) v[j] = s[lane + 32*j][tt];
        float sum = 0.f;
        #pragma unroll
        for (int j = 0; j < 6; j++) sum += v[j];
        #pragma unroll
        for (int o = 16; o > 0; o >>= 1) sum += __shfl_xor_sync(0xffffffffu, sum, o);
        float mean = sum * (1.f/CDIM);
        float q = 0.f;
        #pragma unroll
        for (int j = 0; j < 6; j++) { float d = v[j]-mean; q += d*d; }
        #pragma unroll
        for (int o = 16; o > 0; o >>= 1) q += __shfl_xor_sync(0xffffffffu, q, o);
        float rstd = rsqrtf(q * (1.f/CDIM) + 1e-5f);
        size_t tok = (size_t)bt*NSP + n0 + tt;
        #pragma unroll
        for (int j = 0; j < 6; j++) {
            int c = lane + 32*j;
            g_xn[tok*CDIM + c] = (v[j]-mean)*rstd*w[c] + b[c];
            g_short[tok*CDIM + c] = v[j];
        }
    }
}

// ---------------- LN2 (contiguous, warp per token) ----------------
__global__ void ln2_kernel(const float* __restrict__ src, float* __restrict__ dst,
                           const float* __restrict__ w, const float* __restrict__ b)
{
    int tok  = blockIdx.x * 4 + (threadIdx.x >> 5);
    int lane = threadIdx.x & 31;
    const float* base = src + (size_t)tok * CDIM;
    float v[6];
    #pragma unroll
    for (int j = 0; j < 6; j++) v[j] = base[lane + 32*j];
    float s = 0.f;
    #pragma unroll
    for (int j = 0; j < 6; j++) s += v[j];
    #pragma unroll
    for (int o = 16; o > 0; o >>= 1) s += __shfl_xor_sync(0xffffffffu, s, o);
    float mean = s * (1.f / CDIM);
    float q = 0.f;
    #pragma unroll
    for (int j = 0; j < 6; j++) { float d = v[j] - mean; q += d * d; }
    #pragma unroll
    for (int o = 16; o > 0; o >>= 1) q += __shfl_xor_sync(0xffffffffu, q, o);
    float rstd = rsqrtf(q * (1.f / CDIM) + 1e-5f);
    #pragma unroll
    for (int j = 0; j < 6; j++) {
        int c = lane + 32*j;
        dst[(size_t)tok * CDIM + c] = (v[j] - mean) * rstd * w[c] + b[c];
    }
}

// ---------------- tgemm: tf32 tensor-core GEMM, 128x128 block ---------------------------
// flags: bit0 gelu
__global__ __launch_bounds__(256) void tgemm_kernel(
    const float* __restrict__ A, const float* __restrict__ B, float* __restrict__ C,
    const float* __restrict__ bias, const float* __restrict__ addend,
    int M, int N, int K, int flags)
{
    __shared__ uint32_t As[2][128][20];
    __shared__ uint32_t Bs[2][128][20];
    int tid = threadIdx.x;
    int m0 = blockIdx.y * 128, n0 = blockIdx.x * 128;

    int lrow = tid >> 1;
    int lk   = (tid & 1) * 8;
    const float* Ap = A + (size_t)(m0 + lrow) * K + lk;
    const float* Bp = B + (size_t)(n0 + lrow) * K + lk;

    {
        float4 a0 = *reinterpret_cast<const float4*>(Ap);
        float4 a1 = *reinterpret_cast<const float4*>(Ap + 4);
        float4 b0 = *reinterpret_cast<const float4*>(Bp);
        float4 b1 = *reinterpret_cast<const float4*>(Bp + 4);
        float av[8] = {a0.x,a0.y,a0.z,a0.w,a1.x,a1.y,a1.z,a1.w};
        float bv[8] = {b0.x,b0.y,b0.z,b0.w,b1.x,b1.y,b1.z,b1.w};
        #pragma unroll
        for (int j = 0; j < 8; j++) {
            As[0][lrow][lk+j] = f2tf(av[j]);
            Bs[0][lrow][lk+j] = f2tf(bv[j]);
        }
    }
    __syncthreads();

    int wid = tid >> 5, lane = tid & 31;
    int wm = wid >> 1, wn = wid & 1;
    int lr = lane >> 2, lc = lane & 3;

    float acc[2][8][4];
    #pragma unroll
    for (int mt = 0; mt < 2; mt++)
        #pragma unroll
        for (int nt = 0; nt < 8; nt++)
            #pragma unroll
            for (int j = 0; j < 4; j++) acc[mt][nt][j] = 0.f;

    int p = 0;
    for (int kt = 0; kt < K; kt += 16) {
        float av[8], bv[8];
        bool more = (kt + 16) < K;
        if (more) {
            float4 a0 = *reinterpret_cast<const float4*>(Ap + kt + 16);
            float4 a1 = *reinterpret_cast<const float4*>(Ap + kt + 20);
            float4 b0 = *reinterpret_cast<const float4*>(Bp + kt + 16);
            float4 b1 = *reinterpret_cast<const float4*>(Bp + kt + 20);
            av[0]=a0.x;av[1]=a0.y;av[2]=a0.z;av[3]=a0.w;av[4]=a1.x;av[5]=a1.y;av[6]=a1.z;av[7]=a1.w;
            bv[0]=b0.x;bv[1]=b0.y;bv[2]=b0.z;bv[3]=b0.w;bv[4]=b1.x;bv[5]=b1.y;bv[6]=b1.z;bv[7]=b1.w;
        }
        #pragma unroll
        for (int ks = 0; ks < 16; ks += 8) {
            uint32_t afr[2][4];
            #pragma unroll
            for (int mt = 0; mt < 2; mt++) {
                int row = wm*32 + mt*16 + lr;
                afr[mt][0] = As[p][row    ][ks + lc];
                afr[mt][1] = As[p][row + 8][ks + lc];
                afr[mt][2] = As[p][row    ][ks + lc + 4];
                afr[mt][3] = As[p][row + 8][ks + lc + 4];
            }
            uint32_t bfr[8][2];
            #pragma unroll
            for (int nt = 0; nt < 8; nt++) {
                int row = wn*64 + nt*8 + lr;
                bfr[nt][0] = Bs[p][row][ks + lc];
                bfr[nt][1] = Bs[p][row][ks + lc + 4];
            }
            #pragma unroll
            for (int mt = 0; mt < 2; mt++)
                #pragma unroll
                for (int nt = 0; nt < 8; nt++)
                    mma_tf32(acc[mt][nt], afr[mt], bfr[nt]);
        }
        if (more) {
            int q = p ^ 1;
            #pragma unroll
            for (int j = 0; j < 8; j++) {
                As[q][lrow][lk+j] = f2tf(av[j]);
                Bs[q][lrow][lk+j] = f2tf(bv[j]);
            }
        }
        __syncthreads();
        p ^= 1;
    }

    #pragma unroll
    for (int nt = 0; nt < 8; nt++) {
        int col = n0 + wn*64 + nt*8 + lc*2;
        float b0 = 0.f, b1 = 0.f;
        if (bias) { b0 = bias[col]; b1 = bias[col+1]; }
        #pragma unroll
        for (int mt = 0; mt < 2; mt++) {
            int r0 = m0 + wm*32 + mt*16 + lr;
            int r1 = r0 + 8;
            float v00 = acc[mt][nt][0] + b0;
            float v01 = acc[mt][nt][1] + b1;
            float v10 = acc[mt][nt][2] + b0;
            float v11 = acc[mt][nt][3] + b1;
            if (addend) {
                const float* ad0 = addend + (size_t)r0*N + col;
                const float* ad1 = addend + (size_t)r1*N + col;
                v00 += ad0[0]; v01 += ad0[1];
                v10 += ad1[0]; v11 += ad1[1];
            }
            if (flags & 1) {
                v00 = 0.5f*v00*(1.f + erff(v00*0.70710678118654752f));
                v01 = 0.5f*v01*(1.f + erff(v01*0.70710678118654752f));
                v10 = 0.5f*v10*(1.f + erff(v10*0.70710678118654752f));
                v11 = 0.5f*v11*(1.f + erff(v11*0.70710678118654752f));
            }
            *reinterpret_cast<float2*>(&C[(size_t)r0*N + col]) = make_float2(v00, v01);
            *reinterpret_cast<float2*>(&C[(size_t)r1*N + col]) = make_float2(v10, v11);
        }
    }
}

// ---------------- tgemm64: tf32 GEMM, 128x64 block (no wasted N) ------------------------
// 8 warps, each 16(M)x64(N). flags: bit0 gelu | bit2 transposed store | bit3 z-split
__global__ __launch_bounds__(256) void tgemm64_kernel(
    const float* __restrict__ A, const float* __restrict__ B, float* __restrict__ C,
    const float* __restrict__ bias, const float* __restrict__ addend,
    int M, int N, int K, int flags)
{
    __shared__ uint32_t As[2][128][20];
    __shared__ uint32_t Bs[2][64][20];
    int tid = threadIdx.x;
    int m0 = blockIdx.y * 128, n0 = blockIdx.x * 64;
    if (flags & 8) {
        int z = blockIdx.z;
        A += (size_t)z * M * K;
        B += (size_t)z * N * K;
        C += (size_t)z * M * N;
    }

    int lrow = tid >> 1;               // A: 128 rows x 8 floats
    int lk   = (tid & 1) * 8;
    const float* Ap = A + (size_t)(m0 + lrow) * K + lk;
    int lrowB = tid >> 2;              // B: 64 rows x 4 floats
    int lkB   = (tid & 3) * 4;
    const float* Bp = B + (size_t)(n0 + lrowB) * K + lkB;

    {
        float4 a0 = *reinterpret_cast<const float4*>(Ap);
        float4 a1 = *reinterpret_cast<const float4*>(Ap + 4);
        float4 b0 = *reinterpret_cast<const float4*>(Bp);
        float av[8] = {a0.x,a0.y,a0.z,a0.w,a1.x,a1.y,a1.z,a1.w};
        float bv[4] = {b0.x,b0.y,b0.z,b0.w};
        #pragma unroll
        for (int j = 0; j < 8; j++) As[0][lrow][lk+j] = f2tf(av[j]);
        #pragma unroll
        for (int j = 0; j < 4; j++) Bs[0][lrowB][lkB+j] = f2tf(bv[j]);
    }
    __syncthreads();

    int wid = tid >> 5, lane = tid & 31;
    int lr = lane >> 2, lc = lane & 3;

    float acc[8][4];
    #pragma unroll
    for (int nt = 0; nt < 8; nt++)
        #pragma unroll
        for (int j = 0; j < 4; j++) acc[nt][j] = 0.f;

    int p = 0;
    for (int kt = 0; kt < K; kt += 16) {
        float av[8], bv[4];
        bool more = (kt + 16) < K;
        if (more) {
            float4 a0 = *reinterpret_cast<const float4*>(Ap + kt + 16);
            float4 a1 = *reinterpret_cast<const float4*>(Ap + kt + 20);
            float4 b0 = *reinterpret_cast<const float4*>(Bp + kt + 16);
            av[0]=a0.x;av[1]=a0.y;av[2]=a0.z;av[3]=a0.w;av[4]=a1.x;av[5]=a1.y;av[6]=a1.z;av[7]=a1.w;
            bv[0]=b0.x;bv[1]=b0.y;bv[2]=b0.z;bv[3]=b0.w;
        }
        #pragma unroll
        for (int ks = 0; ks < 16; ks += 8) {
            uint32_t afr[4];
            int arow = wid*16 + lr;
            afr[0] = As[p][arow    ][ks + lc];
            afr[1] = As[p][arow + 8][ks + lc];
            afr[2] = As[p][arow    ][ks + lc + 4];
            afr[3] = As[p][arow + 8][ks + lc + 4];
            uint32_t bfr[8][2];
            #pragma unroll
            for (int nt = 0; nt < 8; nt++) {
                int row = nt*8 + lr;
                bfr[nt][0] = Bs[p][row][ks + lc];
                bfr[nt][1] = Bs[p][row][ks + lc + 4];
            }
            #pragma unroll
            for (int nt = 0; nt < 8; nt++)
                mma_tf32(acc[nt], afr, bfr[nt]);
        }
        if (more) {
            int q = p ^ 1;
            #pragma unroll
            for (int j = 0; j < 8; j++) As[q][lrow][lk+j] = f2tf(av[j]);
            #pragma unroll
            for (int j = 0; j < 4; j++) Bs[q][lrowB][lkB+j] = f2tf(bv[j]);
        }
        __syncthreads();
        p ^= 1;
    }

    #pragma unroll
    for (int nt = 0; nt < 8; nt++) {
        int col = n0 + nt*8 + lc*2;
        float b0 = 0.f, b1 = 0.f;
        if (bias) { b0 = bias[col]; b1 = bias[col+1]; }
        int r0 = m0 + wid*16 + lr;
        int r1 = r0 + 8;
        float v00 = acc[nt][0] + b0;
        float v01 = acc[nt][1] + b1;
        float v10 = acc[nt][2] + b0;
        float v11 = acc[nt][3] + b1;
        if (addend) {
            const float* ad0 = addend + (size_t)r0*N + col;
            const float* ad1 = addend + (size_t)r1*N + col;
            v00 += ad0[0]; v01 += ad0[1];
            v10 += ad1[0]; v11 += ad1[1];
        }
        if (flags & 1) {
            v00 = 0.5f*v00*(1.f + erff(v00*0.70710678118654752f));
            v01 = 0.5f*v01*(1.f + erff(v01*0.70710678118654752f));
            v10 = 0.5f*v10*(1.f + erff(v10*0.70710678118654752f));
            v11 = 0.5f*v11*(1.f + erff(v11*0.70710678118654752f));
        }
        if (flags & 4) {   // transposed store: token r -> out[bt, c, n]
            int bt0 = r0 / NSP, nn0 = r0 % NSP;
            int bt1 = r1 / NSP, nn1 = r1 % NSP;
            C[((size_t)bt0*CDIM + col  )*NSP + nn0] = v00;
            C[((size_t)bt0*CDIM + col+1)*NSP + nn0] = v01;
            C[((size_t)bt1*CDIM + col  )*NSP + nn1] = v10;
            C[((size_t)bt1*CDIM + col+1)*NSP + nn1] = v11;
        } else {
            *reinterpret_cast<float2*>(&C[(size_t)r0*N + col]) = make_float2(v00, v01);
            *reinterpret_cast<float2*>(&C[(size_t)r1*N + col]) = make_float2(v10, v11);
        }
    }
}

// ---------------- conv4 depthwise + silu (float4) ----------------
__global__ __launch_bounds__(192) void conv_kernel(const float* __restrict__ scb,
                                                   const float* __restrict__ tcb)
{
    int m = blockIdx.y;
    int tid = threadIdx.x;
    int rl = tid / 96, v = tid % 96;          // 2 tokens x 96 float4 lanes
    int r = blockIdx.x * 2 + rl;
    int pos  = m ? ((r / NSP) & (TT-1)) : (r % NSP);
    int strd = m ? NSP : 1;
    const float* cb = m ? tcb : scb;
    float4 acc = *reinterpret_cast<const float4*>(&cb[4*v]);
    #pragma unroll
    for (int k = 0; k < 4; k++) {
        if (pos - 3 + k >= 0) {
            float4 xv = *reinterpret_cast<const float4*>(&g_xz[(size_t)(r - (3-k)*strd)*XZW + m*768 + 4*v]);
            float4 cw = *reinterpret_cast<const float4*>(&g_cwT[m][k*DI + 4*v]);
            acc.x = fmaf(cw.x, xv.x, acc.x);
            acc.y = fmaf(cw.y, xv.y, acc.y);
            acc.z = fmaf(cw.z, xv.z, acc.z);
            acc.w = fmaf(cw.w, xv.w, acc.w);
        }
    }
    acc.x = acc.x / (1.f + __expf(-acc.x));
    acc.y = acc.y / (1.f + __expf(-acc.y));
    acc.z = acc.z / (1.f + __expf(-acc.z));
    acc.w = acc.w / (1.f + __expf(-acc.w));
    *reinterpret_cast<float4*>(&g_u[m][(size_t)r*DI + 4*v]) = acc;
}

// ---------------- delta: softplus(dbc[:,:12] @ dpw^T + dpb), 16 tokens/block ------------
__global__ __launch_bounds__(384) void delta_kernel(const float* __restrict__ sdpb,
                                                    const float* __restrict__ tdpb)
{
    __shared__ float sw[DTR][DI];
    __shared__ float sdbc[16][DTR];
    int m = blockIdx.y;
    int r0 = blockIdx.x * 16;
    int d = threadIdx.x;
    const float* dpb = m ? tdpb : sdpb;
    #pragma unroll
    for (int rr = 0; rr < DTR; rr++)
        sw[rr][d] = g_dpwT[m][rr*DI + d];
    if (d < 16*DTR) {
        int t = d / DTR, c = d % DTR;
        sdbc[t][c] = g_dbc[m][(size_t)(r0 + t)*64 + c];
    }
    __syncthreads();
    float base = dpb[d];
    #pragma unroll 4
    for (int t = 0; t < 16; t++) {
        float acc = base;
        #pragma unroll
        for (int rr = 0; rr < DTR; rr++)
            acc = fmaf(sdbc[t][rr], sw[rr][d], acc);
        g_delta[m][(size_t)(r0 + t)*DI + d] = (acc > 15.f) ? acc : log1pf(__expf(acc));
    }
}

// ---------------- merged scans -----------------------------------------------------------
// blocks [0, 768):    spatial scan, lane=n mapping, smem-staged coalesced y flush
// blocks [768, 4224): temporal scan, thread-per-d, fully coalesced
#define SPATIAL_BLOCKS 768
__global__ __launch_bounds__(128) void scan_kernel(const float* __restrict__ sD,
                                                   const float* __restrict__ tD)
{
    int bx = blockIdx.x;
    int tid = threadIdx.x;

    if (bx < SPATIAL_BLOCKS) {
        // ---- spatial: 16 seqs x 48 d-groups (8 d per block), L=576 ----
        __shared__ float sbuf[64][8];
        int s   = bx / 48;
        int dpg = bx % 48;
        int w = tid >> 5, lane = tid & 31;
        int sub = lane >> 4, n = lane & 15;
        int d = dpg*8 + w*2 + sub;
        int ycol0 = dpg*8;

        float a  = g_A[0][d*DS + n];
        float Dd = sD[d];
        const float* delta = g_delta[0];
        const float* u     = g_u[0];
        const float* dbc   = g_dbc[0];
        int base = s * NSP;

        float h = 0.f;
        for (int pos = 0; pos < NSP; pos += 4) {
            float dl[4], uu[4], Bv[4], Cv[4];
            #pragma unroll
            for (int j = 0; j < 4; j++) {
                size_t r = base + pos + j;
                dl[j] = __ldg(&delta[r*DI + d]);
                uu[j] = __ldg(&u[r*DI + d]);
                Bv[j] = __ldg(&dbc[r*64 + DTR + n]);
                Cv[j] = __ldg(&dbc[r*64 + DTR + DS + n]);
            }
            float dA[4], dBu[4];
            #pragma unroll
            for (int j = 0; j < 4; j++) {
                dA[j]  = __expf(dl[j] * a);
                dBu[j] = dl[j] * uu[j] * Bv[j];
            }
            float part[4];
            #pragma unroll
            for (int j = 0; j < 4; j++) {
                h = fmaf(h, dA[j], dBu[j]);
                part[j] = h * Cv[j];
            }
            #pragma unroll
            for (int off = 1; off <= 8; off <<= 1)
                #pragma unroll
                for (int j = 0; j < 4; j++)
                    part[j] += __shfl_xor_sync(0xffffffffu, part[j], off);
            if (n == 0) {
                #pragma unroll
                for (int j = 0; j < 4; j++)
                    sbuf[(pos + j) & 63][w*2 + sub] = part[j] + uu[j] * Dd;
            }
            if ((pos & 63) == 60) {     // flush 64 tokens, coalesced 16B runs
                __syncthreads();
                int p2 = tid >> 1, half = tid & 1;
                size_t r = base + (pos & ~63) + p2;
                float4 v = *reinterpret_cast<float4*>(&sbuf[p2][half*4]);
                float4 z4 = *reinterpret_cast<const float4*>(&g_xz[r*XZW + 384 + ycol0 + half*4]);
                v.x *= z4.x / (1.f + __expf(-z4.x));
                v.y *= z4.y / (1.f + __expf(-z4.y));
                v.z *= z4.z / (1.f + __expf(-z4.z));
                v.w *= z4.w / (1.f + __expf(-z4.w));
                *reinterpret_cast<float4*>(&g_y[r*(2*DI) + ycol0 + half*4]) = v;
                __syncthreads();
            }
        }
    } else {
        // ---- temporal: 1152 seqs x 3 d-parts (128 d per block), L=8 ----
        int b2 = bx - SPATIAL_BLOCKS;
        int seq = b2 / 3;
        int d = (b2 % 3) * 128 + tid;
        int lane = tid & 31;
        int b = seq / NSP, nsp = seq % NSP;
        int base = b * (TT*NSP) + nsp;

        float a[DS];
        #pragma unroll
        for (int q = 0; q < 4; q++)
            *reinterpret_cast<float4*>(&a[q*4]) = *reinterpret_cast<const float4*>(&g_A[1][d*DS + q*4]);
        float Dd = tD[d];
        const float* delta = g_delta[1];
        const float* u     = g_u[1];
        const float* dbc   = g_dbc[1];

        float h[DS];
        #pragma unroll
        for (int q = 0; q < DS; q++) h[q] = 0.f;

        for (int t = 0; t < TT; t++) {
            size_t r = base + (size_t)t * NSP;
            float dl = delta[r*DI + d];
            float uu = u[r*DI + d];
            float bc = dbc[r*64 + DTR + lane];   // lanes 0-15: B, 16-31: C
            float dlu = dl * uu;
            float y = 0.f;
            #pragma unroll
            for (int q = 0; q < DS; q++) {
                float Bn = __shfl_sync(0xffffffffu, bc, q);
                float Cn = __shfl_sync(0xffffffffu, bc, q + 16);
                float dA = __expf(dl * a[q]);
                h[q] = fmaf(h[q], dA, dlu * Bn);
                y = fmaf(h[q], Cn, y);
            }
            float z = g_xz[r*XZW + 1152 + d];
            float g = z / (1.f + __expf(-z));
            g_y[r*(2*DI) + DI + d] = (y + uu * Dd) * g;
        }
    }
}

// ---------------- host launcher ----------------
extern "C" void kernel_launch(void* const* d_in, const int* in_sizes, int n_in,
                              void* d_out, int out_size)
{
    const float* x_in   = (const float*)d_in[0];
    const float* n1w    = (const float*)d_in[1];
    const float* n1b    = (const float*)d_in[2];
    const float* s_inw  = (const float*)d_in[3];
    const float* s_cw   = (const float*)d_in[4];
    const float* s_cb   = (const float*)d_in[5];
    const float* s_xpw  = (const float*)d_in[6];
    const float* s_dpw  = (const float*)d_in[7];
    const float* s_dpb  = (const float*)d_in[8];
    const float* s_Alog = (const float*)d_in[9];
    const float* s_D    = (const float*)d_in[10];
    const float* s_outw = (const float*)d_in[11];
    const float* t_inw  = (const float*)d_in[12];
    const float* t_cw   = (const float*)d_in[13];
    const float* t_cb   = (const float*)d_in[14];
    const float* t_xpw  = (const float*)d_in[15];
    const float* t_dpw  = (const float*)d_in[16];
    const float* t_dpb  = (const float*)d_in[17];
    const float* t_Alog = (const float*)d_in[18];
    const float* t_D    = (const float*)d_in[19];
    const float* t_outw = (const float*)d_in[20];
    const float* fw     = (const float*)d_in[21];
    const float* fb     = (const float*)d_in[22];
    const float* n2w    = (const float*)d_in[23];
    const float* n2b    = (const float*)d_in[24];
    const float* w1     = (const float*)d_in[25];
    const float* b1     = (const float*)d_in[26];
    const float* w2     = (const float*)d_in[27];
    const float* b2     = (const float*)d_in[28];
    float* out = (float*)d_out;

    float *p_xn, *p_short, *p_xz, *p_y, *p_x2, *p_h, *p_hid, *p_W12, *p_Win, *p_u, *p_dbc, *p_xpwP;
    cudaGetSymbolAddress((void**)&p_xn,   g_xn);
    cudaGetSymbolAddress((void**)&p_short,g_short);
    cudaGetSymbolAddress((void**)&p_xz,   g_xz);
    cudaGetSymbolAddress((void**)&p_y,    g_y);
    cudaGetSymbolAddress((void**)&p_x2,   g_x2);
    cudaGetSymbolAddress((void**)&p_h,    g_h);
    cudaGetSymbolAddress((void**)&p_hid,  g_hid);
    cudaGetSymbolAddress((void**)&p_W12,  g_W12);
    cudaGetSymbolAddress((void**)&p_Win,  g_Win);
    cudaGetSymbolAddress((void**)&p_u,    g_u);
    cudaGetSymbolAddress((void**)&p_dbc,  g_dbc);
    cudaGetSymbolAddress((void**)&p_xpwP, g_xpwP);

    // 0. prep
    prep_kernel<<<1152, 256>>>(s_Alog, t_Alog, fw, s_outw, t_outw,
                               s_cw, t_cw, s_dpw, t_dpw, s_inw, t_inw, s_xpw, t_xpw);

    // 1. transpose + LN1
    ln1_kernel<<<dim3(16, 18), 256>>>(x_in, n1w, n1b);

    // 2. merged in_proj GEMM (N=1536, K=192)
    tgemm_kernel<<<dim3(XZW/128, TOK/128), 256>>>(p_xn, p_Win, p_xz, nullptr, nullptr, TOK, XZW, CDIM, 0);

    // 3. conv+silu (vectorized)
    conv_kernel<<<dim3(TOK/2, 2), 192>>>(s_cb, t_cb);

    // 4. dbc = u @ xpwP^T  (N=64, K=384), both mambas via z
    tgemm64_kernel<<<dim3(1, TOK/128, 2), 256>>>(p_u, p_xpwP, p_dbc, nullptr, nullptr, TOK, 64, DI, 8);

    // 5. delta = softplus(dt @ dpw^T + dpb)
    delta_kernel<<<dim3(TOK/16, 2), 384>>>(s_dpb, t_dpb);

    // 6. both selective scans, one launch (overlapping)
    scan_kernel<<<SPATIAL_BLOCKS + 3456, 128>>>(s_D, t_D);

    // 7. merged out_proj + fusion + residual (N=192, K=768)
    tgemm64_kernel<<<dim3(3, TOK/128), 256>>>(p_y, p_W12, p_x2, fb, p_short, TOK, CDIM, 2*DI, 0);

    // 8. LN2 + MLP (mlp2 stores directly transposed into d_out)
    ln2_kernel<<<TOK/4, 128>>>(p_x2, p_h, n2w, n2b);
    tgemm_kernel<<<dim3(MLPH/128, TOK/128), 256>>>(p_h, w1, p_hid, b1, nullptr, TOK, MLPH, CDIM, 1);
    tgemm64_kernel<<<dim3(3, TOK/128), 256>>>(p_hid, w2, out, b2, p_x2, TOK, CDIM, MLPH, 4);
}

// round 8
// speedup vs baseline: 2.9555x; 1.1596x over previous
#include <cuda_runtime.h>
#include <math.h>
#include <stdint.h>

// ---------------- problem constants ----------------
#define BQ    2
#define TT    8
#define CDIM  192
#define NSP   576          // H*W
#define TOK   9216         // B*T*N
#define DI    384          // d_inner
#define DS    16           // d_state
#define DTR   12
#define MLPH  768
#define XZW   1536         // merged in_proj width (s:768 | t:768)

// ---------------- scratch (device globals; allocation-free) ----------------
__device__ float g_xn[TOK*CDIM];
__device__ float g_short[TOK*CDIM];
__device__ float g_xz[TOK*XZW];
__device__ float g_u[2][TOK*DI];
__device__ float g_delta[2][TOK*DI];
__device__ float g_dbc[2][TOK*64];        // dt:0-11, B:12-27, C:28-43
__device__ float g_y[TOK*2*DI];
__device__ float g_x2[TOK*CDIM];
__device__ float g_h[TOK*CDIM];
__device__ float g_hid[TOK*MLPH];
__device__ float g_Win[XZW*CDIM];
__device__ float g_W12[CDIM*2*DI];
__device__ float g_xpwP[2][64*DI];
__device__ float g_A[2][DI*DS];
__device__ float g_cwT[2][4*DI];
__device__ float g_dpwT[2][DTR*DI];

// ---------------- bf16 helpers ----------------
__device__ __forceinline__ uint32_t packbf(float lo, float hi) {
    uint32_t r;
    asm("cvt.rn.bf16x2.f32 %0, %1, %2;" : "=r"(r) : "f"(hi), "f"(lo));
    return r;
}
__device__ __forceinline__ void mma_bf16(float c[4], const uint32_t a[4], const uint32_t b[2]) {
    asm("mma.sync.aligned.m16n8k16.row.col.f32.bf16.bf16.f32 "
        "{%0,%1,%2,%3}, {%4,%5,%6,%7}, {%8,%9}, {%0,%1,%2,%3};"
        : "+f"(c[0]), "+f"(c[1]), "+f"(c[2]), "+f"(c[3])
        : "r"(a[0]), "r"(a[1]), "r"(a[2]), "r"(a[3]), "r"(b[0]), "r"(b[1]));
}

// ---------------- prep (small weights; no fold here) ----------------
__global__ void prep_kernel(const float* __restrict__ sAlog, const float* __restrict__ tAlog,
                            const float* __restrict__ scw, const float* __restrict__ tcw,
                            const float* __restrict__ sdpw, const float* __restrict__ tdpw,
                            const float* __restrict__ sinw, const float* __restrict__ tinw,
                            const float* __restrict__ sxpw, const float* __restrict__ txpw)
{
    int i = blockIdx.x * blockDim.x + threadIdx.x;
    if (i < 2*DI*DS) {
        int m = i / (DI*DS), j = i % (DI*DS);
        g_A[m][j] = -expf(m ? tAlog[j] : sAlog[j]);
    }
    if (i < 2*4*DI) {
        int m = i / (4*DI), rem = i % (4*DI);
        int k = rem / DI, d = rem % DI;
        g_cwT[m][k*DI + d] = (m ? tcw : scw)[d*4 + k];
    }
    if (i < 2*DTR*DI) {
        int m = i / (DTR*DI), rem = i % (DTR*DI);
        int rr = rem / DI, d = rem % DI;
        g_dpwT[m][rr*DI + d] = (m ? tdpw : sdpw)[d*DTR + rr];
    }
    if (i < 2*64*DI) {
        int m = i / (64*DI), rem = i % (64*DI);
        int row = rem / DI, col = rem % DI;
        g_xpwP[m][rem] = (row < DTR + 2*DS) ? (m ? txpw : sxpw)[row*DI + col] : 0.f;
    }
    if (i < XZW*CDIM) {
        int row = i / CDIM;
        g_Win[i] = (row < 768) ? sinw[i] : tinw[i - 768*CDIM];
    }
}

// ---------------- fold: W12[c][m*384+j] = sum_cp fw[c][m*192+cp] * ow_m[cp][j] ----------
__global__ __launch_bounds__(384) void fold_kernel(const float* __restrict__ fw,
                                                   const float* __restrict__ soutw,
                                                   const float* __restrict__ toutw)
{
    __shared__ float fwS[8][192];
    int m  = blockIdx.y;
    int c0 = blockIdx.x * 8;
    const float* ow = m ? toutw : soutw;
    int tid = threadIdx.x;
    for (int i = tid; i < 8*192; i += 384) {
        int c = i / 192, cp = i % 192;
        fwS[c][cp] = fw[(size_t)(c0 + c)*(2*CDIM) + m*CDIM + cp];
    }
    __syncthreads();
    float acc[8] = {0,0,0,0,0,0,0,0};
    #pragma unroll 4
    for (int cp = 0; cp < 192; cp++) {
        float owv = ow[(size_t)cp*DI + tid];
        #pragma unroll
        for (int c = 0; c < 8; c++) acc[c] = fmaf(fwS[c][cp], owv, acc[c]);
    }
    #pragma unroll
    for (int c = 0; c < 8; c++)
        g_W12[(size_t)(c0 + c)*(2*DI) + m*DI + tid] = acc[c];
}

// ---------------- LN1 with tiled transpose (src is [BT, C, N]) ----------------
__global__ __launch_bounds__(256) void ln1_kernel(const float* __restrict__ src,
                                                  const float* __restrict__ w, const float* __restrict__ b)
{
    __shared__ float s[CDIM][33];
    int bt = blockIdx.x;
    int n0 = blockIdx.y * 32;
    int tid = threadIdx.x;
    #pragma unroll
    for (int i = 0; i < 24; i++) {
        int idx = tid + 256*i;
        int c = idx >> 5, nl = idx & 31;
        s[c][nl] = src[((size_t)bt*CDIM + c)*NSP + n0 + nl];
    }
    __syncthreads();
    int warp = tid >> 5, lane = tid & 31;
    for (int jj = 0; jj < 4; jj++) {
        int tt = warp + 8*jj;
        float v[6];
        #pragma unroll
        for (int j = 0; j < 6; j++) v[j] = s[lane + 32*j][tt];
        float sum = 0.f;
        #pragma unroll
        for (int j = 0; j < 6; j++) sum += v[j];
        #pragma unroll
        for (int o = 16; o > 0; o >>= 1) sum += __shfl_xor_sync(0xffffffffu, sum, o);
        float mean = sum * (1.f/CDIM);
        float q = 0.f;
        #pragma unroll
        for (int j = 0; j < 6; j++) { float d = v[j]-mean; q += d*d; }
        #pragma unroll
        for (int o = 16; o > 0; o >>= 1) q += __shfl_xor_sync(0xffffffffu, q, o);
        float rstd = rsqrtf(q * (1.f/CDIM) + 1e-5f);
        size_t tok = (size_t)bt*NSP + n0 + tt;
        #pragma unroll
        for (int j = 0; j < 6; j++) {
            int c = lane + 32*j;
            g_xn[tok*CDIM + c] = (v[j]-mean)*rstd*w[c] + b[c];
            g_short[tok*CDIM + c] = v[j];
        }
    }
}

// ---------------- LN2 (contiguous, warp per token) ----------------
__global__ void ln2_kernel(const float* __restrict__ src, float* __restrict__ dst,
                           const float* __restrict__ w, const float* __restrict__ b)
{
    int tok  = blockIdx.x * 4 + (threadIdx.x >> 5);
    int lane = threadIdx.x & 31;
    const float* base = src + (size_t)tok * CDIM;
    float v[6];
    #pragma unroll
    for (int j = 0; j < 6; j++) v[j] = base[lane + 32*j];
    float s = 0.f;
    #pragma unroll
    for (int j = 0; j < 6; j++) s += v[j];
    #pragma unroll
    for (int o = 16; o > 0; o >>= 1) s += __shfl_xor_sync(0xffffffffu, s, o);
    float mean = s * (1.f / CDIM);
    float q = 0.f;
    #pragma unroll
    for (int j = 0; j < 6; j++) { float d = v[j] - mean; q += d * d; }
    #pragma unroll
    for (int o = 16; o > 0; o >>= 1) q += __shfl_xor_sync(0xffffffffu, q, o);
    float rstd = rsqrtf(q * (1.f / CDIM) + 1e-5f);
    #pragma unroll
    for (int j = 0; j < 6; j++) {
        int c = lane + 32*j;
        dst[(size_t)tok * CDIM + c] = (v[j] - mean) * rstd * w[c] + b[c];
    }
}

// ---------------- bgemm: bf16 tensor-core GEMM, 128x128 block ---------------------------
// smem: uint32 bf16x2 k-pairs, 8 used cols + pad to 12 (conflict-free frags).
// flags: bit0 gelu
__global__ __launch_bounds__(256) void bgemm_kernel(
    const float* __restrict__ A, const float* __restrict__ B, float* __restrict__ C,
    const float* __restrict__ bias, const float* __restrict__ addend,
    int M, int N, int K, int flags)
{
    __shared__ uint32_t As[2][128][12];
    __shared__ uint32_t Bs[2][128][12];
    int tid = threadIdx.x;
    int m0 = blockIdx.y * 128, n0 = blockIdx.x * 128;

    int lrow = tid >> 1;
    int lk   = (tid & 1) * 8;          // float offset
    int kb   = (tid & 1) * 4;          // kpair offset
    const float* Ap = A + (size_t)(m0 + lrow) * K + lk;
    const float* Bp = B + (size_t)(n0 + lrow) * K + lk;

    {
        float4 a0 = *reinterpret_cast<const float4*>(Ap);
        float4 a1 = *reinterpret_cast<const float4*>(Ap + 4);
        float4 b0 = *reinterpret_cast<const float4*>(Bp);
        float4 b1 = *reinterpret_cast<const float4*>(Bp + 4);
        As[0][lrow][kb+0] = packbf(a0.x, a0.y);
        As[0][lrow][kb+1] = packbf(a0.z, a0.w);
        As[0][lrow][kb+2] = packbf(a1.x, a1.y);
        As[0][lrow][kb+3] = packbf(a1.z, a1.w);
        Bs[0][lrow][kb+0] = packbf(b0.x, b0.y);
        Bs[0][lrow][kb+1] = packbf(b0.z, b0.w);
        Bs[0][lrow][kb+2] = packbf(b1.x, b1.y);
        Bs[0][lrow][kb+3] = packbf(b1.z, b1.w);
    }
    __syncthreads();

    int wid = tid >> 5, lane = tid & 31;
    int wm = wid >> 1, wn = wid & 1;
    int lr = lane >> 2, lc = lane & 3;

    float acc[2][8][4];
    #pragma unroll
    for (int mt = 0; mt < 2; mt++)
        #pragma unroll
        for (int nt = 0; nt < 8; nt++)
            #pragma unroll
            for (int j = 0; j < 4; j++) acc[mt][nt][j] = 0.f;

    int p = 0;
    for (int kt = 0; kt < K; kt += 16) {
        float4 a0, a1, b0, b1;
        bool more = (kt + 16) < K;
        if (more) {
            a0 = *reinterpret_cast<const float4*>(Ap + kt + 16);
            a1 = *reinterpret_cast<const float4*>(Ap + kt + 20);
            b0 = *reinterpret_cast<const float4*>(Bp + kt + 16);
            b1 = *reinterpret_cast<const float4*>(Bp + kt + 20);
        }
        uint32_t afr[2][4];
        #pragma unroll
        for (int mt = 0; mt < 2; mt++) {
            int row = wm*32 + mt*16 + lr;
            afr[mt][0] = As[p][row    ][lc];
            afr[mt][1] = As[p][row + 8][lc];
            afr[mt][2] = As[p][row    ][lc + 4];
            afr[mt][3] = As[p][row + 8][lc + 4];
        }
        uint32_t bfr[8][2];
        #pragma unroll
        for (int nt = 0; nt < 8; nt++) {
            int row = wn*64 + nt*8 + lr;
            bfr[nt][0] = Bs[p][row][lc];
            bfr[nt][1] = Bs[p][row][lc + 4];
        }
        #pragma unroll
        for (int mt = 0; mt < 2; mt++)
            #pragma unroll
            for (int nt = 0; nt < 8; nt++)
                mma_bf16(acc[mt][nt], afr[mt], bfr[nt]);
        if (more) {
            int q = p ^ 1;
            As[q][lrow][kb+0] = packbf(a0.x, a0.y);
            As[q][lrow][kb+1] = packbf(a0.z, a0.w);
            As[q][lrow][kb+2] = packbf(a1.x, a1.y);
            As[q][lrow][kb+3] = packbf(a1.z, a1.w);
            Bs[q][lrow][kb+0] = packbf(b0.x, b0.y);
            Bs[q][lrow][kb+1] = packbf(b0.z, b0.w);
            Bs[q][lrow][kb+2] = packbf(b1.x, b1.y);
            Bs[q][lrow][kb+3] = packbf(b1.z, b1.w);
        }
        __syncthreads();
        p ^= 1;
    }

    #pragma unroll
    for (int nt = 0; nt < 8; nt++) {
        int col = n0 + wn*64 + nt*8 + lc*2;
        float b0 = 0.f, b1 = 0.f;
        if (bias) { b0 = bias[col]; b1 = bias[col+1]; }
        #pragma unroll
        for (int mt = 0; mt < 2; mt++) {
            int r0 = m0 + wm*32 + mt*16 + lr;
            int r1 = r0 + 8;
            float v00 = acc[mt][nt][0] + b0;
            float v01 = acc[mt][nt][1] + b1;
            float v10 = acc[mt][nt][2] + b0;
            float v11 = acc[mt][nt][3] + b1;
            if (addend) {
                const float* ad0 = addend + (size_t)r0*N + col;
                const float* ad1 = addend + (size_t)r1*N + col;
                v00 += ad0[0]; v01 += ad0[1];
                v10 += ad1[0]; v11 += ad1[1];
            }
            if (flags & 1) {
                v00 = 0.5f*v00*(1.f + erff(v00*0.70710678118654752f));
                v01 = 0.5f*v01*(1.f + erff(v01*0.70710678118654752f));
                v10 = 0.5f*v10*(1.f + erff(v10*0.70710678118654752f));
                v11 = 0.5f*v11*(1.f + erff(v11*0.70710678118654752f));
            }
            *reinterpret_cast<float2*>(&C[(size_t)r0*N + col]) = make_float2(v00, v01);
            *reinterpret_cast<float2*>(&C[(size_t)r1*N + col]) = make_float2(v10, v11);
        }
    }
}

// ---------------- bgemm64: bf16 GEMM, 128x64 block ---------------------------------------
// 8 warps, each 16(M)x64(N). flags: bit0 gelu | bit2 transposed store | bit3 z-split
__global__ __launch_bounds__(256) void bgemm64_kernel(
    const float* __restrict__ A, const float* __restrict__ B, float* __restrict__ C,
    const float* __restrict__ bias, const float* __restrict__ addend,
    int M, int N, int K, int flags)
{
    __shared__ uint32_t As[2][128][12];
    __shared__ uint32_t Bs[2][64][12];
    int tid = threadIdx.x;
    int m0 = blockIdx.y * 128, n0 = blockIdx.x * 64;
    if (flags & 8) {
        int z = blockIdx.z;
        A += (size_t)z * M * K;
        B += (size_t)z * N * K;
        C += (size_t)z * M * N;
    }

    int lrow = tid >> 1;               // A: 128 rows x 8 floats
    int lk   = (tid & 1) * 8;
    int kb   = (tid & 1) * 4;
    const float* Ap = A + (size_t)(m0 + lrow) * K + lk;
    int lrowB = tid >> 2;              // B: 64 rows x 4 floats
    int lkB   = (tid & 3) * 4;
    int kbB   = (tid & 3) * 2;
    const float* Bp = B + (size_t)(n0 + lrowB) * K + lkB;

    {
        float4 a0 = *reinterpret_cast<const float4*>(Ap);
        float4 a1 = *reinterpret_cast<const float4*>(Ap + 4);
        float4 b0 = *reinterpret_cast<const float4*>(Bp);
        As[0][lrow][kb+0] = packbf(a0.x, a0.y);
        As[0][lrow][kb+1] = packbf(a0.z, a0.w);
        As[0][lrow][kb+2] = packbf(a1.x, a1.y);
        As[0][lrow][kb+3] = packbf(a1.z, a1.w);
        Bs[0][lrowB][kbB+0] = packbf(b0.x, b0.y);
        Bs[0][lrowB][kbB+1] = packbf(b0.z, b0.w);
    }
    __syncthreads();

    int wid = tid >> 5, lane = tid & 31;
    int lr = lane >> 2, lc = lane & 3;

    float acc[8][4];
    #pragma unroll
    for (int nt = 0; nt < 8; nt++)
        #pragma unroll
        for (int j = 0; j < 4; j++) acc[nt][j] = 0.f;

    int p = 0;
    for (int kt = 0; kt < K; kt += 16) {
        float4 a0, a1, b0;
        bool more = (kt + 16) < K;
        if (more) {
            a0 = *reinterpret_cast<const float4*>(Ap + kt + 16);
            a1 = *reinterpret_cast<const float4*>(Ap + kt + 20);
            b0 = *reinterpret_cast<const float4*>(Bp + kt + 16);
        }
        uint32_t afr[4];
        int arow = wid*16 + lr;
        afr[0] = As[p][arow    ][lc];
        afr[1] = As[p][arow + 8][lc];
        afr[2] = As[p][arow    ][lc + 4];
        afr[3] = As[p][arow + 8][lc + 4];
        uint32_t bfr[8][2];
        #pragma unroll
        for (int nt = 0; nt < 8; nt++) {
            int row = nt*8 + lr;
            bfr[nt][0] = Bs[p][row][lc];
            bfr[nt][1] = Bs[p][row][lc + 4];
        }
        #pragma unroll
        for (int nt = 0; nt < 8; nt++)
            mma_bf16(acc[nt], afr, bfr[nt]);
        if (more) {
            int q = p ^ 1;
            As[q][lrow][kb+0] = packbf(a0.x, a0.y);
            As[q][lrow][kb+1] = packbf(a0.z, a0.w);
            As[q][lrow][kb+2] = packbf(a1.x, a1.y);
            As[q][lrow][kb+3] = packbf(a1.z, a1.w);
            Bs[q][lrowB][kbB+0] = packbf(b0.x, b0.y);
            Bs[q][lrowB][kbB+1] = packbf(b0.z, b0.w);
        }
        __syncthreads();
        p ^= 1;
    }

    #pragma unroll
    for (int nt = 0; nt < 8; nt++) {
        int col = n0 + nt*8 + lc*2;
        float b0 = 0.f, b1 = 0.f;
        if (bias) { b0 = bias[col]; b1 = bias[col+1]; }
        int r0 = m0 + wid*16 + lr;
        int r1 = r0 + 8;
        float v00 = acc[nt][0] + b0;
        float v01 = acc[nt][1] + b1;
        float v10 = acc[nt][2] + b0;
        float v11 = acc[nt][3] + b1;
        if (addend) {
            const float* ad0 = addend + (size_t)r0*N + col;
            const float* ad1 = addend + (size_t)r1*N + col;
            v00 += ad0[0]; v01 += ad0[1];
            v10 += ad1[0]; v11 += ad1[1];
        }
        if (flags & 1) {
            v00 = 0.5f*v00*(1.f + erff(v00*0.70710678118654752f));
            v01 = 0.5f*v01*(1.f + erff(v01*0.70710678118654752f));
            v10 = 0.5f*v10*(1.f + erff(v10*0.70710678118654752f));
            v11 = 0.5f*v11*(1.f + erff(v11*0.70710678118654752f));
        }
        if (flags & 4) {   // transposed store: token r -> out[bt, c, n]
            int bt0 = r0 / NSP, nn0 = r0 % NSP;
            int bt1 = r1 / NSP, nn1 = r1 % NSP;
            C[((size_t)bt0*CDIM + col  )*NSP + nn0] = v00;
            C[((size_t)bt0*CDIM + col+1)*NSP + nn0] = v01;
            C[((size_t)bt1*CDIM + col  )*NSP + nn1] = v10;
            C[((size_t)bt1*CDIM + col+1)*NSP + nn1] = v11;
        } else {
            *reinterpret_cast<float2*>(&C[(size_t)r0*N + col]) = make_float2(v00, v01);
            *reinterpret_cast<float2*>(&C[(size_t)r1*N + col]) = make_float2(v10, v11);
        }
    }
}

// ---------------- conv4 depthwise + silu (float4) ----------------
__global__ __launch_bounds__(192) void conv_kernel(const float* __restrict__ scb,
                                                   const float* __restrict__ tcb)
{
    int m = blockIdx.y;
    int tid = threadIdx.x;
    int rl = tid / 96, v = tid % 96;
    int r = blockIdx.x * 2 + rl;
    int pos  = m ? ((r / NSP) & (TT-1)) : (r % NSP);
    int strd = m ? NSP : 1;
    const float* cb = m ? tcb : scb;
    float4 acc = *reinterpret_cast<const float4*>(&cb[4*v]);
    #pragma unroll
    for (int k = 0; k < 4; k++) {
        if (pos - 3 + k >= 0) {
            float4 xv = *reinterpret_cast<const float4*>(&g_xz[(size_t)(r - (3-k)*strd)*XZW + m*768 + 4*v]);
            float4 cw = *reinterpret_cast<const float4*>(&g_cwT[m][k*DI + 4*v]);
            acc.x = fmaf(cw.x, xv.x, acc.x);
            acc.y = fmaf(cw.y, xv.y, acc.y);
            acc.z = fmaf(cw.z, xv.z, acc.z);
            acc.w = fmaf(cw.w, xv.w, acc.w);
        }
    }
    acc.x = acc.x / (1.f + __expf(-acc.x));
    acc.y = acc.y / (1.f + __expf(-acc.y));
    acc.z = acc.z / (1.f + __expf(-acc.z));
    acc.w = acc.w / (1.f + __expf(-acc.w));
    *reinterpret_cast<float4*>(&g_u[m][(size_t)r*DI + 4*v]) = acc;
}

// ---------------- delta: softplus(dbc[:,:12] @ dpw^T + dpb), 16 tokens/block ------------
__global__ __launch_bounds__(384) void delta_kernel(const float* __restrict__ sdpb,
                                                    const float* __restrict__ tdpb)
{
    __shared__ float sw[DTR][DI];
    __shared__ float sdbc[16][DTR];
    int m = blockIdx.y;
    int r0 = blockIdx.x * 16;
    int d = threadIdx.x;
    const float* dpb = m ? tdpb : sdpb;
    #pragma unroll
    for (int rr = 0; rr < DTR; rr++)
        sw[rr][d] = g_dpwT[m][rr*DI + d];
    if (d < 16*DTR) {
        int t = d / DTR, c = d % DTR;
        sdbc[t][c] = g_dbc[m][(size_t)(r0 + t)*64 + c];
    }
    __syncthreads();
    float base = dpb[d];
    #pragma unroll 4
    for (int t = 0; t < 16; t++) {
        float acc = base;
        #pragma unroll
        for (int rr = 0; rr < DTR; rr++)
            acc = fmaf(sdbc[t][rr], sw[rr][d], acc);
        g_delta[m][(size_t)(r0 + t)*DI + d] = (acc > 15.f) ? acc : log1pf(__expf(acc));
    }
}

// ---------------- merged scans -----------------------------------------------------------
#define SPATIAL_BLOCKS 768
__global__ __launch_bounds__(128) void scan_kernel(const float* __restrict__ sD,
                                                   const float* __restrict__ tD)
{
    int bx = blockIdx.x;
    int tid = threadIdx.x;

    if (bx < SPATIAL_BLOCKS) {
        __shared__ float sbuf[64][8];
        int s   = bx / 48;
        int dpg = bx % 48;
        int w = tid >> 5, lane = tid & 31;
        int sub = lane >> 4, n = lane & 15;
        int d = dpg*8 + w*2 + sub;
        int ycol0 = dpg*8;

        float a  = g_A[0][d*DS + n];
        float Dd = sD[d];
        const float* delta = g_delta[0];
        const float* u     = g_u[0];
        const float* dbc   = g_dbc[0];
        int base = s * NSP;

        float h = 0.f;
        for (int pos = 0; pos < NSP; pos += 4) {
            float dl[4], uu[4], Bv[4], Cv[4];
            #pragma unroll
            for (int j = 0; j < 4; j++) {
                size_t r = base + pos + j;
                dl[j] = __ldg(&delta[r*DI + d]);
                uu[j] = __ldg(&u[r*DI + d]);
                Bv[j] = __ldg(&dbc[r*64 + DTR + n]);
                Cv[j] = __ldg(&dbc[r*64 + DTR + DS + n]);
            }
            float dA[4], dBu[4];
            #pragma unroll
            for (int j = 0; j < 4; j++) {
                dA[j]  = __expf(dl[j] * a);
                dBu[j] = dl[j] * uu[j] * Bv[j];
            }
            float part[4];
            #pragma unroll
            for (int j = 0; j < 4; j++) {
                h = fmaf(h, dA[j], dBu[j]);
                part[j] = h * Cv[j];
            }
            #pragma unroll
            for (int off = 1; off <= 8; off <<= 1)
                #pragma unroll
                for (int j = 0; j < 4; j++)
                    part[j] += __shfl_xor_sync(0xffffffffu, part[j], off);
            if (n == 0) {
                #pragma unroll
                for (int j = 0; j < 4; j++)
                    sbuf[(pos + j) & 63][w*2 + sub] = part[j] + uu[j] * Dd;
            }
            if ((pos & 63) == 60) {
                __syncthreads();
                int p2 = tid >> 1, half = tid & 1;
                size_t r = base + (pos & ~63) + p2;
                float4 v = *reinterpret_cast<float4*>(&sbuf[p2][half*4]);
                float4 z4 = *reinterpret_cast<const float4*>(&g_xz[r*XZW + 384 + ycol0 + half*4]);
                v.x *= z4.x / (1.f + __expf(-z4.x));
                v.y *= z4.y / (1.f + __expf(-z4.y));
                v.z *= z4.z / (1.f + __expf(-z4.z));
                v.w *= z4.w / (1.f + __expf(-z4.w));
                *reinterpret_cast<float4*>(&g_y[r*(2*DI) + ycol0 + half*4]) = v;
                __syncthreads();
            }
        }
    } else {
        int b2 = bx - SPATIAL_BLOCKS;
        int seq = b2 / 3;
        int d = (b2 % 3) * 128 + tid;
        int lane = tid & 31;
        int b = seq / NSP, nsp = seq % NSP;
        int base = b * (TT*NSP) + nsp;

        float a[DS];
        #pragma unroll
        for (int q = 0; q < 4; q++)
            *reinterpret_cast<float4*>(&a[q*4]) = *reinterpret_cast<const float4*>(&g_A[1][d*DS + q*4]);
        float Dd = tD[d];
        const float* delta = g_delta[1];
        const float* u     = g_u[1];
        const float* dbc   = g_dbc[1];

        float h[DS];
        #pragma unroll
        for (int q = 0; q < DS; q++) h[q] = 0.f;

        for (int t = 0; t < TT; t++) {
            size_t r = base + (size_t)t * NSP;
            float dl = delta[r*DI + d];
            float uu = u[r*DI + d];
            float bc = dbc[r*64 + DTR + lane];
            float dlu = dl * uu;
            float y = 0.f;
            #pragma unroll
            for (int q = 0; q < DS; q++) {
                float Bn = __shfl_sync(0xffffffffu, bc, q);
                float Cn = __shfl_sync(0xffffffffu, bc, q + 16);
                float dA = __expf(dl * a[q]);
                h[q] = fmaf(h[q], dA, dlu * Bn);
                y = fmaf(h[q], Cn, y);
            }
            float z = g_xz[r*XZW + 1152 + d];
            float g = z / (1.f + __expf(-z));
            g_y[r*(2*DI) + DI + d] = (y + uu * Dd) * g;
        }
    }
}

// ---------------- host launcher ----------------
extern "C" void kernel_launch(void* const* d_in, const int* in_sizes, int n_in,
                              void* d_out, int out_size)
{
    const float* x_in   = (const float*)d_in[0];
    const float* n1w    = (const float*)d_in[1];
    const float* n1b    = (const float*)d_in[2];
    const float* s_inw  = (const float*)d_in[3];
    const float* s_cw   = (const float*)d_in[4];
    const float* s_cb   = (const float*)d_in[5];
    const float* s_xpw  = (const float*)d_in[6];
    const float* s_dpw  = (const float*)d_in[7];
    const float* s_dpb  = (const float*)d_in[8];
    const float* s_Alog = (const float*)d_in[9];
    const float* s_D    = (const float*)d_in[10];
    const float* s_outw = (const float*)d_in[11];
    const float* t_inw  = (const float*)d_in[12];
    const float* t_cw   = (const float*)d_in[13];
    const float* t_cb   = (const float*)d_in[14];
    const float* t_xpw  = (const float*)d_in[15];
    const float* t_dpw  = (const float*)d_in[16];
    const float* t_dpb  = (const float*)d_in[17];
    const float* t_Alog = (const float*)d_in[18];
    const float* t_D    = (const float*)d_in[19];
    const float* t_outw = (const float*)d_in[20];
    const float* fw     = (const float*)d_in[21];
    const float* fb     = (const float*)d_in[22];
    const float* n2w    = (const float*)d_in[23];
    const float* n2b    = (const float*)d_in[24];
    const float* w1     = (const float*)d_in[25];
    const float* b1     = (const float*)d_in[26];
    const float* w2     = (const float*)d_in[27];
    const float* b2     = (const float*)d_in[28];
    float* out = (float*)d_out;

    float *p_xn, *p_short, *p_xz, *p_y, *p_x2, *p_h, *p_hid, *p_W12, *p_Win, *p_u, *p_dbc, *p_xpwP;
    cudaGetSymbolAddress((void**)&p_xn,   g_xn);
    cudaGetSymbolAddress((void**)&p_short,g_short);
    cudaGetSymbolAddress((void**)&p_xz,   g_xz);
    cudaGetSymbolAddress((void**)&p_y,    g_y);
    cudaGetSymbolAddress((void**)&p_x2,   g_x2);
    cudaGetSymbolAddress((void**)&p_h,    g_h);
    cudaGetSymbolAddress((void**)&p_hid,  g_hid);
    cudaGetSymbolAddress((void**)&p_W12,  g_W12);
    cudaGetSymbolAddress((void**)&p_Win,  g_Win);
    cudaGetSymbolAddress((void**)&p_u,    g_u);
    cudaGetSymbolAddress((void**)&p_dbc,  g_dbc);
    cudaGetSymbolAddress((void**)&p_xpwP, g_xpwP);

    // 0. prep + fold (independent)
    prep_kernel<<<1152, 256>>>(s_Alog, t_Alog, s_cw, t_cw, s_dpw, t_dpw,
                               s_inw, t_inw, s_xpw, t_xpw);
    fold_kernel<<<dim3(24, 2), 384>>>(fw, s_outw, t_outw);

    // 1. transpose + LN1
    ln1_kernel<<<dim3(16, 18), 256>>>(x_in, n1w, n1b);

    // 2. merged in_proj GEMM (N=1536, K=192)
    bgemm_kernel<<<dim3(XZW/128, TOK/128), 256>>>(p_xn, p_Win, p_xz, nullptr, nullptr, TOK, XZW, CDIM, 0);

    // 3. conv+silu
    conv_kernel<<<dim3(TOK/2, 2), 192>>>(s_cb, t_cb);

    // 4. dbc = u @ xpwP^T (N=64, K=384), both mambas via z
    bgemm64_kernel<<<dim3(1, TOK/128, 2), 256>>>(p_u, p_xpwP, p_dbc, nullptr, nullptr, TOK, 64, DI, 8);

    // 5. delta = softplus(dt @ dpw^T + dpb)
    delta_kernel<<<dim3(TOK/16, 2), 384>>>(s_dpb, t_dpb);

    // 6. both selective scans, one launch
    scan_kernel<<<SPATIAL_BLOCKS + 3456, 128>>>(s_D, t_D);

    // 7. merged out_proj + fusion + residual (N=192, K=768)
    bgemm64_kernel<<<dim3(3, TOK/128), 256>>>(p_y, p_W12, p_x2, fb, p_short, TOK, CDIM, 2*DI, 0);

    // 8. LN2 + MLP (mlp2 stores directly transposed into d_out)
    ln2_kernel<<<TOK/4, 128>>>(p_x2, p_h, n2w, n2b);
    bgemm_kernel<<<dim3(MLPH/128, TOK/128), 256>>>(p_h, w1, p_hid, b1, nullptr, TOK, MLPH, CDIM, 1);
    bgemm64_kernel<<<dim3(3, TOK/128), 256>>>(p_hid, w2, out, b2, p_x2, TOK, CDIM, MLPH, 4);
}

// round 9
// speedup vs baseline: 3.0385x; 1.0281x over previous
#include <cuda_runtime.h>
#include <cuda_bf16.h>
#include <math.h>
#include <stdint.h>

// ---------------- problem constants ----------------
#define BQ    2
#define TT    8
#define CDIM  192
#define NSP   576
#define TOK   9216
#define DI    384
#define DS    16
#define DTR   12
#define MLPH  768
#define XZW   1536

typedef __nv_bfloat16 bf16;

// ---------------- scratch ----------------
__device__ bf16  g_xn_bf[TOK*CDIM];
__device__ float g_short[TOK*CDIM];
__device__ float g_xz[TOK*XZW];
__device__ float g_u[2][TOK*DI];
__device__ bf16  g_u_bf[2][TOK*DI];
__device__ float g_delta[2][TOK*DI];
__device__ float g_dbc[2][TOK*64];
__device__ bf16  g_y_bf[TOK*2*DI];
__device__ float g_x2[TOK*CDIM];
__device__ bf16  g_h_bf[TOK*CDIM];
__device__ bf16  g_hid_bf[TOK*MLPH];
__device__ bf16  g_Win_bf[XZW*CDIM];
__device__ bf16  g_W12_bf[CDIM*2*DI];
__device__ bf16  g_xpwP_bf[2][64*DI];
__device__ bf16  g_w1_bf[MLPH*CDIM];
__device__ bf16  g_w2_bf[CDIM*MLPH];
__device__ float g_A[2][DI*DS];
__device__ float g_cwT[2][4*DI];
__device__ float g_dpwT[2][DTR*DI];

// ---------------- helpers ----------------
__device__ __forceinline__ uint32_t packbf(float lo, float hi) {
    uint32_t r;
    asm("cvt.rn.bf16x2.f32 %0, %1, %2;" : "=r"(r) : "f"(hi), "f"(lo));
    return r;
}
__device__ __forceinline__ void mma_bf16(float c[4], const uint32_t a[4], const uint32_t b[2]) {
    asm("mma.sync.aligned.m16n8k16.row.col.f32.bf16.bf16.f32 "
        "{%0,%1,%2,%3}, {%4,%5,%6,%7}, {%8,%9}, {%0,%1,%2,%3};"
        : "+f"(c[0]), "+f"(c[1]), "+f"(c[2]), "+f"(c[3])
        : "r"(a[0]), "r"(a[1]), "r"(a[2]), "r"(a[3]), "r"(b[0]), "r"(b[1]));
}

// ---------------- prep ----------------
__global__ void prep_kernel(const float* __restrict__ sAlog, const float* __restrict__ tAlog,
                            const float* __restrict__ scw, const float* __restrict__ tcw,
                            const float* __restrict__ sdpw, const float* __restrict__ tdpw,
                            const float* __restrict__ sinw, const float* __restrict__ tinw,
                            const float* __restrict__ sxpw, const float* __restrict__ txpw,
                            const float* __restrict__ w1, const float* __restrict__ w2)
{
    int i = blockIdx.x * blockDim.x + threadIdx.x;
    if (i < 2*DI*DS) {
        int m = i / (DI*DS), j = i % (DI*DS);
        g_A[m][j] = -expf(m ? tAlog[j] : sAlog[j]);
    }
    if (i < 2*4*DI) {
        int m = i / (4*DI), rem = i % (4*DI);
        int k = rem / DI, d = rem % DI;
        g_cwT[m][k*DI + d] = (m ? tcw : scw)[d*4 + k];
    }
    if (i < 2*DTR*DI) {
        int m = i / (DTR*DI), rem = i % (DTR*DI);
        int rr = rem / DI, d = rem % DI;
        g_dpwT[m][rr*DI + d] = (m ? tdpw : sdpw)[d*DTR + rr];
    }
    if (i < 2*64*DI) {
        int m = i / (64*DI), rem = i % (64*DI);
        int row = rem / DI;
        g_xpwP_bf[m][rem] = __float2bfloat16(
            (row < DTR + 2*DS) ? (m ? txpw : sxpw)[rem] : 0.f);
    }
    if (i < XZW*CDIM) {
        int row = i / CDIM;
        g_Win_bf[i] = __float2bfloat16((row < 768) ? sinw[i] : tinw[i - 768*CDIM]);
    }
    if (i < MLPH*CDIM) g_w1_bf[i] = __float2bfloat16(w1[i]);
    if (i < CDIM*MLPH) g_w2_bf[i] = __float2bfloat16(w2[i]);
}

// ---------------- fold ----------------
__global__ __launch_bounds__(384) void fold_kernel(const float* __restrict__ fw,
                                                   const float* __restrict__ soutw,
                                                   const float* __restrict__ toutw)
{
    __shared__ float fwS[8][192];
    int m  = blockIdx.y;
    int c0 = blockIdx.x * 8;
    const float* ow = m ? toutw : soutw;
    int tid = threadIdx.x;
    for (int i = tid; i < 8*192; i += 384) {
        int c = i / 192, cp = i % 192;
        fwS[c][cp] = fw[(size_t)(c0 + c)*(2*CDIM) + m*CDIM + cp];
    }
    __syncthreads();
    float acc[8] = {0,0,0,0,0,0,0,0};
    #pragma unroll 4
    for (int cp = 0; cp < 192; cp++) {
        float owv = ow[(size_t)cp*DI + tid];
        #pragma unroll
        for (int c = 0; c < 8; c++) acc[c] = fmaf(fwS[c][cp], owv, acc[c]);
    }
    #pragma unroll
    for (int c = 0; c < 8; c++)
        g_W12_bf[(size_t)(c0 + c)*(2*DI) + m*DI + tid] = __float2bfloat16(acc[c]);
}

// ---------------- LN1 (transpose + norm; bf16 out, fp32 shortcut) ----------------
__global__ __launch_bounds__(256) void ln1_kernel(const float* __restrict__ src,
                                                  const float* __restrict__ w, const float* __restrict__ b)
{
    __shared__ float s[CDIM][33];
    int bt = blockIdx.x;
    int n0 = blockIdx.y * 32;
    int tid = threadIdx.x;
    #pragma unroll
    for (int i = 0; i < 24; i++) {
        int idx = tid + 256*i;
        int c = idx >> 5, nl = idx & 31;
        s[c][nl] = src[((size_t)bt*CDIM + c)*NSP + n0 + nl];
    }
    __syncthreads();
    int warp = tid >> 5, lane = tid & 31;
    for (int jj = 0; jj < 4; jj++) {
        int tt = warp + 8*jj;
        float v[3][2];
        #pragma unroll
        for (int q = 0; q < 3; q++) {
            int c = 2*lane + 64*q;
            v[q][0] = s[c][tt];
            v[q][1] = s[c+1][tt];
        }
        float sum = 0.f;
        #pragma unroll
        for (int q = 0; q < 3; q++) sum += v[q][0] + v[q][1];
        #pragma unroll
        for (int o = 16; o > 0; o >>= 1) sum += __shfl_xor_sync(0xffffffffu, sum, o);
        float mean = sum * (1.f/CDIM);
        float qv = 0.f;
        #pragma unroll
        for (int q = 0; q < 3; q++) {
            float d0 = v[q][0]-mean, d1 = v[q][1]-mean;
            qv += d0*d0 + d1*d1;
        }
        #pragma unroll
        for (int o = 16; o > 0; o >>= 1) qv += __shfl_xor_sync(0xffffffffu, qv, o);
        float rstd = rsqrtf(qv * (1.f/CDIM) + 1e-5f);
        size_t tok = (size_t)bt*NSP + n0 + tt;
        #pragma unroll
        for (int q = 0; q < 3; q++) {
            int c = 2*lane + 64*q;
            float o0 = (v[q][0]-mean)*rstd*w[c]   + b[c];
            float o1 = (v[q][1]-mean)*rstd*w[c+1] + b[c+1];
            *reinterpret_cast<uint32_t*>(&g_xn_bf[tok*CDIM + c]) = packbf(o0, o1);
            *reinterpret_cast<float2*>(&g_short[tok*CDIM + c]) = make_float2(v[q][0], v[q][1]);
        }
    }
}

// ---------------- LN2 (bf16 out) ----------------
__global__ void ln2_kernel(const float* __restrict__ src,
                           const float* __restrict__ w, const float* __restrict__ b)
{
    int tok  = blockIdx.x * 4 + (threadIdx.x >> 5);
    int lane = threadIdx.x & 31;
    const float* base = src + (size_t)tok * CDIM;
    float v[3][2];
    #pragma unroll
    for (int q = 0; q < 3; q++) {
        float2 t = *reinterpret_cast<const float2*>(&base[2*lane + 64*q]);
        v[q][0] = t.x; v[q][1] = t.y;
    }
    float s = 0.f;
    #pragma unroll
    for (int q = 0; q < 3; q++) s += v[q][0] + v[q][1];
    #pragma unroll
    for (int o = 16; o > 0; o >>= 1) s += __shfl_xor_sync(0xffffffffu, s, o);
    float mean = s * (1.f / CDIM);
    float qv = 0.f;
    #pragma unroll
    for (int q = 0; q < 3; q++) {
        float d0 = v[q][0]-mean, d1 = v[q][1]-mean;
        qv += d0*d0 + d1*d1;
    }
    #pragma unroll
    for (int o = 16; o > 0; o >>= 1) qv += __shfl_xor_sync(0xffffffffu, qv, o);
    float rstd = rsqrtf(qv * (1.f / CDIM) + 1e-5f);
    #pragma unroll
    for (int q = 0; q < 3; q++) {
        int c = 2*lane + 64*q;
        float o0 = (v[q][0]-mean)*rstd*w[c]   + b[c];
        float o1 = (v[q][1]-mean)*rstd*w[c+1] + b[c+1];
        *reinterpret_cast<uint32_t*>(&g_h_bf[(size_t)tok*CDIM + c]) = packbf(o0, o1);
    }
}

// ---------------- bgemm: bf16-native GEMM, 128x128 block --------------------------------
// flags: bit0 gelu | bit4 bf16 C store
__global__ __launch_bounds__(256) void bgemm_kernel(
    const bf16* __restrict__ A, const bf16* __restrict__ B, void* __restrict__ Cv,
    const float* __restrict__ bias, const float* __restrict__ addend,
    int M, int N, int K, int flags)
{
    __shared__ uint32_t As[2][128][12];
    __shared__ uint32_t Bs[2][128][12];
    int tid = threadIdx.x;
    int m0 = blockIdx.y * 128, n0 = blockIdx.x * 128;

    int lrow = tid >> 1;
    int lk   = (tid & 1) * 8;
    int kb   = (tid & 1) * 4;
    const bf16* Ap = A + (size_t)(m0 + lrow) * K + lk;
    const bf16* Bp = B + (size_t)(n0 + lrow) * K + lk;

    {
        uint4 a = *reinterpret_cast<const uint4*>(Ap);
        uint4 b = *reinterpret_cast<const uint4*>(Bp);
        *reinterpret_cast<uint4*>(&As[0][lrow][kb]) = a;
        *reinterpret_cast<uint4*>(&Bs[0][lrow][kb]) = b;
    }
    __syncthreads();

    int wid = tid >> 5, lane = tid & 31;
    int wm = wid >> 1, wn = wid & 1;
    int lr = lane >> 2, lc = lane & 3;

    float acc[2][8][4];
    #pragma unroll
    for (int mt = 0; mt < 2; mt++)
        #pragma unroll
        for (int nt = 0; nt < 8; nt++)
            #pragma unroll
            for (int j = 0; j < 4; j++) acc[mt][nt][j] = 0.f;

    int p = 0;
    for (int kt = 0; kt < K; kt += 16) {
        uint4 a, b;
        bool more = (kt + 16) < K;
        if (more) {
            a = *reinterpret_cast<const uint4*>(Ap + kt + 16);
            b = *reinterpret_cast<const uint4*>(Bp + kt + 16);
        }
        uint32_t afr[2][4];
        #pragma unroll
        for (int mt = 0; mt < 2; mt++) {
            int row = wm*32 + mt*16 + lr;
            afr[mt][0] = As[p][row    ][lc];
            afr[mt][1] = As[p][row + 8][lc];
            afr[mt][2] = As[p][row    ][lc + 4];
            afr[mt][3] = As[p][row + 8][lc + 4];
        }
        uint32_t bfr[8][2];
        #pragma unroll
        for (int nt = 0; nt < 8; nt++) {
            int row = wn*64 + nt*8 + lr;
            bfr[nt][0] = Bs[p][row][lc];
            bfr[nt][1] = Bs[p][row][lc + 4];
        }
        #pragma unroll
        for (int mt = 0; mt < 2; mt++)
            #pragma unroll
            for (int nt = 0; nt < 8; nt++)
                mma_bf16(acc[mt][nt], afr[mt], bfr[nt]);
        if (more) {
            int q = p ^ 1;
            *reinterpret_cast<uint4*>(&As[q][lrow][kb]) = a;
            *reinterpret_cast<uint4*>(&Bs[q][lrow][kb]) = b;
        }
        __syncthreads();
        p ^= 1;
    }

    float* C = (float*)Cv;
    bf16*  Cb = (bf16*)Cv;
    #pragma unroll
    for (int nt = 0; nt < 8; nt++) {
        int col = n0 + wn*64 + nt*8 + lc*2;
        float b0 = 0.f, b1 = 0.f;
        if (bias) { b0 = bias[col]; b1 = bias[col+1]; }
        #pragma unroll
        for (int mt = 0; mt < 2; mt++) {
            int r0 = m0 + wm*32 + mt*16 + lr;
            int r1 = r0 + 8;
            float v00 = acc[mt][nt][0] + b0;
            float v01 = acc[mt][nt][1] + b1;
            float v10 = acc[mt][nt][2] + b0;
            float v11 = acc[mt][nt][3] + b1;
            if (addend) {
                const float* ad0 = addend + (size_t)r0*N + col;
                const float* ad1 = addend + (size_t)r1*N + col;
                v00 += ad0[0]; v01 += ad0[1];
                v10 += ad1[0]; v11 += ad1[1];
            }
            if (flags & 1) {
                v00 = 0.5f*v00*(1.f + erff(v00*0.70710678118654752f));
                v01 = 0.5f*v01*(1.f + erff(v01*0.70710678118654752f));
                v10 = 0.5f*v10*(1.f + erff(v10*0.70710678118654752f));
                v11 = 0.5f*v11*(1.f + erff(v11*0.70710678118654752f));
            }
            if (flags & 16) {
                *reinterpret_cast<uint32_t*>(&Cb[(size_t)r0*N + col]) = packbf(v00, v01);
                *reinterpret_cast<uint32_t*>(&Cb[(size_t)r1*N + col]) = packbf(v10, v11);
            } else {
                *reinterpret_cast<float2*>(&C[(size_t)r0*N + col]) = make_float2(v00, v01);
                *reinterpret_cast<float2*>(&C[(size_t)r1*N + col]) = make_float2(v10, v11);
            }
        }
    }
}

// ---------------- bgemm64: bf16-native GEMM, 128x64 block -------------------------------
// flags: bit0 gelu | bit2 transposed store | bit3 z-split
__global__ __launch_bounds__(256) void bgemm64_kernel(
    const bf16* __restrict__ A, const bf16* __restrict__ B, float* __restrict__ C,
    const float* __restrict__ bias, const float* __restrict__ addend,
    int M, int N, int K, int flags)
{
    __shared__ uint32_t As[2][128][12];
    __shared__ uint32_t Bs[2][64][12];
    int tid = threadIdx.x;
    int m0 = blockIdx.y * 128, n0 = blockIdx.x * 64;
    if (flags & 8) {
        int z = blockIdx.z;
        A += (size_t)z * M * K;
        B += (size_t)z * N * K;
        C += (size_t)z * M * N;
    }

    int lrow = tid >> 1;
    int lk   = (tid & 1) * 8;
    int kb   = (tid & 1) * 4;
    const bf16* Ap = A + (size_t)(m0 + lrow) * K + lk;
    int lrowB = tid >> 2;
    int lkB   = (tid & 3) * 4;
    int kbB   = (tid & 3) * 2;
    const bf16* Bp = B + (size_t)(n0 + lrowB) * K + lkB;

    {
        uint4 a = *reinterpret_cast<const uint4*>(Ap);
        uint2 b = *reinterpret_cast<const uint2*>(Bp);
        *reinterpret_cast<uint4*>(&As[0][lrow][kb]) = a;
        *reinterpret_cast<uint2*>(&Bs[0][lrowB][kbB]) = b;
    }
    __syncthreads();

    int wid = tid >> 5, lane = tid & 31;
    int lr = lane >> 2, lc = lane & 3;

    float acc[8][4];
    #pragma unroll
    for (int nt = 0; nt < 8; nt++)
        #pragma unroll
        for (int j = 0; j < 4; j++) acc[nt][j] = 0.f;

    int p = 0;
    for (int kt = 0; kt < K; kt += 16) {
        uint4 a; uint2 b;
        bool more = (kt + 16) < K;
        if (more) {
            a = *reinterpret_cast<const uint4*>(Ap + kt + 16);
            b = *reinterpret_cast<const uint2*>(Bp + kt + 16);
        }
        uint32_t afr[4];
        int arow = wid*16 + lr;
        afr[0] = As[p][arow    ][lc];
        afr[1] = As[p][arow + 8][lc];
        afr[2] = As[p][arow    ][lc + 4];
        afr[3] = As[p][arow + 8][lc + 4];
        uint32_t bfr[8][2];
        #pragma unroll
        for (int nt = 0; nt < 8; nt++) {
            int row = nt*8 + lr;
            bfr[nt][0] = Bs[p][row][lc];
            bfr[nt][1] = Bs[p][row][lc + 4];
        }
        #pragma unroll
        for (int nt = 0; nt < 8; nt++)
            mma_bf16(acc[nt], afr, bfr[nt]);
        if (more) {
            int q = p ^ 1;
            *reinterpret_cast<uint4*>(&As[q][lrow][kb]) = a;
            *reinterpret_cast<uint2*>(&Bs[q][lrowB][kbB]) = b;
        }
        __syncthreads();
        p ^= 1;
    }

    #pragma unroll
    for (int nt = 0; nt < 8; nt++) {
        int col = n0 + nt*8 + lc*2;
        float b0 = 0.f, b1 = 0.f;
        if (bias) { b0 = bias[col]; b1 = bias[col+1]; }
        int r0 = m0 + wid*16 + lr;
        int r1 = r0 + 8;
        float v00 = acc[nt][0] + b0;
        float v01 = acc[nt][1] + b1;
        float v10 = acc[nt][2] + b0;
        float v11 = acc[nt][3] + b1;
        if (addend) {
            const float* ad0 = addend + (size_t)r0*N + col;
            const float* ad1 = addend + (size_t)r1*N + col;
            v00 += ad0[0]; v01 += ad0[1];
            v10 += ad1[0]; v11 += ad1[1];
        }
        if (flags & 1) {
            v00 = 0.5f*v00*(1.f + erff(v00*0.70710678118654752f));
            v01 = 0.5f*v01*(1.f + erff(v01*0.70710678118654752f));
            v10 = 0.5f*v10*(1.f + erff(v10*0.70710678118654752f));
            v11 = 0.5f*v11*(1.f + erff(v11*0.70710678118654752f));
        }
        if (flags & 4) {
            int bt0 = r0 / NSP, nn0 = r0 % NSP;
            int bt1 = r1 / NSP, nn1 = r1 % NSP;
            C[((size_t)bt0*CDIM + col  )*NSP + nn0] = v00;
            C[((size_t)bt0*CDIM + col+1)*NSP + nn0] = v01;
            C[((size_t)bt1*CDIM + col  )*NSP + nn1] = v10;
            C[((size_t)bt1*CDIM + col+1)*NSP + nn1] = v11;
        } else {
            *reinterpret_cast<float2*>(&C[(size_t)r0*N + col]) = make_float2(v00, v01);
            *reinterpret_cast<float2*>(&C[(size_t)r1*N + col]) = make_float2(v10, v11);
        }
    }
}

// ---------------- conv4 depthwise + silu ----------------
__global__ __launch_bounds__(192) void conv_kernel(const float* __restrict__ scb,
                                                   const float* __restrict__ tcb)
{
    int m = blockIdx.y;
    int tid = threadIdx.x;
    int rl = tid / 96, v = tid % 96;
    int r = blockIdx.x * 2 + rl;
    int pos  = m ? ((r / NSP) & (TT-1)) : (r % NSP);
    int strd = m ? NSP : 1;
    const float* cb = m ? tcb : scb;
    float4 acc = *reinterpret_cast<const float4*>(&cb[4*v]);
    #pragma unroll
    for (int k = 0; k < 4; k++) {
        if (pos - 3 + k >= 0) {
            float4 xv = *reinterpret_cast<const float4*>(&g_xz[(size_t)(r - (3-k)*strd)*XZW + m*768 + 4*v]);
            float4 cw = *reinterpret_cast<const float4*>(&g_cwT[m][k*DI + 4*v]);
            acc.x = fmaf(cw.x, xv.x, acc.x);
            acc.y = fmaf(cw.y, xv.y, acc.y);
            acc.z = fmaf(cw.z, xv.z, acc.z);
            acc.w = fmaf(cw.w, xv.w, acc.w);
        }
    }
    acc.x = acc.x / (1.f + __expf(-acc.x));
    acc.y = acc.y / (1.f + __expf(-acc.y));
    acc.z = acc.z / (1.f + __expf(-acc.z));
    acc.w = acc.w / (1.f + __expf(-acc.w));
    *reinterpret_cast<float4*>(&g_u[m][(size_t)r*DI + 4*v]) = acc;
    uint2 pk = make_uint2(packbf(acc.x, acc.y), packbf(acc.z, acc.w));
    *reinterpret_cast<uint2*>(&g_u_bf[m][(size_t)r*DI + 4*v]) = pk;
}

// ---------------- delta ----------------
__global__ __launch_bounds__(384) void delta_kernel(const float* __restrict__ sdpb,
                                                    const float* __restrict__ tdpb)
{
    __shared__ float sw[DTR][DI];
    __shared__ float sdbc[16][DTR];
    int m = blockIdx.y;
    int r0 = blockIdx.x * 16;
    int d = threadIdx.x;
    const float* dpb = m ? tdpb : sdpb;
    #pragma unroll
    for (int rr = 0; rr < DTR; rr++)
        sw[rr][d] = g_dpwT[m][rr*DI + d];
    if (d < 16*DTR) {
        int t = d / DTR, c = d % DTR;
        sdbc[t][c] = g_dbc[m][(size_t)(r0 + t)*64 + c];
    }
    __syncthreads();
    float base = dpb[d];
    #pragma unroll 4
    for (int t = 0; t < 16; t++) {
        float acc = base;
        #pragma unroll
        for (int rr = 0; rr < DTR; rr++)
            acc = fmaf(sdbc[t][rr], sw[rr][d], acc);
        g_delta[m][(size_t)(r0 + t)*DI + d] = (acc > 15.f) ? acc : log1pf(__expf(acc));
    }
}

// ---------------- merged scans ----------------
#define SPATIAL_BLOCKS 768
__global__ __launch_bounds__(128) void scan_kernel(const float* __restrict__ sD,
                                                   const float* __restrict__ tD)
{
    int bx = blockIdx.x;
    int tid = threadIdx.x;

    if (bx < SPATIAL_BLOCKS) {
        __shared__ float sbuf[64][8];
        int s   = bx / 48;
        int dpg = bx % 48;
        int w = tid >> 5, lane = tid & 31;
        int sub = lane >> 4, n = lane & 15;
        int d = dpg*8 + w*2 + sub;
        int ycol0 = dpg*8;

        float a  = g_A[0][d*DS + n];
        float Dd = sD[d];
        const float* delta = g_delta[0];
        const float* u     = g_u[0];
        const float* dbc   = g_dbc[0];
        int base = s * NSP;

        float h = 0.f;
        for (int pos = 0; pos < NSP; pos += 4) {
            float dl[4], uu[4], Bv[4], Cv[4];
            #pragma unroll
            for (int j = 0; j < 4; j++) {
                size_t r = base + pos + j;
                dl[j] = __ldg(&delta[r*DI + d]);
                uu[j] = __ldg(&u[r*DI + d]);
                Bv[j] = __ldg(&dbc[r*64 + DTR + n]);
                Cv[j] = __ldg(&dbc[r*64 + DTR + DS + n]);
            }
            float dA[4], dBu[4];
            #pragma unroll
            for (int j = 0; j < 4; j++) {
                dA[j]  = __expf(dl[j] * a);
                dBu[j] = dl[j] * uu[j] * Bv[j];
            }
            float part[4];
            #pragma unroll
            for (int j = 0; j < 4; j++) {
                h = fmaf(h, dA[j], dBu[j]);
                part[j] = h * Cv[j];
            }
            #pragma unroll
            for (int off = 1; off <= 8; off <<= 1)
                #pragma unroll
                for (int j = 0; j < 4; j++)
                    part[j] += __shfl_xor_sync(0xffffffffu, part[j], off);
            if (n == 0) {
                #pragma unroll
                for (int j = 0; j < 4; j++)
                    sbuf[(pos + j) & 63][w*2 + sub] = part[j] + uu[j] * Dd;
            }
            if ((pos & 63) == 60) {
                __syncthreads();
                int p2 = tid >> 1, half = tid & 1;
                size_t r = base + (pos & ~63) + p2;
                float4 v = *reinterpret_cast<float4*>(&sbuf[p2][half*4]);
                float4 z4 = *reinterpret_cast<const float4*>(&g_xz[r*XZW + 384 + ycol0 + half*4]);
                v.x *= z4.x / (1.f + __expf(-z4.x));
                v.y *= z4.y / (1.f + __expf(-z4.y));
                v.z *= z4.z / (1.f + __expf(-z4.z));
                v.w *= z4.w / (1.f + __expf(-z4.w));
                uint2 pk = make_uint2(packbf(v.x, v.y), packbf(v.z, v.w));
                *reinterpret_cast<uint2*>(&g_y_bf[r*(2*DI) + ycol0 + half*4]) = pk;
                __syncthreads();
            }
        }
    } else {
        int b2 = bx - SPATIAL_BLOCKS;
        int seq = b2 / 3;
        int d = (b2 % 3) * 128 + tid;
        int lane = tid & 31;
        int b = seq / NSP, nsp = seq % NSP;
        int base = b * (TT*NSP) + nsp;

        float a[DS];
        #pragma unroll
        for (int q = 0; q < 4; q++)
            *reinterpret_cast<float4*>(&a[q*4]) = *reinterpret_cast<const float4*>(&g_A[1][d*DS + q*4]);
        float Dd = tD[d];
        const float* delta = g_delta[1];
        const float* u     = g_u[1];
        const float* dbc   = g_dbc[1];

        float h[DS];
        #pragma unroll
        for (int q = 0; q < DS; q++) h[q] = 0.f;

        for (int t = 0; t < TT; t++) {
            size_t r = base + (size_t)t * NSP;
            float dl = delta[r*DI + d];
            float uu = u[r*DI + d];
            float bc = dbc[r*64 + DTR + lane];
            float dlu = dl * uu;
            float y = 0.f;
            #pragma unroll
            for (int q = 0; q < DS; q++) {
                float Bn = __shfl_sync(0xffffffffu, bc, q);
                float Cn = __shfl_sync(0xffffffffu, bc, q + 16);
                float dA = __expf(dl * a[q]);
                h[q] = fmaf(h[q], dA, dlu * Bn);
                y = fmaf(h[q], Cn, y);
            }
            float z = g_xz[r*XZW + 1152 + d];
            float g = z / (1.f + __expf(-z));
            g_y_bf[r*(2*DI) + DI + d] = __float2bfloat16((y + uu * Dd) * g);
        }
    }
}

// ---------------- host launcher ----------------
extern "C" void kernel_launch(void* const* d_in, const int* in_sizes, int n_in,
                              void* d_out, int out_size)
{
    const float* x_in   = (const float*)d_in[0];
    const float* n1w    = (const float*)d_in[1];
    const float* n1b    = (const float*)d_in[2];
    const float* s_inw  = (const float*)d_in[3];
    const float* s_cw   = (const float*)d_in[4];
    const float* s_cb   = (const float*)d_in[5];
    const float* s_xpw  = (const float*)d_in[6];
    const float* s_dpw  = (const float*)d_in[7];
    const float* s_dpb  = (const float*)d_in[8];
    const float* s_Alog = (const float*)d_in[9];
    const float* s_D    = (const float*)d_in[10];
    const float* s_outw = (const float*)d_in[11];
    const float* t_inw  = (const float*)d_in[12];
    const float* t_cw   = (const float*)d_in[13];
    const float* t_cb   = (const float*)d_in[14];
    const float* t_xpw  = (const float*)d_in[15];
    const float* t_dpw  = (const float*)d_in[16];
    const float* t_dpb  = (const float*)d_in[17];
    const float* t_Alog = (const float*)d_in[18];
    const float* t_D    = (const float*)d_in[19];
    const float* t_outw = (const float*)d_in[20];
    const float* fw     = (const float*)d_in[21];
    const float* fb     = (const float*)d_in[22];
    const float* n2w    = (const float*)d_in[23];
    const float* n2b    = (const float*)d_in[24];
    const float* w1     = (const float*)d_in[25];
    const float* b1     = (const float*)d_in[26];
    const float* w2     = (const float*)d_in[27];
    const float* b2     = (const float*)d_in[28];
    float* out = (float*)d_out;

    bf16 *p_xn_bf, *p_u_bf, *p_y_bf, *p_h_bf, *p_hid_bf, *p_Win_bf, *p_W12_bf, *p_xpwP_bf, *p_w1_bf, *p_w2_bf;
    float *p_short, *p_xz, *p_x2, *p_dbc;
    cudaGetSymbolAddress((void**)&p_xn_bf, g_xn_bf);
    cudaGetSymbolAddress((void**)&p_short, g_short);
    cudaGetSymbolAddress((void**)&p_xz,    g_xz);
    cudaGetSymbolAddress((void**)&p_u_bf,  g_u_bf);
    cudaGetSymbolAddress((void**)&p_dbc,   g_dbc);
    cudaGetSymbolAddress((void**)&p_y_bf,  g_y_bf);
    cudaGetSymbolAddress((void**)&p_x2,    g_x2);
    cudaGetSymbolAddress((void**)&p_h_bf,  g_h_bf);
    cudaGetSymbolAddress((void**)&p_hid_bf,g_hid_bf);
    cudaGetSymbolAddress((void**)&p_Win_bf,g_Win_bf);
    cudaGetSymbolAddress((void**)&p_W12_bf,g_W12_bf);
    cudaGetSymbolAddress((void**)&p_xpwP_bf,g_xpwP_bf);
    cudaGetSymbolAddress((void**)&p_w1_bf, g_w1_bf);
    cudaGetSymbolAddress((void**)&p_w2_bf, g_w2_bf);

    // 0. prep + fold
    prep_kernel<<<1152, 256>>>(s_Alog, t_Alog, s_cw, t_cw, s_dpw, t_dpw,
                               s_inw, t_inw, s_xpw, t_xpw, w1, w2);
    fold_kernel<<<dim3(24, 2), 384>>>(fw, s_outw, t_outw);

    // 1. transpose + LN1 (bf16 out + fp32 shortcut)
    ln1_kernel<<<dim3(16, 18), 256>>>(x_in, n1w, n1b);

    // 2. merged in_proj GEMM (N=1536, K=192), fp32 out
    bgemm_kernel<<<dim3(XZW/128, TOK/128), 256>>>(p_xn_bf, p_Win_bf, p_xz, nullptr, nullptr, TOK, XZW, CDIM, 0);

    // 3. conv+silu (fp32 + bf16 out)
    conv_kernel<<<dim3(TOK/2, 2), 192>>>(s_cb, t_cb);

    // 4. dbc = u @ xpwP^T (N=64, K=384), both mambas via z, fp32 out
    bgemm64_kernel<<<dim3(1, TOK/128, 2), 256>>>(p_u_bf, p_xpwP_bf, p_dbc, nullptr, nullptr, TOK, 64, DI, 8);

    // 5. delta
    delta_kernel<<<dim3(TOK/16, 2), 384>>>(s_dpb, t_dpb);

    // 6. scans (bf16 y out)
    scan_kernel<<<SPATIAL_BLOCKS + 3456, 128>>>(s_D, t_D);

    // 7. fusion + residual (N=192, K=768), fp32 out
    bgemm64_kernel<<<dim3(3, TOK/128), 256>>>(p_y_bf, p_W12_bf, p_x2, fb, p_short, TOK, CDIM, 2*DI, 0);

    // 8. LN2 + MLP
    ln2_kernel<<<TOK/4, 128>>>(p_x2, n2w, n2b);
    bgemm_kernel<<<dim3(MLPH/128, TOK/128), 256>>>(p_h_bf, p_w1_bf, p_hid_bf, b1, nullptr, TOK, MLPH, CDIM, 1 | 16);
    bgemm64_kernel<<<dim3(3, TOK/128), 256>>>(p_hid_bf, p_w2_bf, out, b2, p_x2, TOK, CDIM, MLPH, 4);
}

// round 10
// speedup vs baseline: 3.1087x; 1.0231x over previous
#include <cuda_runtime.h>
#include <cuda_bf16.h>
#include <math.h>
#include <stdint.h>

// ---------------- problem constants ----------------
#define BQ    2
#define TT    8
#define CDIM  192
#define NSP   576
#define TOK   9216
#define DI    384
#define DS    16
#define DTR   12
#define MLPH  768
#define XZW   1536

typedef __nv_bfloat16 bf16;

// ---------------- scratch ----------------
__device__ bf16  g_xn_bf[TOK*CDIM];
__device__ float g_short[TOK*CDIM];
__device__ float g_xz[TOK*XZW];
__device__ float g_u[2][TOK*DI];
__device__ bf16  g_u_bf[2][TOK*DI];
__device__ float g_delta[2][TOK*DI];
__device__ float g_dbc[2][TOK*64];
__device__ bf16  g_y_bf[TOK*2*DI];
__device__ float g_x2[TOK*CDIM];
__device__ bf16  g_h_bf[TOK*CDIM];
__device__ bf16  g_hid_bf[TOK*MLPH];
__device__ bf16  g_Win_bf[XZW*CDIM];
__device__ bf16  g_W12_bf[CDIM*2*DI];
__device__ bf16  g_xpwP_bf[2][64*DI];
__device__ bf16  g_w1_bf[MLPH*CDIM];
__device__ bf16  g_w2_bf[CDIM*MLPH];
__device__ float g_A[2][DI*DS];
__device__ float g_cwT[2][4*DI];
__device__ float g_dpwT[2][DTR*DI];

// ---------------- helpers ----------------
__device__ __forceinline__ uint32_t packbf(float lo, float hi) {
    uint32_t r;
    asm("cvt.rn.bf16x2.f32 %0, %1, %2;" : "=r"(r) : "f"(hi), "f"(lo));
    return r;
}
__device__ __forceinline__ void mma_bf16(float c[4], const uint32_t a[4], const uint32_t b[2]) {
    asm("mma.sync.aligned.m16n8k16.row.col.f32.bf16.bf16.f32 "
        "{%0,%1,%2,%3}, {%4,%5,%6,%7}, {%8,%9}, {%0,%1,%2,%3};"
        : "+f"(c[0]), "+f"(c[1]), "+f"(c[2]), "+f"(c[3])
        : "r"(a[0]), "r"(a[1]), "r"(a[2]), "r"(a[3]), "r"(b[0]), "r"(b[1]));
}
__device__ __forceinline__ void ldsm_x4(uint32_t& r0, uint32_t& r1, uint32_t& r2, uint32_t& r3,
                                        uint32_t addr) {
    asm volatile("ldmatrix.sync.aligned.m8n8.x4.shared.b16 {%0,%1,%2,%3}, [%4];"
                 : "=r"(r0), "=r"(r1), "=r"(r2), "=r"(r3) : "r"(addr));
}
__device__ __forceinline__ uint32_t smem_u32(const void* p) {
    return (uint32_t)__cvta_generic_to_shared(p);
}

// ---------------- prep ----------------
__global__ void prep_kernel(const float* __restrict__ sAlog, const float* __restrict__ tAlog,
                            const float* __restrict__ scw, const float* __restrict__ tcw,
                            const float* __restrict__ sdpw, const float* __restrict__ tdpw,
                            const float* __restrict__ sinw, const float* __restrict__ tinw,
                            const float* __restrict__ sxpw, const float* __restrict__ txpw,
                            const float* __restrict__ w1, const float* __restrict__ w2)
{
    int i = blockIdx.x * blockDim.x + threadIdx.x;
    if (i < 2*DI*DS) {
        int m = i / (DI*DS), j = i % (DI*DS);
        g_A[m][j] = -expf(m ? tAlog[j] : sAlog[j]);
    }
    if (i < 2*4*DI) {
        int m = i / (4*DI), rem = i % (4*DI);
        int k = rem / DI, d = rem % DI;
        g_cwT[m][k*DI + d] = (m ? tcw : scw)[d*4 + k];
    }
    if (i < 2*DTR*DI) {
        int m = i / (DTR*DI), rem = i % (DTR*DI);
        int rr = rem / DI, d = rem % DI;
        g_dpwT[m][rr*DI + d] = (m ? tdpw : sdpw)[d*DTR + rr];
    }
    if (i < 2*64*DI) {
        int m = i / (64*DI), rem = i % (64*DI);
        int row = rem / DI;
        g_xpwP_bf[m][rem] = __float2bfloat16(
            (row < DTR + 2*DS) ? (m ? txpw : sxpw)[rem] : 0.f);
    }
    if (i < XZW*CDIM) {
        int row = i / CDIM;
        g_Win_bf[i] = __float2bfloat16((row < 768) ? sinw[i] : tinw[i - 768*CDIM]);
    }
    if (i < MLPH*CDIM) g_w1_bf[i] = __float2bfloat16(w1[i]);
    if (i < CDIM*MLPH) g_w2_bf[i] = __float2bfloat16(w2[i]);
}

// ---------------- fold ----------------
__global__ __launch_bounds__(384) void fold_kernel(const float* __restrict__ fw,
                                                   const float* __restrict__ soutw,
                                                   const float* __restrict__ toutw)
{
    __shared__ float fwS[8][192];
    int m  = blockIdx.y;
    int c0 = blockIdx.x * 8;
    const float* ow = m ? toutw : soutw;
    int tid = threadIdx.x;
    for (int i = tid; i < 8*192; i += 384) {
        int c = i / 192, cp = i % 192;
        fwS[c][cp] = fw[(size_t)(c0 + c)*(2*CDIM) + m*CDIM + cp];
    }
    __syncthreads();
    float acc[8] = {0,0,0,0,0,0,0,0};
    #pragma unroll 4
    for (int cp = 0; cp < 192; cp++) {
        float owv = ow[(size_t)cp*DI + tid];
        #pragma unroll
        for (int c = 0; c < 8; c++) acc[c] = fmaf(fwS[c][cp], owv, acc[c]);
    }
    #pragma unroll
    for (int c = 0; c < 8; c++)
        g_W12_bf[(size_t)(c0 + c)*(2*DI) + m*DI + tid] = __float2bfloat16(acc[c]);
}

// ---------------- LN1 ----------------
__global__ __launch_bounds__(256) void ln1_kernel(const float* __restrict__ src,
                                                  const float* __restrict__ w, const float* __restrict__ b)
{
    __shared__ float s[CDIM][33];
    int bt = blockIdx.x;
    int n0 = blockIdx.y * 32;
    int tid = threadIdx.x;
    #pragma unroll
    for (int i = 0; i < 24; i++) {
        int idx = tid + 256*i;
        int c = idx >> 5, nl = idx & 31;
        s[c][nl] = src[((size_t)bt*CDIM + c)*NSP + n0 + nl];
    }
    __syncthreads();
    int warp = tid >> 5, lane = tid & 31;
    for (int jj = 0; jj < 4; jj++) {
        int tt = warp + 8*jj;
        float v[3][2];
        #pragma unroll
        for (int q = 0; q < 3; q++) {
            int c = 2*lane + 64*q;
            v[q][0] = s[c][tt];
            v[q][1] = s[c+1][tt];
        }
        float sum = 0.f;
        #pragma unroll
        for (int q = 0; q < 3; q++) sum += v[q][0] + v[q][1];
        #pragma unroll
        for (int o = 16; o > 0; o >>= 1) sum += __shfl_xor_sync(0xffffffffu, sum, o);
        float mean = sum * (1.f/CDIM);
        float qv = 0.f;
        #pragma unroll
        for (int q = 0; q < 3; q++) {
            float d0 = v[q][0]-mean, d1 = v[q][1]-mean;
            qv += d0*d0 + d1*d1;
        }
        #pragma unroll
        for (int o = 16; o > 0; o >>= 1) qv += __shfl_xor_sync(0xffffffffu, qv, o);
        float rstd = rsqrtf(qv * (1.f/CDIM) + 1e-5f);
        size_t tok = (size_t)bt*NSP + n0 + tt;
        #pragma unroll
        for (int q = 0; q < 3; q++) {
            int c = 2*lane + 64*q;
            float o0 = (v[q][0]-mean)*rstd*w[c]   + b[c];
            float o1 = (v[q][1]-mean)*rstd*w[c+1] + b[c+1];
            *reinterpret_cast<uint32_t*>(&g_xn_bf[tok*CDIM + c]) = packbf(o0, o1);
            *reinterpret_cast<float2*>(&g_short[tok*CDIM + c]) = make_float2(v[q][0], v[q][1]);
        }
    }
}

// ---------------- LN2 ----------------
__global__ void ln2_kernel(const float* __restrict__ src,
                           const float* __restrict__ w, const float* __restrict__ b)
{
    int tok  = blockIdx.x * 4 + (threadIdx.x >> 5);
    int lane = threadIdx.x & 31;
    const float* base = src + (size_t)tok * CDIM;
    float v[3][2];
    #pragma unroll
    for (int q = 0; q < 3; q++) {
        float2 t = *reinterpret_cast<const float2*>(&base[2*lane + 64*q]);
        v[q][0] = t.x; v[q][1] = t.y;
    }
    float s = 0.f;
    #pragma unroll
    for (int q = 0; q < 3; q++) s += v[q][0] + v[q][1];
    #pragma unroll
    for (int o = 16; o > 0; o >>= 1) s += __shfl_xor_sync(0xffffffffu, s, o);
    float mean = s * (1.f / CDIM);
    float qv = 0.f;
    #pragma unroll
    for (int q = 0; q < 3; q++) {
        float d0 = v[q][0]-mean, d1 = v[q][1]-mean;
        qv += d0*d0 + d1*d1;
    }
    #pragma unroll
    for (int o = 16; o > 0; o >>= 1) qv += __shfl_xor_sync(0xffffffffu, qv, o);
    float rstd = rsqrtf(qv * (1.f / CDIM) + 1e-5f);
    #pragma unroll
    for (int q = 0; q < 3; q++) {
        int c = 2*lane + 64*q;
        float o0 = (v[q][0]-mean)*rstd*w[c]   + b[c];
        float o1 = (v[q][1]-mean)*rstd*w[c+1] + b[c+1];
        *reinterpret_cast<uint32_t*>(&g_h_bf[(size_t)tok*CDIM + c]) = packbf(o0, o1);
    }
}

// ---------------- bgemm: bf16 GEMM, 128x128 block, ldmatrix frags -----------------------
// flags: bit0 gelu | bit4 bf16 C store
__global__ __launch_bounds__(256) void bgemm_kernel(
    const bf16* __restrict__ A, const bf16* __restrict__ B, void* __restrict__ Cv,
    const float* __restrict__ bias, const float* __restrict__ addend,
    int M, int N, int K, int flags)
{
    __shared__ uint32_t As[2][128][12];
    __shared__ uint32_t Bs[2][128][12];
    int tid = threadIdx.x;
    int m0 = blockIdx.y * 128, n0 = blockIdx.x * 128;

    int lrow = tid >> 1;
    int lk   = (tid & 1) * 8;
    int kb   = (tid & 1) * 4;
    const bf16* Ap = A + (size_t)(m0 + lrow) * K + lk;
    const bf16* Bp = B + (size_t)(n0 + lrow) * K + lk;

    {
        uint4 a = *reinterpret_cast<const uint4*>(Ap);
        uint4 b = *reinterpret_cast<const uint4*>(Bp);
        *reinterpret_cast<uint4*>(&As[0][lrow][kb]) = a;
        *reinterpret_cast<uint4*>(&Bs[0][lrow][kb]) = b;
    }
    __syncthreads();

    int wid = tid >> 5, lane = tid & 31;
    int wm = wid >> 1, wn = wid & 1;
    int lr = lane >> 2, lc = lane & 3;

    // ldmatrix addresses (per double-buffer)
    uint32_t aAddr[2][2], bAddr[2][4];
    {
        int ar = (lane & 15);
        int ac = (lane >> 4) * 4;
        int br = ((lane >> 4) & 1) * 8 + (lane & 7);
        int bc = ((lane >> 3) & 1) * 4;
        #pragma unroll
        for (int p = 0; p < 2; p++) {
            #pragma unroll
            for (int mt = 0; mt < 2; mt++)
                aAddr[p][mt] = smem_u32(&As[p][wm*32 + mt*16 + ar][ac]);
            #pragma unroll
            for (int np = 0; np < 4; np++)
                bAddr[p][np] = smem_u32(&Bs[p][wn*64 + np*16 + br][bc]);
        }
    }

    float acc[2][8][4];
    #pragma unroll
    for (int mt = 0; mt < 2; mt++)
        #pragma unroll
        for (int nt = 0; nt < 8; nt++)
            #pragma unroll
            for (int j = 0; j < 4; j++) acc[mt][nt][j] = 0.f;

    int p = 0;
    for (int kt = 0; kt < K; kt += 16) {
        uint4 a, b;
        bool more = (kt + 16) < K;
        if (more) {
            a = *reinterpret_cast<const uint4*>(Ap + kt + 16);
            b = *reinterpret_cast<const uint4*>(Bp + kt + 16);
        }
        uint32_t afr[2][4];
        #pragma unroll
        for (int mt = 0; mt < 2; mt++)
            ldsm_x4(afr[mt][0], afr[mt][1], afr[mt][2], afr[mt][3], aAddr[p][mt]);
        uint32_t bfr[8][2];
        #pragma unroll
        for (int np = 0; np < 4; np++)
            ldsm_x4(bfr[2*np][0], bfr[2*np][1], bfr[2*np+1][0], bfr[2*np+1][1], bAddr[p][np]);
        #pragma unroll
        for (int mt = 0; mt < 2; mt++)
            #pragma unroll
            for (int nt = 0; nt < 8; nt++)
                mma_bf16(acc[mt][nt], afr[mt], bfr[nt]);
        if (more) {
            int q = p ^ 1;
            *reinterpret_cast<uint4*>(&As[q][lrow][kb]) = a;
            *reinterpret_cast<uint4*>(&Bs[q][lrow][kb]) = b;
        }
        __syncthreads();
        p ^= 1;
    }

    float* C = (float*)Cv;
    bf16*  Cb = (bf16*)Cv;
    #pragma unroll
    for (int nt = 0; nt < 8; nt++) {
        int col = n0 + wn*64 + nt*8 + lc*2;
        float b0 = 0.f, b1 = 0.f;
        if (bias) { b0 = bias[col]; b1 = bias[col+1]; }
        #pragma unroll
        for (int mt = 0; mt < 2; mt++) {
            int r0 = m0 + wm*32 + mt*16 + lr;
            int r1 = r0 + 8;
            float v00 = acc[mt][nt][0] + b0;
            float v01 = acc[mt][nt][1] + b1;
            float v10 = acc[mt][nt][2] + b0;
            float v11 = acc[mt][nt][3] + b1;
            if (addend) {
                const float* ad0 = addend + (size_t)r0*N + col;
                const float* ad1 = addend + (size_t)r1*N + col;
                v00 += ad0[0]; v01 += ad0[1];
                v10 += ad1[0]; v11 += ad1[1];
            }
            if (flags & 1) {
                v00 = 0.5f*v00*(1.f + erff(v00*0.70710678118654752f));
                v01 = 0.5f*v01*(1.f + erff(v01*0.70710678118654752f));
                v10 = 0.5f*v10*(1.f + erff(v10*0.70710678118654752f));
                v11 = 0.5f*v11*(1.f + erff(v11*0.70710678118654752f));
            }
            if (flags & 16) {
                *reinterpret_cast<uint32_t*>(&Cb[(size_t)r0*N + col]) = packbf(v00, v01);
                *reinterpret_cast<uint32_t*>(&Cb[(size_t)r1*N + col]) = packbf(v10, v11);
            } else {
                *reinterpret_cast<float2*>(&C[(size_t)r0*N + col]) = make_float2(v00, v01);
                *reinterpret_cast<float2*>(&C[(size_t)r1*N + col]) = make_float2(v10, v11);
            }
        }
    }
}

// ---------------- bgemm64: bf16 GEMM, 128x64 block, ldmatrix frags ----------------------
// flags: bit0 gelu | bit2 transposed store | bit3 z-split
__global__ __launch_bounds__(256) void bgemm64_kernel(
    const bf16* __restrict__ A, const bf16* __restrict__ B, float* __restrict__ C,
    const float* __restrict__ bias, const float* __restrict__ addend,
    int M, int N, int K, int flags)
{
    __shared__ uint32_t As[2][128][12];
    __shared__ uint32_t Bs[2][64][12];
    int tid = threadIdx.x;
    int m0 = blockIdx.y * 128, n0 = blockIdx.x * 64;
    if (flags & 8) {
        int z = blockIdx.z;
        A += (size_t)z * M * K;
        B += (size_t)z * N * K;
        C += (size_t)z * M * N;
    }

    int lrow = tid >> 1;
    int lk   = (tid & 1) * 8;
    int kb   = (tid & 1) * 4;
    const bf16* Ap = A + (size_t)(m0 + lrow) * K + lk;
    int lrowB = tid >> 2;
    int lkB   = (tid & 3) * 4;
    int kbB   = (tid & 3) * 2;
    const bf16* Bp = B + (size_t)(n0 + lrowB) * K + lkB;

    {
        uint4 a = *reinterpret_cast<const uint4*>(Ap);
        uint2 b = *reinterpret_cast<const uint2*>(Bp);
        *reinterpret_cast<uint4*>(&As[0][lrow][kb]) = a;
        *reinterpret_cast<uint2*>(&Bs[0][lrowB][kbB]) = b;
    }
    __syncthreads();

    int wid = tid >> 5, lane = tid & 31;
    int lr = lane >> 2, lc = lane & 3;

    uint32_t aAddr[2], bAddr[2][4];
    {
        int ar = (lane & 15);
        int ac = (lane >> 4) * 4;
        int br = ((lane >> 4) & 1) * 8 + (lane & 7);
        int bc = ((lane >> 3) & 1) * 4;
        #pragma unroll
        for (int p = 0; p < 2; p++) {
            aAddr[p] = smem_u32(&As[p][wid*16 + ar][ac]);
            #pragma unroll
            for (int np = 0; np < 4; np++)
                bAddr[p][np] = smem_u32(&Bs[p][np*16 + br][bc]);
        }
    }

    float acc[8][4];
    #pragma unroll
    for (int nt = 0; nt < 8; nt++)
        #pragma unroll
        for (int j = 0; j < 4; j++) acc[nt][j] = 0.f;

    int p = 0;
    for (int kt = 0; kt < K; kt += 16) {
        uint4 a; uint2 b;
        bool more = (kt + 16) < K;
        if (more) {
            a = *reinterpret_cast<const uint4*>(Ap + kt + 16);
            b = *reinterpret_cast<const uint2*>(Bp + kt + 16);
        }
        uint32_t afr[4];
        ldsm_x4(afr[0], afr[1], afr[2], afr[3], aAddr[p]);
        uint32_t bfr[8][2];
        #pragma unroll
        for (int np = 0; np < 4; np++)
            ldsm_x4(bfr[2*np][0], bfr[2*np][1], bfr[2*np+1][0], bfr[2*np+1][1], bAddr[p][np]);
        #pragma unroll
        for (int nt = 0; nt < 8; nt++)
            mma_bf16(acc[nt], afr, bfr[nt]);
        if (more) {
            int q = p ^ 1;
            *reinterpret_cast<uint4*>(&As[q][lrow][kb]) = a;
            *reinterpret_cast<uint2*>(&Bs[q][lrowB][kbB]) = b;
        }
        __syncthreads();
        p ^= 1;
    }

    #pragma unroll
    for (int nt = 0; nt < 8; nt++) {
        int col = n0 + nt*8 + lc*2;
        float b0 = 0.f, b1 = 0.f;
        if (bias) { b0 = bias[col]; b1 = bias[col+1]; }
        int r0 = m0 + wid*16 + lr;
        int r1 = r0 + 8;
        float v00 = acc[nt][0] + b0;
        float v01 = acc[nt][1] + b1;
        float v10 = acc[nt][2] + b0;
        float v11 = acc[nt][3] + b1;
        if (addend) {
            const float* ad0 = addend + (size_t)r0*N + col;
            const float* ad1 = addend + (size_t)r1*N + col;
            v00 += ad0[0]; v01 += ad0[1];
            v10 += ad1[0]; v11 += ad1[1];
        }
        if (flags & 1) {
            v00 = 0.5f*v00*(1.f + erff(v00*0.70710678118654752f));
            v01 = 0.5f*v01*(1.f + erff(v01*0.70710678118654752f));
            v10 = 0.5f*v10*(1.f + erff(v10*0.70710678118654752f));
            v11 = 0.5f*v11*(1.f + erff(v11*0.70710678118654752f));
        }
        if (flags & 4) {
            int bt0 = r0 / NSP, nn0 = r0 % NSP;
            int bt1 = r1 / NSP, nn1 = r1 % NSP;
            C[((size_t)bt0*CDIM + col  )*NSP + nn0] = v00;
            C[((size_t)bt0*CDIM + col+1)*NSP + nn0] = v01;
            C[((size_t)bt1*CDIM + col  )*NSP + nn1] = v10;
            C[((size_t)bt1*CDIM + col+1)*NSP + nn1] = v11;
        } else {
            *reinterpret_cast<float2*>(&C[(size_t)r0*N + col]) = make_float2(v00, v01);
            *reinterpret_cast<float2*>(&C[(size_t)r1*N + col]) = make_float2(v10, v11);
        }
    }
}

// ---------------- conv4 depthwise + silu ----------------
__global__ __launch_bounds__(192) void conv_kernel(const float* __restrict__ scb,
                                                   const float* __restrict__ tcb)
{
    int m = blockIdx.y;
    int tid = threadIdx.x;
    int rl = tid / 96, v = tid % 96;
    int r = blockIdx.x * 2 + rl;
    int pos  = m ? ((r / NSP) & (TT-1)) : (r % NSP);
    int strd = m ? NSP : 1;
    const float* cb = m ? tcb : scb;
    float4 acc = *reinterpret_cast<const float4*>(&cb[4*v]);
    #pragma unroll
    for (int k = 0; k < 4; k++) {
        if (pos - 3 + k >= 0) {
            float4 xv = *reinterpret_cast<const float4*>(&g_xz[(size_t)(r - (3-k)*strd)*XZW + m*768 + 4*v]);
            float4 cw = *reinterpret_cast<const float4*>(&g_cwT[m][k*DI + 4*v]);
            acc.x = fmaf(cw.x, xv.x, acc.x);
            acc.y = fmaf(cw.y, xv.y, acc.y);
            acc.z = fmaf(cw.z, xv.z, acc.z);
            acc.w = fmaf(cw.w, xv.w, acc.w);
        }
    }
    acc.x = acc.x / (1.f + __expf(-acc.x));
    acc.y = acc.y / (1.f + __expf(-acc.y));
    acc.z = acc.z / (1.f + __expf(-acc.z));
    acc.w = acc.w / (1.f + __expf(-acc.w));
    *reinterpret_cast<float4*>(&g_u[m][(size_t)r*DI + 4*v]) = acc;
    uint2 pk = make_uint2(packbf(acc.x, acc.y), packbf(acc.z, acc.w));
    *reinterpret_cast<uint2*>(&g_u_bf[m][(size_t)r*DI + 4*v]) = pk;
}

// ---------------- delta ----------------
__global__ __launch_bounds__(384) void delta_kernel(const float* __restrict__ sdpb,
                                                    const float* __restrict__ tdpb)
{
    __shared__ float sw[DTR][DI];
    __shared__ float sdbc[16][DTR];
    int m = blockIdx.y;
    int r0 = blockIdx.x * 16;
    int d = threadIdx.x;
    const float* dpb = m ? tdpb : sdpb;
    #pragma unroll
    for (int rr = 0; rr < DTR; rr++)
        sw[rr][d] = g_dpwT[m][rr*DI + d];
    if (d < 16*DTR) {
        int t = d / DTR, c = d % DTR;
        sdbc[t][c] = g_dbc[m][(size_t)(r0 + t)*64 + c];
    }
    __syncthreads();
    float base = dpb[d];
    #pragma unroll 4
    for (int t = 0; t < 16; t++) {
        float acc = base;
        #pragma unroll
        for (int rr = 0; rr < DTR; rr++)
            acc = fmaf(sdbc[t][rr], sw[rr][d], acc);
        g_delta[m][(size_t)(r0 + t)*DI + d] = (acc > 15.f) ? acc : log1pf(__expf(acc));
    }
}

// ---------------- merged scans ----------------
#define SPATIAL_BLOCKS 768
__global__ __launch_bounds__(128) void scan_kernel(const float* __restrict__ sD,
                                                   const float* __restrict__ tD)
{
    int bx = blockIdx.x;
    int tid = threadIdx.x;

    if (bx < SPATIAL_BLOCKS) {
        __shared__ float sbuf[64][8];
        int s   = bx / 48;
        int dpg = bx % 48;
        int w = tid >> 5, lane = tid & 31;
        int sub = lane >> 4, n = lane & 15;
        int d = dpg*8 + w*2 + sub;
        int ycol0 = dpg*8;

        float a  = g_A[0][d*DS + n];
        float Dd = sD[d];
        const float* delta = g_delta[0];
        const float* u     = g_u[0];
        const float* dbc   = g_dbc[0];
        int base = s * NSP;

        float h = 0.f;
        for (int pos = 0; pos < NSP; pos += 4) {
            float dl[4], uu[4], Bv[4], Cv[4];
            #pragma unroll
            for (int j = 0; j < 4; j++) {
                size_t r = base + pos + j;
                dl[j] = __ldg(&delta[r*DI + d]);
                uu[j] = __ldg(&u[r*DI + d]);
                Bv[j] = __ldg(&dbc[r*64 + DTR + n]);
                Cv[j] = __ldg(&dbc[r*64 + DTR + DS + n]);
            }
            float dA[4], dBu[4];
            #pragma unroll
            for (int j = 0; j < 4; j++) {
                dA[j]  = __expf(dl[j] * a);
                dBu[j] = dl[j] * uu[j] * Bv[j];
            }
            float part[4];
            #pragma unroll
            for (int j = 0; j < 4; j++) {
                h = fmaf(h, dA[j], dBu[j]);
                part[j] = h * Cv[j];
            }
            #pragma unroll
            for (int off = 1; off <= 8; off <<= 1)
                #pragma unroll
                for (int j = 0; j < 4; j++)
                    part[j] += __shfl_xor_sync(0xffffffffu, part[j], off);
            if (n == 0) {
                #pragma unroll
                for (int j = 0; j < 4; j++)
                    sbuf[(pos + j) & 63][w*2 + sub] = part[j] + uu[j] * Dd;
            }
            if ((pos & 63) == 60) {
                __syncthreads();
                int p2 = tid >> 1, half = tid & 1;
                size_t r = base + (pos & ~63) + p2;
                float4 v = *reinterpret_cast<float4*>(&sbuf[p2][half*4]);
                float4 z4 = *reinterpret_cast<const float4*>(&g_xz[r*XZW + 384 + ycol0 + half*4]);
                v.x *= z4.x / (1.f + __expf(-z4.x));
                v.y *= z4.y / (1.f + __expf(-z4.y));
                v.z *= z4.z / (1.f + __expf(-z4.z));
                v.w *= z4.w / (1.f + __expf(-z4.w));
                uint2 pk = make_uint2(packbf(v.x, v.y), packbf(v.z, v.w));
                *reinterpret_cast<uint2*>(&g_y_bf[r*(2*DI) + ycol0 + half*4]) = pk;
                __syncthreads();
            }
        }
    } else {
        int b2 = bx - SPATIAL_BLOCKS;
        int seq = b2 / 3;
        int d = (b2 % 3) * 128 + tid;
        int lane = tid & 31;
        int b = seq / NSP, nsp = seq % NSP;
        int base = b * (TT*NSP) + nsp;

        float a[DS];
        #pragma unroll
        for (int q = 0; q < 4; q++)
            *reinterpret_cast<float4*>(&a[q*4]) = *reinterpret_cast<const float4*>(&g_A[1][d*DS + q*4]);
        float Dd = tD[d];
        const float* delta = g_delta[1];
        const float* u     = g_u[1];
        const float* dbc   = g_dbc[1];

        float h[DS];
        #pragma unroll
        for (int q = 0; q < DS; q++) h[q] = 0.f;

        for (int t = 0; t < TT; t++) {
            size_t r = base + (size_t)t * NSP;
            float dl = delta[r*DI + d];
            float uu = u[r*DI + d];
            float bc = dbc[r*64 + DTR + lane];
            float dlu = dl * uu;
            float y = 0.f;
            #pragma unroll
            for (int q = 0; q < DS; q++) {
                float Bn = __shfl_sync(0xffffffffu, bc, q);
                float Cn = __shfl_sync(0xffffffffu, bc, q + 16);
                float dA = __expf(dl * a[q]);
                h[q] = fmaf(h[q], dA, dlu * Bn);
                y = fmaf(h[q], Cn, y);
            }
            float z = g_xz[r*XZW + 1152 + d];
            float g = z / (1.f + __expf(-z));
            g_y_bf[r*(2*DI) + DI + d] = __float2bfloat16((y + uu * Dd) * g);
        }
    }
}

// ---------------- host launcher ----------------
extern "C" void kernel_launch(void* const* d_in, const int* in_sizes, int n_in,
                              void* d_out, int out_size)
{
    const float* x_in   = (const float*)d_in[0];
    const float* n1w    = (const float*)d_in[1];
    const float* n1b    = (const float*)d_in[2];
    const float* s_inw  = (const float*)d_in[3];
    const float* s_cw   = (const float*)d_in[4];
    const float* s_cb   = (const float*)d_in[5];
    const float* s_xpw  = (const float*)d_in[6];
    const float* s_dpw  = (const float*)d_in[7];
    const float* s_dpb  = (const float*)d_in[8];
    const float* s_Alog = (const float*)d_in[9];
    const float* s_D    = (const float*)d_in[10];
    const float* s_outw = (const float*)d_in[11];
    const float* t_inw  = (const float*)d_in[12];
    const float* t_cw   = (const float*)d_in[13];
    const float* t_cb   = (const float*)d_in[14];
    const float* t_xpw  = (const float*)d_in[15];
    const float* t_dpw  = (const float*)d_in[16];
    const float* t_dpb  = (const float*)d_in[17];
    const float* t_Alog = (const float*)d_in[18];
    const float* t_D    = (const float*)d_in[19];
    const float* t_outw = (const float*)d_in[20];
    const float* fw     = (const float*)d_in[21];
    const float* fb     = (const float*)d_in[22];
    const float* n2w    = (const float*)d_in[23];
    const float* n2b    = (const float*)d_in[24];
    const float* w1     = (const float*)d_in[25];
    const float* b1     = (const float*)d_in[26];
    const float* w2     = (const float*)d_in[27];
    const float* b2     = (const float*)d_in[28];
    float* out = (float*)d_out;

    bf16 *p_xn_bf, *p_u_bf, *p_y_bf, *p_h_bf, *p_hid_bf, *p_Win_bf, *p_W12_bf, *p_xpwP_bf, *p_w1_bf, *p_w2_bf;
    float *p_short, *p_xz, *p_x2, *p_dbc;
    cudaGetSymbolAddress((void**)&p_xn_bf, g_xn_bf);
    cudaGetSymbolAddress((void**)&p_short, g_short);
    cudaGetSymbolAddress((void**)&p_xz,    g_xz);
    cudaGetSymbolAddress((void**)&p_u_bf,  g_u_bf);
    cudaGetSymbolAddress((void**)&p_dbc,   g_dbc);
    cudaGetSymbolAddress((void**)&p_y_bf,  g_y_bf);
    cudaGetSymbolAddress((void**)&p_x2,    g_x2);
    cudaGetSymbolAddress((void**)&p_h_bf,  g_h_bf);
    cudaGetSymbolAddress((void**)&p_hid_bf,g_hid_bf);
    cudaGetSymbolAddress((void**)&p_Win_bf,g_Win_bf);
    cudaGetSymbolAddress((void**)&p_W12_bf,g_W12_bf);
    cudaGetSymbolAddress((void**)&p_xpwP_bf,g_xpwP_bf);
    cudaGetSymbolAddress((void**)&p_w1_bf, g_w1_bf);
    cudaGetSymbolAddress((void**)&p_w2_bf, g_w2_bf);

    // 0. prep + fold
    prep_kernel<<<1152, 256>>>(s_Alog, t_Alog, s_cw, t_cw, s_dpw, t_dpw,
                               s_inw, t_inw, s_xpw, t_xpw, w1, w2);
    fold_kernel<<<dim3(24, 2), 384>>>(fw, s_outw, t_outw);

    // 1. transpose + LN1
    ln1_kernel<<<dim3(16, 18), 256>>>(x_in, n1w, n1b);

    // 2. merged in_proj GEMM (N=1536, K=192)
    bgemm_kernel<<<dim3(XZW/128, TOK/128), 256>>>(p_xn_bf, p_Win_bf, p_xz, nullptr, nullptr, TOK, XZW, CDIM, 0);

    // 3. conv+silu
    conv_kernel<<<dim3(TOK/2, 2), 192>>>(s_cb, t_cb);

    // 4. dbc = u @ xpwP^T (N=64, K=384), both mambas via z
    bgemm64_kernel<<<dim3(1, TOK/128, 2), 256>>>(p_u_bf, p_xpwP_bf, p_dbc, nullptr, nullptr, TOK, 64, DI, 8);

    // 5. delta
    delta_kernel<<<dim3(TOK/16, 2), 384>>>(s_dpb, t_dpb);

    // 6. scans
    scan_kernel<<<SPATIAL_BLOCKS + 3456, 128>>>(s_D, t_D);

    // 7. fusion + residual (N=192, K=768)
    bgemm64_kernel<<<dim3(3, TOK/128), 256>>>(p_y_bf, p_W12_bf, p_x2, fb, p_short, TOK, CDIM, 2*DI, 0);

    // 8. LN2 + MLP
    ln2_kernel<<<TOK/4, 128>>>(p_x2, n2w, n2b);
    bgemm_kernel<<<dim3(MLPH/128, TOK/128), 256>>>(p_h_bf, p_w1_bf, p_hid_bf, b1, nullptr, TOK, MLPH, CDIM, 1 | 16);
    bgemm64_kernel<<<dim3(3, TOK/128), 256>>>(p_hid_bf, p_w2_bf, out, b2, p_x2, TOK, CDIM, MLPH, 4);
}

// round 11
// speedup vs baseline: 3.2796x; 1.0550x over previous
#include <cuda_runtime.h>
#include <cuda_bf16.h>
#include <math.h>
#include <stdint.h>

// ---------------- problem constants ----------------
#define BQ    2
#define TT    8
#define CDIM  192
#define NSP   576
#define TOK   9216
#define DI    384
#define DS    16
#define DTR   12
#define MLPH  768
#define XZW   1536

typedef __nv_bfloat16 bf16;

// ---------------- scratch ----------------
__device__ bf16  g_xn_bf[TOK*CDIM];
__device__ float g_short[TOK*CDIM];
__device__ float g_xz[TOK*XZW];
__device__ float g_u[2][TOK*DI];
__device__ bf16  g_u_bf[2][TOK*DI];
__device__ float g_delta[2][TOK*DI];
__device__ float g_dbc[2][TOK*64];
__device__ bf16  g_y_bf[TOK*2*DI];
__device__ float g_x2[TOK*CDIM];
__device__ bf16  g_h_bf[TOK*CDIM];
__device__ bf16  g_hid_bf[TOK*MLPH];
__device__ bf16  g_Win_bf[XZW*CDIM];
__device__ bf16  g_W12_bf[CDIM*2*DI];
__device__ bf16  g_xpwP_bf[2][64*DI];
__device__ bf16  g_w1_bf[MLPH*CDIM];
__device__ bf16  g_w2_bf[CDIM*MLPH];
__device__ float g_A[2][DI*DS];
__device__ float g_cwT[2][4*DI];
__device__ float g_dpwT[2][DTR*DI];

// ---------------- helpers ----------------
__device__ __forceinline__ uint32_t packbf(float lo, float hi) {
    uint32_t r;
    asm("cvt.rn.bf16x2.f32 %0, %1, %2;" : "=r"(r) : "f"(hi), "f"(lo));
    return r;
}
__device__ __forceinline__ void mma_bf16(float c[4], const uint32_t a[4], const uint32_t b[2]) {
    asm("mma.sync.aligned.m16n8k16.row.col.f32.bf16.bf16.f32 "
        "{%0,%1,%2,%3}, {%4,%5,%6,%7}, {%8,%9}, {%0,%1,%2,%3};"
        : "+f"(c[0]), "+f"(c[1]), "+f"(c[2]), "+f"(c[3])
        : "r"(a[0]), "r"(a[1]), "r"(a[2]), "r"(a[3]), "r"(b[0]), "r"(b[1]));
}
__device__ __forceinline__ void ldsm_x4(uint32_t& r0, uint32_t& r1, uint32_t& r2, uint32_t& r3,
                                        uint32_t addr) {
    asm volatile("ldmatrix.sync.aligned.m8n8.x4.shared.b16 {%0,%1,%2,%3}, [%4];"
                 : "=r"(r0), "=r"(r1), "=r"(r2), "=r"(r3) : "r"(addr));
}
__device__ __forceinline__ uint32_t smem_u32(const void* p) {
    return (uint32_t)__cvta_generic_to_shared(p);
}
__device__ __forceinline__ void cpa16(uint32_t dst, const void* src) {
    asm volatile("cp.async.ca.shared.global [%0], [%1], 16;" :: "r"(dst), "l"(src));
}
#define CP_COMMIT() asm volatile("cp.async.commit_group;" ::: "memory")
#define CP_WAIT0()  asm volatile("cp.async.wait_group 0;" ::: "memory")

// ---------------- prep ----------------
__global__ void prep_kernel(const float* __restrict__ sAlog, const float* __restrict__ tAlog,
                            const float* __restrict__ scw, const float* __restrict__ tcw,
                            const float* __restrict__ sdpw, const float* __restrict__ tdpw,
                            const float* __restrict__ sinw, const float* __restrict__ tinw,
                            const float* __restrict__ sxpw, const float* __restrict__ txpw,
                            const float* __restrict__ w1, const float* __restrict__ w2)
{
    int i = blockIdx.x * blockDim.x + threadIdx.x;
    if (i < 2*DI*DS) {
        int m = i / (DI*DS), j = i % (DI*DS);
        g_A[m][j] = -expf(m ? tAlog[j] : sAlog[j]);
    }
    if (i < 2*4*DI) {
        int m = i / (4*DI), rem = i % (4*DI);
        int k = rem / DI, d = rem % DI;
        g_cwT[m][k*DI + d] = (m ? tcw : scw)[d*4 + k];
    }
    if (i < 2*DTR*DI) {
        int m = i / (DTR*DI), rem = i % (DTR*DI);
        int rr = rem / DI, d = rem % DI;
        g_dpwT[m][rr*DI + d] = (m ? tdpw : sdpw)[d*DTR + rr];
    }
    if (i < 2*64*DI) {
        int m = i / (64*DI), rem = i % (64*DI);
        int row = rem / DI;
        g_xpwP_bf[m][rem] = __float2bfloat16(
            (row < DTR + 2*DS) ? (m ? txpw : sxpw)[rem] : 0.f);
    }
    if (i < XZW*CDIM) {
        int row = i / CDIM;
        g_Win_bf[i] = __float2bfloat16((row < 768) ? sinw[i] : tinw[i - 768*CDIM]);
    }
    if (i < MLPH*CDIM) g_w1_bf[i] = __float2bfloat16(w1[i]);
    if (i < CDIM*MLPH) g_w2_bf[i] = __float2bfloat16(w2[i]);
}

// ---------------- fold ----------------
__global__ __launch_bounds__(384) void fold_kernel(const float* __restrict__ fw,
                                                   const float* __restrict__ soutw,
                                                   const float* __restrict__ toutw)
{
    __shared__ float fwS[8][192];
    int m  = blockIdx.y;
    int c0 = blockIdx.x * 8;
    const float* ow = m ? toutw : soutw;
    int tid = threadIdx.x;
    for (int i = tid; i < 8*192; i += 384) {
        int c = i / 192, cp = i % 192;
        fwS[c][cp] = fw[(size_t)(c0 + c)*(2*CDIM) + m*CDIM + cp];
    }
    __syncthreads();
    float acc[8] = {0,0,0,0,0,0,0,0};
    #pragma unroll 4
    for (int cp = 0; cp < 192; cp++) {
        float owv = ow[(size_t)cp*DI + tid];
        #pragma unroll
        for (int c = 0; c < 8; c++) acc[c] = fmaf(fwS[c][cp], owv, acc[c]);
    }
    #pragma unroll
    for (int c = 0; c < 8; c++)
        g_W12_bf[(size_t)(c0 + c)*(2*DI) + m*DI + tid] = __float2bfloat16(acc[c]);
}

// ---------------- LN1 ----------------
__global__ __launch_bounds__(256) void ln1_kernel(const float* __restrict__ src,
                                                  const float* __restrict__ w, const float* __restrict__ b)
{
    __shared__ float s[CDIM][33];
    int bt = blockIdx.x;
    int n0 = blockIdx.y * 32;
    int tid = threadIdx.x;
    #pragma unroll
    for (int i = 0; i < 24; i++) {
        int idx = tid + 256*i;
        int c = idx >> 5, nl = idx & 31;
        s[c][nl] = src[((size_t)bt*CDIM + c)*NSP + n0 + nl];
    }
    __syncthreads();
    int warp = tid >> 5, lane = tid & 31;
    for (int jj = 0; jj < 4; jj++) {
        int tt = warp + 8*jj;
        float v[3][2];
        #pragma unroll
        for (int q = 0; q < 3; q++) {
            int c = 2*lane + 64*q;
            v[q][0] = s[c][tt];
            v[q][1] = s[c+1][tt];
        }
        float sum = 0.f;
        #pragma unroll
        for (int q = 0; q < 3; q++) sum += v[q][0] + v[q][1];
        #pragma unroll
        for (int o = 16; o > 0; o >>= 1) sum += __shfl_xor_sync(0xffffffffu, sum, o);
        float mean = sum * (1.f/CDIM);
        float qv = 0.f;
        #pragma unroll
        for (int q = 0; q < 3; q++) {
            float d0 = v[q][0]-mean, d1 = v[q][1]-mean;
            qv += d0*d0 + d1*d1;
        }
        #pragma unroll
        for (int o = 16; o > 0; o >>= 1) qv += __shfl_xor_sync(0xffffffffu, qv, o);
        float rstd = rsqrtf(qv * (1.f/CDIM) + 1e-5f);
        size_t tok = (size_t)bt*NSP + n0 + tt;
        #pragma unroll
        for (int q = 0; q < 3; q++) {
            int c = 2*lane + 64*q;
            float o0 = (v[q][0]-mean)*rstd*w[c]   + b[c];
            float o1 = (v[q][1]-mean)*rstd*w[c+1] + b[c+1];
            *reinterpret_cast<uint32_t*>(&g_xn_bf[tok*CDIM + c]) = packbf(o0, o1);
            *reinterpret_cast<float2*>(&g_short[tok*CDIM + c]) = make_float2(v[q][0], v[q][1]);
        }
    }
}

// ---------------- LN2 ----------------
__global__ void ln2_kernel(const float* __restrict__ src,
                           const float* __restrict__ w, const float* __restrict__ b)
{
    int tok  = blockIdx.x * 4 + (threadIdx.x >> 5);
    int lane = threadIdx.x & 31;
    const float* base = src + (size_t)tok * CDIM;
    float v[3][2];
    #pragma unroll
    for (int q = 0; q < 3; q++) {
        float2 t = *reinterpret_cast<const float2*>(&base[2*lane + 64*q]);
        v[q][0] = t.x; v[q][1] = t.y;
    }
    float s = 0.f;
    #pragma unroll
    for (int q = 0; q < 3; q++) s += v[q][0] + v[q][1];
    #pragma unroll
    for (int o = 16; o > 0; o >>= 1) s += __shfl_xor_sync(0xffffffffu, s, o);
    float mean = s * (1.f / CDIM);
    float qv = 0.f;
    #pragma unroll
    for (int q = 0; q < 3; q++) {
        float d0 = v[q][0]-mean, d1 = v[q][1]-mean;
        qv += d0*d0 + d1*d1;
    }
    #pragma unroll
    for (int o = 16; o > 0; o >>= 1) qv += __shfl_xor_sync(0xffffffffu, qv, o);
    float rstd = rsqrtf(qv * (1.f / CDIM) + 1e-5f);
    #pragma unroll
    for (int q = 0; q < 3; q++) {
        int c = 2*lane + 64*q;
        float o0 = (v[q][0]-mean)*rstd*w[c]   + b[c];
        float o1 = (v[q][1]-mean)*rstd*w[c+1] + b[c+1];
        *reinterpret_cast<uint32_t*>(&g_h_bf[(size_t)tok*CDIM + c]) = packbf(o0, o1);
    }
}

// ---------------- bgemm: bf16 GEMM, 128x128 block, cp.async + ldmatrix ------------------
// flags: bit0 gelu | bit4 bf16 C store
#define ABUF_STRIDE 6144   // 128*12*4 bytes
__global__ __launch_bounds__(256, 2) void bgemm_kernel(
    const bf16* __restrict__ A, const bf16* __restrict__ B, void* __restrict__ Cv,
    const float* __restrict__ bias, const float* __restrict__ addend,
    int M, int N, int K, int flags)
{
    __shared__ uint32_t As[2][128][12];
    __shared__ uint32_t Bs[2][128][12];
    int tid = threadIdx.x;
    int m0 = blockIdx.y * 128, n0 = blockIdx.x * 128;

    int lrow = tid >> 1;
    int lk   = (tid & 1) * 8;
    const bf16* Ag = A + (size_t)(m0 + lrow) * K + lk;
    const bf16* Bg = B + (size_t)(n0 + lrow) * K + lk;
    uint32_t aDst0 = smem_u32(&As[0][lrow][(tid & 1) * 4]);
    uint32_t bDst0 = smem_u32(&Bs[0][lrow][(tid & 1) * 4]);

    // prologue: tile 0 via cp.async
    cpa16(aDst0, Ag);
    cpa16(bDst0, Bg);
    CP_COMMIT();

    int wid = tid >> 5, lane = tid & 31;
    int wm = wid >> 1, wn = wid & 1;
    int lr = lane >> 2, lc = lane & 3;

    uint32_t aAddr0[2], bAddr0[4];
    {
        int ar = (lane & 15);
        int ac = (lane >> 4) * 4;
        int br = ((lane >> 4) & 1) * 8 + (lane & 7);
        int bc = ((lane >> 3) & 1) * 4;
        #pragma unroll
        for (int mt = 0; mt < 2; mt++)
            aAddr0[mt] = smem_u32(&As[0][wm*32 + mt*16 + ar][ac]);
        #pragma unroll
        for (int np = 0; np < 4; np++)
            bAddr0[np] = smem_u32(&Bs[0][wn*64 + np*16 + br][bc]);
    }

    float acc[2][8][4];
    #pragma unroll
    for (int mt = 0; mt < 2; mt++)
        #pragma unroll
        for (int nt = 0; nt < 8; nt++)
            #pragma unroll
            for (int j = 0; j < 4; j++) acc[mt][nt][j] = 0.f;

    CP_WAIT0();
    __syncthreads();

    int buf = 0;
    for (int kt = 0; kt < K; kt += 16) {
        bool more = (kt + 16) < K;
        if (more) {
            int nb = ABUF_STRIDE - buf;
            cpa16(aDst0 + nb, Ag + kt + 16);
            cpa16(bDst0 + nb, Bg + kt + 16);
            CP_COMMIT();
        }
        uint32_t afr[2][4];
        #pragma unroll
        for (int mt = 0; mt < 2; mt++)
            ldsm_x4(afr[mt][0], afr[mt][1], afr[mt][2], afr[mt][3], aAddr0[mt] + buf);
        uint32_t bfr[8][2];
        #pragma unroll
        for (int np = 0; np < 4; np++)
            ldsm_x4(bfr[2*np][0], bfr[2*np][1], bfr[2*np+1][0], bfr[2*np+1][1], bAddr0[np] + buf);
        #pragma unroll
        for (int mt = 0; mt < 2; mt++)
            #pragma unroll
            for (int nt = 0; nt < 8; nt++)
                mma_bf16(acc[mt][nt], afr[mt], bfr[nt]);
        if (more) CP_WAIT0();
        __syncthreads();
        buf = ABUF_STRIDE - buf;
    }

    float* C = (float*)Cv;
    bf16*  Cb = (bf16*)Cv;
    #pragma unroll
    for (int nt = 0; nt < 8; nt++) {
        int col = n0 + wn*64 + nt*8 + lc*2;
        float b0 = 0.f, b1 = 0.f;
        if (bias) { b0 = bias[col]; b1 = bias[col+1]; }
        #pragma unroll
        for (int mt = 0; mt < 2; mt++) {
            int r0 = m0 + wm*32 + mt*16 + lr;
            int r1 = r0 + 8;
            float v00 = acc[mt][nt][0] + b0;
            float v01 = acc[mt][nt][1] + b1;
            float v10 = acc[mt][nt][2] + b0;
            float v11 = acc[mt][nt][3] + b1;
            if (addend) {
                const float* ad0 = addend + (size_t)r0*N + col;
                const float* ad1 = addend + (size_t)r1*N + col;
                v00 += ad0[0]; v01 += ad0[1];
                v10 += ad1[0]; v11 += ad1[1];
            }
            if (flags & 1) {
                v00 = 0.5f*v00*(1.f + erff(v00*0.70710678118654752f));
                v01 = 0.5f*v01*(1.f + erff(v01*0.70710678118654752f));
                v10 = 0.5f*v10*(1.f + erff(v10*0.70710678118654752f));
                v11 = 0.5f*v11*(1.f + erff(v11*0.70710678118654752f));
            }
            if (flags & 16) {
                *reinterpret_cast<uint32_t*>(&Cb[(size_t)r0*N + col]) = packbf(v00, v01);
                *reinterpret_cast<uint32_t*>(&Cb[(size_t)r1*N + col]) = packbf(v10, v11);
            } else {
                *reinterpret_cast<float2*>(&C[(size_t)r0*N + col]) = make_float2(v00, v01);
                *reinterpret_cast<float2*>(&C[(size_t)r1*N + col]) = make_float2(v10, v11);
            }
        }
    }
}

// ---------------- bgemm64: bf16 GEMM, 128x64 block, cp.async + ldmatrix -----------------
// flags: bit0 gelu | bit2 transposed store | bit3 z-split
#define BBUF_STRIDE 3072   // 64*12*4 bytes
__global__ __launch_bounds__(256, 2) void bgemm64_kernel(
    const bf16* __restrict__ A, const bf16* __restrict__ B, float* __restrict__ C,
    const float* __restrict__ bias, const float* __restrict__ addend,
    int M, int N, int K, int flags)
{
    __shared__ uint32_t As[2][128][12];
    __shared__ uint32_t Bs[2][64][12];
    int tid = threadIdx.x;
    int m0 = blockIdx.y * 128, n0 = blockIdx.x * 64;
    if (flags & 8) {
        int z = blockIdx.z;
        A += (size_t)z * M * K;
        B += (size_t)z * N * K;
        C += (size_t)z * M * N;
    }

    int lrow = tid >> 1;
    int lk   = (tid & 1) * 8;
    const bf16* Ag = A + (size_t)(m0 + lrow) * K + lk;
    const bf16* Bg = B + (size_t)(n0 + lrow) * K + lk;   // valid for tid<128
    uint32_t aDst0 = smem_u32(&As[0][lrow][(tid & 1) * 4]);
    uint32_t bDst0 = (tid < 128) ? smem_u32(&Bs[0][lrow][(tid & 1) * 4]) : 0;

    cpa16(aDst0, Ag);
    if (tid < 128) cpa16(bDst0, Bg);
    CP_COMMIT();

    int wid = tid >> 5, lane = tid & 31;
    int lr = lane >> 2, lc = lane & 3;

    uint32_t aAddr0, bAddr0[4];
    {
        int ar = (lane & 15);
        int ac = (lane >> 4) * 4;
        int br = ((lane >> 4) & 1) * 8 + (lane & 7);
        int bc = ((lane >> 3) & 1) * 4;
        aAddr0 = smem_u32(&As[0][wid*16 + ar][ac]);
        #pragma unroll
        for (int np = 0; np < 4; np++)
            bAddr0[np] = smem_u32(&Bs[0][np*16 + br][bc]);
    }

    float acc[8][4];
    #pragma unroll
    for (int nt = 0; nt < 8; nt++)
        #pragma unroll
        for (int j = 0; j < 4; j++) acc[nt][j] = 0.f;

    CP_WAIT0();
    __syncthreads();

    int abuf = 0, bbuf = 0;
    for (int kt = 0; kt < K; kt += 16) {
        bool more = (kt + 16) < K;
        if (more) {
            cpa16(aDst0 + (ABUF_STRIDE - abuf), Ag + kt + 16);
            if (tid < 128) cpa16(bDst0 + (BBUF_STRIDE - bbuf), Bg + kt + 16);
            CP_COMMIT();
        }
        uint32_t afr[4];
        ldsm_x4(afr[0], afr[1], afr[2], afr[3], aAddr0 + abuf);
        uint32_t bfr[8][2];
        #pragma unroll
        for (int np = 0; np < 4; np++)
            ldsm_x4(bfr[2*np][0], bfr[2*np][1], bfr[2*np+1][0], bfr[2*np+1][1], bAddr0[np] + bbuf);
        #pragma unroll
        for (int nt = 0; nt < 8; nt++)
            mma_bf16(acc[nt], afr, bfr[nt]);
        if (more) CP_WAIT0();
        __syncthreads();
        abuf = ABUF_STRIDE - abuf;
        bbuf = BBUF_STRIDE - bbuf;
    }

    #pragma unroll
    for (int nt = 0; nt < 8; nt++) {
        int col = n0 + nt*8 + lc*2;
        float b0 = 0.f, b1 = 0.f;
        if (bias) { b0 = bias[col]; b1 = bias[col+1]; }
        int r0 = m0 + wid*16 + lr;
        int r1 = r0 + 8;
        float v00 = acc[nt][0] + b0;
        float v01 = acc[nt][1] + b1;
        float v10 = acc[nt][2] + b0;
        float v11 = acc[nt][3] + b1;
        if (addend) {
            const float* ad0 = addend + (size_t)r0*N + col;
            const float* ad1 = addend + (size_t)r1*N + col;
            v00 += ad0[0]; v01 += ad0[1];
            v10 += ad1[0]; v11 += ad1[1];
        }
        if (flags & 1) {
            v00 = 0.5f*v00*(1.f + erff(v00*0.70710678118654752f));
            v01 = 0.5f*v01*(1.f + erff(v01*0.70710678118654752f));
            v10 = 0.5f*v10*(1.f + erff(v10*0.70710678118654752f));
            v11 = 0.5f*v11*(1.f + erff(v11*0.70710678118654752f));
        }
        if (flags & 4) {
            int bt0 = r0 / NSP, nn0 = r0 % NSP;
            int bt1 = r1 / NSP, nn1 = r1 % NSP;
            C[((size_t)bt0*CDIM + col  )*NSP + nn0] = v00;
            C[((size_t)bt0*CDIM + col+1)*NSP + nn0] = v01;
            C[((size_t)bt1*CDIM + col  )*NSP + nn1] = v10;
            C[((size_t)bt1*CDIM + col+1)*NSP + nn1] = v11;
        } else {
            *reinterpret_cast<float2*>(&C[(size_t)r0*N + col]) = make_float2(v00, v01);
            *reinterpret_cast<float2*>(&C[(size_t)r1*N + col]) = make_float2(v10, v11);
        }
    }
}

// ---------------- conv4 depthwise + silu ----------------
__global__ __launch_bounds__(192) void conv_kernel(const float* __restrict__ scb,
                                                   const float* __restrict__ tcb)
{
    int m = blockIdx.y;
    int tid = threadIdx.x;
    int rl = tid / 96, v = tid % 96;
    int r = blockIdx.x * 2 + rl;
    int pos  = m ? ((r / NSP) & (TT-1)) : (r % NSP);
    int strd = m ? NSP : 1;
    const float* cb = m ? tcb : scb;
    float4 acc = *reinterpret_cast<const float4*>(&cb[4*v]);
    #pragma unroll
    for (int k = 0; k < 4; k++) {
        if (pos - 3 + k >= 0) {
            float4 xv = *reinterpret_cast<const float4*>(&g_xz[(size_t)(r - (3-k)*strd)*XZW + m*768 + 4*v]);
            float4 cw = *reinterpret_cast<const float4*>(&g_cwT[m][k*DI + 4*v]);
            acc.x = fmaf(cw.x, xv.x, acc.x);
            acc.y = fmaf(cw.y, xv.y, acc.y);
            acc.z = fmaf(cw.z, xv.z, acc.z);
            acc.w = fmaf(cw.w, xv.w, acc.w);
        }
    }
    acc.x = acc.x / (1.f + __expf(-acc.x));
    acc.y = acc.y / (1.f + __expf(-acc.y));
    acc.z = acc.z / (1.f + __expf(-acc.z));
    acc.w = acc.w / (1.f + __expf(-acc.w));
    *reinterpret_cast<float4*>(&g_u[m][(size_t)r*DI + 4*v]) = acc;
    uint2 pk = make_uint2(packbf(acc.x, acc.y), packbf(acc.z, acc.w));
    *reinterpret_cast<uint2*>(&g_u_bf[m][(size_t)r*DI + 4*v]) = pk;
}

// ---------------- delta ----------------
__global__ __launch_bounds__(384) void delta_kernel(const float* __restrict__ sdpb,
                                                    const float* __restrict__ tdpb)
{
    __shared__ float sw[DTR][DI];
    __shared__ float sdbc[16][DTR];
    int m = blockIdx.y;
    int r0 = blockIdx.x * 16;
    int d = threadIdx.x;
    const float* dpb = m ? tdpb : sdpb;
    #pragma unroll
    for (int rr = 0; rr < DTR; rr++)
        sw[rr][d] = g_dpwT[m][rr*DI + d];
    if (d < 16*DTR) {
        int t = d / DTR, c = d % DTR;
        sdbc[t][c] = g_dbc[m][(size_t)(r0 + t)*64 + c];
    }
    __syncthreads();
    float base = dpb[d];
    #pragma unroll 4
    for (int t = 0; t < 16; t++) {
        float acc = base;
        #pragma unroll
        for (int rr = 0; rr < DTR; rr++)
            acc = fmaf(sdbc[t][rr], sw[rr][d], acc);
        g_delta[m][(size_t)(r0 + t)*DI + d] = (acc > 15.f) ? acc : log1pf(__expf(acc));
    }
}

// ---------------- merged scans ----------------
#define SPATIAL_BLOCKS 768
__global__ __launch_bounds__(128) void scan_kernel(const float* __restrict__ sD,
                                                   const float* __restrict__ tD)
{
    int bx = blockIdx.x;
    int tid = threadIdx.x;

    if (bx < SPATIAL_BLOCKS) {
        __shared__ float sbuf[64][8];
        int s   = bx / 48;
        int dpg = bx % 48;
        int w = tid >> 5, lane = tid & 31;
        int sub = lane >> 4, n = lane & 15;
        int d = dpg*8 + w*2 + sub;
        int ycol0 = dpg*8;

        float a  = g_A[0][d*DS + n];
        float Dd = sD[d];
        const float* delta = g_delta[0];
        const float* u     = g_u[0];
        const float* dbc   = g_dbc[0];
        int base = s * NSP;

        float h = 0.f;
        for (int pos = 0; pos < NSP; pos += 4) {
            float dl[4], uu[4], Bv[4], Cv[4];
            #pragma unroll
            for (int j = 0; j < 4; j++) {
                size_t r = base + pos + j;
                dl[j] = __ldg(&delta[r*DI + d]);
                uu[j] = __ldg(&u[r*DI + d]);
                Bv[j] = __ldg(&dbc[r*64 + DTR + n]);
                Cv[j] = __ldg(&dbc[r*64 + DTR + DS + n]);
            }
            float dA[4], dBu[4];
            #pragma unroll
            for (int j = 0; j < 4; j++) {
                dA[j]  = __expf(dl[j] * a);
                dBu[j] = dl[j] * uu[j] * Bv[j];
            }
            float part[4];
            #pragma unroll
            for (int j = 0; j < 4; j++) {
                h = fmaf(h, dA[j], dBu[j]);
                part[j] = h * Cv[j];
            }
            #pragma unroll
            for (int off = 1; off <= 8; off <<= 1)
                #pragma unroll
                for (int j = 0; j < 4; j++)
                    part[j] += __shfl_xor_sync(0xffffffffu, part[j], off);
            if (n == 0) {
                #pragma unroll
                for (int j = 0; j < 4; j++)
                    sbuf[(pos + j) & 63][w*2 + sub] = part[j] + uu[j] * Dd;
            }
            if ((pos & 63) == 60) {
                __syncthreads();
                int p2 = tid >> 1, half = tid & 1;
                size_t r = base + (pos & ~63) + p2;
                float4 v = *reinterpret_cast<float4*>(&sbuf[p2][half*4]);
                float4 z4 = *reinterpret_cast<const float4*>(&g_xz[r*XZW + 384 + ycol0 + half*4]);
                v.x *= z4.x / (1.f + __expf(-z4.x));
                v.y *= z4.y / (1.f + __expf(-z4.y));
                v.z *= z4.z / (1.f + __expf(-z4.z));
                v.w *= z4.w / (1.f + __expf(-z4.w));
                uint2 pk = make_uint2(packbf(v.x, v.y), packbf(v.z, v.w));
                *reinterpret_cast<uint2*>(&g_y_bf[r*(2*DI) + ycol0 + half*4]) = pk;
                __syncthreads();
            }
        }
    } else {
        int b2 = bx - SPATIAL_BLOCKS;
        int seq = b2 / 3;
        int d = (b2 % 3) * 128 + tid;
        int lane = tid & 31;
        int b = seq / NSP, nsp = seq % NSP;
        int base = b * (TT*NSP) + nsp;

        float a[DS];
        #pragma unroll
        for (int q = 0; q < 4; q++)
            *reinterpret_cast<float4*>(&a[q*4]) = *reinterpret_cast<const float4*>(&g_A[1][d*DS + q*4]);
        float Dd = tD[d];
        const float* delta = g_delta[1];
        const float* u     = g_u[1];
        const float* dbc   = g_dbc[1];

        float h[DS];
        #pragma unroll
        for (int q = 0; q < DS; q++) h[q] = 0.f;

        for (int t = 0; t < TT; t++) {
            size_t r = base + (size_t)t * NSP;
            float dl = delta[r*DI + d];
            float uu = u[r*DI + d];
            float bc = dbc[r*64 + DTR + lane];
            float dlu = dl * uu;
            float y = 0.f;
            #pragma unroll
            for (int q = 0; q < DS; q++) {
                float Bn = __shfl_sync(0xffffffffu, bc, q);
                float Cn = __shfl_sync(0xffffffffu, bc, q + 16);
                float dA = __expf(dl * a[q]);
                h[q] = fmaf(h[q], dA, dlu * Bn);
                y = fmaf(h[q], Cn, y);
            }
            float z = g_xz[r*XZW + 1152 + d];
            float g = z / (1.f + __expf(-z));
            g_y_bf[r*(2*DI) + DI + d] = __float2bfloat16((y + uu * Dd) * g);
        }
    }
}

// ---------------- host launcher ----------------
extern "C" void kernel_launch(void* const* d_in, const int* in_sizes, int n_in,
                              void* d_out, int out_size)
{
    const float* x_in   = (const float*)d_in[0];
    const float* n1w    = (const float*)d_in[1];
    const float* n1b    = (const float*)d_in[2];
    const float* s_inw  = (const float*)d_in[3];
    const float* s_cw   = (const float*)d_in[4];
    const float* s_cb   = (const float*)d_in[5];
    const float* s_xpw  = (const float*)d_in[6];
    const float* s_dpw  = (const float*)d_in[7];
    const float* s_dpb  = (const float*)d_in[8];
    const float* s_Alog = (const float*)d_in[9];
    const float* s_D    = (const float*)d_in[10];
    const float* s_outw = (const float*)d_in[11];
    const float* t_inw  = (const float*)d_in[12];
    const float* t_cw   = (const float*)d_in[13];
    const float* t_cb   = (const float*)d_in[14];
    const float* t_xpw  = (const float*)d_in[15];
    const float* t_dpw  = (const float*)d_in[16];
    const float* t_dpb  = (const float*)d_in[17];
    const float* t_Alog = (const float*)d_in[18];
    const float* t_D    = (const float*)d_in[19];
    const float* t_outw = (const float*)d_in[20];
    const float* fw     = (const float*)d_in[21];
    const float* fb     = (const float*)d_in[22];
    const float* n2w    = (const float*)d_in[23];
    const float* n2b    = (const float*)d_in[24];
    const float* w1     = (const float*)d_in[25];
    const float* b1     = (const float*)d_in[26];
    const float* w2     = (const float*)d_in[27];
    const float* b2     = (const float*)d_in[28];
    float* out = (float*)d_out;

    bf16 *p_xn_bf, *p_u_bf, *p_y_bf, *p_h_bf, *p_hid_bf, *p_Win_bf, *p_W12_bf, *p_xpwP_bf, *p_w1_bf, *p_w2_bf;
    float *p_short, *p_xz, *p_x2, *p_dbc;
    cudaGetSymbolAddress((void**)&p_xn_bf, g_xn_bf);
    cudaGetSymbolAddress((void**)&p_short, g_short);
    cudaGetSymbolAddress((void**)&p_xz,    g_xz);
    cudaGetSymbolAddress((void**)&p_u_bf,  g_u_bf);
    cudaGetSymbolAddress((void**)&p_dbc,   g_dbc);
    cudaGetSymbolAddress((void**)&p_y_bf,  g_y_bf);
    cudaGetSymbolAddress((void**)&p_x2,    g_x2);
    cudaGetSymbolAddress((void**)&p_h_bf,  g_h_bf);
    cudaGetSymbolAddress((void**)&p_hid_bf,g_hid_bf);
    cudaGetSymbolAddress((void**)&p_Win_bf,g_Win_bf);
    cudaGetSymbolAddress((void**)&p_W12_bf,g_W12_bf);
    cudaGetSymbolAddress((void**)&p_xpwP_bf,g_xpwP_bf);
    cudaGetSymbolAddress((void**)&p_w1_bf, g_w1_bf);
    cudaGetSymbolAddress((void**)&p_w2_bf, g_w2_bf);

    // 0. prep + fold
    prep_kernel<<<1152, 256>>>(s_Alog, t_Alog, s_cw, t_cw, s_dpw, t_dpw,
                               s_inw, t_inw, s_xpw, t_xpw, w1, w2);
    fold_kernel<<<dim3(24, 2), 384>>>(fw, s_outw, t_outw);

    // 1. transpose + LN1
    ln1_kernel<<<dim3(16, 18), 256>>>(x_in, n1w, n1b);

    // 2. merged in_proj GEMM (N=1536, K=192)
    bgemm_kernel<<<dim3(XZW/128, TOK/128), 256>>>(p_xn_bf, p_Win_bf, p_xz, nullptr, nullptr, TOK, XZW, CDIM, 0);

    // 3. conv+silu
    conv_kernel<<<dim3(TOK/2, 2), 192>>>(s_cb, t_cb);

    // 4. dbc = u @ xpwP^T (N=64, K=384), both mambas via z
    bgemm64_kernel<<<dim3(1, TOK/128, 2), 256>>>(p_u_bf, p_xpwP_bf, p_dbc, nullptr, nullptr, TOK, 64, DI, 8);

    // 5. delta
    delta_kernel<<<dim3(TOK/16, 2), 384>>>(s_dpb, t_dpb);

    // 6. scans
    scan_kernel<<<SPATIAL_BLOCKS + 3456, 128>>>(s_D, t_D);

    // 7. fusion + residual (N=192, K=768)
    bgemm64_kernel<<<dim3(3, TOK/128), 256>>>(p_y_bf, p_W12_bf, p_x2, fb, p_short, TOK, CDIM, 2*DI, 0);

    // 8. LN2 + MLP
    ln2_kernel<<<TOK/4, 128>>>(p_x2, n2w, n2b);
    bgemm_kernel<<<dim3(MLPH/128, TOK/128), 256>>>(p_h_bf, p_w1_bf, p_hid_bf, b1, nullptr, TOK, MLPH, CDIM, 1 | 16);
    bgemm64_kernel<<<dim3(3, TOK/128), 256>>>(p_hid_bf, p_w2_bf, out, b2, p_x2, TOK, CDIM, MLPH, 4);
}

// round 12
// speedup vs baseline: 3.4491x; 1.0517x over previous
#include <cuda_runtime.h>
#include <cuda_bf16.h>
#include <math.h>
#include <stdint.h>

// ---------------- problem constants ----------------
#define BQ    2
#define TT    8
#define CDIM  192
#define NSP   576
#define TOK   9216
#define DI    384
#define DS    16
#define DTR   12
#define MLPH  768
#define XZW   1536

typedef __nv_bfloat16 bf16;

// ---------------- scratch ----------------
__device__ bf16  g_xn_bf[TOK*CDIM];
__device__ float g_short[TOK*CDIM];
__device__ float g_xz[TOK*XZW];
__device__ float g_u[2][TOK*DI];
__device__ bf16  g_u_bf[2][TOK*DI];
__device__ float g_delta[2][TOK*DI];
__device__ float g_dbc[2][TOK*64];
__device__ bf16  g_y_bf[TOK*2*DI];
__device__ float g_x2[TOK*CDIM];
__device__ bf16  g_h_bf[TOK*CDIM];
__device__ bf16  g_hid_bf[TOK*MLPH];
__device__ bf16  g_Win_bf[XZW*CDIM];
__device__ bf16  g_W12_bf[CDIM*2*DI];
__device__ bf16  g_xpwP_bf[2][64*DI];
__device__ bf16  g_w1_bf[MLPH*CDIM];
__device__ bf16  g_w2_bf[CDIM*MLPH];
__device__ float g_A[2][DI*DS];
__device__ float g_cwT[2][4*DI];
__device__ float g_dpwT[2][DTR*DI];

// ---------------- helpers ----------------
__device__ __forceinline__ uint32_t packbf(float lo, float hi) {
    uint32_t r;
    asm("cvt.rn.bf16x2.f32 %0, %1, %2;" : "=r"(r) : "f"(hi), "f"(lo));
    return r;
}
__device__ __forceinline__ void mma_bf16(float c[4], const uint32_t a[4], const uint32_t b[2]) {
    asm("mma.sync.aligned.m16n8k16.row.col.f32.bf16.bf16.f32 "
        "{%0,%1,%2,%3}, {%4,%5,%6,%7}, {%8,%9}, {%0,%1,%2,%3};"
        : "+f"(c[0]), "+f"(c[1]), "+f"(c[2]), "+f"(c[3])
        : "r"(a[0]), "r"(a[1]), "r"(a[2]), "r"(a[3]), "r"(b[0]), "r"(b[1]));
}
__device__ __forceinline__ void ldsm_x4(uint32_t& r0, uint32_t& r1, uint32_t& r2, uint32_t& r3,
                                        uint32_t addr) {
    asm volatile("ldmatrix.sync.aligned.m8n8.x4.shared.b16 {%0,%1,%2,%3}, [%4];"
                 : "=r"(r0), "=r"(r1), "=r"(r2), "=r"(r3) : "r"(addr));
}
__device__ __forceinline__ uint32_t smem_u32(const void* p) {
    return (uint32_t)__cvta_generic_to_shared(p);
}
__device__ __forceinline__ void cpa16(uint32_t dst, const void* src) {
    asm volatile("cp.async.ca.shared.global [%0], [%1], 16;" :: "r"(dst), "l"(src));
}
#define CP_COMMIT() asm volatile("cp.async.commit_group;" ::: "memory")
#define CP_WAIT2()  asm volatile("cp.async.wait_group 2;" ::: "memory")

// ---------------- prep ----------------
__global__ void prep_kernel(const float* __restrict__ sAlog, const float* __restrict__ tAlog,
                            const float* __restrict__ scw, const float* __restrict__ tcw,
                            const float* __restrict__ sdpw, const float* __restrict__ tdpw,
                            const float* __restrict__ sinw, const float* __restrict__ tinw,
                            const float* __restrict__ sxpw, const float* __restrict__ txpw,
                            const float* __restrict__ w1, const float* __restrict__ w2)
{
    int i = blockIdx.x * blockDim.x + threadIdx.x;
    if (i < 2*DI*DS) {
        int m = i / (DI*DS), j = i % (DI*DS);
        g_A[m][j] = -expf(m ? tAlog[j] : sAlog[j]);
    }
    if (i < 2*4*DI) {
        int m = i / (4*DI), rem = i % (4*DI);
        int k = rem / DI, d = rem % DI;
        g_cwT[m][k*DI + d] = (m ? tcw : scw)[d*4 + k];
    }
    if (i < 2*DTR*DI) {
        int m = i / (DTR*DI), rem = i % (DTR*DI);
        int rr = rem / DI, d = rem % DI;
        g_dpwT[m][rr*DI + d] = (m ? tdpw : sdpw)[d*DTR + rr];
    }
    if (i < 2*64*DI) {
        int m = i / (64*DI), rem = i % (64*DI);
        int row = rem / DI;
        g_xpwP_bf[m][rem] = __float2bfloat16(
            (row < DTR + 2*DS) ? (m ? txpw : sxpw)[rem] : 0.f);
    }
    if (i < XZW*CDIM) {
        int row = i / CDIM;
        g_Win_bf[i] = __float2bfloat16((row < 768) ? sinw[i] : tinw[i - 768*CDIM]);
    }
    if (i < MLPH*CDIM) g_w1_bf[i] = __float2bfloat16(w1[i]);
    if (i < CDIM*MLPH) g_w2_bf[i] = __float2bfloat16(w2[i]);
}

// ---------------- fold ----------------
__global__ __launch_bounds__(384) void fold_kernel(const float* __restrict__ fw,
                                                   const float* __restrict__ soutw,
                                                   const float* __restrict__ toutw)
{
    __shared__ float fwS[8][192];
    int m  = blockIdx.y;
    int c0 = blockIdx.x * 8;
    const float* ow = m ? toutw : soutw;
    int tid = threadIdx.x;
    for (int i = tid; i < 8*192; i += 384) {
        int c = i / 192, cp = i % 192;
        fwS[c][cp] = fw[(size_t)(c0 + c)*(2*CDIM) + m*CDIM + cp];
    }
    __syncthreads();
    float acc[8] = {0,0,0,0,0,0,0,0};
    #pragma unroll 4
    for (int cp = 0; cp < 192; cp++) {
        float owv = ow[(size_t)cp*DI + tid];
        #pragma unroll
        for (int c = 0; c < 8; c++) acc[c] = fmaf(fwS[c][cp], owv, acc[c]);
    }
    #pragma unroll
    for (int c = 0; c < 8; c++)
        g_W12_bf[(size_t)(c0 + c)*(2*DI) + m*DI + tid] = __float2bfloat16(acc[c]);
}

// ---------------- LN1 ----------------
__global__ __launch_bounds__(256) void ln1_kernel(const float* __restrict__ src,
                                                  const float* __restrict__ w, const float* __restrict__ b)
{
    __shared__ float s[CDIM][33];
    int bt = blockIdx.x;
    int n0 = blockIdx.y * 32;
    int tid = threadIdx.x;
    #pragma unroll
    for (int i = 0; i < 24; i++) {
        int idx = tid + 256*i;
        int c = idx >> 5, nl = idx & 31;
        s[c][nl] = src[((size_t)bt*CDIM + c)*NSP + n0 + nl];
    }
    __syncthreads();
    int warp = tid >> 5, lane = tid & 31;
    for (int jj = 0; jj < 4; jj++) {
        int tt = warp + 8*jj;
        float v[3][2];
        #pragma unroll
        for (int q = 0; q < 3; q++) {
            int c = 2*lane + 64*q;
            v[q][0] = s[c][tt];
            v[q][1] = s[c+1][tt];
        }
        float sum = 0.f;
        #pragma unroll
        for (int q = 0; q < 3; q++) sum += v[q][0] + v[q][1];
        #pragma unroll
        for (int o = 16; o > 0; o >>= 1) sum += __shfl_xor_sync(0xffffffffu, sum, o);
        float mean = sum * (1.f/CDIM);
        float qv = 0.f;
        #pragma unroll
        for (int q = 0; q < 3; q++) {
            float d0 = v[q][0]-mean, d1 = v[q][1]-mean;
            qv += d0*d0 + d1*d1;
        }
        #pragma unroll
        for (int o = 16; o > 0; o >>= 1) qv += __shfl_xor_sync(0xffffffffu, qv, o);
        float rstd = rsqrtf(qv * (1.f/CDIM) + 1e-5f);
        size_t tok = (size_t)bt*NSP + n0 + tt;
        #pragma unroll
        for (int q = 0; q < 3; q++) {
            int c = 2*lane + 64*q;
            float o0 = (v[q][0]-mean)*rstd*w[c]   + b[c];
            float o1 = (v[q][1]-mean)*rstd*w[c+1] + b[c+1];
            *reinterpret_cast<uint32_t*>(&g_xn_bf[tok*CDIM + c]) = packbf(o0, o1);
            *reinterpret_cast<float2*>(&g_short[tok*CDIM + c]) = make_float2(v[q][0], v[q][1]);
        }
    }
}

// ---------------- LN2 ----------------
__global__ void ln2_kernel(const float* __restrict__ src,
                           const float* __restrict__ w, const float* __restrict__ b)
{
    int tok  = blockIdx.x * 4 + (threadIdx.x >> 5);
    int lane = threadIdx.x & 31;
    const float* base = src + (size_t)tok * CDIM;
    float v[3][2];
    #pragma unroll
    for (int q = 0; q < 3; q++) {
        float2 t = *reinterpret_cast<const float2*>(&base[2*lane + 64*q]);
        v[q][0] = t.x; v[q][1] = t.y;
    }
    float s = 0.f;
    #pragma unroll
    for (int q = 0; q < 3; q++) s += v[q][0] + v[q][1];
    #pragma unroll
    for (int o = 16; o > 0; o >>= 1) s += __shfl_xor_sync(0xffffffffu, s, o);
    float mean = s * (1.f / CDIM);
    float qv = 0.f;
    #pragma unroll
    for (int q = 0; q < 3; q++) {
        float d0 = v[q][0]-mean, d1 = v[q][1]-mean;
        qv += d0*d0 + d1*d1;
    }
    #pragma unroll
    for (int o = 16; o > 0; o >>= 1) qv += __shfl_xor_sync(0xffffffffu, qv, o);
    float rstd = rsqrtf(qv * (1.f / CDIM) + 1e-5f);
    #pragma unroll
    for (int q = 0; q < 3; q++) {
        int c = 2*lane + 64*q;
        float o0 = (v[q][0]-mean)*rstd*w[c]   + b[c];
        float o1 = (v[q][1]-mean)*rstd*w[c+1] + b[c+1];
        *reinterpret_cast<uint32_t*>(&g_h_bf[(size_t)tok*CDIM + c]) = packbf(o0, o1);
    }
}

// ---------------- bgemm: bf16 GEMM, 128x128 block, 4-stage cp.async ---------------------
// flags: bit0 gelu | bit4 bf16 C store
#define ABUF_STRIDE 6144   // 128*12*4 bytes per stage
__global__ __launch_bounds__(256, 2) void bgemm_kernel(
    const bf16* __restrict__ A, const bf16* __restrict__ B, void* __restrict__ Cv,
    const float* __restrict__ bias, const float* __restrict__ addend,
    int M, int N, int K, int flags)
{
    __shared__ uint32_t As[4][128][12];
    __shared__ uint32_t Bs[4][128][12];
    int tid = threadIdx.x;
    int m0 = blockIdx.y * 128, n0 = blockIdx.x * 128;

    int lrow = tid >> 1;
    int lk   = (tid & 1) * 8;
    const bf16* Ag = A + (size_t)(m0 + lrow) * K + lk;
    const bf16* Bg = B + (size_t)(n0 + lrow) * K + lk;
    uint32_t aDst0 = smem_u32(&As[0][lrow][(tid & 1) * 4]);
    uint32_t bDst0 = smem_u32(&Bs[0][lrow][(tid & 1) * 4]);

    int ntiles = K >> 4;
    // prologue: stage tiles 0..2
    #pragma unroll
    for (int s = 0; s < 3; s++) {
        cpa16(aDst0 + s*ABUF_STRIDE, Ag + s*16);
        cpa16(bDst0 + s*ABUF_STRIDE, Bg + s*16);
        CP_COMMIT();
    }

    int wid = tid >> 5, lane = tid & 31;
    int wm = wid >> 1, wn = wid & 1;
    int lr = lane >> 2, lc = lane & 3;

    uint32_t aAddr0[2], bAddr0[4];
    {
        int ar = (lane & 15);
        int ac = (lane >> 4) * 4;
        int br = ((lane >> 4) & 1) * 8 + (lane & 7);
        int bc = ((lane >> 3) & 1) * 4;
        #pragma unroll
        for (int mt = 0; mt < 2; mt++)
            aAddr0[mt] = smem_u32(&As[0][wm*32 + mt*16 + ar][ac]);
        #pragma unroll
        for (int np = 0; np < 4; np++)
            bAddr0[np] = smem_u32(&Bs[0][wn*64 + np*16 + br][bc]);
    }

    float acc[2][8][4];
    #pragma unroll
    for (int mt = 0; mt < 2; mt++)
        #pragma unroll
        for (int nt = 0; nt < 8; nt++)
            #pragma unroll
            for (int j = 0; j < 4; j++) acc[mt][nt][j] = 0.f;

    for (int k = 0; k < ntiles; k++) {
        CP_WAIT2();
        __syncthreads();
        int buf = (k & 3) * ABUF_STRIDE;
        uint32_t afr[2][4];
        #pragma unroll
        for (int mt = 0; mt < 2; mt++)
            ldsm_x4(afr[mt][0], afr[mt][1], afr[mt][2], afr[mt][3], aAddr0[mt] + buf);
        uint32_t bfr[8][2];
        #pragma unroll
        for (int np = 0; np < 4; np++)
            ldsm_x4(bfr[2*np][0], bfr[2*np][1], bfr[2*np+1][0], bfr[2*np+1][1], bAddr0[np] + buf);
        #pragma unroll
        for (int mt = 0; mt < 2; mt++)
            #pragma unroll
            for (int nt = 0; nt < 8; nt++)
                mma_bf16(acc[mt][nt], afr[mt], bfr[nt]);
        int nk = k + 3;
        if (nk < ntiles) {
            int nb = (nk & 3) * ABUF_STRIDE;
            cpa16(aDst0 + nb, Ag + nk*16);
            cpa16(bDst0 + nb, Bg + nk*16);
        }
        CP_COMMIT();
    }

    float* C = (float*)Cv;
    bf16*  Cb = (bf16*)Cv;
    #pragma unroll
    for (int nt = 0; nt < 8; nt++) {
        int col = n0 + wn*64 + nt*8 + lc*2;
        float b0 = 0.f, b1 = 0.f;
        if (bias) { b0 = bias[col]; b1 = bias[col+1]; }
        #pragma unroll
        for (int mt = 0; mt < 2; mt++) {
            int r0 = m0 + wm*32 + mt*16 + lr;
            int r1 = r0 + 8;
            float v00 = acc[mt][nt][0] + b0;
            float v01 = acc[mt][nt][1] + b1;
            float v10 = acc[mt][nt][2] + b0;
            float v11 = acc[mt][nt][3] + b1;
            if (addend) {
                const float* ad0 = addend + (size_t)r0*N + col;
                const float* ad1 = addend + (size_t)r1*N + col;
                v00 += ad0[0]; v01 += ad0[1];
                v10 += ad1[0]; v11 += ad1[1];
            }
            if (flags & 1) {
                v00 = 0.5f*v00*(1.f + erff(v00*0.70710678118654752f));
                v01 = 0.5f*v01*(1.f + erff(v01*0.70710678118654752f));
                v10 = 0.5f*v10*(1.f + erff(v10*0.70710678118654752f));
                v11 = 0.5f*v11*(1.f + erff(v11*0.70710678118654752f));
            }
            if (flags & 16) {
                *reinterpret_cast<uint32_t*>(&Cb[(size_t)r0*N + col]) = packbf(v00, v01);
                *reinterpret_cast<uint32_t*>(&Cb[(size_t)r1*N + col]) = packbf(v10, v11);
            } else {
                *reinterpret_cast<float2*>(&C[(size_t)r0*N + col]) = make_float2(v00, v01);
                *reinterpret_cast<float2*>(&C[(size_t)r1*N + col]) = make_float2(v10, v11);
            }
        }
    }
}

// ---------------- bgemm64: bf16 GEMM, 128x64 block, 4-stage cp.async --------------------
// flags: bit0 gelu | bit2 transposed store | bit3 z-split
#define BBUF_STRIDE 3072   // 64*12*4 bytes per stage
__global__ __launch_bounds__(256, 2) void bgemm64_kernel(
    const bf16* __restrict__ A, const bf16* __restrict__ B, float* __restrict__ C,
    const float* __restrict__ bias, const float* __restrict__ addend,
    int M, int N, int K, int flags)
{
    __shared__ uint32_t As[4][128][12];
    __shared__ uint32_t Bs[4][64][12];
    int tid = threadIdx.x;
    int m0 = blockIdx.y * 128, n0 = blockIdx.x * 64;
    if (flags & 8) {
        int z = blockIdx.z;
        A += (size_t)z * M * K;
        B += (size_t)z * N * K;
        C += (size_t)z * M * N;
    }

    int lrow = tid >> 1;
    int lk   = (tid & 1) * 8;
    const bf16* Ag = A + (size_t)(m0 + lrow) * K + lk;
    const bf16* Bg = B + (size_t)(n0 + lrow) * K + lk;   // valid for tid<128
    uint32_t aDst0 = smem_u32(&As[0][lrow][(tid & 1) * 4]);
    uint32_t bDst0 = (tid < 128) ? smem_u32(&Bs[0][lrow][(tid & 1) * 4]) : 0;

    int ntiles = K >> 4;
    #pragma unroll
    for (int s = 0; s < 3; s++) {
        cpa16(aDst0 + s*ABUF_STRIDE, Ag + s*16);
        if (tid < 128) cpa16(bDst0 + s*BBUF_STRIDE, Bg + s*16);
        CP_COMMIT();
    }

    int wid = tid >> 5, lane = tid & 31;
    int lr = lane >> 2, lc = lane & 3;

    uint32_t aAddr0, bAddr0[4];
    {
        int ar = (lane & 15);
        int ac = (lane >> 4) * 4;
        int br = ((lane >> 4) & 1) * 8 + (lane & 7);
        int bc = ((lane >> 3) & 1) * 4;
        aAddr0 = smem_u32(&As[0][wid*16 + ar][ac]);
        #pragma unroll
        for (int np = 0; np < 4; np++)
            bAddr0[np] = smem_u32(&Bs[0][np*16 + br][bc]);
    }

    float acc[8][4];
    #pragma unroll
    for (int nt = 0; nt < 8; nt++)
        #pragma unroll
        for (int j = 0; j < 4; j++) acc[nt][j] = 0.f;

    for (int k = 0; k < ntiles; k++) {
        CP_WAIT2();
        __syncthreads();
        int ab = (k & 3) * ABUF_STRIDE;
        int bb = (k & 3) * BBUF_STRIDE;
        uint32_t afr[4];
        ldsm_x4(afr[0], afr[1], afr[2], afr[3], aAddr0 + ab);
        uint32_t bfr[8][2];
        #pragma unroll
        for (int np = 0; np < 4; np++)
            ldsm_x4(bfr[2*np][0], bfr[2*np][1], bfr[2*np+1][0], bfr[2*np+1][1], bAddr0[np] + bb);
        #pragma unroll
        for (int nt = 0; nt < 8; nt++)
            mma_bf16(acc[nt], afr, bfr[nt]);
        int nk = k + 3;
        if (nk < ntiles) {
            cpa16(aDst0 + (nk & 3)*ABUF_STRIDE, Ag + nk*16);
            if (tid < 128) cpa16(bDst0 + (nk & 3)*BBUF_STRIDE, Bg + nk*16);
        }
        CP_COMMIT();
    }

    #pragma unroll
    for (int nt = 0; nt < 8; nt++) {
        int col = n0 + nt*8 + lc*2;
        float b0 = 0.f, b1 = 0.f;
        if (bias) { b0 = bias[col]; b1 = bias[col+1]; }
        int r0 = m0 + wid*16 + lr;
        int r1 = r0 + 8;
        float v00 = acc[nt][0] + b0;
        float v01 = acc[nt][1] + b1;
        float v10 = acc[nt][2] + b0;
        float v11 = acc[nt][3] + b1;
        if (addend) {
            const float* ad0 = addend + (size_t)r0*N + col;
            const float* ad1 = addend + (size_t)r1*N + col;
            v00 += ad0[0]; v01 += ad0[1];
            v10 += ad1[0]; v11 += ad1[1];
        }
        if (flags & 1) {
            v00 = 0.5f*v00*(1.f + erff(v00*0.70710678118654752f));
            v01 = 0.5f*v01*(1.f + erff(v01*0.70710678118654752f));
            v10 = 0.5f*v10*(1.f + erff(v10*0.70710678118654752f));
            v11 = 0.5f*v11*(1.f + erff(v11*0.70710678118654752f));
        }
        if (flags & 4) {
            int bt0 = r0 / NSP, nn0 = r0 % NSP;
            int bt1 = r1 / NSP, nn1 = r1 % NSP;
            C[((size_t)bt0*CDIM + col  )*NSP + nn0] = v00;
            C[((size_t)bt0*CDIM + col+1)*NSP + nn0] = v01;
            C[((size_t)bt1*CDIM + col  )*NSP + nn1] = v10;
            C[((size_t)bt1*CDIM + col+1)*NSP + nn1] = v11;
        } else {
            *reinterpret_cast<float2*>(&C[(size_t)r0*N + col]) = make_float2(v00, v01);
            *reinterpret_cast<float2*>(&C[(size_t)r1*N + col]) = make_float2(v10, v11);
        }
    }
}

// ---------------- conv4 depthwise + silu ----------------
__global__ __launch_bounds__(192) void conv_kernel(const float* __restrict__ scb,
                                                   const float* __restrict__ tcb)
{
    int m = blockIdx.y;
    int tid = threadIdx.x;
    int rl = tid / 96, v = tid % 96;
    int r = blockIdx.x * 2 + rl;
    int pos  = m ? ((r / NSP) & (TT-1)) : (r % NSP);
    int strd = m ? NSP : 1;
    const float* cb = m ? tcb : scb;
    float4 acc = *reinterpret_cast<const float4*>(&cb[4*v]);
    #pragma unroll
    for (int k = 0; k < 4; k++) {
        if (pos - 3 + k >= 0) {
            float4 xv = *reinterpret_cast<const float4*>(&g_xz[(size_t)(r - (3-k)*strd)*XZW + m*768 + 4*v]);
            float4 cw = *reinterpret_cast<const float4*>(&g_cwT[m][k*DI + 4*v]);
            acc.x = fmaf(cw.x, xv.x, acc.x);
            acc.y = fmaf(cw.y, xv.y, acc.y);
            acc.z = fmaf(cw.z, xv.z, acc.z);
            acc.w = fmaf(cw.w, xv.w, acc.w);
        }
    }
    acc.x = acc.x / (1.f + __expf(-acc.x));
    acc.y = acc.y / (1.f + __expf(-acc.y));
    acc.z = acc.z / (1.f + __expf(-acc.z));
    acc.w = acc.w / (1.f + __expf(-acc.w));
    *reinterpret_cast<float4*>(&g_u[m][(size_t)r*DI + 4*v]) = acc;
    uint2 pk = make_uint2(packbf(acc.x, acc.y), packbf(acc.z, acc.w));
    *reinterpret_cast<uint2*>(&g_u_bf[m][(size_t)r*DI + 4*v]) = pk;
}

// ---------------- delta ----------------
__global__ __launch_bounds__(384) void delta_kernel(const float* __restrict__ sdpb,
                                                    const float* __restrict__ tdpb)
{
    __shared__ float sw[DTR][DI];
    __shared__ float sdbc[16][DTR];
    int m = blockIdx.y;
    int r0 = blockIdx.x * 16;
    int d = threadIdx.x;
    const float* dpb = m ? tdpb : sdpb;
    #pragma unroll
    for (int rr = 0; rr < DTR; rr++)
        sw[rr][d] = g_dpwT[m][rr*DI + d];
    if (d < 16*DTR) {
        int t = d / DTR, c = d % DTR;
        sdbc[t][c] = g_dbc[m][(size_t)(r0 + t)*64 + c];
    }
    __syncthreads();
    float base = dpb[d];
    #pragma unroll 4
    for (int t = 0; t < 16; t++) {
        float acc = base;
        #pragma unroll
        for (int rr = 0; rr < DTR; rr++)
            acc = fmaf(sdbc[t][rr], sw[rr][d], acc);
        g_delta[m][(size_t)(r0 + t)*DI + d] = (acc > 15.f) ? acc : log1pf(__expf(acc));
    }
}

// ---------------- merged scans ----------------
#define SPATIAL_BLOCKS 768
__global__ __launch_bounds__(128) void scan_kernel(const float* __restrict__ sD,
                                                   const float* __restrict__ tD)
{
    int bx = blockIdx.x;
    int tid = threadIdx.x;

    if (bx < SPATIAL_BLOCKS) {
        __shared__ float sbuf[64][8];
        int s   = bx / 48;
        int dpg = bx % 48;
        int w = tid >> 5, lane = tid & 31;
        int sub = lane >> 4, n = lane & 15;
        int d = dpg*8 + w*2 + sub;
        int ycol0 = dpg*8;

        float a  = g_A[0][d*DS + n];
        float Dd = sD[d];
        const float* delta = g_delta[0];
        const float* u     = g_u[0];
        const float* dbc   = g_dbc[0];
        int base = s * NSP;

        float h = 0.f;
        for (int pos = 0; pos < NSP; pos += 4) {
            float dl[4], uu[4], Bv[4], Cv[4];
            #pragma unroll
            for (int j = 0; j < 4; j++) {
                size_t r = base + pos + j;
                dl[j] = __ldg(&delta[r*DI + d]);
                uu[j] = __ldg(&u[r*DI + d]);
                Bv[j] = __ldg(&dbc[r*64 + DTR + n]);
                Cv[j] = __ldg(&dbc[r*64 + DTR + DS + n]);
            }
            float dA[4], dBu[4];
            #pragma unroll
            for (int j = 0; j < 4; j++) {
                dA[j]  = __expf(dl[j] * a);
                dBu[j] = dl[j] * uu[j] * Bv[j];
            }
            float part[4];
            #pragma unroll
            for (int j = 0; j < 4; j++) {
                h = fmaf(h, dA[j], dBu[j]);
                part[j] = h * Cv[j];
            }
            #pragma unroll
            for (int off = 1; off <= 8; off <<= 1)
                #pragma unroll
                for (int j = 0; j < 4; j++)
                    part[j] += __shfl_xor_sync(0xffffffffu, part[j], off);
            if (n == 0) {
                #pragma unroll
                for (int j = 0; j < 4; j++)
                    sbuf[(pos + j) & 63][w*2 + sub] = part[j] + uu[j] * Dd;
            }
            if ((pos & 63) == 60) {
                __syncthreads();
                int p2 = tid >> 1, half = tid & 1;
                size_t r = base + (pos & ~63) + p2;
                float4 v = *reinterpret_cast<float4*>(&sbuf[p2][half*4]);
                float4 z4 = *reinterpret_cast<const float4*>(&g_xz[r*XZW + 384 + ycol0 + half*4]);
                v.x *= z4.x / (1.f + __expf(-z4.x));
                v.y *= z4.y / (1.f + __expf(-z4.y));
                v.z *= z4.z / (1.f + __expf(-z4.z));
                v.w *= z4.w / (1.f + __expf(-z4.w));
                uint2 pk = make_uint2(packbf(v.x, v.y), packbf(v.z, v.w));
                *reinterpret_cast<uint2*>(&g_y_bf[r*(2*DI) + ycol0 + half*4]) = pk;
                __syncthreads();
            }
        }
    } else {
        int b2 = bx - SPATIAL_BLOCKS;
        int seq = b2 / 3;
        int d = (b2 % 3) * 128 + tid;
        int lane = tid & 31;
        int b = seq / NSP, nsp = seq % NSP;
        int base = b * (TT*NSP) + nsp;

        float a[DS];
        #pragma unroll
        for (int q = 0; q < 4; q++)
            *reinterpret_cast<float4*>(&a[q*4]) = *reinterpret_cast<const float4*>(&g_A[1][d*DS + q*4]);
        float Dd = tD[d];
        const float* delta = g_delta[1];
        const float* u     = g_u[1];
        const float* dbc   = g_dbc[1];

        float h[DS];
        #pragma unroll
        for (int q = 0; q < DS; q++) h[q] = 0.f;

        for (int t = 0; t < TT; t++) {
            size_t r = base + (size_t)t * NSP;
            float dl = delta[r*DI + d];
            float uu = u[r*DI + d];
            float bc = dbc[r*64 + DTR + lane];
            float dlu = dl * uu;
            float y = 0.f;
            #pragma unroll
            for (int q = 0; q < DS; q++) {
                float Bn = __shfl_sync(0xffffffffu, bc, q);
                float Cn = __shfl_sync(0xffffffffu, bc, q + 16);
                float dA = __expf(dl * a[q]);
                h[q] = fmaf(h[q], dA, dlu * Bn);
                y = fmaf(h[q], Cn, y);
            }
            float z = g_xz[r*XZW + 1152 + d];
            float g = z / (1.f + __expf(-z));
            g_y_bf[r*(2*DI) + DI + d] = __float2bfloat16((y + uu * Dd) * g);
        }
    }
}

// ---------------- host launcher ----------------
extern "C" void kernel_launch(void* const* d_in, const int* in_sizes, int n_in,
                              void* d_out, int out_size)
{
    const float* x_in   = (const float*)d_in[0];
    const float* n1w    = (const float*)d_in[1];
    const float* n1b    = (const float*)d_in[2];
    const float* s_inw  = (const float*)d_in[3];
    const float* s_cw   = (const float*)d_in[4];
    const float* s_cb   = (const float*)d_in[5];
    const float* s_xpw  = (const float*)d_in[6];
    const float* s_dpw  = (const float*)d_in[7];
    const float* s_dpb  = (const float*)d_in[8];
    const float* s_Alog = (const float*)d_in[9];
    const float* s_D    = (const float*)d_in[10];
    const float* s_outw = (const float*)d_in[11];
    const float* t_inw  = (const float*)d_in[12];
    const float* t_cw   = (const float*)d_in[13];
    const float* t_cb   = (const float*)d_in[14];
    const float* t_xpw  = (const float*)d_in[15];
    const float* t_dpw  = (const float*)d_in[16];
    const float* t_dpb  = (const float*)d_in[17];
    const float* t_Alog = (const float*)d_in[18];
    const float* t_D    = (const float*)d_in[19];
    const float* t_outw = (const float*)d_in[20];
    const float* fw     = (const float*)d_in[21];
    const float* fb     = (const float*)d_in[22];
    const float* n2w    = (const float*)d_in[23];
    const float* n2b    = (const float*)d_in[24];
    const float* w1     = (const float*)d_in[25];
    const float* b1     = (const float*)d_in[26];
    const float* w2     = (const float*)d_in[27];
    const float* b2     = (const float*)d_in[28];
    float* out = (float*)d_out;

    bf16 *p_xn_bf, *p_u_bf, *p_y_bf, *p_h_bf, *p_hid_bf, *p_Win_bf, *p_W12_bf, *p_xpwP_bf, *p_w1_bf, *p_w2_bf;
    float *p_short, *p_xz, *p_x2, *p_dbc;
    cudaGetSymbolAddress((void**)&p_xn_bf, g_xn_bf);
    cudaGetSymbolAddress((void**)&p_short, g_short);
    cudaGetSymbolAddress((void**)&p_xz,    g_xz);
    cudaGetSymbolAddress((void**)&p_u_bf,  g_u_bf);
    cudaGetSymbolAddress((void**)&p_dbc,   g_dbc);
    cudaGetSymbolAddress((void**)&p_y_bf,  g_y_bf);
    cudaGetSymbolAddress((void**)&p_x2,    g_x2);
    cudaGetSymbolAddress((void**)&p_h_bf,  g_h_bf);
    cudaGetSymbolAddress((void**)&p_hid_bf,g_hid_bf);
    cudaGetSymbolAddress((void**)&p_Win_bf,g_Win_bf);
    cudaGetSymbolAddress((void**)&p_W12_bf,g_W12_bf);
    cudaGetSymbolAddress((void**)&p_xpwP_bf,g_xpwP_bf);
    cudaGetSymbolAddress((void**)&p_w1_bf, g_w1_bf);
    cudaGetSymbolAddress((void**)&p_w2_bf, g_w2_bf);

    // 0. prep + fold
    prep_kernel<<<1152, 256>>>(s_Alog, t_Alog, s_cw, t_cw, s_dpw, t_dpw,
                               s_inw, t_inw, s_xpw, t_xpw, w1, w2);
    fold_kernel<<<dim3(24, 2), 384>>>(fw, s_outw, t_outw);

    // 1. transpose + LN1
    ln1_kernel<<<dim3(16, 18), 256>>>(x_in, n1w, n1b);

    // 2. merged in_proj GEMM (N=1536, K=192)
    bgemm_kernel<<<dim3(XZW/128, TOK/128), 256>>>(p_xn_bf, p_Win_bf, p_xz, nullptr, nullptr, TOK, XZW, CDIM, 0);

    // 3. conv+silu
    conv_kernel<<<dim3(TOK/2, 2), 192>>>(s_cb, t_cb);

    // 4. dbc = u @ xpwP^T (N=64, K=384), both mambas via z
    bgemm64_kernel<<<dim3(1, TOK/128, 2), 256>>>(p_u_bf, p_xpwP_bf, p_dbc, nullptr, nullptr, TOK, 64, DI, 8);

    // 5. delta
    delta_kernel<<<dim3(TOK/16, 2), 384>>>(s_dpb, t_dpb);

    // 6. scans
    scan_kernel<<<SPATIAL_BLOCKS + 3456, 128>>>(s_D, t_D);

    // 7. fusion + residual (N=192, K=768)
    bgemm64_kernel<<<dim3(3, TOK/128), 256>>>(p_y_bf, p_W12_bf, p_x2, fb, p_short, TOK, CDIM, 2*DI, 0);

    // 8. LN2 + MLP
    ln2_kernel<<<TOK/4, 128>>>(p_x2, n2w, n2b);
    bgemm_kernel<<<dim3(MLPH/128, TOK/128), 256>>>(p_h_bf, p_w1_bf, p_hid_bf, b1, nullptr, TOK, MLPH, CDIM, 1 | 16);
    bgemm64_kernel<<<dim3(3, TOK/128), 256>>>(p_hid_bf, p_w2_bf, out, b2, p_x2, TOK, CDIM, MLPH, 4);
}

// round 13
// speedup vs baseline: 3.5146x; 1.0190x over previous
#include <cuda_runtime.h>
#include <cuda_bf16.h>
#include <math.h>
#include <stdint.h>

// ---------------- problem constants ----------------
#define BQ    2
#define TT    8
#define CDIM  192
#define NSP   576
#define TOK   9216
#define DI    384
#define DS    16
#define DTR   12
#define MLPH  768
#define XZW   1536

typedef __nv_bfloat16 bf16;

// ---------------- scratch ----------------
__device__ bf16  g_xn_bf[TOK*CDIM];
__device__ float g_short[TOK*CDIM];
__device__ float g_xz[TOK*XZW];
__device__ float g_u[2][TOK*DI];
__device__ bf16  g_u_bf[2][TOK*DI];
__device__ float g_delta[2][TOK*DI];
__device__ float g_dbc[2][TOK*64];
__device__ bf16  g_y_bf[TOK*2*DI];
__device__ float g_x2[TOK*CDIM];
__device__ bf16  g_h_bf[TOK*CDIM];
__device__ bf16  g_hid_bf[TOK*MLPH];
__device__ bf16  g_Win_bf[XZW*CDIM];
__device__ bf16  g_W12_bf[CDIM*2*DI];
__device__ bf16  g_xpwP_bf[2][64*DI];
__device__ bf16  g_w1_bf[MLPH*CDIM];
__device__ bf16  g_w2_bf[CDIM*MLPH];
__device__ float g_A[2][DI*DS];
__device__ float g_cwT[2][4*DI];
__device__ float g_dpwT[2][DTR*DI];

// ---------------- helpers ----------------
__device__ __forceinline__ uint32_t packbf(float lo, float hi) {
    uint32_t r;
    asm("cvt.rn.bf16x2.f32 %0, %1, %2;" : "=r"(r) : "f"(hi), "f"(lo));
    return r;
}
__device__ __forceinline__ void mma_bf16(float c[4], const uint32_t a[4], const uint32_t b[2]) {
    asm("mma.sync.aligned.m16n8k16.row.col.f32.bf16.bf16.f32 "
        "{%0,%1,%2,%3}, {%4,%5,%6,%7}, {%8,%9}, {%0,%1,%2,%3};"
        : "+f"(c[0]), "+f"(c[1]), "+f"(c[2]), "+f"(c[3])
        : "r"(a[0]), "r"(a[1]), "r"(a[2]), "r"(a[3]), "r"(b[0]), "r"(b[1]));
}
__device__ __forceinline__ void ldsm_x4(uint32_t& r0, uint32_t& r1, uint32_t& r2, uint32_t& r3,
                                        uint32_t addr) {
    asm volatile("ldmatrix.sync.aligned.m8n8.x4.shared.b16 {%0,%1,%2,%3}, [%4];"
                 : "=r"(r0), "=r"(r1), "=r"(r2), "=r"(r3) : "r"(addr));
}
__device__ __forceinline__ uint32_t smem_u32(const void* p) {
    return (uint32_t)__cvta_generic_to_shared(p);
}
__device__ __forceinline__ void cpa16(uint32_t dst, const void* src) {
    asm volatile("cp.async.ca.shared.global [%0], [%1], 16;" :: "r"(dst), "l"(src));
}
#define CP_COMMIT() asm volatile("cp.async.commit_group;" ::: "memory")
#define CP_WAIT1()  asm volatile("cp.async.wait_group 1;" ::: "memory")

// ---------------- prep ----------------
__global__ void prep_kernel(const float* __restrict__ sAlog, const float* __restrict__ tAlog,
                            const float* __restrict__ scw, const float* __restrict__ tcw,
                            const float* __restrict__ sdpw, const float* __restrict__ tdpw,
                            const float* __restrict__ sinw, const float* __restrict__ tinw,
                            const float* __restrict__ sxpw, const float* __restrict__ txpw,
                            const float* __restrict__ w1, const float* __restrict__ w2)
{
    int i = blockIdx.x * blockDim.x + threadIdx.x;
    if (i < 2*DI*DS) {
        int m = i / (DI*DS), j = i % (DI*DS);
        g_A[m][j] = -expf(m ? tAlog[j] : sAlog[j]);
    }
    if (i < 2*4*DI) {
        int m = i / (4*DI), rem = i % (4*DI);
        int k = rem / DI, d = rem % DI;
        g_cwT[m][k*DI + d] = (m ? tcw : scw)[d*4 + k];
    }
    if (i < 2*DTR*DI) {
        int m = i / (DTR*DI), rem = i % (DTR*DI);
        int rr = rem / DI, d = rem % DI;
        g_dpwT[m][rr*DI + d] = (m ? tdpw : sdpw)[d*DTR + rr];
    }
    if (i < 2*64*DI) {
        int m = i / (64*DI), rem = i % (64*DI);
        int row = rem / DI;
        g_xpwP_bf[m][rem] = __float2bfloat16(
            (row < DTR + 2*DS) ? (m ? txpw : sxpw)[rem] : 0.f);
    }
    if (i < XZW*CDIM) {
        int row = i / CDIM;
        g_Win_bf[i] = __float2bfloat16((row < 768) ? sinw[i] : tinw[i - 768*CDIM]);
    }
    if (i < MLPH*CDIM) g_w1_bf[i] = __float2bfloat16(w1[i]);
    if (i < CDIM*MLPH) g_w2_bf[i] = __float2bfloat16(w2[i]);
}

// ---------------- fold ----------------
__global__ __launch_bounds__(384) void fold_kernel(const float* __restrict__ fw,
                                                   const float* __restrict__ soutw,
                                                   const float* __restrict__ toutw)
{
    __shared__ float fwS[8][192];
    int m  = blockIdx.y;
    int c0 = blockIdx.x * 8;
    const float* ow = m ? toutw : soutw;
    int tid = threadIdx.x;
    for (int i = tid; i < 8*192; i += 384) {
        int c = i / 192, cp = i % 192;
        fwS[c][cp] = fw[(size_t)(c0 + c)*(2*CDIM) + m*CDIM + cp];
    }
    __syncthreads();
    float acc[8] = {0,0,0,0,0,0,0,0};
    #pragma unroll 4
    for (int cp = 0; cp < 192; cp++) {
        float owv = ow[(size_t)cp*DI + tid];
        #pragma unroll
        for (int c = 0; c < 8; c++) acc[c] = fmaf(fwS[c][cp], owv, acc[c]);
    }
    #pragma unroll
    for (int c = 0; c < 8; c++)
        g_W12_bf[(size_t)(c0 + c)*(2*DI) + m*DI + tid] = __float2bfloat16(acc[c]);
}

// ---------------- LN1 ----------------
__global__ __launch_bounds__(256) void ln1_kernel(const float* __restrict__ src,
                                                  const float* __restrict__ w, const float* __restrict__ b)
{
    __shared__ float s[CDIM][33];
    int bt = blockIdx.x;
    int n0 = blockIdx.y * 32;
    int tid = threadIdx.x;
    #pragma unroll
    for (int i = 0; i < 24; i++) {
        int idx = tid + 256*i;
        int c = idx >> 5, nl = idx & 31;
        s[c][nl] = src[((size_t)bt*CDIM + c)*NSP + n0 + nl];
    }
    __syncthreads();
    int warp = tid >> 5, lane = tid & 31;
    for (int jj = 0; jj < 4; jj++) {
        int tt = warp + 8*jj;
        float v[3][2];
        #pragma unroll
        for (int q = 0; q < 3; q++) {
            int c = 2*lane + 64*q;
            v[q][0] = s[c][tt];
            v[q][1] = s[c+1][tt];
        }
        float sum = 0.f;
        #pragma unroll
        for (int q = 0; q < 3; q++) sum += v[q][0] + v[q][1];
        #pragma unroll
        for (int o = 16; o > 0; o >>= 1) sum += __shfl_xor_sync(0xffffffffu, sum, o);
        float mean = sum * (1.f/CDIM);
        float qv = 0.f;
        #pragma unroll
        for (int q = 0; q < 3; q++) {
            float d0 = v[q][0]-mean, d1 = v[q][1]-mean;
            qv += d0*d0 + d1*d1;
        }
        #pragma unroll
        for (int o = 16; o > 0; o >>= 1) qv += __shfl_xor_sync(0xffffffffu, qv, o);
        float rstd = rsqrtf(qv * (1.f/CDIM) + 1e-5f);
        size_t tok = (size_t)bt*NSP + n0 + tt;
        #pragma unroll
        for (int q = 0; q < 3; q++) {
            int c = 2*lane + 64*q;
            float o0 = (v[q][0]-mean)*rstd*w[c]   + b[c];
            float o1 = (v[q][1]-mean)*rstd*w[c+1] + b[c+1];
            *reinterpret_cast<uint32_t*>(&g_xn_bf[tok*CDIM + c]) = packbf(o0, o1);
            *reinterpret_cast<float2*>(&g_short[tok*CDIM + c]) = make_float2(v[q][0], v[q][1]);
        }
    }
}

// ---------------- LN2 ----------------
__global__ void ln2_kernel(const float* __restrict__ src,
                           const float* __restrict__ w, const float* __restrict__ b)
{
    int tok  = blockIdx.x * 4 + (threadIdx.x >> 5);
    int lane = threadIdx.x & 31;
    const float* base = src + (size_t)tok * CDIM;
    float v[3][2];
    #pragma unroll
    for (int q = 0; q < 3; q++) {
        float2 t = *reinterpret_cast<const float2*>(&base[2*lane + 64*q]);
        v[q][0] = t.x; v[q][1] = t.y;
    }
    float s = 0.f;
    #pragma unroll
    for (int q = 0; q < 3; q++) s += v[q][0] + v[q][1];
    #pragma unroll
    for (int o = 16; o > 0; o >>= 1) s += __shfl_xor_sync(0xffffffffu, s, o);
    float mean = s * (1.f / CDIM);
    float qv = 0.f;
    #pragma unroll
    for (int q = 0; q < 3; q++) {
        float d0 = v[q][0]-mean, d1 = v[q][1]-mean;
        qv += d0*d0 + d1*d1;
    }
    #pragma unroll
    for (int o = 16; o > 0; o >>= 1) qv += __shfl_xor_sync(0xffffffffu, qv, o);
    float rstd = rsqrtf(qv * (1.f / CDIM) + 1e-5f);
    #pragma unroll
    for (int q = 0; q < 3; q++) {
        int c = 2*lane + 64*q;
        float o0 = (v[q][0]-mean)*rstd*w[c]   + b[c];
        float o1 = (v[q][1]-mean)*rstd*w[c+1] + b[c+1];
        *reinterpret_cast<uint32_t*>(&g_h_bf[(size_t)tok*CDIM + c]) = packbf(o0, o1);
    }
}

// ---------------- bgemm: bf16 GEMM, 128x128 block, Ktile=32, 3-stage cp.async -----------
// flags: bit0 gelu | bit4 bf16 C store
#define ASTRIDE 10240   // 128*20*4 bytes per stage
__global__ __launch_bounds__(256, 2) void bgemm_kernel(
    const bf16* __restrict__ A, const bf16* __restrict__ B, void* __restrict__ Cv,
    const float* __restrict__ bias, const float* __restrict__ addend,
    int M, int N, int K, int flags)
{
    __shared__ uint32_t As[3][128][20];
    __shared__ uint32_t Bs[3][128][20];
    int tid = threadIdx.x;
    int m0 = blockIdx.y * 128, n0 = blockIdx.x * 128;

    int lrow = tid >> 1;
    int lk   = (tid & 1) * 16;           // bf16 element offset within 32-wide row
    int kb   = (tid & 1) * 8;            // uint32 col offset
    const bf16* Ag = A + (size_t)(m0 + lrow) * K + lk;
    const bf16* Bg = B + (size_t)(n0 + lrow) * K + lk;
    uint32_t aDst0 = smem_u32(&As[0][lrow][kb]);
    uint32_t bDst0 = smem_u32(&Bs[0][lrow][kb]);

    int ntiles = K >> 5;
    // prologue: stage tiles 0..1
    #pragma unroll
    for (int s = 0; s < 2; s++) {
        cpa16(aDst0 + s*ASTRIDE,      Ag + s*32);
        cpa16(aDst0 + s*ASTRIDE + 16, Ag + s*32 + 8);
        cpa16(bDst0 + s*ASTRIDE,      Bg + s*32);
        cpa16(bDst0 + s*ASTRIDE + 16, Bg + s*32 + 8);
        CP_COMMIT();
    }

    int wid = tid >> 5, lane = tid & 31;
    int wm = wid >> 1, wn = wid & 1;
    int lr = lane >> 2, lc = lane & 3;

    uint32_t aAddr0[2], bAddr0[4];
    {
        int ar = (lane & 15);
        int ac = (lane >> 4) * 4;
        int br = ((lane >> 4) & 1) * 8 + (lane & 7);
        int bc = ((lane >> 3) & 1) * 4;
        #pragma unroll
        for (int mt = 0; mt < 2; mt++)
            aAddr0[mt] = smem_u32(&As[0][wm*32 + mt*16 + ar][ac]);
        #pragma unroll
        for (int np = 0; np < 4; np++)
            bAddr0[np] = smem_u32(&Bs[0][wn*64 + np*16 + br][bc]);
    }

    float acc[2][8][4];
    #pragma unroll
    for (int mt = 0; mt < 2; mt++)
        #pragma unroll
        for (int nt = 0; nt < 8; nt++)
            #pragma unroll
            for (int j = 0; j < 4; j++) acc[mt][nt][j] = 0.f;

    for (int k = 0; k < ntiles; k++) {
        CP_WAIT1();
        __syncthreads();
        int buf = (k % 3) * ASTRIDE;
        #pragma unroll
        for (int ks = 0; ks < 2; ks++) {
            int off = buf + ks*32;
            uint32_t afr[2][4];
            #pragma unroll
            for (int mt = 0; mt < 2; mt++)
                ldsm_x4(afr[mt][0], afr[mt][1], afr[mt][2], afr[mt][3], aAddr0[mt] + off);
            uint32_t bfr[8][2];
            #pragma unroll
            for (int np = 0; np < 4; np++)
                ldsm_x4(bfr[2*np][0], bfr[2*np][1], bfr[2*np+1][0], bfr[2*np+1][1], bAddr0[np] + off);
            #pragma unroll
            for (int mt = 0; mt < 2; mt++)
                #pragma unroll
                for (int nt = 0; nt < 8; nt++)
                    mma_bf16(acc[mt][nt], afr[mt], bfr[nt]);
        }
        int nk = k + 2;
        if (nk < ntiles) {
            int nb = (nk % 3) * ASTRIDE;
            cpa16(aDst0 + nb,      Ag + nk*32);
            cpa16(aDst0 + nb + 16, Ag + nk*32 + 8);
            cpa16(bDst0 + nb,      Bg + nk*32);
            cpa16(bDst0 + nb + 16, Bg + nk*32 + 8);
        }
        CP_COMMIT();
    }

    float* C = (float*)Cv;
    bf16*  Cb = (bf16*)Cv;
    #pragma unroll
    for (int nt = 0; nt < 8; nt++) {
        int col = n0 + wn*64 + nt*8 + lc*2;
        float b0 = 0.f, b1 = 0.f;
        if (bias) { b0 = bias[col]; b1 = bias[col+1]; }
        #pragma unroll
        for (int mt = 0; mt < 2; mt++) {
            int r0 = m0 + wm*32 + mt*16 + lr;
            int r1 = r0 + 8;
            float v00 = acc[mt][nt][0] + b0;
            float v01 = acc[mt][nt][1] + b1;
            float v10 = acc[mt][nt][2] + b0;
            float v11 = acc[mt][nt][3] + b1;
            if (addend) {
                const float* ad0 = addend + (size_t)r0*N + col;
                const float* ad1 = addend + (size_t)r1*N + col;
                v00 += ad0[0]; v01 += ad0[1];
                v10 += ad1[0]; v11 += ad1[1];
            }
            if (flags & 1) {
                v00 = 0.5f*v00*(1.f + erff(v00*0.70710678118654752f));
                v01 = 0.5f*v01*(1.f + erff(v01*0.70710678118654752f));
                v10 = 0.5f*v10*(1.f + erff(v10*0.70710678118654752f));
                v11 = 0.5f*v11*(1.f + erff(v11*0.70710678118654752f));
            }
            if (flags & 16) {
                *reinterpret_cast<uint32_t*>(&Cb[(size_t)r0*N + col]) = packbf(v00, v01);
                *reinterpret_cast<uint32_t*>(&Cb[(size_t)r1*N + col]) = packbf(v10, v11);
            } else {
                *reinterpret_cast<float2*>(&C[(size_t)r0*N + col]) = make_float2(v00, v01);
                *reinterpret_cast<float2*>(&C[(size_t)r1*N + col]) = make_float2(v10, v11);
            }
        }
    }
}

// ---------------- bgemm64: bf16 GEMM, 128x64 block, Ktile=32, 3-stage -------------------
// flags: bit0 gelu | bit2 transposed store | bit3 z-split
#define BSTRIDE64 5120   // 64*20*4 bytes per stage
__global__ __launch_bounds__(256, 2) void bgemm64_kernel(
    const bf16* __restrict__ A, const bf16* __restrict__ B, float* __restrict__ C,
    const float* __restrict__ bias, const float* __restrict__ addend,
    int M, int N, int K, int flags)
{
    __shared__ uint32_t As[3][128][20];
    __shared__ uint32_t Bs[3][64][20];
    int tid = threadIdx.x;
    int m0 = blockIdx.y * 128, n0 = blockIdx.x * 64;
    if (flags & 8) {
        int z = blockIdx.z;
        A += (size_t)z * M * K;
        B += (size_t)z * N * K;
        C += (size_t)z * M * N;
    }

    int lrow = tid >> 1;
    int lk   = (tid & 1) * 16;
    int kb   = (tid & 1) * 8;
    const bf16* Ag = A + (size_t)(m0 + lrow) * K + lk;
    int lrowB = tid >> 2;
    int lkB   = (tid & 3) * 8;
    int kbB   = (tid & 3) * 4;
    const bf16* Bg = B + (size_t)(n0 + lrowB) * K + lkB;
    uint32_t aDst0 = smem_u32(&As[0][lrow][kb]);
    uint32_t bDst0 = smem_u32(&Bs[0][lrowB][kbB]);

    int ntiles = K >> 5;
    #pragma unroll
    for (int s = 0; s < 2; s++) {
        cpa16(aDst0 + s*ASTRIDE,      Ag + s*32);
        cpa16(aDst0 + s*ASTRIDE + 16, Ag + s*32 + 8);
        cpa16(bDst0 + s*BSTRIDE64,    Bg + s*32);
        CP_COMMIT();
    }

    int wid = tid >> 5, lane = tid & 31;
    int lr = lane >> 2, lc = lane & 3;

    uint32_t aAddr0, bAddr0[4];
    {
        int ar = (lane & 15);
        int ac = (lane >> 4) * 4;
        int br = ((lane >> 4) & 1) * 8 + (lane & 7);
        int bc = ((lane >> 3) & 1) * 4;
        aAddr0 = smem_u32(&As[0][wid*16 + ar][ac]);
        #pragma unroll
        for (int np = 0; np < 4; np++)
            bAddr0[np] = smem_u32(&Bs[0][np*16 + br][bc]);
    }

    float acc[8][4];
    #pragma unroll
    for (int nt = 0; nt < 8; nt++)
        #pragma unroll
        for (int j = 0; j < 4; j++) acc[nt][j] = 0.f;

    for (int k = 0; k < ntiles; k++) {
        CP_WAIT1();
        __syncthreads();
        int ab = (k % 3) * ASTRIDE;
        int bb = (k % 3) * BSTRIDE64;
        #pragma unroll
        for (int ks = 0; ks < 2; ks++) {
            uint32_t afr[4];
            ldsm_x4(afr[0], afr[1], afr[2], afr[3], aAddr0 + ab + ks*32);
            uint32_t bfr[8][2];
            #pragma unroll
            for (int np = 0; np < 4; np++)
                ldsm_x4(bfr[2*np][0], bfr[2*np][1], bfr[2*np+1][0], bfr[2*np+1][1], bAddr0[np] + bb + ks*32);
            #pragma unroll
            for (int nt = 0; nt < 8; nt++)
                mma_bf16(acc[nt], afr, bfr[nt]);
        }
        int nk = k + 2;
        if (nk < ntiles) {
            cpa16(aDst0 + (nk % 3)*ASTRIDE,      Ag + nk*32);
            cpa16(aDst0 + (nk % 3)*ASTRIDE + 16, Ag + nk*32 + 8);
            cpa16(bDst0 + (nk % 3)*BSTRIDE64,    Bg + nk*32);
        }
        CP_COMMIT();
    }

    #pragma unroll
    for (int nt = 0; nt < 8; nt++) {
        int col = n0 + nt*8 + lc*2;
        float b0 = 0.f, b1 = 0.f;
        if (bias) { b0 = bias[col]; b1 = bias[col+1]; }
        int r0 = m0 + wid*16 + lr;
        int r1 = r0 + 8;
        float v00 = acc[nt][0] + b0;
        float v01 = acc[nt][1] + b1;
        float v10 = acc[nt][2] + b0;
        float v11 = acc[nt][3] + b1;
        if (addend) {
            const float* ad0 = addend + (size_t)r0*N + col;
            const float* ad1 = addend + (size_t)r1*N + col;
            v00 += ad0[0]; v01 += ad0[1];
            v10 += ad1[0]; v11 += ad1[1];
        }
        if (flags & 1) {
            v00 = 0.5f*v00*(1.f + erff(v00*0.70710678118654752f));
            v01 = 0.5f*v01*(1.f + erff(v01*0.70710678118654752f));
            v10 = 0.5f*v10*(1.f + erff(v10*0.70710678118654752f));
            v11 = 0.5f*v11*(1.f + erff(v11*0.70710678118654752f));
        }
        if (flags & 4) {
            int bt0 = r0 / NSP, nn0 = r0 % NSP;
            int bt1 = r1 / NSP, nn1 = r1 % NSP;
            C[((size_t)bt0*CDIM + col  )*NSP + nn0] = v00;
            C[((size_t)bt0*CDIM + col+1)*NSP + nn0] = v01;
            C[((size_t)bt1*CDIM + col  )*NSP + nn1] = v10;
            C[((size_t)bt1*CDIM + col+1)*NSP + nn1] = v11;
        } else {
            *reinterpret_cast<float2*>(&C[(size_t)r0*N + col]) = make_float2(v00, v01);
            *reinterpret_cast<float2*>(&C[(size_t)r1*N + col]) = make_float2(v10, v11);
        }
    }
}

// ---------------- conv4 depthwise + silu ----------------
__global__ __launch_bounds__(192) void conv_kernel(const float* __restrict__ scb,
                                                   const float* __restrict__ tcb)
{
    int m = blockIdx.y;
    int tid = threadIdx.x;
    int rl = tid / 96, v = tid % 96;
    int r = blockIdx.x * 2 + rl;
    int pos  = m ? ((r / NSP) & (TT-1)) : (r % NSP);
    int strd = m ? NSP : 1;
    const float* cb = m ? tcb : scb;
    float4 acc = *reinterpret_cast<const float4*>(&cb[4*v]);
    #pragma unroll
    for (int k = 0; k < 4; k++) {
        if (pos - 3 + k >= 0) {
            float4 xv = *reinterpret_cast<const float4*>(&g_xz[(size_t)(r - (3-k)*strd)*XZW + m*768 + 4*v]);
            float4 cw = *reinterpret_cast<const float4*>(&g_cwT[m][k*DI + 4*v]);
            acc.x = fmaf(cw.x, xv.x, acc.x);
            acc.y = fmaf(cw.y, xv.y, acc.y);
            acc.z = fmaf(cw.z, xv.z, acc.z);
            acc.w = fmaf(cw.w, xv.w, acc.w);
        }
    }
    acc.x = acc.x / (1.f + __expf(-acc.x));
    acc.y = acc.y / (1.f + __expf(-acc.y));
    acc.z = acc.z / (1.f + __expf(-acc.z));
    acc.w = acc.w / (1.f + __expf(-acc.w));
    *reinterpret_cast<float4*>(&g_u[m][(size_t)r*DI + 4*v]) = acc;
    uint2 pk = make_uint2(packbf(acc.x, acc.y), packbf(acc.z, acc.w));
    *reinterpret_cast<uint2*>(&g_u_bf[m][(size_t)r*DI + 4*v]) = pk;
}

// ---------------- delta ----------------
__global__ __launch_bounds__(384) void delta_kernel(const float* __restrict__ sdpb,
                                                    const float* __restrict__ tdpb)
{
    __shared__ float sw[DTR][DI];
    __shared__ float sdbc[16][DTR];
    int m = blockIdx.y;
    int r0 = blockIdx.x * 16;
    int d = threadIdx.x;
    const float* dpb = m ? tdpb : sdpb;
    #pragma unroll
    for (int rr = 0; rr < DTR; rr++)
        sw[rr][d] = g_dpwT[m][rr*DI + d];
    if (d < 16*DTR) {
        int t = d / DTR, c = d % DTR;
        sdbc[t][c] = g_dbc[m][(size_t)(r0 + t)*64 + c];
    }
    __syncthreads();
    float base = dpb[d];
    #pragma unroll 4
    for (int t = 0; t < 16; t++) {
        float acc = base;
        #pragma unroll
        for (int rr = 0; rr < DTR; rr++)
            acc = fmaf(sdbc[t][rr], sw[rr][d], acc);
        g_delta[m][(size_t)(r0 + t)*DI + d] = (acc > 15.f) ? acc : log1pf(__expf(acc));
    }
}

// ---------------- merged scans ----------------
#define SPATIAL_BLOCKS 768
__global__ __launch_bounds__(128) void scan_kernel(const float* __restrict__ sD,
                                                   const float* __restrict__ tD)
{
    int bx = blockIdx.x;
    int tid = threadIdx.x;

    if (bx < SPATIAL_BLOCKS) {
        __shared__ float sbuf[64][8];
        int s   = bx / 48;
        int dpg = bx % 48;
        int w = tid >> 5, lane = tid & 31;
        int sub = lane >> 4, n = lane & 15;
        int d = dpg*8 + w*2 + sub;
        int ycol0 = dpg*8;

        float a  = g_A[0][d*DS + n];
        float Dd = sD[d];
        const float* delta = g_delta[0];
        const float* u     = g_u[0];
        const float* dbc   = g_dbc[0];
        int base = s * NSP;

        float h = 0.f;
        for (int pos = 0; pos < NSP; pos += 4) {
            float dl[4], uu[4], Bv[4], Cv[4];
            #pragma unroll
            for (int j = 0; j < 4; j++) {
                size_t r = base + pos + j;
                dl[j] = __ldg(&delta[r*DI + d]);
                uu[j] = __ldg(&u[r*DI + d]);
                Bv[j] = __ldg(&dbc[r*64 + DTR + n]);
                Cv[j] = __ldg(&dbc[r*64 + DTR + DS + n]);
            }
            float dA[4], dBu[4];
            #pragma unroll
            for (int j = 0; j < 4; j++) {
                dA[j]  = __expf(dl[j] * a);
                dBu[j] = dl[j] * uu[j] * Bv[j];
            }
            float part[4];
            #pragma unroll
            for (int j = 0; j < 4; j++) {
                h = fmaf(h, dA[j], dBu[j]);
                part[j] = h * Cv[j];
            }
            #pragma unroll
            for (int off = 1; off <= 8; off <<= 1)
                #pragma unroll
                for (int j = 0; j < 4; j++)
                    part[j] += __shfl_xor_sync(0xffffffffu, part[j], off);
            if (n == 0) {
                #pragma unroll
                for (int j = 0; j < 4; j++)
                    sbuf[(pos + j) & 63][w*2 + sub] = part[j] + uu[j] * Dd;
            }
            if ((pos & 63) == 60) {
                __syncthreads();
                int p2 = tid >> 1, half = tid & 1;
                size_t r = base + (pos & ~63) + p2;
                float4 v = *reinterpret_cast<float4*>(&sbuf[p2][half*4]);
                float4 z4 = *reinterpret_cast<const float4*>(&g_xz[r*XZW + 384 + ycol0 + half*4]);
                v.x *= z4.x / (1.f + __expf(-z4.x));
                v.y *= z4.y / (1.f + __expf(-z4.y));
                v.z *= z4.z / (1.f + __expf(-z4.z));
                v.w *= z4.w / (1.f + __expf(-z4.w));
                uint2 pk = make_uint2(packbf(v.x, v.y), packbf(v.z, v.w));
                *reinterpret_cast<uint2*>(&g_y_bf[r*(2*DI) + ycol0 + half*4]) = pk;
                __syncthreads();
            }
        }
    } else {
        int b2 = bx - SPATIAL_BLOCKS;
        int seq = b2 / 3;
        int d = (b2 % 3) * 128 + tid;
        int lane = tid & 31;
        int b = seq / NSP, nsp = seq % NSP;
        int base = b * (TT*NSP) + nsp;

        float a[DS];
        #pragma unroll
        for (int q = 0; q < 4; q++)
            *reinterpret_cast<float4*>(&a[q*4]) = *reinterpret_cast<const float4*>(&g_A[1][d*DS + q*4]);
        float Dd = tD[d];
        const float* delta = g_delta[1];
        const float* u     = g_u[1];
        const float* dbc   = g_dbc[1];

        float h[DS];
        #pragma unroll
        for (int q = 0; q < DS; q++) h[q] = 0.f;

        for (int t = 0; t < TT; t++) {
            size_t r = base + (size_t)t * NSP;
            float dl = delta[r*DI + d];
            float uu = u[r*DI + d];
            float bc = dbc[r*64 + DTR + lane];
            float dlu = dl * uu;
            float y = 0.f;
            #pragma unroll
            for (int q = 0; q < DS; q++) {
                float Bn = __shfl_sync(0xffffffffu, bc, q);
                float Cn = __shfl_sync(0xffffffffu, bc, q + 16);
                float dA = __expf(dl * a[q]);
                h[q] = fmaf(h[q], dA, dlu * Bn);
                y = fmaf(h[q], Cn, y);
            }
            float z = g_xz[r*XZW + 1152 + d];
            float g = z / (1.f + __expf(-z));
            g_y_bf[r*(2*DI) + DI + d] = __float2bfloat16((y + uu * Dd) * g);
        }
    }
}

// ---------------- host launcher ----------------
extern "C" void kernel_launch(void* const* d_in, const int* in_sizes, int n_in,
                              void* d_out, int out_size)
{
    const float* x_in   = (const float*)d_in[0];
    const float* n1w    = (const float*)d_in[1];
    const float* n1b    = (const float*)d_in[2];
    const float* s_inw  = (const float*)d_in[3];
    const float* s_cw   = (const float*)d_in[4];
    const float* s_cb   = (const float*)d_in[5];
    const float* s_xpw  = (const float*)d_in[6];
    const float* s_dpw  = (const float*)d_in[7];
    const float* s_dpb  = (const float*)d_in[8];
    const float* s_Alog = (const float*)d_in[9];
    const float* s_D    = (const float*)d_in[10];
    const float* s_outw = (const float*)d_in[11];
    const float* t_inw  = (const float*)d_in[12];
    const float* t_cw   = (const float*)d_in[13];
    const float* t_cb   = (const float*)d_in[14];
    const float* t_xpw  = (const float*)d_in[15];
    const float* t_dpw  = (const float*)d_in[16];
    const float* t_dpb  = (const float*)d_in[17];
    const float* t_Alog = (const float*)d_in[18];
    const float* t_D    = (const float*)d_in[19];
    const float* t_outw = (const float*)d_in[20];
    const float* fw     = (const float*)d_in[21];
    const float* fb     = (const float*)d_in[22];
    const float* n2w    = (const float*)d_in[23];
    const float* n2b    = (const float*)d_in[24];
    const float* w1     = (const float*)d_in[25];
    const float* b1     = (const float*)d_in[26];
    const float* w2     = (const float*)d_in[27];
    const float* b2     = (const float*)d_in[28];
    float* out = (float*)d_out;

    bf16 *p_xn_bf, *p_u_bf, *p_y_bf, *p_h_bf, *p_hid_bf, *p_Win_bf, *p_W12_bf, *p_xpwP_bf, *p_w1_bf, *p_w2_bf;
    float *p_short, *p_xz, *p_x2, *p_dbc;
    cudaGetSymbolAddress((void**)&p_xn_bf, g_xn_bf);
    cudaGetSymbolAddress((void**)&p_short, g_short);
    cudaGetSymbolAddress((void**)&p_xz,    g_xz);
    cudaGetSymbolAddress((void**)&p_u_bf,  g_u_bf);
    cudaGetSymbolAddress((void**)&p_dbc,   g_dbc);
    cudaGetSymbolAddress((void**)&p_y_bf,  g_y_bf);
    cudaGetSymbolAddress((void**)&p_x2,    g_x2);
    cudaGetSymbolAddress((void**)&p_h_bf,  g_h_bf);
    cudaGetSymbolAddress((void**)&p_hid_bf,g_hid_bf);
    cudaGetSymbolAddress((void**)&p_Win_bf,g_Win_bf);
    cudaGetSymbolAddress((void**)&p_W12_bf,g_W12_bf);
    cudaGetSymbolAddress((void**)&p_xpwP_bf,g_xpwP_bf);
    cudaGetSymbolAddress((void**)&p_w1_bf, g_w1_bf);
    cudaGetSymbolAddress((void**)&p_w2_bf, g_w2_bf);

    // 0. prep + fold
    prep_kernel<<<1152, 256>>>(s_Alog, t_Alog, s_cw, t_cw, s_dpw, t_dpw,
                               s_inw, t_inw, s_xpw, t_xpw, w1, w2);
    fold_kernel<<<dim3(24, 2), 384>>>(fw, s_outw, t_outw);

    // 1. transpose + LN1
    ln1_kernel<<<dim3(16, 18), 256>>>(x_in, n1w, n1b);

    // 2. merged in_proj GEMM (N=1536, K=192)
    bgemm_kernel<<<dim3(XZW/128, TOK/128), 256>>>(p_xn_bf, p_Win_bf, p_xz, nullptr, nullptr, TOK, XZW, CDIM, 0);

    // 3. conv+silu
    conv_kernel<<<dim3(TOK/2, 2), 192>>>(s_cb, t_cb);

    // 4. dbc = u @ xpwP^T (N=64, K=384), both mambas via z
    bgemm64_kernel<<<dim3(1, TOK/128, 2), 256>>>(p_u_bf, p_xpwP_bf, p_dbc, nullptr, nullptr, TOK, 64, DI, 8);

    // 5. delta
    delta_kernel<<<dim3(TOK/16, 2), 384>>>(s_dpb, t_dpb);

    // 6. scans
    scan_kernel<<<SPATIAL_BLOCKS + 3456, 128>>>(s_D, t_D);

    // 7. fusion + residual (N=192, K=768)
    bgemm64_kernel<<<dim3(3, TOK/128), 256>>>(p_y_bf, p_W12_bf, p_x2, fb, p_short, TOK, CDIM, 2*DI, 0);

    // 8. LN2 + MLP
    ln2_kernel<<<TOK/4, 128>>>(p_x2, n2w, n2b);
    bgemm_kernel<<<dim3(MLPH/128, TOK/128), 256>>>(p_h_bf, p_w1_bf, p_hid_bf, b1, nullptr, TOK, MLPH, CDIM, 1 | 16);
    bgemm64_kernel<<<dim3(3, TOK/128), 256>>>(p_hid_bf, p_w2_bf, out, b2, p_x2, TOK, CDIM, MLPH, 4);
}

// round 14
// speedup vs baseline: 3.8855x; 1.1055x over previous
#include <cuda_runtime.h>
#include <cuda_bf16.h>
#include <math.h>
#include <stdint.h>

// ---------------- problem constants ----------------
#define BQ    2
#define TT    8
#define CDIM  192
#define NSP   576
#define TOK   9216
#define DI    384
#define DS    16
#define DTR   12
#define MLPH  768
#define XZW   1536

typedef __nv_bfloat16 bf16;

// ---------------- scratch ----------------
__device__ bf16  g_xn_bf[TOK*CDIM];
__device__ float g_short[TOK*CDIM];
__device__ float g_xz[TOK*XZW];
__device__ float g_u[2][TOK*DI];
__device__ bf16  g_u_bf[2][TOK*DI];
__device__ float g_delta[2][TOK*DI];
__device__ float g_dbc[2][TOK*64];
__device__ bf16  g_y_bf[TOK*2*DI];
__device__ float g_x2[TOK*CDIM];
__device__ bf16  g_h_bf[TOK*CDIM];
__device__ bf16  g_hid_bf[TOK*MLPH];
__device__ bf16  g_Win_bf[XZW*CDIM];
__device__ bf16  g_W12_bf[CDIM*2*DI];
__device__ bf16  g_xpwP_bf[2][64*DI];
__device__ bf16  g_w1_bf[MLPH*CDIM];
__device__ bf16  g_w2_bf[CDIM*MLPH];
__device__ float g_A[2][DI*DS];
__device__ float g_cwT[2][4*DI];
__device__ float g_dpwT[2][DTR*DI];

// ---------------- helpers ----------------
__device__ __forceinline__ uint32_t packbf(float lo, float hi) {
    uint32_t r;
    asm("cvt.rn.bf16x2.f32 %0, %1, %2;" : "=r"(r) : "f"(hi), "f"(lo));
    return r;
}
__device__ __forceinline__ void mma_bf16(float c[4], const uint32_t a[4], const uint32_t b[2]) {
    asm("mma.sync.aligned.m16n8k16.row.col.f32.bf16.bf16.f32 "
        "{%0,%1,%2,%3}, {%4,%5,%6,%7}, {%8,%9}, {%0,%1,%2,%3};"
        : "+f"(c[0]), "+f"(c[1]), "+f"(c[2]), "+f"(c[3])
        : "r"(a[0]), "r"(a[1]), "r"(a[2]), "r"(a[3]), "r"(b[0]), "r"(b[1]));
}
__device__ __forceinline__ void ldsm_x4(uint32_t& r0, uint32_t& r1, uint32_t& r2, uint32_t& r3,
                                        uint32_t addr) {
    asm volatile("ldmatrix.sync.aligned.m8n8.x4.shared.b16 {%0,%1,%2,%3}, [%4];"
                 : "=r"(r0), "=r"(r1), "=r"(r2), "=r"(r3) : "r"(addr));
}
__device__ __forceinline__ uint32_t smem_u32(const void* p) {
    return (uint32_t)__cvta_generic_to_shared(p);
}
__device__ __forceinline__ void cpa16(uint32_t dst, const void* src) {
    asm volatile("cp.async.ca.shared.global [%0], [%1], 16;" :: "r"(dst), "l"(src));
}
#define CP_COMMIT() asm volatile("cp.async.commit_group;" ::: "memory")
#define CP_WAIT1()  asm volatile("cp.async.wait_group 1;" ::: "memory")

// ---------------- prep + fold (merged) ----------------
__global__ __launch_bounds__(384) void prepfold_kernel(
    const float* __restrict__ sAlog, const float* __restrict__ tAlog,
    const float* __restrict__ scw, const float* __restrict__ tcw,
    const float* __restrict__ sdpw, const float* __restrict__ tdpw,
    const float* __restrict__ sinw, const float* __restrict__ tinw,
    const float* __restrict__ sxpw, const float* __restrict__ txpw,
    const float* __restrict__ w1, const float* __restrict__ w2,
    const float* __restrict__ fw,
    const float* __restrict__ soutw, const float* __restrict__ toutw)
{
    int tid = threadIdx.x;
    if (blockIdx.x < 768) {
        int i = blockIdx.x * 384 + tid;
        if (i < 2*DI*DS) {
            int m = i / (DI*DS), j = i % (DI*DS);
            g_A[m][j] = -expf(m ? tAlog[j] : sAlog[j]);
        }
        if (i < 2*4*DI) {
            int m = i / (4*DI), rem = i % (4*DI);
            int k = rem / DI, d = rem % DI;
            g_cwT[m][k*DI + d] = (m ? tcw : scw)[d*4 + k];
        }
        if (i < 2*DTR*DI) {
            int m = i / (DTR*DI), rem = i % (DTR*DI);
            int rr = rem / DI, d = rem % DI;
            g_dpwT[m][rr*DI + d] = (m ? tdpw : sdpw)[d*DTR + rr];
        }
        if (i < 2*64*DI) {
            int m = i / (64*DI), rem = i % (64*DI);
            int row = rem / DI;
            g_xpwP_bf[m][rem] = __float2bfloat16(
                (row < DTR + 2*DS) ? (m ? txpw : sxpw)[rem] : 0.f);
        }
        if (i < XZW*CDIM) {
            int row = i / CDIM;
            g_Win_bf[i] = __float2bfloat16((row < 768) ? sinw[i] : tinw[i - 768*CDIM]);
        }
        if (i < MLPH*CDIM) g_w1_bf[i] = __float2bfloat16(w1[i]);
        if (i < CDIM*MLPH) g_w2_bf[i] = __float2bfloat16(w2[i]);
    } else {
        // fold: W12[c][m*384+j] = sum_cp fw[c][m*192+cp] * ow_m[cp][j]
        __shared__ float fwS[8][192];
        int bx = blockIdx.x - 768;          // 0..47
        int m  = bx / 24;
        int c0 = (bx % 24) * 8;
        const float* ow = m ? toutw : soutw;
        for (int i = tid; i < 8*192; i += 384) {
            int c = i / 192, cp = i % 192;
            fwS[c][cp] = fw[(size_t)(c0 + c)*(2*CDIM) + m*CDIM + cp];
        }
        __syncthreads();
        float acc[8] = {0,0,0,0,0,0,0,0};
        #pragma unroll 4
        for (int cp = 0; cp < 192; cp++) {
            float owv = ow[(size_t)cp*DI + tid];
            #pragma unroll
            for (int c = 0; c < 8; c++) acc[c] = fmaf(fwS[c][cp], owv, acc[c]);
        }
        #pragma unroll
        for (int c = 0; c < 8; c++)
            g_W12_bf[(size_t)(c0 + c)*(2*DI) + m*DI + tid] = __float2bfloat16(acc[c]);
    }
}

// ---------------- LN1 ----------------
__global__ __launch_bounds__(256) void ln1_kernel(const float* __restrict__ src,
                                                  const float* __restrict__ w, const float* __restrict__ b)
{
    __shared__ float s[CDIM][33];
    int bt = blockIdx.x;
    int n0 = blockIdx.y * 32;
    int tid = threadIdx.x;
    #pragma unroll
    for (int i = 0; i < 24; i++) {
        int idx = tid + 256*i;
        int c = idx >> 5, nl = idx & 31;
        s[c][nl] = src[((size_t)bt*CDIM + c)*NSP + n0 + nl];
    }
    __syncthreads();
    int warp = tid >> 5, lane = tid & 31;
    for (int jj = 0; jj < 4; jj++) {
        int tt = warp + 8*jj;
        float v[3][2];
        #pragma unroll
        for (int q = 0; q < 3; q++) {
            int c = 2*lane + 64*q;
            v[q][0] = s[c][tt];
            v[q][1] = s[c+1][tt];
        }
        float sum = 0.f;
        #pragma unroll
        for (int q = 0; q < 3; q++) sum += v[q][0] + v[q][1];
        #pragma unroll
        for (int o = 16; o > 0; o >>= 1) sum += __shfl_xor_sync(0xffffffffu, sum, o);
        float mean = sum * (1.f/CDIM);
        float qv = 0.f;
        #pragma unroll
        for (int q = 0; q < 3; q++) {
            float d0 = v[q][0]-mean, d1 = v[q][1]-mean;
            qv += d0*d0 + d1*d1;
        }
        #pragma unroll
        for (int o = 16; o > 0; o >>= 1) qv += __shfl_xor_sync(0xffffffffu, qv, o);
        float rstd = rsqrtf(qv * (1.f/CDIM) + 1e-5f);
        size_t tok = (size_t)bt*NSP + n0 + tt;
        #pragma unroll
        for (int q = 0; q < 3; q++) {
            int c = 2*lane + 64*q;
            float o0 = (v[q][0]-mean)*rstd*w[c]   + b[c];
            float o1 = (v[q][1]-mean)*rstd*w[c+1] + b[c+1];
            *reinterpret_cast<uint32_t*>(&g_xn_bf[tok*CDIM + c]) = packbf(o0, o1);
            *reinterpret_cast<float2*>(&g_short[tok*CDIM + c]) = make_float2(v[q][0], v[q][1]);
        }
    }
}

// ---------------- LN2 ----------------
__global__ void ln2_kernel(const float* __restrict__ src,
                           const float* __restrict__ w, const float* __restrict__ b)
{
    int tok  = blockIdx.x * 4 + (threadIdx.x >> 5);
    int lane = threadIdx.x & 31;
    const float* base = src + (size_t)tok * CDIM;
    float v[3][2];
    #pragma unroll
    for (int q = 0; q < 3; q++) {
        float2 t = *reinterpret_cast<const float2*>(&base[2*lane + 64*q]);
        v[q][0] = t.x; v[q][1] = t.y;
    }
    float s = 0.f;
    #pragma unroll
    for (int q = 0; q < 3; q++) s += v[q][0] + v[q][1];
    #pragma unroll
    for (int o = 16; o > 0; o >>= 1) s += __shfl_xor_sync(0xffffffffu, s, o);
    float mean = s * (1.f / CDIM);
    float qv = 0.f;
    #pragma unroll
    for (int q = 0; q < 3; q++) {
        float d0 = v[q][0]-mean, d1 = v[q][1]-mean;
        qv += d0*d0 + d1*d1;
    }
    #pragma unroll
    for (int o = 16; o > 0; o >>= 1) qv += __shfl_xor_sync(0xffffffffu, qv, o);
    float rstd = rsqrtf(qv * (1.f / CDIM) + 1e-5f);
    #pragma unroll
    for (int q = 0; q < 3; q++) {
        int c = 2*lane + 64*q;
        float o0 = (v[q][0]-mean)*rstd*w[c]   + b[c];
        float o1 = (v[q][1]-mean)*rstd*w[c+1] + b[c+1];
        *reinterpret_cast<uint32_t*>(&g_h_bf[(size_t)tok*CDIM + c]) = packbf(o0, o1);
    }
}

// ---------------- bgemm: bf16 GEMM, 128x128 block, Ktile=32, 3-stage cp.async -----------
// flags: bit0 gelu | bit4 bf16 C store
#define ASTRIDE 10240   // 128*20*4 bytes per stage
__global__ __launch_bounds__(256, 2) void bgemm_kernel(
    const bf16* __restrict__ A, const bf16* __restrict__ B, void* __restrict__ Cv,
    const float* __restrict__ bias, const float* __restrict__ addend,
    int M, int N, int K, int flags)
{
    __shared__ uint32_t As[3][128][20];
    __shared__ uint32_t Bs[3][128][20];
    int tid = threadIdx.x;
    int m0 = blockIdx.y * 128, n0 = blockIdx.x * 128;

    int lrow = tid >> 1;
    int lk   = (tid & 1) * 16;
    int kb   = (tid & 1) * 8;
    const bf16* Ag = A + (size_t)(m0 + lrow) * K + lk;
    const bf16* Bg = B + (size_t)(n0 + lrow) * K + lk;
    uint32_t aDst0 = smem_u32(&As[0][lrow][kb]);
    uint32_t bDst0 = smem_u32(&Bs[0][lrow][kb]);

    int ntiles = K >> 5;
    #pragma unroll
    for (int s = 0; s < 2; s++) {
        cpa16(aDst0 + s*ASTRIDE,      Ag + s*32);
        cpa16(aDst0 + s*ASTRIDE + 16, Ag + s*32 + 8);
        cpa16(bDst0 + s*ASTRIDE,      Bg + s*32);
        cpa16(bDst0 + s*ASTRIDE + 16, Bg + s*32 + 8);
        CP_COMMIT();
    }

    int wid = tid >> 5, lane = tid & 31;
    int wm = wid >> 1, wn = wid & 1;
    int lr = lane >> 2, lc = lane & 3;

    uint32_t aAddr0[2], bAddr0[4];
    {
        int ar = (lane & 15);
        int ac = (lane >> 4) * 4;
        int br = ((lane >> 4) & 1) * 8 + (lane & 7);
        int bc = ((lane >> 3) & 1) * 4;
        #pragma unroll
        for (int mt = 0; mt < 2; mt++)
            aAddr0[mt] = smem_u32(&As[0][wm*32 + mt*16 + ar][ac]);
        #pragma unroll
        for (int np = 0; np < 4; np++)
            bAddr0[np] = smem_u32(&Bs[0][wn*64 + np*16 + br][bc]);
    }

    float acc[2][8][4];
    #pragma unroll
    for (int mt = 0; mt < 2; mt++)
        #pragma unroll
        for (int nt = 0; nt < 8; nt++)
            #pragma unroll
            for (int j = 0; j < 4; j++) acc[mt][nt][j] = 0.f;

    for (int k = 0; k < ntiles; k++) {
        CP_WAIT1();
        __syncthreads();
        int buf = (k % 3) * ASTRIDE;
        #pragma unroll
        for (int ks = 0; ks < 2; ks++) {
            int off = buf + ks*32;
            uint32_t afr[2][4];
            #pragma unroll
            for (int mt = 0; mt < 2; mt++)
                ldsm_x4(afr[mt][0], afr[mt][1], afr[mt][2], afr[mt][3], aAddr0[mt] + off);
            uint32_t bfr[8][2];
            #pragma unroll
            for (int np = 0; np < 4; np++)
                ldsm_x4(bfr[2*np][0], bfr[2*np][1], bfr[2*np+1][0], bfr[2*np+1][1], bAddr0[np] + off);
            #pragma unroll
            for (int mt = 0; mt < 2; mt++)
                #pragma unroll
                for (int nt = 0; nt < 8; nt++)
                    mma_bf16(acc[mt][nt], afr[mt], bfr[nt]);
        }
        int nk = k + 2;
        if (nk < ntiles) {
            int nb = (nk % 3) * ASTRIDE;
            cpa16(aDst0 + nb,      Ag + nk*32);
            cpa16(aDst0 + nb + 16, Ag + nk*32 + 8);
            cpa16(bDst0 + nb,      Bg + nk*32);
            cpa16(bDst0 + nb + 16, Bg + nk*32 + 8);
        }
        CP_COMMIT();
    }

    float* C = (float*)Cv;
    bf16*  Cb = (bf16*)Cv;
    #pragma unroll
    for (int nt = 0; nt < 8; nt++) {
        int col = n0 + wn*64 + nt*8 + lc*2;
        float b0 = 0.f, b1 = 0.f;
        if (bias) { b0 = bias[col]; b1 = bias[col+1]; }
        #pragma unroll
        for (int mt = 0; mt < 2; mt++) {
            int r0 = m0 + wm*32 + mt*16 + lr;
            int r1 = r0 + 8;
            float v00 = acc[mt][nt][0] + b0;
            float v01 = acc[mt][nt][1] + b1;
            float v10 = acc[mt][nt][2] + b0;
            float v11 = acc[mt][nt][3] + b1;
            if (addend) {
                const float* ad0 = addend + (size_t)r0*N + col;
                const float* ad1 = addend + (size_t)r1*N + col;
                v00 += ad0[0]; v01 += ad0[1];
                v10 += ad1[0]; v11 += ad1[1];
            }
            if (flags & 1) {
                v00 = 0.5f*v00*(1.f + erff(v00*0.70710678118654752f));
                v01 = 0.5f*v01*(1.f + erff(v01*0.70710678118654752f));
                v10 = 0.5f*v10*(1.f + erff(v10*0.70710678118654752f));
                v11 = 0.5f*v11*(1.f + erff(v11*0.70710678118654752f));
            }
            if (flags & 16) {
                *reinterpret_cast<uint32_t*>(&Cb[(size_t)r0*N + col]) = packbf(v00, v01);
                *reinterpret_cast<uint32_t*>(&Cb[(size_t)r1*N + col]) = packbf(v10, v11);
            } else {
                *reinterpret_cast<float2*>(&C[(size_t)r0*N + col]) = make_float2(v00, v01);
                *reinterpret_cast<float2*>(&C[(size_t)r1*N + col]) = make_float2(v10, v11);
            }
        }
    }
}

// ---------------- bgemm64: bf16 GEMM, 64x64 block, Ktile=32, 3-stage --------------------
// 8 warps = 4m x 2n; warp computes 16(M)x32(N). Better chip fill for small-N GEMMs.
// flags: bit0 gelu | bit2 transposed store | bit3 z-split
#define STRIDE64 5120   // 64*20*4 bytes per stage
__global__ __launch_bounds__(256, 3) void bgemm64_kernel(
    const bf16* __restrict__ A, const bf16* __restrict__ B, float* __restrict__ C,
    const float* __restrict__ bias, const float* __restrict__ addend,
    int M, int N, int K, int flags)
{
    __shared__ uint32_t As[3][64][20];
    __shared__ uint32_t Bs[3][64][20];
    int tid = threadIdx.x;
    int m0 = blockIdx.y * 64, n0 = blockIdx.x * 64;
    if (flags & 8) {
        int z = blockIdx.z;
        A += (size_t)z * M * K;
        B += (size_t)z * N * K;
        C += (size_t)z * M * N;
    }

    int lrow = tid >> 2;           // 0..63
    int lk   = (tid & 3) * 8;      // bf16 elem offset (0,8,16,24)
    int kb   = (tid & 3) * 4;      // uint32 col offset
    const bf16* Ag = A + (size_t)(m0 + lrow) * K + lk;
    const bf16* Bg = B + (size_t)(n0 + lrow) * K + lk;
    uint32_t aDst0 = smem_u32(&As[0][lrow][kb]);
    uint32_t bDst0 = smem_u32(&Bs[0][lrow][kb]);

    int ntiles = K >> 5;
    #pragma unroll
    for (int s = 0; s < 2; s++) {
        cpa16(aDst0 + s*STRIDE64, Ag + s*32);
        cpa16(bDst0 + s*STRIDE64, Bg + s*32);
        CP_COMMIT();
    }

    int wid = tid >> 5, lane = tid & 31;
    int wm = wid >> 1, wn = wid & 1;   // 4m x 2n
    int lr = lane >> 2, lc = lane & 3;

    uint32_t aAddr0, bAddr0[2];
    {
        int ar = (lane & 15);
        int ac = (lane >> 4) * 4;
        int br = ((lane >> 4) & 1) * 8 + (lane & 7);
        int bc = ((lane >> 3) & 1) * 4;
        aAddr0 = smem_u32(&As[0][wm*16 + ar][ac]);
        #pragma unroll
        for (int np = 0; np < 2; np++)
            bAddr0[np] = smem_u32(&Bs[0][wn*32 + np*16 + br][bc]);
    }

    float acc[4][4];
    #pragma unroll
    for (int nt = 0; nt < 4; nt++)
        #pragma unroll
        for (int j = 0; j < 4; j++) acc[nt][j] = 0.f;

    for (int k = 0; k < ntiles; k++) {
        CP_WAIT1();
        __syncthreads();
        int buf = (k % 3) * STRIDE64;
        #pragma unroll
        for (int ks = 0; ks < 2; ks++) {
            int off = buf + ks*32;
            uint32_t afr[4];
            ldsm_x4(afr[0], afr[1], afr[2], afr[3], aAddr0 + off);
            uint32_t bfr[4][2];
            #pragma unroll
            for (int np = 0; np < 2; np++)
                ldsm_x4(bfr[2*np][0], bfr[2*np][1], bfr[2*np+1][0], bfr[2*np+1][1], bAddr0[np] + off);
            #pragma unroll
            for (int nt = 0; nt < 4; nt++)
                mma_bf16(acc[nt], afr, bfr[nt]);
        }
        int nk = k + 2;
        if (nk < ntiles) {
            int nb = (nk % 3) * STRIDE64;
            cpa16(aDst0 + nb, Ag + nk*32);
            cpa16(bDst0 + nb, Bg + nk*32);
        }
        CP_COMMIT();
    }

    #pragma unroll
    for (int nt = 0; nt < 4; nt++) {
        int col = n0 + wn*32 + nt*8 + lc*2;
        float b0 = 0.f, b1 = 0.f;
        if (bias) { b0 = bias[col]; b1 = bias[col+1]; }
        int r0 = m0 + wm*16 + lr;
        int r1 = r0 + 8;
        float v00 = acc[nt][0] + b0;
        float v01 = acc[nt][1] + b1;
        float v10 = acc[nt][2] + b0;
        float v11 = acc[nt][3] + b1;
        if (addend) {
            const float* ad0 = addend + (size_t)r0*N + col;
            const float* ad1 = addend + (size_t)r1*N + col;
            v00 += ad0[0]; v01 += ad0[1];
            v10 += ad1[0]; v11 += ad1[1];
        }
        if (flags & 1) {
            v00 = 0.5f*v00*(1.f + erff(v00*0.70710678118654752f));
            v01 = 0.5f*v01*(1.f + erff(v01*0.70710678118654752f));
            v10 = 0.5f*v10*(1.f + erff(v10*0.70710678118654752f));
            v11 = 0.5f*v11*(1.f + erff(v11*0.70710678118654752f));
        }
        if (flags & 4) {
            int bt0 = r0 / NSP, nn0 = r0 % NSP;
            int bt1 = r1 / NSP, nn1 = r1 % NSP;
            C[((size_t)bt0*CDIM + col  )*NSP + nn0] = v00;
            C[((size_t)bt0*CDIM + col+1)*NSP + nn0] = v01;
            C[((size_t)bt1*CDIM + col  )*NSP + nn1] = v10;
            C[((size_t)bt1*CDIM + col+1)*NSP + nn1] = v11;
        } else {
            *reinterpret_cast<float2*>(&C[(size_t)r0*N + col]) = make_float2(v00, v01);
            *reinterpret_cast<float2*>(&C[(size_t)r1*N + col]) = make_float2(v10, v11);
        }
    }
}

// ---------------- conv4 depthwise + silu ----------------
__global__ __launch_bounds__(192) void conv_kernel(const float* __restrict__ scb,
                                                   const float* __restrict__ tcb)
{
    int m = blockIdx.y;
    int tid = threadIdx.x;
    int rl = tid / 96, v = tid % 96;
    int r = blockIdx.x * 2 + rl;
    int pos  = m ? ((r / NSP) & (TT-1)) : (r % NSP);
    int strd = m ? NSP : 1;
    const float* cb = m ? tcb : scb;
    float4 acc = *reinterpret_cast<const float4*>(&cb[4*v]);
    #pragma unroll
    for (int k = 0; k < 4; k++) {
        if (pos - 3 + k >= 0) {
            float4 xv = *reinterpret_cast<const float4*>(&g_xz[(size_t)(r - (3-k)*strd)*XZW + m*768 + 4*v]);
            float4 cw = *reinterpret_cast<const float4*>(&g_cwT[m][k*DI + 4*v]);
            acc.x = fmaf(cw.x, xv.x, acc.x);
            acc.y = fmaf(cw.y, xv.y, acc.y);
            acc.z = fmaf(cw.z, xv.z, acc.z);
            acc.w = fmaf(cw.w, xv.w, acc.w);
        }
    }
    acc.x = acc.x / (1.f + __expf(-acc.x));
    acc.y = acc.y / (1.f + __expf(-acc.y));
    acc.z = acc.z / (1.f + __expf(-acc.z));
    acc.w = acc.w / (1.f + __expf(-acc.w));
    *reinterpret_cast<float4*>(&g_u[m][(size_t)r*DI + 4*v]) = acc;
    uint2 pk = make_uint2(packbf(acc.x, acc.y), packbf(acc.z, acc.w));
    *reinterpret_cast<uint2*>(&g_u_bf[m][(size_t)r*DI + 4*v]) = pk;
}

// ---------------- delta ----------------
__global__ __launch_bounds__(384) void delta_kernel(const float* __restrict__ sdpb,
                                                    const float* __restrict__ tdpb)
{
    __shared__ float sw[DTR][DI];
    __shared__ float sdbc[16][DTR];
    int m = blockIdx.y;
    int r0 = blockIdx.x * 16;
    int d = threadIdx.x;
    const float* dpb = m ? tdpb : sdpb;
    #pragma unroll
    for (int rr = 0; rr < DTR; rr++)
        sw[rr][d] = g_dpwT[m][rr*DI + d];
    if (d < 16*DTR) {
        int t = d / DTR, c = d % DTR;
        sdbc[t][c] = g_dbc[m][(size_t)(r0 + t)*64 + c];
    }
    __syncthreads();
    float base = dpb[d];
    #pragma unroll 4
    for (int t = 0; t < 16; t++) {
        float acc = base;
        #pragma unroll
        for (int rr = 0; rr < DTR; rr++)
            acc = fmaf(sdbc[t][rr], sw[rr][d], acc);
        g_delta[m][(size_t)(r0 + t)*DI + d] = (acc > 15.f) ? acc : log1pf(__expf(acc));
    }
}

// ---------------- merged scans (spatial part double-buffered) ----------------
#define SPATIAL_BLOCKS 768
__global__ __launch_bounds__(128) void scan_kernel(const float* __restrict__ sD,
                                                   const float* __restrict__ tD)
{
    int bx = blockIdx.x;
    int tid = threadIdx.x;

    if (bx < SPATIAL_BLOCKS) {
        __shared__ float sbuf[64][8];
        int s   = bx / 48;
        int dpg = bx % 48;
        int w = tid >> 5, lane = tid & 31;
        int sub = lane >> 4, n = lane & 15;
        int d = dpg*8 + w*2 + sub;
        int ycol0 = dpg*8;

        float a  = g_A[0][d*DS + n];
        float Dd = sD[d];
        const float* delta = g_delta[0];
        const float* u     = g_u[0];
        const float* dbc   = g_dbc[0];
        int base = s * NSP;

        // preload group 0
        float dl[4], uu[4], Bv[4], Cv[4];
        #pragma unroll
        for (int j = 0; j < 4; j++) {
            size_t r = base + j;
            dl[j] = __ldg(&delta[r*DI + d]);
            uu[j] = __ldg(&u[r*DI + d]);
            Bv[j] = __ldg(&dbc[r*64 + DTR + n]);
            Cv[j] = __ldg(&dbc[r*64 + DTR + DS + n]);
        }

        float h = 0.f;
        for (int pos = 0; pos < NSP; pos += 4) {
            // prefetch next group (hides L2 latency under compute + flush)
            float ndl[4], nuu[4], nBv[4], nCv[4];
            if (pos + 4 < NSP) {
                #pragma unroll
                for (int j = 0; j < 4; j++) {
                    size_t r = base + pos + 4 + j;
                    ndl[j] = __ldg(&delta[r*DI + d]);
                    nuu[j] = __ldg(&u[r*DI + d]);
                    nBv[j] = __ldg(&dbc[r*64 + DTR + n]);
                    nCv[j] = __ldg(&dbc[r*64 + DTR + DS + n]);
                }
            }
            float dA[4], dBu[4];
            #pragma unroll
            for (int j = 0; j < 4; j++) {
                dA[j]  = __expf(dl[j] * a);
                dBu[j] = dl[j] * uu[j] * Bv[j];
            }
            float part[4];
            #pragma unroll
            for (int j = 0; j < 4; j++) {
                h = fmaf(h, dA[j], dBu[j]);
                part[j] = h * Cv[j];
            }
            #pragma unroll
            for (int off = 1; off <= 8; off <<= 1)
                #pragma unroll
                for (int j = 0; j < 4; j++)
                    part[j] += __shfl_xor_sync(0xffffffffu, part[j], off);
            if (n == 0) {
                #pragma unroll
                for (int j = 0; j < 4; j++)
                    sbuf[(pos + j) & 63][w*2 + sub] = part[j] + uu[j] * Dd;
            }
            if ((pos & 63) == 60) {
                __syncthreads();
                int p2 = tid >> 1, half = tid & 1;
                size_t r = base + (pos & ~63) + p2;
                float4 v = *reinterpret_cast<float4*>(&sbuf[p2][half*4]);
                float4 z4 = *reinterpret_cast<const float4*>(&g_xz[r*XZW + 384 + ycol0 + half*4]);
                v.x *= z4.x / (1.f + __expf(-z4.x));
                v.y *= z4.y / (1.f + __expf(-z4.y));
                v.z *= z4.z / (1.f + __expf(-z4.z));
                v.w *= z4.w / (1.f + __expf(-z4.w));
                uint2 pk = make_uint2(packbf(v.x, v.y), packbf(v.z, v.w));
                *reinterpret_cast<uint2*>(&g_y_bf[r*(2*DI) + ycol0 + half*4]) = pk;
                __syncthreads();
            }
            #pragma unroll
            for (int j = 0; j < 4; j++) {
                dl[j] = ndl[j]; uu[j] = nuu[j]; Bv[j] = nBv[j]; Cv[j] = nCv[j];
            }
        }
    } else {
        int b2 = bx - SPATIAL_BLOCKS;
        int seq = b2 / 3;
        int d = (b2 % 3) * 128 + tid;
        int lane = tid & 31;
        int b = seq / NSP, nsp = seq % NSP;
        int base = b * (TT*NSP) + nsp;

        float a[DS];
        #pragma unroll
        for (int q = 0; q < 4; q++)
            *reinterpret_cast<float4*>(&a[q*4]) = *reinterpret_cast<const float4*>(&g_A[1][d*DS + q*4]);
        float Dd = tD[d];
        const float* delta = g_delta[1];
        const float* u     = g_u[1];
        const float* dbc   = g_dbc[1];

        float h[DS];
        #pragma unroll
        for (int q = 0; q < DS; q++) h[q] = 0.f;

        for (int t = 0; t < TT; t++) {
            size_t r = base + (size_t)t * NSP;
            float dl = delta[r*DI + d];
            float uu = u[r*DI + d];
            float bc = dbc[r*64 + DTR + lane];
            float dlu = dl * uu;
            float y = 0.f;
            #pragma unroll
            for (int q = 0; q < DS; q++) {
                float Bn = __shfl_sync(0xffffffffu, bc, q);
                float Cn = __shfl_sync(0xffffffffu, bc, q + 16);
                float dA = __expf(dl * a[q]);
                h[q] = fmaf(h[q], dA, dlu * Bn);
                y = fmaf(h[q], Cn, y);
            }
            float z = g_xz[r*XZW + 1152 + d];
            float g = z / (1.f + __expf(-z));
            g_y_bf[r*(2*DI) + DI + d] = __float2bfloat16((y + uu * Dd) * g);
        }
    }
}

// ---------------- host launcher ----------------
extern "C" void kernel_launch(void* const* d_in, const int* in_sizes, int n_in,
                              void* d_out, int out_size)
{
    const float* x_in   = (const float*)d_in[0];
    const float* n1w    = (const float*)d_in[1];
    const float* n1b    = (const float*)d_in[2];
    const float* s_inw  = (const float*)d_in[3];
    const float* s_cw   = (const float*)d_in[4];
    const float* s_cb   = (const float*)d_in[5];
    const float* s_xpw  = (const float*)d_in[6];
    const float* s_dpw  = (const float*)d_in[7];
    const float* s_dpb  = (const float*)d_in[8];
    const float* s_Alog = (const float*)d_in[9];
    const float* s_D    = (const float*)d_in[10];
    const float* s_outw = (const float*)d_in[11];
    const float* t_inw  = (const float*)d_in[12];
    const float* t_cw   = (const float*)d_in[13];
    const float* t_cb   = (const float*)d_in[14];
    const float* t_xpw  = (const float*)d_in[15];
    const float* t_dpw  = (const float*)d_in[16];
    const float* t_dpb  = (const float*)d_in[17];
    const float* t_Alog = (const float*)d_in[18];
    const float* t_D    = (const float*)d_in[19];
    const float* t_outw = (const float*)d_in[20];
    const float* fw     = (const float*)d_in[21];
    const float* fb     = (const float*)d_in[22];
    const float* n2w    = (const float*)d_in[23];
    const float* n2b    = (const float*)d_in[24];
    const float* w1     = (const float*)d_in[25];
    const float* b1     = (const float*)d_in[26];
    const float* w2     = (const float*)d_in[27];
    const float* b2     = (const float*)d_in[28];
    float* out = (float*)d_out;

    bf16 *p_xn_bf, *p_u_bf, *p_y_bf, *p_h_bf, *p_hid_bf, *p_Win_bf, *p_W12_bf, *p_xpwP_bf, *p_w1_bf, *p_w2_bf;
    float *p_short, *p_xz, *p_x2, *p_dbc;
    cudaGetSymbolAddress((void**)&p_xn_bf, g_xn_bf);
    cudaGetSymbolAddress((void**)&p_short, g_short);
    cudaGetSymbolAddress((void**)&p_xz,    g_xz);
    cudaGetSymbolAddress((void**)&p_u_bf,  g_u_bf);
    cudaGetSymbolAddress((void**)&p_dbc,   g_dbc);
    cudaGetSymbolAddress((void**)&p_y_bf,  g_y_bf);
    cudaGetSymbolAddress((void**)&p_x2,    g_x2);
    cudaGetSymbolAddress((void**)&p_h_bf,  g_h_bf);
    cudaGetSymbolAddress((void**)&p_hid_bf,g_hid_bf);
    cudaGetSymbolAddress((void**)&p_Win_bf,g_Win_bf);
    cudaGetSymbolAddress((void**)&p_W12_bf,g_W12_bf);
    cudaGetSymbolAddress((void**)&p_xpwP_bf,g_xpwP_bf);
    cudaGetSymbolAddress((void**)&p_w1_bf, g_w1_bf);
    cudaGetSymbolAddress((void**)&p_w2_bf, g_w2_bf);

    // 0. prep + fold merged
    prepfold_kernel<<<816, 384>>>(s_Alog, t_Alog, s_cw, t_cw, s_dpw, t_dpw,
                                  s_inw, t_inw, s_xpw, t_xpw, w1, w2,
                                  fw, s_outw, t_outw);

    // 1. transpose + LN1
    ln1_kernel<<<dim3(16, 18), 256>>>(x_in, n1w, n1b);

    // 2. merged in_proj GEMM (N=1536, K=192)
    bgemm_kernel<<<dim3(XZW/128, TOK/128), 256>>>(p_xn_bf, p_Win_bf, p_xz, nullptr, nullptr, TOK, XZW, CDIM, 0);

    // 3. conv+silu
    conv_kernel<<<dim3(TOK/2, 2), 192>>>(s_cb, t_cb);

    // 4. dbc = u @ xpwP^T (N=64, K=384), both mambas via z — 64-tile fill
    bgemm64_kernel<<<dim3(1, TOK/64, 2), 256>>>(p_u_bf, p_xpwP_bf, p_dbc, nullptr, nullptr, TOK, 64, DI, 8);

    // 5. delta
    delta_kernel<<<dim3(TOK/16, 2), 384>>>(s_dpb, t_dpb);

    // 6. scans
    scan_kernel<<<SPATIAL_BLOCKS + 3456, 128>>>(s_D, t_D);

    // 7. fusion + residual (N=192, K=768)
    bgemm64_kernel<<<dim3(3, TOK/64), 256>>>(p_y_bf, p_W12_bf, p_x2, fb, p_short, TOK, CDIM, 2*DI, 0);

    // 8. LN2 + MLP
    ln2_kernel<<<TOK/4, 128>>>(p_x2, n2w, n2b);
    bgemm_kernel<<<dim3(MLPH/128, TOK/128), 256>>>(p_h_bf, p_w1_bf, p_hid_bf, b1, nullptr, TOK, MLPH, CDIM, 1 | 16);
    bgemm64_kernel<<<dim3(3, TOK/64), 256>>>(p_hid_bf, p_w2_bf, out, b2, p_x2, TOK, CDIM, MLPH, 4);
}

// round 15
// speedup vs baseline: 3.9119x; 1.0068x over previous
#include <cuda_runtime.h>
#include <cuda_bf16.h>
#include <math.h>
#include <stdint.h>

// ---------------- problem constants ----------------
#define BQ    2
#define TT    8
#define CDIM  192
#define NSP   576
#define TOK   9216
#define DI    384
#define DS    16
#define DTR   12
#define MLPH  768
#define XZW   1536

typedef __nv_bfloat16 bf16;

// ---------------- scratch ----------------
__device__ bf16  g_xn_bf[TOK*CDIM];
__device__ float g_short[TOK*CDIM];
__device__ bf16  g_xz_bf[TOK*XZW];        // in_proj out (bf16)
__device__ bf16  g_u_bf[2][TOK*DI];
__device__ float g_delta[2][TOK*DI];
__device__ float g_dbc[2][TOK*64];
__device__ bf16  g_y_bf[TOK*2*DI];
__device__ float g_x2[TOK*CDIM];
__device__ bf16  g_h_bf[TOK*CDIM];
__device__ bf16  g_hid_bf[TOK*MLPH];
__device__ bf16  g_Win_bf[XZW*CDIM];
__device__ bf16  g_W12_bf[CDIM*2*DI];
__device__ bf16  g_xpwP_bf[2][64*DI];
__device__ bf16  g_w1_bf[MLPH*CDIM];
__device__ bf16  g_w2_bf[CDIM*MLPH];
__device__ float g_A[2][DI*DS];
__device__ float g_cwT[2][4*DI];
__device__ float g_dpwT[2][DTR*DI];

// ---------------- helpers ----------------
__device__ __forceinline__ uint32_t packbf(float lo, float hi) {
    uint32_t r;
    asm("cvt.rn.bf16x2.f32 %0, %1, %2;" : "=r"(r) : "f"(hi), "f"(lo));
    return r;
}
__device__ __forceinline__ void mma_bf16(float c[4], const uint32_t a[4], const uint32_t b[2]) {
    asm("mma.sync.aligned.m16n8k16.row.col.f32.bf16.bf16.f32 "
        "{%0,%1,%2,%3}, {%4,%5,%6,%7}, {%8,%9}, {%0,%1,%2,%3};"
        : "+f"(c[0]), "+f"(c[1]), "+f"(c[2]), "+f"(c[3])
        : "r"(a[0]), "r"(a[1]), "r"(a[2]), "r"(a[3]), "r"(b[0]), "r"(b[1]));
}
__device__ __forceinline__ void ldsm_x4(uint32_t& r0, uint32_t& r1, uint32_t& r2, uint32_t& r3,
                                        uint32_t addr) {
    asm volatile("ldmatrix.sync.aligned.m8n8.x4.shared.b16 {%0,%1,%2,%3}, [%4];"
                 : "=r"(r0), "=r"(r1), "=r"(r2), "=r"(r3) : "r"(addr));
}
__device__ __forceinline__ uint32_t smem_u32(const void* p) {
    return (uint32_t)__cvta_generic_to_shared(p);
}
__device__ __forceinline__ void cpa16(uint32_t dst, const void* src) {
    asm volatile("cp.async.ca.shared.global [%0], [%1], 16;" :: "r"(dst), "l"(src));
}
#define CP_COMMIT() asm volatile("cp.async.commit_group;" ::: "memory")
#define CP_WAIT1()  asm volatile("cp.async.wait_group 1;" ::: "memory")

// ---------------- prep + fold (merged) ----------------
__global__ __launch_bounds__(384) void prepfold_kernel(
    const float* __restrict__ sAlog, const float* __restrict__ tAlog,
    const float* __restrict__ scw, const float* __restrict__ tcw,
    const float* __restrict__ sdpw, const float* __restrict__ tdpw,
    const float* __restrict__ sinw, const float* __restrict__ tinw,
    const float* __restrict__ sxpw, const float* __restrict__ txpw,
    const float* __restrict__ w1, const float* __restrict__ w2,
    const float* __restrict__ fw,
    const float* __restrict__ soutw, const float* __restrict__ toutw)
{
    int tid = threadIdx.x;
    if (blockIdx.x < 768) {
        int i = blockIdx.x * 384 + tid;
        if (i < 2*DI*DS) {
            int m = i / (DI*DS), j = i % (DI*DS);
            g_A[m][j] = -expf(m ? tAlog[j] : sAlog[j]);
        }
        if (i < 2*4*DI) {
            int m = i / (4*DI), rem = i % (4*DI);
            int k = rem / DI, d = rem % DI;
            g_cwT[m][k*DI + d] = (m ? tcw : scw)[d*4 + k];
        }
        if (i < 2*DTR*DI) {
            int m = i / (DTR*DI), rem = i % (DTR*DI);
            int rr = rem / DI, d = rem % DI;
            g_dpwT[m][rr*DI + d] = (m ? tdpw : sdpw)[d*DTR + rr];
        }
        if (i < 2*64*DI) {
            int m = i / (64*DI), rem = i % (64*DI);
            int row = rem / DI;
            g_xpwP_bf[m][rem] = __float2bfloat16(
                (row < DTR + 2*DS) ? (m ? txpw : sxpw)[rem] : 0.f);
        }
        if (i < XZW*CDIM) {
            int row = i / CDIM;
            g_Win_bf[i] = __float2bfloat16((row < 768) ? sinw[i] : tinw[i - 768*CDIM]);
        }
        if (i < MLPH*CDIM) g_w1_bf[i] = __float2bfloat16(w1[i]);
        if (i < CDIM*MLPH) g_w2_bf[i] = __float2bfloat16(w2[i]);
    } else {
        __shared__ float fwS[8][192];
        int bx = blockIdx.x - 768;
        int m  = bx / 24;
        int c0 = (bx % 24) * 8;
        const float* ow = m ? toutw : soutw;
        for (int i = tid; i < 8*192; i += 384) {
            int c = i / 192, cp = i % 192;
            fwS[c][cp] = fw[(size_t)(c0 + c)*(2*CDIM) + m*CDIM + cp];
        }
        __syncthreads();
        float acc[8] = {0,0,0,0,0,0,0,0};
        #pragma unroll 4
        for (int cp = 0; cp < 192; cp++) {
            float owv = ow[(size_t)cp*DI + tid];
            #pragma unroll
            for (int c = 0; c < 8; c++) acc[c] = fmaf(fwS[c][cp], owv, acc[c]);
        }
        #pragma unroll
        for (int c = 0; c < 8; c++)
            g_W12_bf[(size_t)(c0 + c)*(2*DI) + m*DI + tid] = __float2bfloat16(acc[c]);
    }
}

// ---------------- LN1 ----------------
__global__ __launch_bounds__(256) void ln1_kernel(const float* __restrict__ src,
                                                  const float* __restrict__ w, const float* __restrict__ b)
{
    __shared__ float s[CDIM][33];
    int bt = blockIdx.x;
    int n0 = blockIdx.y * 32;
    int tid = threadIdx.x;
    #pragma unroll
    for (int i = 0; i < 24; i++) {
        int idx = tid + 256*i;
        int c = idx >> 5, nl = idx & 31;
        s[c][nl] = src[((size_t)bt*CDIM + c)*NSP + n0 + nl];
    }
    __syncthreads();
    int warp = tid >> 5, lane = tid & 31;
    for (int jj = 0; jj < 4; jj++) {
        int tt = warp + 8*jj;
        float v[3][2];
        #pragma unroll
        for (int q = 0; q < 3; q++) {
            int c = 2*lane + 64*q;
            v[q][0] = s[c][tt];
            v[q][1] = s[c+1][tt];
        }
        float sum = 0.f;
        #pragma unroll
        for (int q = 0; q < 3; q++) sum += v[q][0] + v[q][1];
        #pragma unroll
        for (int o = 16; o > 0; o >>= 1) sum += __shfl_xor_sync(0xffffffffu, sum, o);
        float mean = sum * (1.f/CDIM);
        float qv = 0.f;
        #pragma unroll
        for (int q = 0; q < 3; q++) {
            float d0 = v[q][0]-mean, d1 = v[q][1]-mean;
            qv += d0*d0 + d1*d1;
        }
        #pragma unroll
        for (int o = 16; o > 0; o >>= 1) qv += __shfl_xor_sync(0xffffffffu, qv, o);
        float rstd = rsqrtf(qv * (1.f/CDIM) + 1e-5f);
        size_t tok = (size_t)bt*NSP + n0 + tt;
        #pragma unroll
        for (int q = 0; q < 3; q++) {
            int c = 2*lane + 64*q;
            float o0 = (v[q][0]-mean)*rstd*w[c]   + b[c];
            float o1 = (v[q][1]-mean)*rstd*w[c+1] + b[c+1];
            *reinterpret_cast<uint32_t*>(&g_xn_bf[tok*CDIM + c]) = packbf(o0, o1);
            *reinterpret_cast<float2*>(&g_short[tok*CDIM + c]) = make_float2(v[q][0], v[q][1]);
        }
    }
}

// ---------------- LN2 ----------------
__global__ void ln2_kernel(const float* __restrict__ src,
                           const float* __restrict__ w, const float* __restrict__ b)
{
    int tok  = blockIdx.x * 4 + (threadIdx.x >> 5);
    int lane = threadIdx.x & 31;
    const float* base = src + (size_t)tok * CDIM;
    float v[3][2];
    #pragma unroll
    for (int q = 0; q < 3; q++) {
        float2 t = *reinterpret_cast<const float2*>(&base[2*lane + 64*q]);
        v[q][0] = t.x; v[q][1] = t.y;
    }
    float s = 0.f;
    #pragma unroll
    for (int q = 0; q < 3; q++) s += v[q][0] + v[q][1];
    #pragma unroll
    for (int o = 16; o > 0; o >>= 1) s += __shfl_xor_sync(0xffffffffu, s, o);
    float mean = s * (1.f / CDIM);
    float qv = 0.f;
    #pragma unroll
    for (int q = 0; q < 3; q++) {
        float d0 = v[q][0]-mean, d1 = v[q][1]-mean;
        qv += d0*d0 + d1*d1;
    }
    #pragma unroll
    for (int o = 16; o > 0; o >>= 1) qv += __shfl_xor_sync(0xffffffffu, qv, o);
    float rstd = rsqrtf(qv * (1.f / CDIM) + 1e-5f);
    #pragma unroll
    for (int q = 0; q < 3; q++) {
        int c = 2*lane + 64*q;
        float o0 = (v[q][0]-mean)*rstd*w[c]   + b[c];
        float o1 = (v[q][1]-mean)*rstd*w[c+1] + b[c+1];
        *reinterpret_cast<uint32_t*>(&g_h_bf[(size_t)tok*CDIM + c]) = packbf(o0, o1);
    }
}

// ---------------- bgemm: bf16 GEMM, 128x128 block, Ktile=32, 3-stage cp.async -----------
// flags: bit0 gelu | bit4 bf16 C store
#define ASTRIDE 10240
__global__ __launch_bounds__(256, 2) void bgemm_kernel(
    const bf16* __restrict__ A, const bf16* __restrict__ B, void* __restrict__ Cv,
    const float* __restrict__ bias, const float* __restrict__ addend,
    int M, int N, int K, int flags)
{
    __shared__ uint32_t As[3][128][20];
    __shared__ uint32_t Bs[3][128][20];
    int tid = threadIdx.x;
    int m0 = blockIdx.y * 128, n0 = blockIdx.x * 128;

    int lrow = tid >> 1;
    int lk   = (tid & 1) * 16;
    int kb   = (tid & 1) * 8;
    const bf16* Ag = A + (size_t)(m0 + lrow) * K + lk;
    const bf16* Bg = B + (size_t)(n0 + lrow) * K + lk;
    uint32_t aDst0 = smem_u32(&As[0][lrow][kb]);
    uint32_t bDst0 = smem_u32(&Bs[0][lrow][kb]);

    int ntiles = K >> 5;
    #pragma unroll
    for (int s = 0; s < 2; s++) {
        cpa16(aDst0 + s*ASTRIDE,      Ag + s*32);
        cpa16(aDst0 + s*ASTRIDE + 16, Ag + s*32 + 8);
        cpa16(bDst0 + s*ASTRIDE,      Bg + s*32);
        cpa16(bDst0 + s*ASTRIDE + 16, Bg + s*32 + 8);
        CP_COMMIT();
    }

    int wid = tid >> 5, lane = tid & 31;
    int wm = wid >> 1, wn = wid & 1;
    int lr = lane >> 2, lc = lane & 3;

    uint32_t aAddr0[2], bAddr0[4];
    {
        int ar = (lane & 15);
        int ac = (lane >> 4) * 4;
        int br = ((lane >> 4) & 1) * 8 + (lane & 7);
        int bc = ((lane >> 3) & 1) * 4;
        #pragma unroll
        for (int mt = 0; mt < 2; mt++)
            aAddr0[mt] = smem_u32(&As[0][wm*32 + mt*16 + ar][ac]);
        #pragma unroll
        for (int np = 0; np < 4; np++)
            bAddr0[np] = smem_u32(&Bs[0][wn*64 + np*16 + br][bc]);
    }

    float acc[2][8][4];
    #pragma unroll
    for (int mt = 0; mt < 2; mt++)
        #pragma unroll
        for (int nt = 0; nt < 8; nt++)
            #pragma unroll
            for (int j = 0; j < 4; j++) acc[mt][nt][j] = 0.f;

    for (int k = 0; k < ntiles; k++) {
        CP_WAIT1();
        __syncthreads();
        int buf = (k % 3) * ASTRIDE;
        #pragma unroll
        for (int ks = 0; ks < 2; ks++) {
            int off = buf + ks*32;
            uint32_t afr[2][4];
            #pragma unroll
            for (int mt = 0; mt < 2; mt++)
                ldsm_x4(afr[mt][0], afr[mt][1], afr[mt][2], afr[mt][3], aAddr0[mt] + off);
            uint32_t bfr[8][2];
            #pragma unroll
            for (int np = 0; np < 4; np++)
                ldsm_x4(bfr[2*np][0], bfr[2*np][1], bfr[2*np+1][0], bfr[2*np+1][1], bAddr0[np] + off);
            #pragma unroll
            for (int mt = 0; mt < 2; mt++)
                #pragma unroll
                for (int nt = 0; nt < 8; nt++)
                    mma_bf16(acc[mt][nt], afr[mt], bfr[nt]);
        }
        int nk = k + 2;
        if (nk < ntiles) {
            int nb = (nk % 3) * ASTRIDE;
            cpa16(aDst0 + nb,      Ag + nk*32);
            cpa16(aDst0 + nb + 16, Ag + nk*32 + 8);
            cpa16(bDst0 + nb,      Bg + nk*32);
            cpa16(bDst0 + nb + 16, Bg + nk*32 + 8);
        }
        CP_COMMIT();
    }

    float* C = (float*)Cv;
    bf16*  Cb = (bf16*)Cv;
    #pragma unroll
    for (int nt = 0; nt < 8; nt++) {
        int col = n0 + wn*64 + nt*8 + lc*2;
        float b0 = 0.f, b1 = 0.f;
        if (bias) { b0 = bias[col]; b1 = bias[col+1]; }
        #pragma unroll
        for (int mt = 0; mt < 2; mt++) {
            int r0 = m0 + wm*32 + mt*16 + lr;
            int r1 = r0 + 8;
            float v00 = acc[mt][nt][0] + b0;
            float v01 = acc[mt][nt][1] + b1;
            float v10 = acc[mt][nt][2] + b0;
            float v11 = acc[mt][nt][3] + b1;
            if (addend) {
                const float* ad0 = addend + (size_t)r0*N + col;
                const float* ad1 = addend + (size_t)r1*N + col;
                v00 += ad0[0]; v01 += ad0[1];
                v10 += ad1[0]; v11 += ad1[1];
            }
            if (flags & 1) {
                v00 = 0.5f*v00*(1.f + erff(v00*0.70710678118654752f));
                v01 = 0.5f*v01*(1.f + erff(v01*0.70710678118654752f));
                v10 = 0.5f*v10*(1.f + erff(v10*0.70710678118654752f));
                v11 = 0.5f*v11*(1.f + erff(v11*0.70710678118654752f));
            }
            if (flags & 16) {
                *reinterpret_cast<uint32_t*>(&Cb[(size_t)r0*N + col]) = packbf(v00, v01);
                *reinterpret_cast<uint32_t*>(&Cb[(size_t)r1*N + col]) = packbf(v10, v11);
            } else {
                *reinterpret_cast<float2*>(&C[(size_t)r0*N + col]) = make_float2(v00, v01);
                *reinterpret_cast<float2*>(&C[(size_t)r1*N + col]) = make_float2(v10, v11);
            }
        }
    }
}

// ---------------- bgemm64: bf16 GEMM, 64x64 block, Ktile=32, 3-stage --------------------
// flags: bit0 gelu | bit2 transposed store | bit3 z-split
#define STRIDE64 5120
__global__ __launch_bounds__(256, 3) void bgemm64_kernel(
    const bf16* __restrict__ A, const bf16* __restrict__ B, float* __restrict__ C,
    const float* __restrict__ bias, const float* __restrict__ addend,
    int M, int N, int K, int flags)
{
    __shared__ uint32_t As[3][64][20];
    __shared__ uint32_t Bs[3][64][20];
    int tid = threadIdx.x;
    int m0 = blockIdx.y * 64, n0 = blockIdx.x * 64;
    if (flags & 8) {
        int z = blockIdx.z;
        A += (size_t)z * M * K;
        B += (size_t)z * N * K;
        C += (size_t)z * M * N;
    }

    int lrow = tid >> 2;
    int lk   = (tid & 3) * 8;
    int kb   = (tid & 3) * 4;
    const bf16* Ag = A + (size_t)(m0 + lrow) * K + lk;
    const bf16* Bg = B + (size_t)(n0 + lrow) * K + lk;
    uint32_t aDst0 = smem_u32(&As[0][lrow][kb]);
    uint32_t bDst0 = smem_u32(&Bs[0][lrow][kb]);

    int ntiles = K >> 5;
    #pragma unroll
    for (int s = 0; s < 2; s++) {
        cpa16(aDst0 + s*STRIDE64, Ag + s*32);
        cpa16(bDst0 + s*STRIDE64, Bg + s*32);
        CP_COMMIT();
    }

    int wid = tid >> 5, lane = tid & 31;
    int wm = wid >> 1, wn = wid & 1;
    int lr = lane >> 2, lc = lane & 3;

    uint32_t aAddr0, bAddr0[2];
    {
        int ar = (lane & 15);
        int ac = (lane >> 4) * 4;
        int br = ((lane >> 4) & 1) * 8 + (lane & 7);
        int bc = ((lane >> 3) & 1) * 4;
        aAddr0 = smem_u32(&As[0][wm*16 + ar][ac]);
        #pragma unroll
        for (int np = 0; np < 2; np++)
            bAddr0[np] = smem_u32(&Bs[0][wn*32 + np*16 + br][bc]);
    }

    float acc[4][4];
    #pragma unroll
    for (int nt = 0; nt < 4; nt++)
        #pragma unroll
        for (int j = 0; j < 4; j++) acc[nt][j] = 0.f;

    for (int k = 0; k < ntiles; k++) {
        CP_WAIT1();
        __syncthreads();
        int buf = (k % 3) * STRIDE64;
        #pragma unroll
        for (int ks = 0; ks < 2; ks++) {
            int off = buf + ks*32;
            uint32_t afr[4];
            ldsm_x4(afr[0], afr[1], afr[2], afr[3], aAddr0 + off);
            uint32_t bfr[4][2];
            #pragma unroll
            for (int np = 0; np < 2; np++)
                ldsm_x4(bfr[2*np][0], bfr[2*np][1], bfr[2*np+1][0], bfr[2*np+1][1], bAddr0[np] + off);
            #pragma unroll
            for (int nt = 0; nt < 4; nt++)
                mma_bf16(acc[nt], afr, bfr[nt]);
        }
        int nk = k + 2;
        if (nk < ntiles) {
            int nb = (nk % 3) * STRIDE64;
            cpa16(aDst0 + nb, Ag + nk*32);
            cpa16(bDst0 + nb, Bg + nk*32);
        }
        CP_COMMIT();
    }

    #pragma unroll
    for (int nt = 0; nt < 4; nt++) {
        int col = n0 + wn*32 + nt*8 + lc*2;
        float b0 = 0.f, b1 = 0.f;
        if (bias) { b0 = bias[col]; b1 = bias[col+1]; }
        int r0 = m0 + wm*16 + lr;
        int r1 = r0 + 8;
        float v00 = acc[nt][0] + b0;
        float v01 = acc[nt][1] + b1;
        float v10 = acc[nt][2] + b0;
        float v11 = acc[nt][3] + b1;
        if (addend) {
            const float* ad0 = addend + (size_t)r0*N + col;
            const float* ad1 = addend + (size_t)r1*N + col;
            v00 += ad0[0]; v01 += ad0[1];
            v10 += ad1[0]; v11 += ad1[1];
        }
        if (flags & 1) {
            v00 = 0.5f*v00*(1.f + erff(v00*0.70710678118654752f));
            v01 = 0.5f*v01*(1.f + erff(v01*0.70710678118654752f));
            v10 = 0.5f*v10*(1.f + erff(v10*0.70710678118654752f));
            v11 = 0.5f*v11*(1.f + erff(v11*0.70710678118654752f));
        }
        if (flags & 4) {
            int bt0 = r0 / NSP, nn0 = r0 % NSP;
            int bt1 = r1 / NSP, nn1 = r1 % NSP;
            C[((size_t)bt0*CDIM + col  )*NSP + nn0] = v00;
            C[((size_t)bt0*CDIM + col+1)*NSP + nn0] = v01;
            C[((size_t)bt1*CDIM + col  )*NSP + nn1] = v10;
            C[((size_t)bt1*CDIM + col+1)*NSP + nn1] = v11;
        } else {
            *reinterpret_cast<float2*>(&C[(size_t)r0*N + col]) = make_float2(v00, v01);
            *reinterpret_cast<float2*>(&C[(size_t)r1*N + col]) = make_float2(v10, v11);
        }
    }
}

// ---------------- conv4 depthwise + silu (bf16 in, bf16 out) ----------------
__global__ __launch_bounds__(192) void conv_kernel(const float* __restrict__ scb,
                                                   const float* __restrict__ tcb)
{
    int m = blockIdx.y;
    int tid = threadIdx.x;
    int rl = tid / 96, v = tid % 96;
    int r = blockIdx.x * 2 + rl;
    int pos  = m ? ((r / NSP) & (TT-1)) : (r % NSP);
    int strd = m ? NSP : 1;
    const float* cb = m ? tcb : scb;
    float4 acc = *reinterpret_cast<const float4*>(&cb[4*v]);
    #pragma unroll
    for (int k = 0; k < 4; k++) {
        if (pos - 3 + k >= 0) {
            const bf16* xp = &g_xz_bf[(size_t)(r - (3-k)*strd)*XZW + m*768 + 4*v];
            uint2 raw = *reinterpret_cast<const uint2*>(xp);
            float2 x01 = __bfloat1622float2(*reinterpret_cast<const __nv_bfloat162*>(&raw.x));
            float2 x23 = __bfloat1622float2(*reinterpret_cast<const __nv_bfloat162*>(&raw.y));
            float4 cw = *reinterpret_cast<const float4*>(&g_cwT[m][k*DI + 4*v]);
            acc.x = fmaf(cw.x, x01.x, acc.x);
            acc.y = fmaf(cw.y, x01.y, acc.y);
            acc.z = fmaf(cw.z, x23.x, acc.z);
            acc.w = fmaf(cw.w, x23.y, acc.w);
        }
    }
    acc.x = acc.x / (1.f + __expf(-acc.x));
    acc.y = acc.y / (1.f + __expf(-acc.y));
    acc.z = acc.z / (1.f + __expf(-acc.z));
    acc.w = acc.w / (1.f + __expf(-acc.w));
    uint2 pk = make_uint2(packbf(acc.x, acc.y), packbf(acc.z, acc.w));
    *reinterpret_cast<uint2*>(&g_u_bf[m][(size_t)r*DI + 4*v]) = pk;
}

// ---------------- delta ----------------
__global__ __launch_bounds__(384) void delta_kernel(const float* __restrict__ sdpb,
                                                    const float* __restrict__ tdpb)
{
    __shared__ float sw[DTR][DI];
    __shared__ float sdbc[16][DTR];
    int m = blockIdx.y;
    int r0 = blockIdx.x * 16;
    int d = threadIdx.x;
    const float* dpb = m ? tdpb : sdpb;
    #pragma unroll
    for (int rr = 0; rr < DTR; rr++)
        sw[rr][d] = g_dpwT[m][rr*DI + d];
    if (d < 16*DTR) {
        int t = d / DTR, c = d % DTR;
        sdbc[t][c] = g_dbc[m][(size_t)(r0 + t)*64 + c];
    }
    __syncthreads();
    float base = dpb[d];
    #pragma unroll 4
    for (int t = 0; t < 16; t++) {
        float acc = base;
        #pragma unroll
        for (int rr = 0; rr < DTR; rr++)
            acc = fmaf(sdbc[t][rr], sw[rr][d], acc);
        g_delta[m][(size_t)(r0 + t)*DI + d] = (acc > 15.f) ? acc : log1pf(__expf(acc));
    }
}

// ---------------- merged scans ----------------
#define SPATIAL_BLOCKS 768
__global__ __launch_bounds__(128) void scan_kernel(const float* __restrict__ sD,
                                                   const float* __restrict__ tD)
{
    int bx = blockIdx.x;
    int tid = threadIdx.x;

    if (bx < SPATIAL_BLOCKS) {
        __shared__ float sbuf[64][8];
        int s   = bx / 48;
        int dpg = bx % 48;
        int w = tid >> 5, lane = tid & 31;
        int sub = lane >> 4, n = lane & 15;
        int d = dpg*8 + w*2 + sub;
        int ycol0 = dpg*8;

        float a  = g_A[0][d*DS + n];
        float Dd = sD[d];
        const float* delta = g_delta[0];
        const bf16*  u     = g_u_bf[0];
        const float* dbc   = g_dbc[0];
        int base = s * NSP;

        float dl[4], uu[4], Bv[4], Cv[4];
        #pragma unroll
        for (int j = 0; j < 4; j++) {
            size_t r = base + j;
            dl[j] = __ldg(&delta[r*DI + d]);
            uu[j] = __bfloat162float(u[r*DI + d]);
            Bv[j] = __ldg(&dbc[r*64 + DTR + n]);
            Cv[j] = __ldg(&dbc[r*64 + DTR + DS + n]);
        }

        float h = 0.f;
        for (int pos = 0; pos < NSP; pos += 4) {
            float ndl[4], nuu[4], nBv[4], nCv[4];
            if (pos + 4 < NSP) {
                #pragma unroll
                for (int j = 0; j < 4; j++) {
                    size_t r = base + pos + 4 + j;
                    ndl[j] = __ldg(&delta[r*DI + d]);
                    nuu[j] = __bfloat162float(u[r*DI + d]);
                    nBv[j] = __ldg(&dbc[r*64 + DTR + n]);
                    nCv[j] = __ldg(&dbc[r*64 + DTR + DS + n]);
                }
            }
            float dA[4], dBu[4];
            #pragma unroll
            for (int j = 0; j < 4; j++) {
                dA[j]  = __expf(dl[j] * a);
                dBu[j] = dl[j] * uu[j] * Bv[j];
            }
            float part[4];
            #pragma unroll
            for (int j = 0; j < 4; j++) {
                h = fmaf(h, dA[j], dBu[j]);
                part[j] = h * Cv[j];
            }
            #pragma unroll
            for (int off = 1; off <= 8; off <<= 1)
                #pragma unroll
                for (int j = 0; j < 4; j++)
                    part[j] += __shfl_xor_sync(0xffffffffu, part[j], off);
            if (n == 0) {
                #pragma unroll
                for (int j = 0; j < 4; j++)
                    sbuf[(pos + j) & 63][w*2 + sub] = part[j] + uu[j] * Dd;
            }
            if ((pos & 63) == 60) {
                __syncthreads();
                int p2 = tid >> 1, half = tid & 1;
                size_t r = base + (pos & ~63) + p2;
                float4 v = *reinterpret_cast<float4*>(&sbuf[p2][half*4]);
                uint2 zraw = *reinterpret_cast<const uint2*>(&g_xz_bf[r*XZW + 384 + ycol0 + half*4]);
                float2 z01 = __bfloat1622float2(*reinterpret_cast<const __nv_bfloat162*>(&zraw.x));
                float2 z23 = __bfloat1622float2(*reinterpret_cast<const __nv_bfloat162*>(&zraw.y));
                v.x *= z01.x / (1.f + __expf(-z01.x));
                v.y *= z01.y / (1.f + __expf(-z01.y));
                v.z *= z23.x / (1.f + __expf(-z23.x));
                v.w *= z23.y / (1.f + __expf(-z23.y));
                uint2 pk = make_uint2(packbf(v.x, v.y), packbf(v.z, v.w));
                *reinterpret_cast<uint2*>(&g_y_bf[r*(2*DI) + ycol0 + half*4]) = pk;
                __syncthreads();
            }
            #pragma unroll
            for (int j = 0; j < 4; j++) {
                dl[j] = ndl[j]; uu[j] = nuu[j]; Bv[j] = nBv[j]; Cv[j] = nCv[j];
            }
        }
    } else {
        int b2 = bx - SPATIAL_BLOCKS;
        int seq = b2 / 3;
        int d = (b2 % 3) * 128 + tid;
        int lane = tid & 31;
        int b = seq / NSP, nsp = seq % NSP;
        int base = b * (TT*NSP) + nsp;

        float a[DS];
        #pragma unroll
        for (int q = 0; q < 4; q++)
            *reinterpret_cast<float4*>(&a[q*4]) = *reinterpret_cast<const float4*>(&g_A[1][d*DS + q*4]);
        float Dd = tD[d];
        const float* delta = g_delta[1];
        const bf16*  u     = g_u_bf[1];
        const float* dbc   = g_dbc[1];

        float h[DS];
        #pragma unroll
        for (int q = 0; q < DS; q++) h[q] = 0.f;

        for (int t = 0; t < TT; t++) {
            size_t r = base + (size_t)t * NSP;
            float dl = delta[r*DI + d];
            float uu = __bfloat162float(u[r*DI + d]);
            float bc = dbc[r*64 + DTR + lane];
            float dlu = dl * uu;
            float y = 0.f;
            #pragma unroll
            for (int q = 0; q < DS; q++) {
                float Bn = __shfl_sync(0xffffffffu, bc, q);
                float Cn = __shfl_sync(0xffffffffu, bc, q + 16);
                float dA = __expf(dl * a[q]);
                h[q] = fmaf(h[q], dA, dlu * Bn);
                y = fmaf(h[q], Cn, y);
            }
            float z = __bfloat162float(g_xz_bf[r*XZW + 1152 + d]);
            float g = z / (1.f + __expf(-z));
            g_y_bf[r*(2*DI) + DI + d] = __float2bfloat16((y + uu * Dd) * g);
        }
    }
}

// ---------------- host launcher ----------------
extern "C" void kernel_launch(void* const* d_in, const int* in_sizes, int n_in,
                              void* d_out, int out_size)
{
    const float* x_in   = (const float*)d_in[0];
    const float* n1w    = (const float*)d_in[1];
    const float* n1b    = (const float*)d_in[2];
    const float* s_inw  = (const float*)d_in[3];
    const float* s_cw   = (const float*)d_in[4];
    const float* s_cb   = (const float*)d_in[5];
    const float* s_xpw  = (const float*)d_in[6];
    const float* s_dpw  = (const float*)d_in[7];
    const float* s_dpb  = (const float*)d_in[8];
    const float* s_Alog = (const float*)d_in[9];
    const float* s_D    = (const float*)d_in[10];
    const float* s_outw = (const float*)d_in[11];
    const float* t_inw  = (const float*)d_in[12];
    const float* t_cw   = (const float*)d_in[13];
    const float* t_cb   = (const float*)d_in[14];
    const float* t_xpw  = (const float*)d_in[15];
    const float* t_dpw  = (const float*)d_in[16];
    const float* t_dpb  = (const float*)d_in[17];
    const float* t_Alog = (const float*)d_in[18];
    const float* t_D    = (const float*)d_in[19];
    const float* t_outw = (const float*)d_in[20];
    const float* fw     = (const float*)d_in[21];
    const float* fb     = (const float*)d_in[22];
    const float* n2w    = (const float*)d_in[23];
    const float* n2b    = (const float*)d_in[24];
    const float* w1     = (const float*)d_in[25];
    const float* b1     = (const float*)d_in[26];
    const float* w2     = (const float*)d_in[27];
    const float* b2     = (const float*)d_in[28];
    float* out = (float*)d_out;

    bf16 *p_xn_bf, *p_xz_bf, *p_u_bf, *p_y_bf, *p_h_bf, *p_hid_bf, *p_Win_bf, *p_W12_bf, *p_xpwP_bf, *p_w1_bf, *p_w2_bf;
    float *p_short, *p_x2, *p_dbc;
    cudaGetSymbolAddress((void**)&p_xn_bf, g_xn_bf);
    cudaGetSymbolAddress((void**)&p_short, g_short);
    cudaGetSymbolAddress((void**)&p_xz_bf, g_xz_bf);
    cudaGetSymbolAddress((void**)&p_u_bf,  g_u_bf);
    cudaGetSymbolAddress((void**)&p_dbc,   g_dbc);
    cudaGetSymbolAddress((void**)&p_y_bf,  g_y_bf);
    cudaGetSymbolAddress((void**)&p_x2,    g_x2);
    cudaGetSymbolAddress((void**)&p_h_bf,  g_h_bf);
    cudaGetSymbolAddress((void**)&p_hid_bf,g_hid_bf);
    cudaGetSymbolAddress((void**)&p_Win_bf,g_Win_bf);
    cudaGetSymbolAddress((void**)&p_W12_bf,g_W12_bf);
    cudaGetSymbolAddress((void**)&p_xpwP_bf,g_xpwP_bf);
    cudaGetSymbolAddress((void**)&p_w1_bf, g_w1_bf);
    cudaGetSymbolAddress((void**)&p_w2_bf, g_w2_bf);

    // 0. prep + fold merged
    prepfold_kernel<<<816, 384>>>(s_Alog, t_Alog, s_cw, t_cw, s_dpw, t_dpw,
                                  s_inw, t_inw, s_xpw, t_xpw, w1, w2,
                                  fw, s_outw, t_outw);

    // 1. transpose + LN1
    ln1_kernel<<<dim3(16, 18), 256>>>(x_in, n1w, n1b);

    // 2. merged in_proj GEMM (N=1536, K=192) -> bf16 xz
    bgemm_kernel<<<dim3(XZW/128, TOK/128), 256>>>(p_xn_bf, p_Win_bf, p_xz_bf, nullptr, nullptr, TOK, XZW, CDIM, 16);

    // 3. conv+silu (bf16 -> bf16)
    conv_kernel<<<dim3(TOK/2, 2), 192>>>(s_cb, t_cb);

    // 4. dbc = u @ xpwP^T (N=64, K=384), both mambas via z
    bgemm64_kernel<<<dim3(1, TOK/64, 2), 256>>>(p_u_bf, p_xpwP_bf, p_dbc, nullptr, nullptr, TOK, 64, DI, 8);

    // 5. delta
    delta_kernel<<<dim3(TOK/16, 2), 384>>>(s_dpb, t_dpb);

    // 6. scans
    scan_kernel<<<SPATIAL_BLOCKS + 3456, 128>>>(s_D, t_D);

    // 7. fusion + residual (N=192, K=768)
    bgemm64_kernel<<<dim3(3, TOK/64), 256>>>(p_y_bf, p_W12_bf, p_x2, fb, p_short, TOK, CDIM, 2*DI, 0);

    // 8. LN2 + MLP
    ln2_kernel<<<TOK/4, 128>>>(p_x2, n2w, n2b);
    bgemm_kernel<<<dim3(MLPH/128, TOK/128), 256>>>(p_h_bf, p_w1_bf, p_hid_bf, b1, nullptr, TOK, MLPH, CDIM, 1 | 16);
    bgemm64_kernel<<<dim3(3, TOK/64), 256>>>(p_hid_bf, p_w2_bf, out, b2, p_x2, TOK, CDIM, MLPH, 4);
}

// round 16
// speedup vs baseline: 3.9551x; 1.0110x over previous
#include <cuda_runtime.h>
#include <cuda_bf16.h>
#include <math.h>
#include <stdint.h>

// ---------------- problem constants ----------------
#define BQ    2
#define TT    8
#define CDIM  192
#define NSP   576
#define TOK   9216
#define DI    384
#define DS    16
#define DTR   12
#define MLPH  768
#define XZW   1536

typedef __nv_bfloat16 bf16;

// ---------------- scratch ----------------
__device__ bf16  g_xn_bf[TOK*CDIM];
__device__ float g_short[TOK*CDIM];
__device__ bf16  g_xz_bf[TOK*XZW];
__device__ bf16  g_u_bf[2][TOK*DI];
__device__ float g_delta[2][TOK*DI];
__device__ float g_dbc[2][TOK*64];
__device__ bf16  g_y_bf[TOK*2*DI];
__device__ float g_x2[TOK*CDIM];
__device__ bf16  g_h_bf[TOK*CDIM];
__device__ bf16  g_hid_bf[TOK*MLPH];
__device__ bf16  g_Win_bf[XZW*CDIM];
__device__ bf16  g_W12_bf[CDIM*2*DI];
__device__ bf16  g_xpwP_bf[2][64*DI];
__device__ bf16  g_w1_bf[MLPH*CDIM];
__device__ bf16  g_w2_bf[CDIM*MLPH];
__device__ float g_A[2][DI*DS];
__device__ float g_cwT[2][4*DI];
__device__ float g_dpwT[2][DTR*DI];

// ---------------- helpers ----------------
__device__ __forceinline__ uint32_t packbf(float lo, float hi) {
    uint32_t r;
    asm("cvt.rn.bf16x2.f32 %0, %1, %2;" : "=r"(r) : "f"(hi), "f"(lo));
    return r;
}
__device__ __forceinline__ void mma_bf16(float c[4], const uint32_t a[4], const uint32_t b[2]) {
    asm("mma.sync.aligned.m16n8k16.row.col.f32.bf16.bf16.f32 "
        "{%0,%1,%2,%3}, {%4,%5,%6,%7}, {%8,%9}, {%0,%1,%2,%3};"
        : "+f"(c[0]), "+f"(c[1]), "+f"(c[2]), "+f"(c[3])
        : "r"(a[0]), "r"(a[1]), "r"(a[2]), "r"(a[3]), "r"(b[0]), "r"(b[1]));
}
__device__ __forceinline__ void ldsm_x4(uint32_t& r0, uint32_t& r1, uint32_t& r2, uint32_t& r3,
                                        uint32_t addr) {
    asm volatile("ldmatrix.sync.aligned.m8n8.x4.shared.b16 {%0,%1,%2,%3}, [%4];"
                 : "=r"(r0), "=r"(r1), "=r"(r2), "=r"(r3) : "r"(addr));
}
__device__ __forceinline__ uint32_t smem_u32(const void* p) {
    return (uint32_t)__cvta_generic_to_shared(p);
}
__device__ __forceinline__ void cpa16(uint32_t dst, const void* src) {
    asm volatile("cp.async.ca.shared.global [%0], [%1], 16;" :: "r"(dst), "l"(src));
}
#define CP_COMMIT() asm volatile("cp.async.commit_group;" ::: "memory")
#define CP_WAIT1()  asm volatile("cp.async.wait_group 1;" ::: "memory")
#define GRID_SYNC() cudaGridDependencySynchronize()

// ---------------- prep + fold (merged) ----------------
__global__ __launch_bounds__(384) void prepfold_kernel(
    const float* __restrict__ sAlog, const float* __restrict__ tAlog,
    const float* __restrict__ scw, const float* __restrict__ tcw,
    const float* __restrict__ sdpw, const float* __restrict__ tdpw,
    const float* __restrict__ sinw, const float* __restrict__ tinw,
    const float* __restrict__ sxpw, const float* __restrict__ txpw,
    const float* __restrict__ w1, const float* __restrict__ w2,
    const float* __restrict__ fw,
    const float* __restrict__ soutw, const float* __restrict__ toutw)
{
    GRID_SYNC();
    int tid = threadIdx.x;
    if (blockIdx.x < 768) {
        int i = blockIdx.x * 384 + tid;
        if (i < 2*DI*DS) {
            int m = i / (DI*DS), j = i % (DI*DS);
            g_A[m][j] = -expf(m ? tAlog[j] : sAlog[j]);
        }
        if (i < 2*4*DI) {
            int m = i / (4*DI), rem = i % (4*DI);
            int k = rem / DI, d = rem % DI;
            g_cwT[m][k*DI + d] = (m ? tcw : scw)[d*4 + k];
        }
        if (i < 2*DTR*DI) {
            int m = i / (DTR*DI), rem = i % (DTR*DI);
            int rr = rem / DI, d = rem % DI;
            g_dpwT[m][rr*DI + d] = (m ? tdpw : sdpw)[d*DTR + rr];
        }
        if (i < 2*64*DI) {
            int m = i / (64*DI), rem = i % (64*DI);
            int row = rem / DI;
            g_xpwP_bf[m][rem] = __float2bfloat16(
                (row < DTR + 2*DS) ? (m ? txpw : sxpw)[rem] : 0.f);
        }
        if (i < XZW*CDIM) {
            int row = i / CDIM;
            g_Win_bf[i] = __float2bfloat16((row < 768) ? sinw[i] : tinw[i - 768*CDIM]);
        }
        if (i < MLPH*CDIM) g_w1_bf[i] = __float2bfloat16(w1[i]);
        if (i < CDIM*MLPH) g_w2_bf[i] = __float2bfloat16(w2[i]);
    } else {
        __shared__ float fwS[8][192];
        int bx = blockIdx.x - 768;
        int m  = bx / 24;
        int c0 = (bx % 24) * 8;
        const float* ow = m ? toutw : soutw;
        for (int i = tid; i < 8*192; i += 384) {
            int c = i / 192, cp = i % 192;
            fwS[c][cp] = fw[(size_t)(c0 + c)*(2*CDIM) + m*CDIM + cp];
        }
        __syncthreads();
        float acc[8] = {0,0,0,0,0,0,0,0};
        #pragma unroll 4
        for (int cp = 0; cp < 192; cp++) {
            float owv = ow[(size_t)cp*DI + tid];
            #pragma unroll
            for (int c = 0; c < 8; c++) acc[c] = fmaf(fwS[c][cp], owv, acc[c]);
        }
        #pragma unroll
        for (int c = 0; c < 8; c++)
            g_W12_bf[(size_t)(c0 + c)*(2*DI) + m*DI + tid] = __float2bfloat16(acc[c]);
    }
}

// ---------------- LN1 ----------------
__global__ __launch_bounds__(256) void ln1_kernel(const float* __restrict__ src,
                                                  const float* __restrict__ w, const float* __restrict__ b)
{
    GRID_SYNC();
    __shared__ float s[CDIM][33];
    int bt = blockIdx.x;
    int n0 = blockIdx.y * 32;
    int tid = threadIdx.x;
    #pragma unroll
    for (int i = 0; i < 24; i++) {
        int idx = tid + 256*i;
        int c = idx >> 5, nl = idx & 31;
        s[c][nl] = src[((size_t)bt*CDIM + c)*NSP + n0 + nl];
    }
    __syncthreads();
    int warp = tid >> 5, lane = tid & 31;
    for (int jj = 0; jj < 4; jj++) {
        int tt = warp + 8*jj;
        float v[3][2];
        #pragma unroll
        for (int q = 0; q < 3; q++) {
            int c = 2*lane + 64*q;
            v[q][0] = s[c][tt];
            v[q][1] = s[c+1][tt];
        }
        float sum = 0.f;
        #pragma unroll
        for (int q = 0; q < 3; q++) sum += v[q][0] + v[q][1];
        #pragma unroll
        for (int o = 16; o > 0; o >>= 1) sum += __shfl_xor_sync(0xffffffffu, sum, o);
        float mean = sum * (1.f/CDIM);
        float qv = 0.f;
        #pragma unroll
        for (int q = 0; q < 3; q++) {
            float d0 = v[q][0]-mean, d1 = v[q][1]-mean;
            qv += d0*d0 + d1*d1;
        }
        #pragma unroll
        for (int o = 16; o > 0; o >>= 1) qv += __shfl_xor_sync(0xffffffffu, qv, o);
        float rstd = rsqrtf(qv * (1.f/CDIM) + 1e-5f);
        size_t tok = (size_t)bt*NSP + n0 + tt;
        #pragma unroll
        for (int q = 0; q < 3; q++) {
            int c = 2*lane + 64*q;
            float o0 = (v[q][0]-mean)*rstd*w[c]   + b[c];
            float o1 = (v[q][1]-mean)*rstd*w[c+1] + b[c+1];
            *reinterpret_cast<uint32_t*>(&g_xn_bf[tok*CDIM + c]) = packbf(o0, o1);
            *reinterpret_cast<float2*>(&g_short[tok*CDIM + c]) = make_float2(v[q][0], v[q][1]);
        }
    }
}

// ---------------- LN2 ----------------
__global__ void ln2_kernel(const float* __restrict__ src,
                           const float* __restrict__ w, const float* __restrict__ b)
{
    GRID_SYNC();
    int tok  = blockIdx.x * 4 + (threadIdx.x >> 5);
    int lane = threadIdx.x & 31;
    const float* base = src + (size_t)tok * CDIM;
    float v[3][2];
    #pragma unroll
    for (int q = 0; q < 3; q++) {
        float2 t = *reinterpret_cast<const float2*>(&base[2*lane + 64*q]);
        v[q][0] = t.x; v[q][1] = t.y;
    }
    float s = 0.f;
    #pragma unroll
    for (int q = 0; q < 3; q++) s += v[q][0] + v[q][1];
    #pragma unroll
    for (int o = 16; o > 0; o >>= 1) s += __shfl_xor_sync(0xffffffffu, s, o);
    float mean = s * (1.f / CDIM);
    float qv = 0.f;
    #pragma unroll
    for (int q = 0; q < 3; q++) {
        float d0 = v[q][0]-mean, d1 = v[q][1]-mean;
        qv += d0*d0 + d1*d1;
    }
    #pragma unroll
    for (int o = 16; o > 0; o >>= 1) qv += __shfl_xor_sync(0xffffffffu, qv, o);
    float rstd = rsqrtf(qv * (1.f / CDIM) + 1e-5f);
    #pragma unroll
    for (int q = 0; q < 3; q++) {
        int c = 2*lane + 64*q;
        float o0 = (v[q][0]-mean)*rstd*w[c]   + b[c];
        float o1 = (v[q][1]-mean)*rstd*w[c+1] + b[c+1];
        *reinterpret_cast<uint32_t*>(&g_h_bf[(size_t)tok*CDIM + c]) = packbf(o0, o1);
    }
}

// ---------------- bgemm: bf16 GEMM, 128x128 block, Ktile=32, 3-stage cp.async -----------
// flags: bit0 gelu | bit4 bf16 C store
#define ASTRIDE 10240
__global__ __launch_bounds__(256, 2) void bgemm_kernel(
    const bf16* __restrict__ A, const bf16* __restrict__ B, void* __restrict__ Cv,
    const float* __restrict__ bias, const float* __restrict__ addend,
    int M, int N, int K, int flags)
{
    GRID_SYNC();
    __shared__ uint32_t As[3][128][20];
    __shared__ uint32_t Bs[3][128][20];
    int tid = threadIdx.x;
    int m0 = blockIdx.y * 128, n0 = blockIdx.x * 128;

    int lrow = tid >> 1;
    int lk   = (tid & 1) * 16;
    int kb   = (tid & 1) * 8;
    const bf16* Ag = A + (size_t)(m0 + lrow) * K + lk;
    const bf16* Bg = B + (size_t)(n0 + lrow) * K + lk;
    uint32_t aDst0 = smem_u32(&As[0][lrow][kb]);
    uint32_t bDst0 = smem_u32(&Bs[0][lrow][kb]);

    int ntiles = K >> 5;
    #pragma unroll
    for (int s = 0; s < 2; s++) {
        cpa16(aDst0 + s*ASTRIDE,      Ag + s*32);
        cpa16(aDst0 + s*ASTRIDE + 16, Ag + s*32 + 8);
        cpa16(bDst0 + s*ASTRIDE,      Bg + s*32);
        cpa16(bDst0 + s*ASTRIDE + 16, Bg + s*32 + 8);
        CP_COMMIT();
    }

    int wid = tid >> 5, lane = tid & 31;
    int wm = wid >> 1, wn = wid & 1;
    int lr = lane >> 2, lc = lane & 3;

    uint32_t aAddr0[2], bAddr0[4];
    {
        int ar = (lane & 15);
        int ac = (lane >> 4) * 4;
        int br = ((lane >> 4) & 1) * 8 + (lane & 7);
        int bc = ((lane >> 3) & 1) * 4;
        #pragma unroll
        for (int mt = 0; mt < 2; mt++)
            aAddr0[mt] = smem_u32(&As[0][wm*32 + mt*16 + ar][ac]);
        #pragma unroll
        for (int np = 0; np < 4; np++)
            bAddr0[np] = smem_u32(&Bs[0][wn*64 + np*16 + br][bc]);
    }

    float acc[2][8][4];
    #pragma unroll
    for (int mt = 0; mt < 2; mt++)
        #pragma unroll
        for (int nt = 0; nt < 8; nt++)
            #pragma unroll
            for (int j = 0; j < 4; j++) acc[mt][nt][j] = 0.f;

    for (int k = 0; k < ntiles; k++) {
        CP_WAIT1();
        __syncthreads();
        int buf = (k % 3) * ASTRIDE;
        #pragma unroll
        for (int ks = 0; ks < 2; ks++) {
            int off = buf + ks*32;
            uint32_t afr[2][4];
            #pragma unroll
            for (int mt = 0; mt < 2; mt++)
                ldsm_x4(afr[mt][0], afr[mt][1], afr[mt][2], afr[mt][3], aAddr0[mt] + off);
            uint32_t bfr[8][2];
            #pragma unroll
            for (int np = 0; np < 4; np++)
                ldsm_x4(bfr[2*np][0], bfr[2*np][1], bfr[2*np+1][0], bfr[2*np+1][1], bAddr0[np] + off);
            #pragma unroll
            for (int mt = 0; mt < 2; mt++)
                #pragma unroll
                for (int nt = 0; nt < 8; nt++)
                    mma_bf16(acc[mt][nt], afr[mt], bfr[nt]);
        }
        int nk = k + 2;
        if (nk < ntiles) {
            int nb = (nk % 3) * ASTRIDE;
            cpa16(aDst0 + nb,      Ag + nk*32);
            cpa16(aDst0 + nb + 16, Ag + nk*32 + 8);
            cpa16(bDst0 + nb,      Bg + nk*32);
            cpa16(bDst0 + nb + 16, Bg + nk*32 + 8);
        }
        CP_COMMIT();
    }

    float* C = (float*)Cv;
    bf16*  Cb = (bf16*)Cv;
    #pragma unroll
    for (int nt = 0; nt < 8; nt++) {
        int col = n0 + wn*64 + nt*8 + lc*2;
        float b0 = 0.f, b1 = 0.f;
        if (bias) { b0 = bias[col]; b1 = bias[col+1]; }
        #pragma unroll
        for (int mt = 0; mt < 2; mt++) {
            int r0 = m0 + wm*32 + mt*16 + lr;
            int r1 = r0 + 8;
            float v00 = acc[mt][nt][0] + b0;
            float v01 = acc[mt][nt][1] + b1;
            float v10 = acc[mt][nt][2] + b0;
            float v11 = acc[mt][nt][3] + b1;
            if (addend) {
                const float* ad0 = addend + (size_t)r0*N + col;
                const float* ad1 = addend + (size_t)r1*N + col;
                v00 += ad0[0]; v01 += ad0[1];
                v10 += ad1[0]; v11 += ad1[1];
            }
            if (flags & 1) {
                v00 = 0.5f*v00*(1.f + erff(v00*0.70710678118654752f));
                v01 = 0.5f*v01*(1.f + erff(v01*0.70710678118654752f));
                v10 = 0.5f*v10*(1.f + erff(v10*0.70710678118654752f));
                v11 = 0.5f*v11*(1.f + erff(v11*0.70710678118654752f));
            }
            if (flags & 16) {
                *reinterpret_cast<uint32_t*>(&Cb[(size_t)r0*N + col]) = packbf(v00, v01);
                *reinterpret_cast<uint32_t*>(&Cb[(size_t)r1*N + col]) = packbf(v10, v11);
            } else {
                *reinterpret_cast<float2*>(&C[(size_t)r0*N + col]) = make_float2(v00, v01);
                *reinterpret_cast<float2*>(&C[(size_t)r1*N + col]) = make_float2(v10, v11);
            }
        }
    }
}

// ---------------- bgemm64: bf16 GEMM, 64x64 block, Ktile=32, 3-stage --------------------
// flags: bit0 gelu | bit2 transposed store | bit3 z-split
#define STRIDE64 5120
__global__ __launch_bounds__(256, 3) void bgemm64_kernel(
    const bf16* __restrict__ A, const bf16* __restrict__ B, float* __restrict__ C,
    const float* __restrict__ bias, const float* __restrict__ addend,
    int M, int N, int K, int flags)
{
    GRID_SYNC();
    __shared__ uint32_t As[3][64][20];
    __shared__ uint32_t Bs[3][64][20];
    int tid = threadIdx.x;
    int m0 = blockIdx.y * 64, n0 = blockIdx.x * 64;
    if (flags & 8) {
        int z = blockIdx.z;
        A += (size_t)z * M * K;
        B += (size_t)z * N * K;
        C += (size_t)z * M * N;
    }

    int lrow = tid >> 2;
    int lk   = (tid & 3) * 8;
    int kb   = (tid & 3) * 4;
    const bf16* Ag = A + (size_t)(m0 + lrow) * K + lk;
    const bf16* Bg = B + (size_t)(n0 + lrow) * K + lk;
    uint32_t aDst0 = smem_u32(&As[0][lrow][kb]);
    uint32_t bDst0 = smem_u32(&Bs[0][lrow][kb]);

    int ntiles = K >> 5;
    #pragma unroll
    for (int s = 0; s < 2; s++) {
        cpa16(aDst0 + s*STRIDE64, Ag + s*32);
        cpa16(bDst0 + s*STRIDE64, Bg + s*32);
        CP_COMMIT();
    }

    int wid = tid >> 5, lane = tid & 31;
    int wm = wid >> 1, wn = wid & 1;
    int lr = lane >> 2, lc = lane & 3;

    uint32_t aAddr0, bAddr0[2];
    {
        int ar = (lane & 15);
        int ac = (lane >> 4) * 4;
        int br = ((lane >> 4) & 1) * 8 + (lane & 7);
        int bc = ((lane >> 3) & 1) * 4;
        aAddr0 = smem_u32(&As[0][wm*16 + ar][ac]);
        #pragma unroll
        for (int np = 0; np < 2; np++)
            bAddr0[np] = smem_u32(&Bs[0][wn*32 + np*16 + br][bc]);
    }

    float acc[4][4];
    #pragma unroll
    for (int nt = 0; nt < 4; nt++)
        #pragma unroll
        for (int j = 0; j < 4; j++) acc[nt][j] = 0.f;

    for (int k = 0; k < ntiles; k++) {
        CP_WAIT1();
        __syncthreads();
        int buf = (k % 3) * STRIDE64;
        #pragma unroll
        for (int ks = 0; ks < 2; ks++) {
            int off = buf + ks*32;
            uint32_t afr[4];
            ldsm_x4(afr[0], afr[1], afr[2], afr[3], aAddr0 + off);
            uint32_t bfr[4][2];
            #pragma unroll
            for (int np = 0; np < 2; np++)
                ldsm_x4(bfr[2*np][0], bfr[2*np][1], bfr[2*np+1][0], bfr[2*np+1][1], bAddr0[np] + off);
            #pragma unroll
            for (int nt = 0; nt < 4; nt++)
                mma_bf16(acc[nt], afr, bfr[nt]);
        }
        int nk = k + 2;
        if (nk < ntiles) {
            int nb = (nk % 3) * STRIDE64;
            cpa16(aDst0 + nb, Ag + nk*32);
            cpa16(bDst0 + nb, Bg + nk*32);
        }
        CP_COMMIT();
    }

    #pragma unroll
    for (int nt = 0; nt < 4; nt++) {
        int col = n0 + wn*32 + nt*8 + lc*2;
        float b0 = 0.f, b1 = 0.f;
        if (bias) { b0 = bias[col]; b1 = bias[col+1]; }
        int r0 = m0 + wm*16 + lr;
        int r1 = r0 + 8;
        float v00 = acc[nt][0] + b0;
        float v01 = acc[nt][1] + b1;
        float v10 = acc[nt][2] + b0;
        float v11 = acc[nt][3] + b1;
        if (addend) {
            const float* ad0 = addend + (size_t)r0*N + col;
            const float* ad1 = addend + (size_t)r1*N + col;
            v00 += ad0[0]; v01 += ad0[1];
            v10 += ad1[0]; v11 += ad1[1];
        }
        if (flags & 1) {
            v00 = 0.5f*v00*(1.f + erff(v00*0.70710678118654752f));
            v01 = 0.5f*v01*(1.f + erff(v01*0.70710678118654752f));
            v10 = 0.5f*v10*(1.f + erff(v10*0.70710678118654752f));
            v11 = 0.5f*v11*(1.f + erff(v11*0.70710678118654752f));
        }
        if (flags & 4) {
            int bt0 = r0 / NSP, nn0 = r0 % NSP;
            int bt1 = r1 / NSP, nn1 = r1 % NSP;
            C[((size_t)bt0*CDIM + col  )*NSP + nn0] = v00;
            C[((size_t)bt0*CDIM + col+1)*NSP + nn0] = v01;
            C[((size_t)bt1*CDIM + col  )*NSP + nn1] = v10;
            C[((size_t)bt1*CDIM + col+1)*NSP + nn1] = v11;
        } else {
            *reinterpret_cast<float2*>(&C[(size_t)r0*N + col]) = make_float2(v00, v01);
            *reinterpret_cast<float2*>(&C[(size_t)r1*N + col]) = make_float2(v10, v11);
        }
    }
}

// ---------------- conv4 depthwise + silu ----------------
__global__ __launch_bounds__(192) void conv_kernel(const float* __restrict__ scb,
                                                   const float* __restrict__ tcb)
{
    GRID_SYNC();
    int m = blockIdx.y;
    int tid = threadIdx.x;
    int rl = tid / 96, v = tid % 96;
    int r = blockIdx.x * 2 + rl;
    int pos  = m ? ((r / NSP) & (TT-1)) : (r % NSP);
    int strd = m ? NSP : 1;
    const float* cb = m ? tcb : scb;
    float4 acc = *reinterpret_cast<const float4*>(&cb[4*v]);
    #pragma unroll
    for (int k = 0; k < 4; k++) {
        if (pos - 3 + k >= 0) {
            const bf16* xp = &g_xz_bf[(size_t)(r - (3-k)*strd)*XZW + m*768 + 4*v];
            uint2 raw = *reinterpret_cast<const uint2*>(xp);
            float2 x01 = __bfloat1622float2(*reinterpret_cast<const __nv_bfloat162*>(&raw.x));
            float2 x23 = __bfloat1622float2(*reinterpret_cast<const __nv_bfloat162*>(&raw.y));
            float4 cw = *reinterpret_cast<const float4*>(&g_cwT[m][k*DI + 4*v]);
            acc.x = fmaf(cw.x, x01.x, acc.x);
            acc.y = fmaf(cw.y, x01.y, acc.y);
            acc.z = fmaf(cw.z, x23.x, acc.z);
            acc.w = fmaf(cw.w, x23.y, acc.w);
        }
    }
    acc.x = acc.x / (1.f + __expf(-acc.x));
    acc.y = acc.y / (1.f + __expf(-acc.y));
    acc.z = acc.z / (1.f + __expf(-acc.z));
    acc.w = acc.w / (1.f + __expf(-acc.w));
    uint2 pk = make_uint2(packbf(acc.x, acc.y), packbf(acc.z, acc.w));
    *reinterpret_cast<uint2*>(&g_u_bf[m][(size_t)r*DI + 4*v]) = pk;
}

// ---------------- delta ----------------
__global__ __launch_bounds__(384) void delta_kernel(const float* __restrict__ sdpb,
                                                    const float* __restrict__ tdpb)
{
    GRID_SYNC();
    __shared__ float sw[DTR][DI];
    __shared__ float sdbc[16][DTR];
    int m = blockIdx.y;
    int r0 = blockIdx.x * 16;
    int d = threadIdx.x;
    const float* dpb = m ? tdpb : sdpb;
    #pragma unroll
    for (int rr = 0; rr < DTR; rr++)
        sw[rr][d] = g_dpwT[m][rr*DI + d];
    if (d < 16*DTR) {
        int t = d / DTR, c = d % DTR;
        sdbc[t][c] = g_dbc[m][(size_t)(r0 + t)*64 + c];
    }
    __syncthreads();
    float base = dpb[d];
    #pragma unroll 4
    for (int t = 0; t < 16; t++) {
        float acc = base;
        #pragma unroll
        for (int rr = 0; rr < DTR; rr++)
            acc = fmaf(sdbc[t][rr], sw[rr][d], acc);
        g_delta[m][(size_t)(r0 + t)*DI + d] = (acc > 15.f) ? acc : log1pf(__expf(acc));
    }
}

// ---------------- merged scans ----------------
#define SPATIAL_BLOCKS 768
__global__ __launch_bounds__(128) void scan_kernel(const float* __restrict__ sD,
                                                   const float* __restrict__ tD)
{
    GRID_SYNC();
    int bx = blockIdx.x;
    int tid = threadIdx.x;

    if (bx < SPATIAL_BLOCKS) {
        __shared__ float sbuf[64][8];
        int s   = bx / 48;
        int dpg = bx % 48;
        int w = tid >> 5, lane = tid & 31;
        int sub = lane >> 4, n = lane & 15;
        int d = dpg*8 + w*2 + sub;
        int ycol0 = dpg*8;

        float a  = g_A[0][d*DS + n];
        float Dd = sD[d];
        const float* delta = g_delta[0];
        const bf16*  u     = g_u_bf[0];
        const float* dbc   = g_dbc[0];
        int base = s * NSP;

        float dl[4], uu[4], Bv[4], Cv[4];
        #pragma unroll
        for (int j = 0; j < 4; j++) {
            size_t r = base + j;
            dl[j] = __ldg(&delta[r*DI + d]);
            uu[j] = __bfloat162float(u[r*DI + d]);
            Bv[j] = __ldg(&dbc[r*64 + DTR + n]);
            Cv[j] = __ldg(&dbc[r*64 + DTR + DS + n]);
        }

        float h = 0.f;
        for (int pos = 0; pos < NSP; pos += 4) {
            float ndl[4], nuu[4], nBv[4], nCv[4];
            if (pos + 4 < NSP) {
                #pragma unroll
                for (int j = 0; j < 4; j++) {
                    size_t r = base + pos + 4 + j;
                    ndl[j] = __ldg(&delta[r*DI + d]);
                    nuu[j] = __bfloat162float(u[r*DI + d]);
                    nBv[j] = __ldg(&dbc[r*64 + DTR + n]);
                    nCv[j] = __ldg(&dbc[r*64 + DTR + DS + n]);
                }
            }
            float dA[4], dBu[4];
            #pragma unroll
            for (int j = 0; j < 4; j++) {
                dA[j]  = __expf(dl[j] * a);
                dBu[j] = dl[j] * uu[j] * Bv[j];
            }
            float part[4];
            #pragma unroll
            for (int j = 0; j < 4; j++) {
                h = fmaf(h, dA[j], dBu[j]);
                part[j] = h * Cv[j];
            }
            #pragma unroll
            for (int off = 1; off <= 8; off <<= 1)
                #pragma unroll
                for (int j = 0; j < 4; j++)
                    part[j] += __shfl_xor_sync(0xffffffffu, part[j], off);
            if (n == 0) {
                #pragma unroll
                for (int j = 0; j < 4; j++)
                    sbuf[(pos + j) & 63][w*2 + sub] = part[j] + uu[j] * Dd;
            }
            if ((pos & 63) == 60) {
                __syncthreads();
                int p2 = tid >> 1, half = tid & 1;
                size_t r = base + (pos & ~63) + p2;
                float4 v = *reinterpret_cast<float4*>(&sbuf[p2][half*4]);
                uint2 zraw = *reinterpret_cast<const uint2*>(&g_xz_bf[r*XZW + 384 + ycol0 + half*4]);
                float2 z01 = __bfloat1622float2(*reinterpret_cast<const __nv_bfloat162*>(&zraw.x));
                float2 z23 = __bfloat1622float2(*reinterpret_cast<const __nv_bfloat162*>(&zraw.y));
                v.x *= z01.x / (1.f + __expf(-z01.x));
                v.y *= z01.y / (1.f + __expf(-z01.y));
                v.z *= z23.x / (1.f + __expf(-z23.x));
                v.w *= z23.y / (1.f + __expf(-z23.y));
                uint2 pk = make_uint2(packbf(v.x, v.y), packbf(v.z, v.w));
                *reinterpret_cast<uint2*>(&g_y_bf[r*(2*DI) + ycol0 + half*4]) = pk;
                __syncthreads();
            }
            #pragma unroll
            for (int j = 0; j < 4; j++) {
                dl[j] = ndl[j]; uu[j] = nuu[j]; Bv[j] = nBv[j]; Cv[j] = nCv[j];
            }
        }
    } else {
        int b2 = bx - SPATIAL_BLOCKS;
        int seq = b2 / 3;
        int d = (b2 % 3) * 128 + tid;
        int lane = tid & 31;
        int b = seq / NSP, nsp = seq % NSP;
        int base = b * (TT*NSP) + nsp;

        float a[DS];
        #pragma unroll
        for (int q = 0; q < 4; q++)
            *reinterpret_cast<float4*>(&a[q*4]) = *reinterpret_cast<const float4*>(&g_A[1][d*DS + q*4]);
        float Dd = tD[d];
        const float* delta = g_delta[1];
        const bf16*  u     = g_u_bf[1];
        const float* dbc   = g_dbc[1];

        float h[DS];
        #pragma unroll
        for (int q = 0; q < DS; q++) h[q] = 0.f;

        for (int t = 0; t < TT; t++) {
            size_t r = base + (size_t)t * NSP;
            float dl = delta[r*DI + d];
            float uu = __bfloat162float(u[r*DI + d]);
            float bc = dbc[r*64 + DTR + lane];
            float dlu = dl * uu;
            float y = 0.f;
            #pragma unroll
            for (int q = 0; q < DS; q++) {
                float Bn = __shfl_sync(0xffffffffu, bc, q);
                float Cn = __shfl_sync(0xffffffffu, bc, q + 16);
                float dA = __expf(dl * a[q]);
                h[q] = fmaf(h[q], dA, dlu * Bn);
                y = fmaf(h[q], Cn, y);
            }
            float z = __bfloat162float(g_xz_bf[r*XZW + 1152 + d]);
            float g = z / (1.f + __expf(-z));
            g_y_bf[r*(2*DI) + DI + d] = __float2bfloat16((y + uu * Dd) * g);
        }
    }
}

// ---------------- PDL launch helper ----------------
template <typename F, typename... Args>
static inline void pdl_launch(dim3 grid, dim3 block, F func, Args... args)
{
    cudaLaunchConfig_t cfg = {};
    cfg.gridDim = grid;
    cfg.blockDim = block;
    cfg.dynamicSmemBytes = 0;
    cfg.stream = 0;
    cudaLaunchAttribute at[1];
    at[0].id = cudaLaunchAttributeProgrammaticStreamSerialization;
    at[0].val.programmaticStreamSerializationAllowed = 1;
    cfg.attrs = at;
    cfg.numAttrs = 1;
    cudaLaunchKernelEx(&cfg, func, args...);
}

// ---------------- host launcher ----------------
extern "C" void kernel_launch(void* const* d_in, const int* in_sizes, int n_in,
                              void* d_out, int out_size)
{
    const float* x_in   = (const float*)d_in[0];
    const float* n1w    = (const float*)d_in[1];
    const float* n1b    = (const float*)d_in[2];
    const float* s_inw  = (const float*)d_in[3];
    const float* s_cw   = (const float*)d_in[4];
    const float* s_cb   = (const float*)d_in[5];
    const float* s_xpw  = (const float*)d_in[6];
    const float* s_dpw  = (const float*)d_in[7];
    const float* s_dpb  = (const float*)d_in[8];
    const float* s_Alog = (const float*)d_in[9];
    const float* s_D    = (const float*)d_in[10];
    const float* s_outw = (const float*)d_in[11];
    const float* t_inw  = (const float*)d_in[12];
    const float* t_cw   = (const float*)d_in[13];
    const float* t_cb   = (const float*)d_in[14];
    const float* t_xpw  = (const float*)d_in[15];
    const float* t_dpw  = (const float*)d_in[16];
    const float* t_dpb  = (const float*)d_in[17];
    const float* t_Alog = (const float*)d_in[18];
    const float* t_D    = (const float*)d_in[19];
    const float* t_outw = (const float*)d_in[20];
    const float* fw     = (const float*)d_in[21];
    const float* fb     = (const float*)d_in[22];
    const float* n2w    = (const float*)d_in[23];
    const float* n2b    = (const float*)d_in[24];
    const float* w1     = (const float*)d_in[25];
    const float* b1     = (const float*)d_in[26];
    const float* w2     = (const float*)d_in[27];
    const float* b2     = (const float*)d_in[28];
    float* out = (float*)d_out;

    bf16 *p_xn_bf, *p_xz_bf, *p_u_bf, *p_y_bf, *p_h_bf, *p_hid_bf, *p_Win_bf, *p_W12_bf, *p_xpwP_bf, *p_w1_bf, *p_w2_bf;
    float *p_short, *p_x2, *p_dbc;
    cudaGetSymbolAddress((void**)&p_xn_bf, g_xn_bf);
    cudaGetSymbolAddress((void**)&p_short, g_short);
    cudaGetSymbolAddress((void**)&p_xz_bf, g_xz_bf);
    cudaGetSymbolAddress((void**)&p_u_bf,  g_u_bf);
    cudaGetSymbolAddress((void**)&p_dbc,   g_dbc);
    cudaGetSymbolAddress((void**)&p_y_bf,  g_y_bf);
    cudaGetSymbolAddress((void**)&p_x2,    g_x2);
    cudaGetSymbolAddress((void**)&p_h_bf,  g_h_bf);
    cudaGetSymbolAddress((void**)&p_hid_bf,g_hid_bf);
    cudaGetSymbolAddress((void**)&p_Win_bf,g_Win_bf);
    cudaGetSymbolAddress((void**)&p_W12_bf,g_W12_bf);
    cudaGetSymbolAddress((void**)&p_xpwP_bf,g_xpwP_bf);
    cudaGetSymbolAddress((void**)&p_w1_bf, g_w1_bf);
    cudaGetSymbolAddress((void**)&p_w2_bf, g_w2_bf);

    // 0. prep + fold merged
    pdl_launch(dim3(816), dim3(384), prepfold_kernel,
               s_Alog, t_Alog, s_cw, t_cw, s_dpw, t_dpw,
               s_inw, t_inw, s_xpw, t_xpw, w1, w2, fw, s_outw, t_outw);

    // 1. transpose + LN1
    pdl_launch(dim3(16, 18), dim3(256), ln1_kernel, x_in, n1w, n1b);

    // 2. merged in_proj GEMM (N=1536, K=192) -> bf16 xz
    pdl_launch(dim3(XZW/128, TOK/128), dim3(256), bgemm_kernel,
               (const bf16*)p_xn_bf, (const bf16*)p_Win_bf, (void*)p_xz_bf,
               (const float*)nullptr, (const float*)nullptr, TOK, XZW, CDIM, 16);

    // 3. conv+silu
    pdl_launch(dim3(TOK/2, 2), dim3(192), conv_kernel, s_cb, t_cb);

    // 4. dbc = u @ xpwP^T (N=64, K=384), both mambas via z
    pdl_launch(dim3(1, TOK/64, 2), dim3(256), bgemm64_kernel,
               (const bf16*)p_u_bf, (const bf16*)p_xpwP_bf, p_dbc,
               (const float*)nullptr, (const float*)nullptr, TOK, 64, DI, 8);

    // 5. delta
    pdl_launch(dim3(TOK/16, 2), dim3(384), delta_kernel, s_dpb, t_dpb);

    // 6. scans
    pdl_launch(dim3(SPATIAL_BLOCKS + 3456), dim3(128), scan_kernel, s_D, t_D);

    // 7. fusion + residual (N=192, K=768)
    pdl_launch(dim3(3, TOK/64), dim3(256), bgemm64_kernel,
               (const bf16*)p_y_bf, (const bf16*)p_W12_bf, p_x2,
               fb, (const float*)p_short, TOK, CDIM, 2*DI, 0);

    // 8. LN2 + MLP
    pdl_launch(dim3(TOK/4), dim3(128), ln2_kernel, (const float*)p_x2, n2w, n2b);
    pdl_launch(dim3(MLPH/128, TOK/128), dim3(256), bgemm_kernel,
               (const bf16*)p_h_bf, (const bf16*)p_w1_bf, (void*)p_hid_bf,
               b1, (const float*)nullptr, TOK, MLPH, CDIM, 1 | 16);
    pdl_launch(dim3(3, TOK/64), dim3(256), bgemm64_kernel,
               (const bf16*)p_hid_bf, (const bf16*)p_w2_bf, out,
               b2, (const float*)p_x2, TOK, CDIM, MLPH, 4);
}